// round 2
// baseline (speedup 1.0000x reference)
#include <cuda_runtime.h>
#include <math.h>

#define NN   512
#define CINC 64
#define HIDC 128
#define HWSZ 1024
#define HH   32
#define WW   32
#define HEADS 4
#define NE   16384
#define TOTE (NE + NN)

// ---------------- packed f32x2 helpers (sm_100 FFMA2) ----------------
__device__ __forceinline__ unsigned long long pk2(float lo, float hi) {
    unsigned long long r;
    asm("mov.b64 %0, {%1, %2};" : "=l"(r) : "f"(lo), "f"(hi));
    return r;
}
__device__ __forceinline__ void fma2(unsigned long long& d,
                                     unsigned long long a,
                                     unsigned long long b) {
    asm("fma.rn.f32x2 %0, %1, %2, %0;" : "+l"(d) : "l"(a), "l"(b));
}
__device__ __forceinline__ float2 up2(unsigned long long v) {
    float2 f;
    asm("mov.b64 {%0, %1}, %2;" : "=f"(f.x), "=f"(f.y) : "l"(v));
    return f;
}

// ---------------- device scratch (no allocations allowed) ----------------
__device__ float g_bufA[NN * HIDC * HWSZ];   // xe, later xp(final)
__device__ float g_bufB[NN * HIDC * HWSZ];   // xp1
__device__ float g_xnode[NN * HIDC];
__device__ float g_hfeat[NN * HEADS * HIDC];
__device__ float g_as[NN * HEADS];
__device__ float g_ad[NN * HEADS];
__device__ float g_xg[NN * HIDC];
__device__ float g_gterm[NN * CINC];
__device__ int   g_cnt[NN];
__device__ int   g_row[NN + 1];
__device__ int   g_fill[NN];
__device__ int   g_csr[TOTE];
__device__ int   g_is64;

// ---------------- edge dtype detect + CSR build ----------------
__global__ void setup_kernel(const int* __restrict__ ei) {
    int t = threadIdx.x;
    if (t < NN) g_cnt[t] = 0;
    if (t == 0) {
        int acc = 0;
        for (int i = 0; i < 128; i++) acc |= ei[2 * i + 1];
        g_is64 = (acc == 0) ? 1 : 0;
    }
}

__device__ __forceinline__ void read_edge(const int* __restrict__ ei, int i,
                                          int is64, int& s, int& d) {
    if (i < NE) {
        if (is64) { s = ei[2 * i]; d = ei[2 * (NE + i)]; }
        else      { s = ei[i];     d = ei[NE + i]; }
    } else {
        s = i - NE; d = i - NE;  // self loop
    }
}

__global__ void count_kernel(const int* __restrict__ ei) {
    int i = blockIdx.x * blockDim.x + threadIdx.x;
    if (i >= TOTE) return;
    int s, d;
    read_edge(ei, i, g_is64, s, d);
    atomicAdd(&g_cnt[d], 1);
}

__global__ void scan_kernel() {
    __shared__ int sc[NN];
    int t = threadIdx.x;
    int c = g_cnt[t];
    sc[t] = c;
    __syncthreads();
    for (int off = 1; off < NN; off <<= 1) {
        int v = (t >= off) ? sc[t - off] : 0;
        __syncthreads();
        sc[t] += v;
        __syncthreads();
    }
    g_row[t + 1] = sc[t];
    if (t == 0) g_row[0] = 0;
    g_fill[t] = sc[t] - c;
}

__global__ void scatter_kernel(const int* __restrict__ ei) {
    int i = blockIdx.x * blockDim.x + threadIdx.x;
    if (i >= TOTE) return;
    int s, d;
    read_edge(ei, i, g_is64, s, d);
    int pos = atomicAdd(&g_fill[d], 1);
    g_csr[pos] = s;
}

// ---------------- fe: 1x1 conv + BN + ReLU + confidence ----------------
__global__ __launch_bounds__(256) void fe_kernel(
    const float* __restrict__ x, const float* __restrict__ fw,
    const float* __restrict__ fb, const float* __restrict__ fg,
    const float* __restrict__ fbe, const float* __restrict__ conf,
    float* __restrict__ xe) {
    __shared__ float xs[32 * 128];
    __shared__ float ws[32 * 128];
    int n = blockIdx.x, px0 = blockIdx.y * 128;
    int tid = threadIdx.x;
    int pg = tid & 31, og = tid >> 5;
    int px = pg * 4, ob = og * 16;
    unsigned long long acc2[16][2];
#pragma unroll
    for (int i = 0; i < 16; i++) { acc2[i][0] = 0ull; acc2[i][1] = 0ull; }

    for (int kc = 0; kc < CINC; kc += 32) {
        __syncthreads();
        for (int idx = tid; idx < 32 * 128; idx += 256) {
            int k = idx >> 7, p = idx & 127;
            xs[idx] = x[(n * CINC + kc + k) * HWSZ + px0 + p];
            int o = idx & 127, k2 = idx >> 7;
            ws[idx] = fw[o * CINC + kc + k2];
        }
        __syncthreads();
#pragma unroll
        for (int k = 0; k < 32; k++) {
            float4 bx = *(const float4*)&xs[k * 128 + px];
            unsigned long long x01 = pk2(bx.x, bx.y);
            unsigned long long x23 = pk2(bx.z, bx.w);
#pragma unroll
            for (int jo = 0; jo < 4; jo++) {
                float4 av = *(const float4*)&ws[k * 128 + ob + jo * 4];
                float wv[4] = {av.x, av.y, av.z, av.w};
#pragma unroll
                for (int l = 0; l < 4; l++) {
                    unsigned long long wp = pk2(wv[l], wv[l]);
                    fma2(acc2[jo * 4 + l][0], x01, wp);
                    fma2(acc2[jo * 4 + l][1], x23, wp);
                }
            }
        }
    }
    float4 cf = *(const float4*)&conf[n * HWSZ + px0 + px];
    const float inv = rsqrtf(1.0f + 1e-5f);
#pragma unroll
    for (int ol = 0; ol < 16; ol++) {
        int o = ob + ol;
        float sc = fg[o] * inv;
        float sh = fbe[o] + fb[o] * sc;
        float2 p01 = up2(acc2[ol][0]);
        float2 p23 = up2(acc2[ol][1]);
        float4 v;
        v.x = fmaxf(p01.x * sc + sh, 0.f) * cf.x;
        v.y = fmaxf(p01.y * sc + sh, 0.f) * cf.y;
        v.z = fmaxf(p23.x * sc + sh, 0.f) * cf.z;
        v.w = fmaxf(p23.y * sc + sh, 0.f) * cf.w;
        *(float4*)&xe[(n * HIDC + o) * HWSZ + px0 + px] = v;
    }
}

// ---------------- 3x3 conv + BN + ReLU (packed f32x2) ----------------
// grid (512, 4, 4): n, co-block(32), h-block(8 rows).
// 256 thr = 32 px-grp(1 row-strip of 8 cols) x 8 co-grp(4 co).
#define CI_CHUNK 16
#define IN_RS 35   // smem row stride (conflict-free: (3r+8s+j) mod 32 distinct)
__global__ __launch_bounds__(256, 2) void conv3x3_kernel(
    const float* __restrict__ in, const float* __restrict__ w,
    const float* __restrict__ bb, const float* __restrict__ gg,
    const float* __restrict__ be, float* __restrict__ out) {
    __shared__ float sIn[CI_CHUNK * 10 * IN_RS];
    __shared__ float sW[CI_CHUNK * 9 * 32];
    int n = blockIdx.x, cob = blockIdx.y, hb = blockIdx.z;
    int tid = threadIdx.x;
    int pxg = tid & 31, cog = tid >> 5;
    int row = pxg >> 2, cs = (pxg & 3) * 8;
    int h0 = hb * 8;

    // acc2[q][pp] = packed (pixel 2pp, pixel 2pp+1) for co = cog*4+q
    unsigned long long acc2[4][4];
#pragma unroll
    for (int q = 0; q < 4; q++)
#pragma unroll
        for (int pp = 0; pp < 4; pp++) acc2[q][pp] = 0ull;

    for (int cc = 0; cc < HIDC; cc += CI_CHUNK) {
        __syncthreads();
        // stage input tile (rows h0-1..h0+8, cols -1..32, zero-padded)
        for (int idx = tid; idx < CI_CHUNK * 10 * 34; idx += 256) {
            int ci = idx / 340;
            int rem = idx - ci * 340;
            int r = rem / 34;
            int c = rem - r * 34;
            int gh = h0 - 1 + r;
            int gw = c - 1;
            float v = 0.f;
            if ((unsigned)gh < 32u && (unsigned)gw < 32u)
                v = in[((n * HIDC + cc + ci) * HH + gh) * WW + gw];
            sIn[(ci * 10 + r) * IN_RS + c] = v;
        }
        // stage weights as [ci][tap][co32]
        for (int idx = tid; idx < CI_CHUNK * 9 * 32; idx += 256) {
            int col = idx & 31;
            int t2 = idx >> 5;
            int tap = t2 % 9;
            int ci = t2 / 9;
            sW[idx] = w[((cob * 32 + col) * HIDC + cc + ci) * 9 + tap];
        }
        __syncthreads();
#pragma unroll 1
        for (int ci = 0; ci < CI_CHUNK; ci++) {
#pragma unroll
            for (int kh = 0; kh < 3; kh++) {
                float a[10];
#pragma unroll
                for (int j = 0; j < 10; j++)
                    a[j] = sIn[(ci * 10 + row + kh) * IN_RS + cs + j];
                unsigned long long pk[9];
#pragma unroll
                for (int j = 0; j < 9; j++) pk[j] = pk2(a[j], a[j + 1]);
#pragma unroll
                for (int kw = 0; kw < 3; kw++) {
                    float4 wv = *(const float4*)&sW[(ci * 9 + kh * 3 + kw) * 32 + cog * 4];
                    unsigned long long w0 = pk2(wv.x, wv.x);
                    unsigned long long w1 = pk2(wv.y, wv.y);
                    unsigned long long w2 = pk2(wv.z, wv.z);
                    unsigned long long w3 = pk2(wv.w, wv.w);
#pragma unroll
                    for (int pp = 0; pp < 4; pp++) {
                        unsigned long long xv = pk[2 * pp + kw];
                        fma2(acc2[0][pp], xv, w0);
                        fma2(acc2[1][pp], xv, w1);
                        fma2(acc2[2][pp], xv, w2);
                        fma2(acc2[3][pp], xv, w3);
                    }
                }
            }
        }
    }
    const float inv = rsqrtf(1.0f + 1e-5f);
    int h = h0 + row;
#pragma unroll
    for (int q = 0; q < 4; q++) {
        int co = cob * 32 + cog * 4 + q;
        float sc = gg[co] * inv;
        float sh = be[co] + bb[co] * sc;
        float2 r0 = up2(acc2[q][0]);
        float2 r1 = up2(acc2[q][1]);
        float2 r2 = up2(acc2[q][2]);
        float2 r3 = up2(acc2[q][3]);
        float4 v0, v1;
        v0.x = fmaxf(r0.x * sc + sh, 0.f);
        v0.y = fmaxf(r0.y * sc + sh, 0.f);
        v0.z = fmaxf(r1.x * sc + sh, 0.f);
        v0.w = fmaxf(r1.y * sc + sh, 0.f);
        v1.x = fmaxf(r2.x * sc + sh, 0.f);
        v1.y = fmaxf(r2.y * sc + sh, 0.f);
        v1.z = fmaxf(r3.x * sc + sh, 0.f);
        v1.w = fmaxf(r3.y * sc + sh, 0.f);
        float* op = &out[((n * HIDC + co) * HH + h) * WW + cs];
        *(float4*)op = v0;
        *(float4*)(op + 4) = v1;
    }
}

// ---------------- global average pool ----------------
__global__ __launch_bounds__(128) void pool_kernel(const float* __restrict__ xp) {
    int bid = blockIdx.x;
    int n = bid >> 7, c = bid & 127;
    const float4* p = (const float4*)&xp[(n * HIDC + c) * HWSZ];
    float s = 0.f;
    for (int i = threadIdx.x; i < 256; i += 128) {
        float4 v = p[i];
        s += v.x + v.y + v.z + v.w;
    }
#pragma unroll
    for (int off = 16; off > 0; off >>= 1)
        s += __shfl_xor_sync(0xffffffffu, s, off);
    __shared__ float wsum[4];
    if ((threadIdx.x & 31) == 0) wsum[threadIdx.x >> 5] = s;
    __syncthreads();
    if (threadIdx.x == 0)
        g_xnode[n * HIDC + c] = (wsum[0] + wsum[1] + wsum[2] + wsum[3]) * (1.f / 1024.f);
}

// ---------------- GAT: h = x@lin, a_s, a_d ----------------
__global__ __launch_bounds__(128) void gat_h_kernel(
    const float* __restrict__ xin, const float* __restrict__ lin,
    const float* __restrict__ asw, const float* __restrict__ adw) {
    int n = blockIdx.x, t = threadIdx.x;
    __shared__ float xr[HIDC];
    __shared__ float red[HIDC];
    xr[t] = xin[n * HIDC + t];
    __syncthreads();
    float hv[HEADS];
#pragma unroll
    for (int j = 0; j < HEADS; j++) {
        int col = j * HIDC + t;
        float s = 0.f;
        for (int k = 0; k < HIDC; k++) s += xr[k] * lin[k * (HEADS * HIDC) + col];
        hv[j] = s;
        g_hfeat[n * (HEADS * HIDC) + col] = s;
    }
#pragma unroll
    for (int j = 0; j < HEADS; j++) {
        red[t] = hv[j] * asw[j * HIDC + t];
        __syncthreads();
        for (int off = 64; off > 0; off >>= 1) {
            if (t < off) red[t] += red[t + off];
            __syncthreads();
        }
        if (t == 0) g_as[n * HEADS + j] = red[0];
        __syncthreads();
        red[t] = hv[j] * adw[j * HIDC + t];
        __syncthreads();
        for (int off = 64; off > 0; off >>= 1) {
            if (t < off) red[t] += red[t + off];
            __syncthreads();
        }
        if (t == 0) g_ad[n * HEADS + j] = red[0];
        __syncthreads();
    }
}

// ---------------- GAT: per-dst softmax + aggregate + head mean + relu ----
__global__ __launch_bounds__(128) void gat_aggr_kernel(
    const float* __restrict__ bias, float* __restrict__ xout) {
    int n = blockIdx.x, t = threadIdx.x;
    float adn[HEADS];
#pragma unroll
    for (int j = 0; j < HEADS; j++) adn[j] = g_ad[n * HEADS + j];
    int rs = g_row[n], re = g_row[n + 1];
    float mx[HEADS] = {-1e30f, -1e30f, -1e30f, -1e30f};
    for (int ei = rs; ei < re; ei++) {
        int s = g_csr[ei];
#pragma unroll
        for (int j = 0; j < HEADS; j++) {
            float e = g_as[s * HEADS + j] + adn[j];
            e = (e > 0.f) ? e : 0.2f * e;
            mx[j] = fmaxf(mx[j], e);
        }
    }
    float den[HEADS] = {0.f, 0.f, 0.f, 0.f};
    float acc[HEADS] = {0.f, 0.f, 0.f, 0.f};
    for (int ei = rs; ei < re; ei++) {
        int s = g_csr[ei];
#pragma unroll
        for (int j = 0; j < HEADS; j++) {
            float e = g_as[s * HEADS + j] + adn[j];
            e = (e > 0.f) ? e : 0.2f * e;
            float ex = __expf(e - mx[j]);
            den[j] += ex;
            acc[j] += ex * g_hfeat[s * (HEADS * HIDC) + j * HIDC + t];
        }
    }
    float o = 0.f;
#pragma unroll
    for (int j = 0; j < HEADS; j++) o += acc[j] / (den[j] + 1e-16f);
    o = o * 0.25f + bias[t];
    xout[n * HIDC + t] = fmaxf(o, 0.f);
}

// ---------------- gterm[n,c] = op_b[c] + sum_o xg[n,o]*op_w[c,o] ----------
__global__ __launch_bounds__(64) void gterm_kernel(
    const float* __restrict__ opw, const float* __restrict__ opb) {
    int n = blockIdx.x, t = threadIdx.x;
    __shared__ float xg[HIDC];
    xg[t] = g_xg[n * HIDC + t];
    xg[t + 64] = g_xg[n * HIDC + t + 64];
    __syncthreads();
    float s = opb[t];
    for (int o = 0; o < HIDC; o++) s += xg[o] * opw[t * HIDC + o];
    g_gterm[n * CINC + t] = s;
}

// ---------------- op: out = gterm + xp @ op_w^T ----------------
__global__ __launch_bounds__(256) void op_kernel(
    const float* __restrict__ xp, const float* __restrict__ opw,
    float* __restrict__ out) {
    __shared__ float xs[32 * 128];
    __shared__ float ws[32 * 64];
    int n = blockIdx.x, px0 = blockIdx.y * 128;
    int tid = threadIdx.x;
    int pg = tid & 31, cog = tid >> 5;
    int px = pg * 4, cb = cog * 8;
    unsigned long long acc2[8][2];
#pragma unroll
    for (int i = 0; i < 8; i++) { acc2[i][0] = 0ull; acc2[i][1] = 0ull; }

    for (int kc = 0; kc < HIDC; kc += 32) {
        __syncthreads();
        for (int idx = tid; idx < 32 * 128; idx += 256) {
            int k = idx >> 7, p = idx & 127;
            xs[idx] = xp[(n * HIDC + kc + k) * HWSZ + px0 + p];
        }
        for (int idx = tid; idx < 32 * 64; idx += 256) {
            int k = idx >> 6, c = idx & 63;
            ws[idx] = opw[c * HIDC + kc + k];
        }
        __syncthreads();
#pragma unroll
        for (int k = 0; k < 32; k++) {
            float4 bx = *(const float4*)&xs[k * 128 + px];
            unsigned long long x01 = pk2(bx.x, bx.y);
            unsigned long long x23 = pk2(bx.z, bx.w);
            float4 a0 = *(const float4*)&ws[k * 64 + cb];
            float4 a1 = *(const float4*)&ws[k * 64 + cb + 4];
            float wv[8] = {a0.x, a0.y, a0.z, a0.w, a1.x, a1.y, a1.z, a1.w};
#pragma unroll
            for (int l = 0; l < 8; l++) {
                unsigned long long wp = pk2(wv[l], wv[l]);
                fma2(acc2[l][0], x01, wp);
                fma2(acc2[l][1], x23, wp);
            }
        }
    }
#pragma unroll
    for (int l = 0; l < 8; l++) {
        int c = cb + l;
        float gt = g_gterm[n * CINC + c];
        float2 p01 = up2(acc2[l][0]);
        float2 p23 = up2(acc2[l][1]);
        float4 v;
        v.x = p01.x + gt;
        v.y = p01.y + gt;
        v.z = p23.x + gt;
        v.w = p23.y + gt;
        *(float4*)&out[(n * CINC + c) * HWSZ + px0 + px] = v;
    }
}

// ---------------- launch ----------------
extern "C" void kernel_launch(void* const* d_in, const int* in_sizes, int n_in,
                              void* d_out, int out_size) {
    const float* x    = (const float*)d_in[0];
    const int*   ei   = (const int*)d_in[1];
    const float* conf = (const float*)d_in[2];
    const float* fe_w = (const float*)d_in[3];
    const float* fe_b = (const float*)d_in[4];
    const float* fe_g = (const float*)d_in[5];
    const float* fe_be= (const float*)d_in[6];
    const float* sp_w1= (const float*)d_in[7];
    const float* sp_b1= (const float*)d_in[8];
    const float* sp_g1= (const float*)d_in[9];
    const float* sp_e1= (const float*)d_in[10];
    const float* sp_w2= (const float*)d_in[11];
    const float* sp_b2= (const float*)d_in[12];
    const float* sp_g2= (const float*)d_in[13];
    const float* sp_e2= (const float*)d_in[14];
    const float* g1_lin=(const float*)d_in[15];
    const float* g1_as= (const float*)d_in[16];
    const float* g1_ad= (const float*)d_in[17];
    const float* g1_b = (const float*)d_in[18];
    const float* g2_lin=(const float*)d_in[19];
    const float* g2_as= (const float*)d_in[20];
    const float* g2_ad= (const float*)d_in[21];
    const float* g2_b = (const float*)d_in[22];
    const float* op_w = (const float*)d_in[23];
    const float* op_b = (const float*)d_in[24];
    float* out = (float*)d_out;

    void *pA, *pB, *pXn, *pXg;
    cudaGetSymbolAddress(&pA, g_bufA);
    cudaGetSymbolAddress(&pB, g_bufB);
    cudaGetSymbolAddress(&pXn, g_xnode);
    cudaGetSymbolAddress(&pXg, g_xg);
    float* bufA = (float*)pA;
    float* bufB = (float*)pB;
    float* xnode = (float*)pXn;
    float* xg = (float*)pXg;

    // Order arranged so a conv3x3 launch sits at profiler indices 3 and 5.
    fe_kernel<<<dim3(NN, 8), 256>>>(x, fe_w, fe_b, fe_g, fe_be, conf, bufA);      // 0
    setup_kernel<<<1, 512>>>(ei);                                                  // 1
    count_kernel<<<(TOTE + 255) / 256, 256>>>(ei);                                 // 2
    conv3x3_kernel<<<dim3(NN, 4, 4), 256>>>(bufA, sp_w1, sp_b1, sp_g1, sp_e1, bufB); // 3
    scan_kernel<<<1, 512>>>();                                                     // 4
    conv3x3_kernel<<<dim3(NN, 4, 4), 256>>>(bufB, sp_w2, sp_b2, sp_g2, sp_e2, bufA); // 5
    scatter_kernel<<<(TOTE + 255) / 256, 256>>>(ei);                               // 6
    pool_kernel<<<NN * HIDC, 128>>>(bufA);                                         // 7
    gat_h_kernel<<<NN, 128>>>(xnode, g1_lin, g1_as, g1_ad);                        // 8
    gat_aggr_kernel<<<NN, 128>>>(g1_b, xg);                                        // 9
    gat_h_kernel<<<NN, 128>>>(xg, g2_lin, g2_as, g2_ad);                           // 10
    gat_aggr_kernel<<<NN, 128>>>(g2_b, xg);                                        // 11
    gterm_kernel<<<NN, 64>>>(op_w, op_b);                                          // 12
    op_kernel<<<dim3(NN, 8), 256>>>(bufA, op_w, out);                              // 13

    (void)in_sizes; (void)n_in; (void)out_size;
}

// round 4
// speedup vs baseline: 2.6050x; 2.6050x over previous
#include <cuda_runtime.h>
#include <cuda_bf16.h>
#include <math.h>
#include <stdint.h>

#define NN   512
#define CINC 64
#define HIDC 128
#define HWSZ 1024
#define HH   32
#define WW   32
#define HEADS 4
#define NE   16384
#define TOTE (NE + NN)
#define POSN 1224          // padded positions per image: 36 rows x 34 cols
#define MTILES 9           // 9 M-tiles of 128 cover p in [0,1152)

#define STAGE_BYTES 40960  // 4 regions (Ah,Al,Bh,Bl) x 128 rows x 80B
#define CONV_SMEM   (2 * STAGE_BYTES)

// ================= helpers =================
__device__ __forceinline__ uint32_t smem_u32(const void* p) {
    return (uint32_t)__cvta_generic_to_shared(p);
}
__device__ __forceinline__ uint32_t lds32(uint32_t a) {
    uint32_t v;
    asm volatile("ld.shared.b32 %0, [%1];" : "=r"(v) : "r"(a));
    return v;
}
__device__ __forceinline__ void mma16816(float* c, const uint32_t* a,
                                         uint32_t b0, uint32_t b1) {
    asm volatile(
        "mma.sync.aligned.m16n8k16.row.col.f32.bf16.bf16.f32 "
        "{%0,%1,%2,%3}, {%4,%5,%6,%7}, {%8,%9}, {%0,%1,%2,%3};"
        : "+f"(c[0]), "+f"(c[1]), "+f"(c[2]), "+f"(c[3])
        : "r"(a[0]), "r"(a[1]), "r"(a[2]), "r"(a[3]), "r"(b0), "r"(b1));
}
__device__ __forceinline__ void cpasync16(uint32_t sa, const void* g) {
    unsigned long long ga = (unsigned long long)__cvta_generic_to_global(g);
    asm volatile("cp.async.cg.shared.global [%0], [%1], 16;" :: "r"(sa), "l"(ga));
}
#define CP_COMMIT() asm volatile("cp.async.commit_group;")
#define CP_WAIT(N)  asm volatile("cp.async.wait_group %0;" :: "n"(N))

__device__ __forceinline__ uint32_t pack_bf2(__nv_bfloat16 a, __nv_bfloat16 b) {
    return (uint32_t)__bfloat16_as_ushort(a) | ((uint32_t)__bfloat16_as_ushort(b) << 16);
}

// ================= device scratch =================
__device__ float g_xe[NN * HIDC * HWSZ];                  // fe output fp32
__device__ float g_xp[NN * HIDC * HWSZ];                  // conv2 output fp32
__device__ __nv_bfloat16 g_x1h[(size_t)NN * POSN * HIDC];
__device__ __nv_bfloat16 g_x1l[(size_t)NN * POSN * HIDC];
__device__ __nv_bfloat16 g_x2h[(size_t)NN * POSN * HIDC];
__device__ __nv_bfloat16 g_x2l[(size_t)NN * POSN * HIDC];
__device__ __nv_bfloat16 g_w1h[9 * HIDC * HIDC];
__device__ __nv_bfloat16 g_w1l[9 * HIDC * HIDC];
__device__ __nv_bfloat16 g_w2h[9 * HIDC * HIDC];
__device__ __nv_bfloat16 g_w2l[9 * HIDC * HIDC];
__device__ float g_xnode[NN * HIDC];
__device__ float g_hfeat[NN * HEADS * HIDC];
__device__ float g_as[NN * HEADS];
__device__ float g_ad[NN * HEADS];
__device__ float g_xg[NN * HIDC];
__device__ float g_gterm[NN * CINC];
__device__ int   g_cnt[NN];
__device__ int   g_row[NN + 1];
__device__ int   g_fill[NN];
__device__ int   g_csr[TOTE];
__device__ int   g_is64;

// ================= CSR build =================
__global__ void setup_kernel(const int* __restrict__ ei) {
    int t = threadIdx.x;
    if (t < NN) g_cnt[t] = 0;
    if (t == 0) {
        int acc = 0;
        for (int i = 0; i < 128; i++) acc |= ei[2 * i + 1];
        g_is64 = (acc == 0) ? 1 : 0;
    }
}
__device__ __forceinline__ void read_edge(const int* __restrict__ ei, int i,
                                          int is64, int& s, int& d) {
    if (i < NE) {
        if (is64) { s = ei[2 * i]; d = ei[2 * (NE + i)]; }
        else      { s = ei[i];     d = ei[NE + i]; }
    } else { s = i - NE; d = i - NE; }
}
__global__ void count_kernel(const int* __restrict__ ei) {
    int i = blockIdx.x * blockDim.x + threadIdx.x;
    if (i >= TOTE) return;
    int s, d; read_edge(ei, i, g_is64, s, d);
    atomicAdd(&g_cnt[d], 1);
}
__global__ void scan_kernel() {
    __shared__ int sc[NN];
    int t = threadIdx.x;
    int c = g_cnt[t];
    sc[t] = c; __syncthreads();
    for (int off = 1; off < NN; off <<= 1) {
        int v = (t >= off) ? sc[t - off] : 0;
        __syncthreads(); sc[t] += v; __syncthreads();
    }
    g_row[t + 1] = sc[t];
    if (t == 0) g_row[0] = 0;
    g_fill[t] = sc[t] - c;
}
__global__ void scatter_kernel(const int* __restrict__ ei) {
    int i = blockIdx.x * blockDim.x + threadIdx.x;
    if (i >= TOTE) return;
    int s, d; read_edge(ei, i, g_is64, s, d);
    int pos = atomicAdd(&g_fill[d], 1);
    g_csr[pos] = s;
}

// ================= weight prep: fp32 [co][ci][tap] -> bf16 hi/lo [tap][co][ci]
__global__ void wprep_kernel(const float* __restrict__ w,
                             __nv_bfloat16* __restrict__ bh,
                             __nv_bfloat16* __restrict__ bl) {
    int idx = blockIdx.x * 256 + threadIdx.x;
    if (idx >= HIDC * HIDC * 9) return;
    int tap = idx % 9;
    int ci = (idx / 9) % HIDC;
    int co = idx / (9 * HIDC);
    float v = w[idx];
    __nv_bfloat16 h = __float2bfloat16(v);
    float r = v - __bfloat162float(h);
    bh[(tap * HIDC + co) * HIDC + ci] = h;
    bl[(tap * HIDC + co) * HIDC + ci] = __float2bfloat16(r);
}

// ================= convert: xe fp32 [n][ci][hw] -> padded bf16 hi/lo [n][pos][ci]
__global__ __launch_bounds__(256) void cvt_kernel(const float* __restrict__ xe,
                                                  __nv_bfloat16* __restrict__ xh,
                                                  __nv_bfloat16* __restrict__ xl) {
    __shared__ float sm[HIDC * 33];
    int n = blockIdx.x, h = blockIdx.y;
    int tid = threadIdx.x;
    for (int i = 0; i < 16; i++) {
        int ci = i * 8 + (tid >> 5);
        int w = tid & 31;
        sm[ci * 33 + w] = xe[((size_t)n * HIDC + ci) * HWSZ + h * WW + w];
    }
    __syncthreads();
    int w2 = tid >> 3, cig = tid & 7;
    int q = (h + 1) * 34 + (w2 + 1);
    size_t base = ((size_t)n * POSN + q) * HIDC + cig * 16;
    uint32_t hv[8], lv[8];
#pragma unroll
    for (int j = 0; j < 8; j++) {
        float v0 = sm[(cig * 16 + 2 * j) * 33 + w2];
        float v1 = sm[(cig * 16 + 2 * j + 1) * 33 + w2];
        __nv_bfloat16 h0 = __float2bfloat16(v0);
        __nv_bfloat16 h1 = __float2bfloat16(v1);
        __nv_bfloat16 l0 = __float2bfloat16(v0 - __bfloat162float(h0));
        __nv_bfloat16 l1 = __float2bfloat16(v1 - __bfloat162float(h1));
        hv[j] = pack_bf2(h0, h1);
        lv[j] = pack_bf2(l0, l1);
    }
    *(uint4*)(xh + base)     = make_uint4(hv[0], hv[1], hv[2], hv[3]);
    *(uint4*)(xh + base + 8) = make_uint4(hv[4], hv[5], hv[6], hv[7]);
    *(uint4*)(xl + base)     = make_uint4(lv[0], lv[1], lv[2], lv[3]);
    *(uint4*)(xl + base + 8) = make_uint4(lv[4], lv[5], lv[6], lv[7]);
}

// ================= mma.sync conv =================
// out[p, co] = sum_{tap,ci} Xpad[p + off(tap), ci] * W[tap, co, ci]
// Block: 128 pos x 128 co. 8 warps in 2(m) x 4(n). Warp: 64x32 via 4x4 m16n8k16.
// 36 stages (9 taps x 4 ci-chunks of 32), cp.async double-buffered.
// MODE 0: write padded bf16 hi/lo. MODE 1: write fp32 [n][co][hw].
template <int MODE>
__global__ __launch_bounds__(256, 2) void conv_mma_kernel(
    const __nv_bfloat16* __restrict__ Xh, const __nv_bfloat16* __restrict__ Xl,
    const __nv_bfloat16* __restrict__ Wh, const __nv_bfloat16* __restrict__ Wl,
    const float* __restrict__ bb, const float* __restrict__ gg,
    const float* __restrict__ be,
    __nv_bfloat16* __restrict__ Oh, __nv_bfloat16* __restrict__ Ol,
    float* __restrict__ Ofp) {
    extern __shared__ __align__(16) char dsm[];
    __shared__ float s_sc[HIDC], s_sh[HIDC];

    int tid = threadIdx.x, lane = tid & 31, warp = tid >> 5;
    int warpm = warp >> 2, warpn = warp & 3;
    int n = blockIdx.x / MTILES, mt = blockIdx.x % MTILES;
    int pbase = mt * 128;

    if (tid < HIDC) {
        const float inv = rsqrtf(1.0f + 1e-5f);
        float sc = gg[tid] * inv;
        s_sc[tid] = sc;
        s_sh[tid] = be[tid] + bb[tid] * sc;
    }

    float C[4][4][4];
#pragma unroll
    for (int m = 0; m < 4; m++)
#pragma unroll
        for (int nt = 0; nt < 4; nt++)
#pragma unroll
            for (int r = 0; r < 4; r++) C[m][nt][r] = 0.f;

    uint32_t sbase = smem_u32(dsm);

    // ---- stage loader ----
    auto load_stage = [&](int it) {
        int buf = it & 1;
        int tap = it >> 2, cic = it & 3;
        int tapoff = (tap / 3) * 34 + (tap % 3);
        size_t abase = ((size_t)(n * POSN + pbase + tapoff)) * HIDC + cic * 32;
        size_t bbase = ((size_t)tap * HIDC) * HIDC + cic * 32;
        uint32_t s0 = sbase + buf * STAGE_BYTES;
#pragma unroll
        for (int i = 0; i < 8; i++) {
            int idx = i * 256 + tid;
            int mat = idx >> 10, term = (idx >> 9) & 1;
            int r = (idx >> 2) & 127, s3 = idx & 3;
            const __nv_bfloat16* g;
            if (mat == 0)
                g = (term ? Xl : Xh) + abase + (size_t)r * HIDC + s3 * 8;
            else
                g = (term ? Wl : Wh) + bbase + (size_t)r * HIDC + s3 * 8;
            uint32_t sa = s0 + (mat * 2 + term) * 10240 + r * 80 + s3 * 16;
            cpasync16(sa, g);
        }
        CP_COMMIT();
    };

    // ---- compute one stage from buffer ----
    int t4 = (lane & 3) * 4, g4 = lane >> 2;
    auto compute_stage = [&](int buf) {
        uint32_t s0 = sbase + buf * STAGE_BYTES;
#pragma unroll
        for (int ks = 0; ks < 2; ks++) {
            uint32_t ko = ks * 32 + t4;
            uint32_t ah[4][4], al[4][4];
#pragma unroll
            for (int m = 0; m < 4; m++) {
                uint32_t r0 = (uint32_t)(warpm * 64 + m * 16 + g4) * 80 + ko;
                ah[m][0] = lds32(s0 + r0);
                ah[m][1] = lds32(s0 + r0 + 640);
                ah[m][2] = lds32(s0 + r0 + 16);
                ah[m][3] = lds32(s0 + r0 + 656);
                al[m][0] = lds32(s0 + 10240 + r0);
                al[m][1] = lds32(s0 + 10240 + r0 + 640);
                al[m][2] = lds32(s0 + 10240 + r0 + 16);
                al[m][3] = lds32(s0 + 10240 + r0 + 656);
            }
#pragma unroll
            for (int nt = 0; nt < 4; nt++) {
                uint32_t rb = (uint32_t)(warpn * 32 + nt * 8 + g4) * 80 + ko;
                uint32_t bh0 = lds32(s0 + 20480 + rb);
                uint32_t bh1 = lds32(s0 + 20480 + rb + 16);
                uint32_t bl0 = lds32(s0 + 30720 + rb);
                uint32_t bl1 = lds32(s0 + 30720 + rb + 16);
#pragma unroll
                for (int m = 0; m < 4; m++) {
                    mma16816(C[m][nt], ah[m], bh0, bh1);
                    mma16816(C[m][nt], ah[m], bl0, bl1);
                    mma16816(C[m][nt], al[m], bh0, bh1);
                }
            }
        }
    };

    // ---- pipelined main loop: 36 stages ----
    load_stage(0);
    load_stage(1);
#pragma unroll 1
    for (int it = 0; it < 36; it++) {
        if (it < 35) { CP_WAIT(1); } else { CP_WAIT(0); }
        __syncthreads();
        compute_stage(it & 1);
        __syncthreads();
        if (it + 2 < 36) load_stage(it + 2);
    }

    // ---- epilogue ----
    int t2 = (lane & 3) * 2;
#pragma unroll
    for (int m = 0; m < 4; m++) {
#pragma unroll
        for (int nt = 0; nt < 4; nt++) {
            int co = warpn * 32 + nt * 8 + t2;
            float sc0 = s_sc[co], sh0 = s_sh[co];
            float sc1 = s_sc[co + 1], sh1 = s_sh[co + 1];
#pragma unroll
            for (int half = 0; half < 2; half++) {
                int p = pbase + warpm * 64 + m * 16 + g4 + half * 8;
                float v0 = C[m][nt][half * 2 + 0] * sc0 + sh0;
                float v1 = C[m][nt][half * 2 + 1] * sc1 + sh1;
                int h = p / 34, w = p % 34;
                bool valid = (w < 32) && (h < 32);
                v0 = valid ? fmaxf(v0, 0.f) : 0.f;
                v1 = valid ? fmaxf(v1, 0.f) : 0.f;
                if (MODE == 0) {
                    __nv_bfloat16 h0 = __float2bfloat16(v0);
                    __nv_bfloat16 h1 = __float2bfloat16(v1);
                    __nv_bfloat16 l0 = __float2bfloat16(v0 - __bfloat162float(h0));
                    __nv_bfloat16 l1 = __float2bfloat16(v1 - __bfloat162float(h1));
                    size_t q = ((size_t)n * POSN + p + 35) * HIDC + co;
                    *(uint32_t*)(Oh + q) = pack_bf2(h0, h1);
                    *(uint32_t*)(Ol + q) = pack_bf2(l0, l1);
                } else if (valid) {
                    size_t o = ((size_t)n * HIDC + co) * HWSZ + h * WW + w;
                    Ofp[o] = v0;
                    Ofp[o + HWSZ] = v1;
                }
            }
        }
    }
}

// ================= fe: 1x1 conv + BN + ReLU + confidence (scalar fp32) ===
__global__ __launch_bounds__(256) void fe_kernel(
    const float* __restrict__ x, const float* __restrict__ fw,
    const float* __restrict__ fb, const float* __restrict__ fg,
    const float* __restrict__ fbe, const float* __restrict__ conf,
    float* __restrict__ xe) {
    __shared__ float xs[32 * 128];
    __shared__ float ws[32 * 128];
    int n = blockIdx.x, px0 = blockIdx.y * 128;
    int tid = threadIdx.x;
    int pg = tid & 31, og = tid >> 5;
    int px = pg * 4, ob = og * 16;
    float acc[16][4];
#pragma unroll
    for (int i = 0; i < 16; i++)
#pragma unroll
        for (int j = 0; j < 4; j++) acc[i][j] = 0.f;

    for (int kc = 0; kc < CINC; kc += 32) {
        __syncthreads();
        for (int idx = tid; idx < 32 * 128; idx += 256) {
            int k = idx >> 7, p = idx & 127;
            xs[idx] = x[(n * CINC + kc + k) * HWSZ + px0 + p];
            int o = idx & 127, k2 = idx >> 7;
            ws[idx] = fw[o * CINC + kc + k2];
        }
        __syncthreads();
#pragma unroll
        for (int k = 0; k < 32; k++) {
            float4 bx = *(const float4*)&xs[k * 128 + px];
#pragma unroll
            for (int jo = 0; jo < 4; jo++) {
                float4 av = *(const float4*)&ws[k * 128 + ob + jo * 4];
                float wv[4] = {av.x, av.y, av.z, av.w};
#pragma unroll
                for (int l = 0; l < 4; l++) {
                    acc[jo * 4 + l][0] += wv[l] * bx.x;
                    acc[jo * 4 + l][1] += wv[l] * bx.y;
                    acc[jo * 4 + l][2] += wv[l] * bx.z;
                    acc[jo * 4 + l][3] += wv[l] * bx.w;
                }
            }
        }
    }
    float4 cf = *(const float4*)&conf[n * HWSZ + px0 + px];
    const float inv = rsqrtf(1.0f + 1e-5f);
#pragma unroll
    for (int ol = 0; ol < 16; ol++) {
        int o = ob + ol;
        float sc = fg[o] * inv;
        float sh = fbe[o] + fb[o] * sc;
        float4 v;
        v.x = fmaxf(acc[ol][0] * sc + sh, 0.f) * cf.x;
        v.y = fmaxf(acc[ol][1] * sc + sh, 0.f) * cf.y;
        v.z = fmaxf(acc[ol][2] * sc + sh, 0.f) * cf.z;
        v.w = fmaxf(acc[ol][3] * sc + sh, 0.f) * cf.w;
        *(float4*)&xe[(n * HIDC + o) * HWSZ + px0 + px] = v;
    }
}

// ================= global average pool =================
__global__ __launch_bounds__(128) void pool_kernel(const float* __restrict__ xp) {
    int bid = blockIdx.x;
    int n = bid >> 7, c = bid & 127;
    const float4* p = (const float4*)&xp[((size_t)n * HIDC + c) * HWSZ];
    float s = 0.f;
    for (int i = threadIdx.x; i < 256; i += 128) {
        float4 v = p[i];
        s += v.x + v.y + v.z + v.w;
    }
#pragma unroll
    for (int off = 16; off > 0; off >>= 1)
        s += __shfl_xor_sync(0xffffffffu, s, off);
    __shared__ float wsum[4];
    if ((threadIdx.x & 31) == 0) wsum[threadIdx.x >> 5] = s;
    __syncthreads();
    if (threadIdx.x == 0)
        g_xnode[n * HIDC + c] = (wsum[0] + wsum[1] + wsum[2] + wsum[3]) * (1.f / 1024.f);
}

// ================= GAT =================
__global__ __launch_bounds__(128) void gat_h_kernel(
    const float* __restrict__ xin, const float* __restrict__ lin,
    const float* __restrict__ asw, const float* __restrict__ adw) {
    int n = blockIdx.x, t = threadIdx.x;
    __shared__ float xr[HIDC];
    __shared__ float red[HIDC];
    xr[t] = xin[n * HIDC + t];
    __syncthreads();
    float hv[HEADS];
#pragma unroll
    for (int j = 0; j < HEADS; j++) {
        int col = j * HIDC + t;
        float s = 0.f;
        for (int k = 0; k < HIDC; k++) s += xr[k] * lin[k * (HEADS * HIDC) + col];
        hv[j] = s;
        g_hfeat[n * (HEADS * HIDC) + col] = s;
    }
#pragma unroll
    for (int j = 0; j < HEADS; j++) {
        red[t] = hv[j] * asw[j * HIDC + t];
        __syncthreads();
        for (int off = 64; off > 0; off >>= 1) {
            if (t < off) red[t] += red[t + off];
            __syncthreads();
        }
        if (t == 0) g_as[n * HEADS + j] = red[0];
        __syncthreads();
        red[t] = hv[j] * adw[j * HIDC + t];
        __syncthreads();
        for (int off = 64; off > 0; off >>= 1) {
            if (t < off) red[t] += red[t + off];
            __syncthreads();
        }
        if (t == 0) g_ad[n * HEADS + j] = red[0];
        __syncthreads();
    }
}

__global__ __launch_bounds__(128) void gat_aggr_kernel(
    const float* __restrict__ bias, float* __restrict__ xout) {
    int n = blockIdx.x, t = threadIdx.x;
    float adn[HEADS];
#pragma unroll
    for (int j = 0; j < HEADS; j++) adn[j] = g_ad[n * HEADS + j];
    int rs = g_row[n], re = g_row[n + 1];
    float mx[HEADS] = {-1e30f, -1e30f, -1e30f, -1e30f};
    for (int ei = rs; ei < re; ei++) {
        int s = g_csr[ei];
#pragma unroll
        for (int j = 0; j < HEADS; j++) {
            float e = g_as[s * HEADS + j] + adn[j];
            e = (e > 0.f) ? e : 0.2f * e;
            mx[j] = fmaxf(mx[j], e);
        }
    }
    float den[HEADS] = {0.f, 0.f, 0.f, 0.f};
    float acc[HEADS] = {0.f, 0.f, 0.f, 0.f};
    for (int ei = rs; ei < re; ei++) {
        int s = g_csr[ei];
#pragma unroll
        for (int j = 0; j < HEADS; j++) {
            float e = g_as[s * HEADS + j] + adn[j];
            e = (e > 0.f) ? e : 0.2f * e;
            float ex = __expf(e - mx[j]);
            den[j] += ex;
            acc[j] += ex * g_hfeat[s * (HEADS * HIDC) + j * HIDC + t];
        }
    }
    float o = 0.f;
#pragma unroll
    for (int j = 0; j < HEADS; j++) o += acc[j] / (den[j] + 1e-16f);
    o = o * 0.25f + bias[t];
    xout[n * HIDC + t] = fmaxf(o, 0.f);
}

// ================= gterm =================
__global__ __launch_bounds__(64) void gterm_kernel(
    const float* __restrict__ opw, const float* __restrict__ opb) {
    int n = blockIdx.x, t = threadIdx.x;
    __shared__ float xg[HIDC];
    xg[t] = g_xg[n * HIDC + t];
    xg[t + 64] = g_xg[n * HIDC + t + 64];
    __syncthreads();
    float s = opb[t];
    for (int o = 0; o < HIDC; o++) s += xg[o] * opw[t * HIDC + o];
    g_gterm[n * CINC + t] = s;
}

// ================= op: out = gterm + xp @ op_w^T =================
__global__ __launch_bounds__(256) void op_kernel(
    const float* __restrict__ xp, const float* __restrict__ opw,
    float* __restrict__ out) {
    __shared__ float xs[32 * 128];
    __shared__ float ws[32 * 64];
    int n = blockIdx.x, px0 = blockIdx.y * 128;
    int tid = threadIdx.x;
    int pg = tid & 31, cog = tid >> 5;
    int px = pg * 4, cb = cog * 8;
    float acc[8][4];
#pragma unroll
    for (int i = 0; i < 8; i++)
#pragma unroll
        for (int j = 0; j < 4; j++) acc[i][j] = 0.f;

    for (int kc = 0; kc < HIDC; kc += 32) {
        __syncthreads();
        for (int idx = tid; idx < 32 * 128; idx += 256) {
            int k = idx >> 7, p = idx & 127;
            xs[idx] = xp[((size_t)n * HIDC + kc + k) * HWSZ + px0 + p];
        }
        for (int idx = tid; idx < 32 * 64; idx += 256) {
            int k = idx >> 6, c = idx & 63;
            ws[idx] = opw[c * HIDC + kc + k];
        }
        __syncthreads();
#pragma unroll
        for (int k = 0; k < 32; k++) {
            float4 bx = *(const float4*)&xs[k * 128 + px];
            float4 a0 = *(const float4*)&ws[k * 64 + cb];
            float4 a1 = *(const float4*)&ws[k * 64 + cb + 4];
            float wv[8] = {a0.x, a0.y, a0.z, a0.w, a1.x, a1.y, a1.z, a1.w};
#pragma unroll
            for (int l = 0; l < 8; l++) {
                acc[l][0] += wv[l] * bx.x;
                acc[l][1] += wv[l] * bx.y;
                acc[l][2] += wv[l] * bx.z;
                acc[l][3] += wv[l] * bx.w;
            }
        }
    }
#pragma unroll
    for (int l = 0; l < 8; l++) {
        int c = cb + l;
        float gt = g_gterm[n * CINC + c];
        float4 v;
        v.x = acc[l][0] + gt;
        v.y = acc[l][1] + gt;
        v.z = acc[l][2] + gt;
        v.w = acc[l][3] + gt;
        *(float4*)&out[((size_t)n * CINC + c) * HWSZ + px0 + px] = v;
    }
}

// ================= launch =================
extern "C" void kernel_launch(void* const* d_in, const int* in_sizes, int n_in,
                              void* d_out, int out_size) {
    const float* x    = (const float*)d_in[0];
    const int*   ei   = (const int*)d_in[1];
    const float* conf = (const float*)d_in[2];
    const float* fe_w = (const float*)d_in[3];
    const float* fe_b = (const float*)d_in[4];
    const float* fe_g = (const float*)d_in[5];
    const float* fe_be= (const float*)d_in[6];
    const float* sp_w1= (const float*)d_in[7];
    const float* sp_b1= (const float*)d_in[8];
    const float* sp_g1= (const float*)d_in[9];
    const float* sp_e1= (const float*)d_in[10];
    const float* sp_w2= (const float*)d_in[11];
    const float* sp_b2= (const float*)d_in[12];
    const float* sp_g2= (const float*)d_in[13];
    const float* sp_e2= (const float*)d_in[14];
    const float* g1_lin=(const float*)d_in[15];
    const float* g1_as= (const float*)d_in[16];
    const float* g1_ad= (const float*)d_in[17];
    const float* g1_b = (const float*)d_in[18];
    const float* g2_lin=(const float*)d_in[19];
    const float* g2_as= (const float*)d_in[20];
    const float* g2_ad= (const float*)d_in[21];
    const float* g2_b = (const float*)d_in[22];
    const float* op_w = (const float*)d_in[23];
    const float* op_b = (const float*)d_in[24];
    float* out = (float*)d_out;

    void *pxe, *pxp, *p1h, *p1l, *p2h, *p2l, *pw1h, *pw1l, *pw2h, *pw2l, *pXn, *pXg;
    cudaGetSymbolAddress(&pxe, g_xe);
    cudaGetSymbolAddress(&pxp, g_xp);
    cudaGetSymbolAddress(&p1h, g_x1h);
    cudaGetSymbolAddress(&p1l, g_x1l);
    cudaGetSymbolAddress(&p2h, g_x2h);
    cudaGetSymbolAddress(&p2l, g_x2l);
    cudaGetSymbolAddress(&pw1h, g_w1h);
    cudaGetSymbolAddress(&pw1l, g_w1l);
    cudaGetSymbolAddress(&pw2h, g_w2h);
    cudaGetSymbolAddress(&pw2l, g_w2l);
    cudaGetSymbolAddress(&pXn, g_xnode);
    cudaGetSymbolAddress(&pXg, g_xg);
    float* xe = (float*)pxe;
    float* xp = (float*)pxp;
    __nv_bfloat16* x1h = (__nv_bfloat16*)p1h;
    __nv_bfloat16* x1l = (__nv_bfloat16*)p1l;
    __nv_bfloat16* x2h = (__nv_bfloat16*)p2h;
    __nv_bfloat16* x2l = (__nv_bfloat16*)p2l;
    __nv_bfloat16* w1h = (__nv_bfloat16*)pw1h;
    __nv_bfloat16* w1l = (__nv_bfloat16*)pw1l;
    __nv_bfloat16* w2h = (__nv_bfloat16*)pw2h;
    __nv_bfloat16* w2l = (__nv_bfloat16*)pw2l;
    float* xnode = (float*)pXn;
    float* xg = (float*)pXg;

    cudaFuncSetAttribute(conv_mma_kernel<0>, cudaFuncAttributeMaxDynamicSharedMemorySize, CONV_SMEM);
    cudaFuncSetAttribute(conv_mma_kernel<1>, cudaFuncAttributeMaxDynamicSharedMemorySize, CONV_SMEM);

    const int WPN = (HIDC * HIDC * 9 + 255) / 256;

    fe_kernel<<<dim3(NN, 8), 256>>>(x, fe_w, fe_b, fe_g, fe_be, conf, xe);   // 0
    wprep_kernel<<<WPN, 256>>>(sp_w1, w1h, w1l);                              // 1
    wprep_kernel<<<WPN, 256>>>(sp_w2, w2h, w2l);                              // 2
    cvt_kernel<<<dim3(NN, HH), 256>>>(xe, x1h, x1l);                          // 3
    setup_kernel<<<1, 512>>>(ei);                                             // 4
    conv_mma_kernel<0><<<NN * MTILES, 256, CONV_SMEM>>>(                      // 5 (ncu)
        x1h, x1l, w1h, w1l, sp_b1, sp_g1, sp_e1, x2h, x2l, nullptr);
    count_kernel<<<(TOTE + 255) / 256, 256>>>(ei);                            // 6
    scan_kernel<<<1, 512>>>();                                                // 7
    scatter_kernel<<<(TOTE + 255) / 256, 256>>>(ei);                          // 8
    conv_mma_kernel<1><<<NN * MTILES, 256, CONV_SMEM>>>(                      // 9
        x2h, x2l, w2h, w2l, sp_b2, sp_g2, sp_e2, nullptr, nullptr, xp);
    pool_kernel<<<NN * HIDC, 128>>>(xp);                                      // 10
    gat_h_kernel<<<NN, 128>>>(xnode, g1_lin, g1_as, g1_ad);                   // 11
    gat_aggr_kernel<<<NN, 128>>>(g1_b, xg);                                   // 12
    gat_h_kernel<<<NN, 128>>>(xg, g2_lin, g2_as, g2_ad);                      // 13
    gat_aggr_kernel<<<NN, 128>>>(g2_b, xg);                                   // 14
    gterm_kernel<<<NN, 64>>>(op_w, op_b);                                     // 15
    op_kernel<<<dim3(NN, 8), 256>>>(xp, op_w, out);                           // 16

    (void)in_sizes; (void)n_in; (void)out_size;
}

// round 5
// speedup vs baseline: 2.8866x; 1.1081x over previous
#include <cuda_runtime.h>
#include <cuda_bf16.h>
#include <math.h>
#include <stdint.h>

#define NN   512
#define CINC 64
#define HIDC 128
#define HWSZ 1024
#define HH   32
#define WW   32
#define HEADS 4
#define NE   16384
#define TOTE (NE + NN)
#define POSN 1224          // padded positions per image: 36 rows x 34 cols
#define MTILES 9           // 9 M-tiles of 128 cover p in [0,1152)

#define STAGE_BYTES 40960  // 4 regions (Ah,Al,Bh,Bl) x 128 rows x 80B
#define CONV_SMEM   (2 * STAGE_BYTES)

// ================= helpers =================
__device__ __forceinline__ uint32_t smem_u32(const void* p) {
    return (uint32_t)__cvta_generic_to_shared(p);
}
__device__ __forceinline__ void ldmx4(uint32_t* r, uint32_t a) {
    asm volatile("ldmatrix.sync.aligned.m8n8.x4.shared.b16 {%0,%1,%2,%3}, [%4];"
                 : "=r"(r[0]), "=r"(r[1]), "=r"(r[2]), "=r"(r[3]) : "r"(a));
}
__device__ __forceinline__ void mma16816(float* c, const uint32_t* a,
                                         uint32_t b0, uint32_t b1) {
    asm volatile(
        "mma.sync.aligned.m16n8k16.row.col.f32.bf16.bf16.f32 "
        "{%0,%1,%2,%3}, {%4,%5,%6,%7}, {%8,%9}, {%0,%1,%2,%3};"
        : "+f"(c[0]), "+f"(c[1]), "+f"(c[2]), "+f"(c[3])
        : "r"(a[0]), "r"(a[1]), "r"(a[2]), "r"(a[3]), "r"(b0), "r"(b1));
}
__device__ __forceinline__ void cpasync16(uint32_t sa, const void* g) {
    unsigned long long ga = (unsigned long long)__cvta_generic_to_global(g);
    asm volatile("cp.async.cg.shared.global [%0], [%1], 16;" :: "r"(sa), "l"(ga));
}
#define CP_COMMIT() asm volatile("cp.async.commit_group;")
#define CP_WAIT(N)  asm volatile("cp.async.wait_group %0;" :: "n"(N))

__device__ __forceinline__ uint32_t pack_bf2(__nv_bfloat16 a, __nv_bfloat16 b) {
    return (uint32_t)__bfloat16_as_ushort(a) | ((uint32_t)__bfloat16_as_ushort(b) << 16);
}

// ================= device scratch =================
__device__ float g_xp[NN * HIDC * HWSZ];                  // conv2 output fp32
__device__ __nv_bfloat16 g_x1h[(size_t)NN * POSN * HIDC]; // border stays zero
__device__ __nv_bfloat16 g_x1l[(size_t)NN * POSN * HIDC];
__device__ __nv_bfloat16 g_x2h[(size_t)NN * POSN * HIDC];
__device__ __nv_bfloat16 g_x2l[(size_t)NN * POSN * HIDC];
__device__ __nv_bfloat16 g_w1h[9 * HIDC * HIDC];
__device__ __nv_bfloat16 g_w1l[9 * HIDC * HIDC];
__device__ __nv_bfloat16 g_w2h[9 * HIDC * HIDC];
__device__ __nv_bfloat16 g_w2l[9 * HIDC * HIDC];
__device__ float g_xnode[NN * HIDC];
__device__ float g_hfeat[NN * HEADS * HIDC];
__device__ float g_as[NN * HEADS];
__device__ float g_ad[NN * HEADS];
__device__ float g_xg[NN * HIDC];
__device__ float g_gterm[NN * CINC];
__device__ int   g_cnt[NN];
__device__ int   g_row[NN + 1];
__device__ int   g_fill[NN];
__device__ int   g_csr[TOTE];
__device__ int   g_is64;

// ================= CSR build =================
__global__ void setup_kernel(const int* __restrict__ ei) {
    int t = threadIdx.x;
    if (t < NN) g_cnt[t] = 0;
    if (t == 0) {
        int acc = 0;
        for (int i = 0; i < 128; i++) acc |= ei[2 * i + 1];
        g_is64 = (acc == 0) ? 1 : 0;
    }
}
__device__ __forceinline__ void read_edge(const int* __restrict__ ei, int i,
                                          int is64, int& s, int& d) {
    if (i < NE) {
        if (is64) { s = ei[2 * i]; d = ei[2 * (NE + i)]; }
        else      { s = ei[i];     d = ei[NE + i]; }
    } else { s = i - NE; d = i - NE; }
}
__global__ void count_kernel(const int* __restrict__ ei) {
    int i = blockIdx.x * blockDim.x + threadIdx.x;
    if (i >= TOTE) return;
    int s, d; read_edge(ei, i, g_is64, s, d);
    atomicAdd(&g_cnt[d], 1);
}
__global__ void scan_kernel() {
    __shared__ int sc[NN];
    int t = threadIdx.x;
    int c = g_cnt[t];
    sc[t] = c; __syncthreads();
    for (int off = 1; off < NN; off <<= 1) {
        int v = (t >= off) ? sc[t - off] : 0;
        __syncthreads(); sc[t] += v; __syncthreads();
    }
    g_row[t + 1] = sc[t];
    if (t == 0) g_row[0] = 0;
    g_fill[t] = sc[t] - c;
}
__global__ void scatter_kernel(const int* __restrict__ ei) {
    int i = blockIdx.x * blockDim.x + threadIdx.x;
    if (i >= TOTE) return;
    int s, d; read_edge(ei, i, g_is64, s, d);
    int pos = atomicAdd(&g_fill[d], 1);
    g_csr[pos] = s;
}

// ================= weight prep: fp32 [co][ci][tap] -> bf16 hi/lo [tap][co][ci]
__global__ void wprep_kernel(const float* __restrict__ w,
                             __nv_bfloat16* __restrict__ bh,
                             __nv_bfloat16* __restrict__ bl) {
    int idx = blockIdx.x * 256 + threadIdx.x;
    if (idx >= HIDC * HIDC * 9) return;
    int tap = idx % 9;
    int ci = (idx / 9) % HIDC;
    int co = idx / (9 * HIDC);
    float v = w[idx];
    __nv_bfloat16 h = __float2bfloat16(v);
    float r = v - __bfloat162float(h);
    bh[(tap * HIDC + co) * HIDC + ci] = h;
    bl[(tap * HIDC + co) * HIDC + ci] = __float2bfloat16(r);
}

// ================= fe: 1x1 conv + BN + ReLU + conf -> padded bf16 hi/lo ===
// grid (512, 8): n, 128-px tile. 256 thr = 32 px-grp(4px) x 8 o-grp(16o).
__global__ __launch_bounds__(256) void fe_kernel(
    const float* __restrict__ x, const float* __restrict__ fw,
    const float* __restrict__ fb, const float* __restrict__ fg,
    const float* __restrict__ fbe, const float* __restrict__ conf,
    __nv_bfloat16* __restrict__ xh, __nv_bfloat16* __restrict__ xl) {
    __shared__ float xs[32 * 128];
    __shared__ float ws[32 * 128];
    int n = blockIdx.x, px0 = blockIdx.y * 128;
    int tid = threadIdx.x;
    int pg = tid & 31, og = tid >> 5;
    int px = pg * 4, ob = og * 16;
    float acc[16][4];
#pragma unroll
    for (int i = 0; i < 16; i++)
#pragma unroll
        for (int j = 0; j < 4; j++) acc[i][j] = 0.f;

    for (int kc = 0; kc < CINC; kc += 32) {
        __syncthreads();
        for (int idx = tid; idx < 32 * 128; idx += 256) {
            int k = idx >> 7, p = idx & 127;
            xs[idx] = x[(n * CINC + kc + k) * HWSZ + px0 + p];
            int o = idx & 127, k2 = idx >> 7;
            ws[idx] = fw[o * CINC + kc + k2];
        }
        __syncthreads();
#pragma unroll
        for (int k = 0; k < 32; k++) {
            float4 bx = *(const float4*)&xs[k * 128 + px];
#pragma unroll
            for (int jo = 0; jo < 4; jo++) {
                float4 av = *(const float4*)&ws[k * 128 + ob + jo * 4];
                float wv[4] = {av.x, av.y, av.z, av.w};
#pragma unroll
                for (int l = 0; l < 4; l++) {
                    acc[jo * 4 + l][0] += wv[l] * bx.x;
                    acc[jo * 4 + l][1] += wv[l] * bx.y;
                    acc[jo * 4 + l][2] += wv[l] * bx.z;
                    acc[jo * 4 + l][3] += wv[l] * bx.w;
                }
            }
        }
    }
    float4 cf = *(const float4*)&conf[n * HWSZ + px0 + px];
    float cfa[4] = {cf.x, cf.y, cf.z, cf.w};
    const float inv = rsqrtf(1.0f + 1e-5f);
    float sc16[16], sh16[16];
#pragma unroll
    for (int ol = 0; ol < 16; ol++) {
        int o = ob + ol;
        sc16[ol] = fg[o] * inv;
        sh16[ol] = fbe[o] + fb[o] * sc16[ol];
    }
#pragma unroll
    for (int j = 0; j < 4; j++) {
        int hw = px0 + px + j;
        int h = hw >> 5, w = hw & 31;
        size_t base = ((size_t)n * POSN + (h + 1) * 34 + (w + 1)) * HIDC + ob;
        uint32_t hv[8], lv[8];
#pragma unroll
        for (int q = 0; q < 8; q++) {
            float v0 = fmaxf(acc[2 * q][j]     * sc16[2 * q]     + sh16[2 * q],     0.f) * cfa[j];
            float v1 = fmaxf(acc[2 * q + 1][j] * sc16[2 * q + 1] + sh16[2 * q + 1], 0.f) * cfa[j];
            __nv_bfloat16 h0 = __float2bfloat16(v0);
            __nv_bfloat16 h1 = __float2bfloat16(v1);
            __nv_bfloat16 l0 = __float2bfloat16(v0 - __bfloat162float(h0));
            __nv_bfloat16 l1 = __float2bfloat16(v1 - __bfloat162float(h1));
            hv[q] = pack_bf2(h0, h1);
            lv[q] = pack_bf2(l0, l1);
        }
        *(uint4*)(xh + base)     = make_uint4(hv[0], hv[1], hv[2], hv[3]);
        *(uint4*)(xh + base + 8) = make_uint4(hv[4], hv[5], hv[6], hv[7]);
        *(uint4*)(xl + base)     = make_uint4(lv[0], lv[1], lv[2], lv[3]);
        *(uint4*)(xl + base + 8) = make_uint4(lv[4], lv[5], lv[6], lv[7]);
    }
}

// ================= mma.sync conv (ldmatrix feeds) =================
// out[p, co] = sum_{tap,ci} Xpad[p + off(tap), ci] * W[tap, co, ci]
// Block: 128 pos x 128 co. 8 warps 2(m)x4(n). Warp: 64x32 via 4x4 m16n8k16.
// 36 stages (9 taps x 4 ci-chunks of 32), cp.async double-buffered.
template <int MODE>
__global__ __launch_bounds__(256, 2) void conv_mma_kernel(
    const __nv_bfloat16* __restrict__ Xh, const __nv_bfloat16* __restrict__ Xl,
    const __nv_bfloat16* __restrict__ Wh, const __nv_bfloat16* __restrict__ Wl,
    const float* __restrict__ bb, const float* __restrict__ gg,
    const float* __restrict__ be,
    __nv_bfloat16* __restrict__ Oh, __nv_bfloat16* __restrict__ Ol,
    float* __restrict__ Ofp) {
    extern __shared__ __align__(16) char dsm[];
    __shared__ float s_sc[HIDC], s_sh[HIDC];

    int tid = threadIdx.x, lane = tid & 31, warp = tid >> 5;
    int warpm = warp >> 2, warpn = warp & 3;
    int n = blockIdx.x / MTILES, mt = blockIdx.x % MTILES;
    int pbase = mt * 128;

    if (tid < HIDC) {
        const float inv = rsqrtf(1.0f + 1e-5f);
        float sc = gg[tid] * inv;
        s_sc[tid] = sc;
        s_sh[tid] = be[tid] + bb[tid] * sc;
    }

    float C[4][4][4];
#pragma unroll
    for (int m = 0; m < 4; m++)
#pragma unroll
        for (int nt = 0; nt < 4; nt++)
#pragma unroll
            for (int r = 0; r < 4; r++) C[m][nt][r] = 0.f;

    uint32_t sbase = smem_u32(dsm);

    auto load_stage = [&](int it) {
        int buf = it & 1;
        int tap = it >> 2, cic = it & 3;
        int tapoff = (tap / 3) * 34 + (tap % 3);
        size_t abase = ((size_t)(n * POSN + pbase + tapoff)) * HIDC + cic * 32;
        size_t bbase = ((size_t)tap * HIDC) * HIDC + cic * 32;
        uint32_t s0 = sbase + buf * STAGE_BYTES;
#pragma unroll
        for (int i = 0; i < 8; i++) {
            int idx = i * 256 + tid;
            int mat = idx >> 10, term = (idx >> 9) & 1;
            int r = (idx >> 2) & 127, s3 = idx & 3;
            const __nv_bfloat16* g;
            if (mat == 0)
                g = (term ? Xl : Xh) + abase + (size_t)r * HIDC + s3 * 8;
            else
                g = (term ? Wl : Wh) + bbase + (size_t)r * HIDC + s3 * 8;
            uint32_t sa = s0 + (mat * 2 + term) * 10240 + r * 80 + s3 * 16;
            cpasync16(sa, g);
        }
        CP_COMMIT();
    };

    // ldmatrix lane addressing (canonical)
    int a_row = lane & 15, a_ko = (lane >> 4) * 16;                 // A frags
    int b_row = (lane & 7) + ((lane >> 4) & 1) * 8;                 // B frags
    int b_ko = ((lane >> 3) & 1) * 16;

    auto compute_stage = [&](int buf) {
        uint32_t s0 = sbase + buf * STAGE_BYTES;
#pragma unroll
        for (int ks = 0; ks < 2; ks++) {
            uint32_t ah[4][4], al[4][4];
#pragma unroll
            for (int m = 0; m < 4; m++) {
                uint32_t ra = (uint32_t)(warpm * 64 + m * 16 + a_row) * 80 + ks * 32 + a_ko;
                ldmx4(ah[m], s0 + ra);
                ldmx4(al[m], s0 + 10240 + ra);
            }
#pragma unroll
            for (int ntp = 0; ntp < 2; ntp++) {
                uint32_t rbh[4], rbl[4];
                uint32_t rb = (uint32_t)(warpn * 32 + ntp * 16 + b_row) * 80 + ks * 32 + b_ko;
                ldmx4(rbh, s0 + 20480 + rb);
                ldmx4(rbl, s0 + 30720 + rb);
#pragma unroll
                for (int q = 0; q < 2; q++) {
                    int nt = ntp * 2 + q;
#pragma unroll
                    for (int m = 0; m < 4; m++) {
                        mma16816(C[m][nt], ah[m], rbh[2 * q], rbh[2 * q + 1]);
                        mma16816(C[m][nt], ah[m], rbl[2 * q], rbl[2 * q + 1]);
                        mma16816(C[m][nt], al[m], rbh[2 * q], rbh[2 * q + 1]);
                    }
                }
            }
        }
    };

    load_stage(0);
    load_stage(1);
#pragma unroll 1
    for (int it = 0; it < 36; it++) {
        if (it < 35) { CP_WAIT(1); } else { CP_WAIT(0); }
        __syncthreads();
        compute_stage(it & 1);
        __syncthreads();
        if (it + 2 < 36) load_stage(it + 2);
    }

    // ---- epilogue ----
    int g4 = lane >> 2;
    int t2 = (lane & 3) * 2;
#pragma unroll
    for (int m = 0; m < 4; m++) {
#pragma unroll
        for (int nt = 0; nt < 4; nt++) {
            int co = warpn * 32 + nt * 8 + t2;
            float sc0 = s_sc[co], sh0 = s_sh[co];
            float sc1 = s_sc[co + 1], sh1 = s_sh[co + 1];
#pragma unroll
            for (int half = 0; half < 2; half++) {
                int p = pbase + warpm * 64 + m * 16 + g4 + half * 8;
                float v0 = C[m][nt][half * 2 + 0] * sc0 + sh0;
                float v1 = C[m][nt][half * 2 + 1] * sc1 + sh1;
                int h = p / 34, w = p % 34;
                bool valid = (w < 32) && (h < 32);
                v0 = valid ? fmaxf(v0, 0.f) : 0.f;
                v1 = valid ? fmaxf(v1, 0.f) : 0.f;
                if (MODE == 0) {
                    __nv_bfloat16 h0 = __float2bfloat16(v0);
                    __nv_bfloat16 h1 = __float2bfloat16(v1);
                    __nv_bfloat16 l0 = __float2bfloat16(v0 - __bfloat162float(h0));
                    __nv_bfloat16 l1 = __float2bfloat16(v1 - __bfloat162float(h1));
                    size_t q2 = ((size_t)n * POSN + p + 35) * HIDC + co;
                    *(uint32_t*)(Oh + q2) = pack_bf2(h0, h1);
                    *(uint32_t*)(Ol + q2) = pack_bf2(l0, l1);
                } else if (valid) {
                    size_t o = ((size_t)n * HIDC + co) * HWSZ + h * WW + w;
                    Ofp[o] = v0;
                    Ofp[o + HWSZ] = v1;
                }
            }
        }
    }
}

// ================= global average pool =================
__global__ __launch_bounds__(128) void pool_kernel(const float* __restrict__ xp) {
    int bid = blockIdx.x;
    int n = bid >> 7, c = bid & 127;
    const float4* p = (const float4*)&xp[((size_t)n * HIDC + c) * HWSZ];
    float s = 0.f;
    for (int i = threadIdx.x; i < 256; i += 128) {
        float4 v = p[i];
        s += v.x + v.y + v.z + v.w;
    }
#pragma unroll
    for (int off = 16; off > 0; off >>= 1)
        s += __shfl_xor_sync(0xffffffffu, s, off);
    __shared__ float wsum[4];
    if ((threadIdx.x & 31) == 0) wsum[threadIdx.x >> 5] = s;
    __syncthreads();
    if (threadIdx.x == 0)
        g_xnode[n * HIDC + c] = (wsum[0] + wsum[1] + wsum[2] + wsum[3]) * (1.f / 1024.f);
}

// ================= GAT =================
__global__ __launch_bounds__(128) void gat_h_kernel(
    const float* __restrict__ xin, const float* __restrict__ lin,
    const float* __restrict__ asw, const float* __restrict__ adw) {
    int n = blockIdx.x, t = threadIdx.x;
    __shared__ float xr[HIDC];
    __shared__ float red[HIDC];
    xr[t] = xin[n * HIDC + t];
    __syncthreads();
    float hv[HEADS];
#pragma unroll
    for (int j = 0; j < HEADS; j++) {
        int col = j * HIDC + t;
        float s = 0.f;
        for (int k = 0; k < HIDC; k++) s += xr[k] * lin[k * (HEADS * HIDC) + col];
        hv[j] = s;
        g_hfeat[n * (HEADS * HIDC) + col] = s;
    }
#pragma unroll
    for (int j = 0; j < HEADS; j++) {
        red[t] = hv[j] * asw[j * HIDC + t];
        __syncthreads();
        for (int off = 64; off > 0; off >>= 1) {
            if (t < off) red[t] += red[t + off];
            __syncthreads();
        }
        if (t == 0) g_as[n * HEADS + j] = red[0];
        __syncthreads();
        red[t] = hv[j] * adw[j * HIDC + t];
        __syncthreads();
        for (int off = 64; off > 0; off >>= 1) {
            if (t < off) red[t] += red[t + off];
            __syncthreads();
        }
        if (t == 0) g_ad[n * HEADS + j] = red[0];
        __syncthreads();
    }
}

__global__ __launch_bounds__(128) void gat_aggr_kernel(
    const float* __restrict__ bias, float* __restrict__ xout) {
    int n = blockIdx.x, t = threadIdx.x;
    float adn[HEADS];
#pragma unroll
    for (int j = 0; j < HEADS; j++) adn[j] = g_ad[n * HEADS + j];
    int rs = g_row[n], re = g_row[n + 1];
    float mx[HEADS] = {-1e30f, -1e30f, -1e30f, -1e30f};
    for (int ei = rs; ei < re; ei++) {
        int s = g_csr[ei];
#pragma unroll
        for (int j = 0; j < HEADS; j++) {
            float e = g_as[s * HEADS + j] + adn[j];
            e = (e > 0.f) ? e : 0.2f * e;
            mx[j] = fmaxf(mx[j], e);
        }
    }
    float den[HEADS] = {0.f, 0.f, 0.f, 0.f};
    float acc[HEADS] = {0.f, 0.f, 0.f, 0.f};
    for (int ei = rs; ei < re; ei++) {
        int s = g_csr[ei];
#pragma unroll
        for (int j = 0; j < HEADS; j++) {
            float e = g_as[s * HEADS + j] + adn[j];
            e = (e > 0.f) ? e : 0.2f * e;
            float ex = __expf(e - mx[j]);
            den[j] += ex;
            acc[j] += ex * g_hfeat[s * (HEADS * HIDC) + j * HIDC + t];
        }
    }
    float o = 0.f;
#pragma unroll
    for (int j = 0; j < HEADS; j++) o += acc[j] / (den[j] + 1e-16f);
    o = o * 0.25f + bias[t];
    xout[n * HIDC + t] = fmaxf(o, 0.f);
}

// ================= gterm =================
__global__ __launch_bounds__(64) void gterm_kernel(
    const float* __restrict__ opw, const float* __restrict__ opb) {
    int n = blockIdx.x, t = threadIdx.x;
    __shared__ float xg[HIDC];
    xg[t] = g_xg[n * HIDC + t];
    xg[t + 64] = g_xg[n * HIDC + t + 64];
    __syncthreads();
    float s = opb[t];
    for (int o = 0; o < HIDC; o++) s += xg[o] * opw[t * HIDC + o];
    g_gterm[n * CINC + t] = s;
}

// ================= op: out = gterm + xp @ op_w^T =================
__global__ __launch_bounds__(256) void op_kernel(
    const float* __restrict__ xp, const float* __restrict__ opw,
    float* __restrict__ out) {
    __shared__ float xs[32 * 128];
    __shared__ float ws[32 * 64];
    int n = blockIdx.x, px0 = blockIdx.y * 128;
    int tid = threadIdx.x;
    int pg = tid & 31, cog = tid >> 5;
    int px = pg * 4, cb = cog * 8;
    float acc[8][4];
#pragma unroll
    for (int i = 0; i < 8; i++)
#pragma unroll
        for (int j = 0; j < 4; j++) acc[i][j] = 0.f;

    for (int kc = 0; kc < HIDC; kc += 32) {
        __syncthreads();
        for (int idx = tid; idx < 32 * 128; idx += 256) {
            int k = idx >> 7, p = idx & 127;
            xs[idx] = xp[((size_t)n * HIDC + kc + k) * HWSZ + px0 + p];
        }
        for (int idx = tid; idx < 32 * 64; idx += 256) {
            int k = idx >> 6, c = idx & 63;
            ws[idx] = opw[c * HIDC + kc + k];
        }
        __syncthreads();
#pragma unroll
        for (int k = 0; k < 32; k++) {
            float4 bx = *(const float4*)&xs[k * 128 + px];
            float4 a0 = *(const float4*)&ws[k * 64 + cb];
            float4 a1 = *(const float4*)&ws[k * 64 + cb + 4];
            float wv[8] = {a0.x, a0.y, a0.z, a0.w, a1.x, a1.y, a1.z, a1.w};
#pragma unroll
            for (int l = 0; l < 8; l++) {
                acc[l][0] += wv[l] * bx.x;
                acc[l][1] += wv[l] * bx.y;
                acc[l][2] += wv[l] * bx.z;
                acc[l][3] += wv[l] * bx.w;
            }
        }
    }
#pragma unroll
    for (int l = 0; l < 8; l++) {
        int c = cb + l;
        float gt = g_gterm[n * CINC + c];
        float4 v;
        v.x = acc[l][0] + gt;
        v.y = acc[l][1] + gt;
        v.z = acc[l][2] + gt;
        v.w = acc[l][3] + gt;
        *(float4*)&out[((size_t)n * CINC + c) * HWSZ + px0 + px] = v;
    }
}

// ================= launch =================
extern "C" void kernel_launch(void* const* d_in, const int* in_sizes, int n_in,
                              void* d_out, int out_size) {
    const float* x    = (const float*)d_in[0];
    const int*   ei   = (const int*)d_in[1];
    const float* conf = (const float*)d_in[2];
    const float* fe_w = (const float*)d_in[3];
    const float* fe_b = (const float*)d_in[4];
    const float* fe_g = (const float*)d_in[5];
    const float* fe_be= (const float*)d_in[6];
    const float* sp_w1= (const float*)d_in[7];
    const float* sp_b1= (const float*)d_in[8];
    const float* sp_g1= (const float*)d_in[9];
    const float* sp_e1= (const float*)d_in[10];
    const float* sp_w2= (const float*)d_in[11];
    const float* sp_b2= (const float*)d_in[12];
    const float* sp_g2= (const float*)d_in[13];
    const float* sp_e2= (const float*)d_in[14];
    const float* g1_lin=(const float*)d_in[15];
    const float* g1_as= (const float*)d_in[16];
    const float* g1_ad= (const float*)d_in[17];
    const float* g1_b = (const float*)d_in[18];
    const float* g2_lin=(const float*)d_in[19];
    const float* g2_as= (const float*)d_in[20];
    const float* g2_ad= (const float*)d_in[21];
    const float* g2_b = (const float*)d_in[22];
    const float* op_w = (const float*)d_in[23];
    const float* op_b = (const float*)d_in[24];
    float* out = (float*)d_out;

    void *pxp, *p1h, *p1l, *p2h, *p2l, *pw1h, *pw1l, *pw2h, *pw2l, *pXn, *pXg;
    cudaGetSymbolAddress(&pxp, g_xp);
    cudaGetSymbolAddress(&p1h, g_x1h);
    cudaGetSymbolAddress(&p1l, g_x1l);
    cudaGetSymbolAddress(&p2h, g_x2h);
    cudaGetSymbolAddress(&p2l, g_x2l);
    cudaGetSymbolAddress(&pw1h, g_w1h);
    cudaGetSymbolAddress(&pw1l, g_w1l);
    cudaGetSymbolAddress(&pw2h, g_w2h);
    cudaGetSymbolAddress(&pw2l, g_w2l);
    cudaGetSymbolAddress(&pXn, g_xnode);
    cudaGetSymbolAddress(&pXg, g_xg);
    float* xp = (float*)pxp;
    __nv_bfloat16* x1h = (__nv_bfloat16*)p1h;
    __nv_bfloat16* x1l = (__nv_bfloat16*)p1l;
    __nv_bfloat16* x2h = (__nv_bfloat16*)p2h;
    __nv_bfloat16* x2l = (__nv_bfloat16*)p2l;
    __nv_bfloat16* w1h = (__nv_bfloat16*)pw1h;
    __nv_bfloat16* w1l = (__nv_bfloat16*)pw1l;
    __nv_bfloat16* w2h = (__nv_bfloat16*)pw2h;
    __nv_bfloat16* w2l = (__nv_bfloat16*)pw2l;
    float* xnode = (float*)pXn;
    float* xg = (float*)pXg;

    cudaFuncSetAttribute(conv_mma_kernel<0>, cudaFuncAttributeMaxDynamicSharedMemorySize, CONV_SMEM);
    cudaFuncSetAttribute(conv_mma_kernel<1>, cudaFuncAttributeMaxDynamicSharedMemorySize, CONV_SMEM);

    const int WPN = (HIDC * HIDC * 9 + 255) / 256;

    fe_kernel<<<dim3(NN, 8), 256>>>(x, fe_w, fe_b, fe_g, fe_be, conf, x1h, x1l); // 0
    wprep_kernel<<<WPN, 256>>>(sp_w1, w1h, w1l);                              // 1
    wprep_kernel<<<WPN, 256>>>(sp_w2, w2h, w2l);                              // 2
    setup_kernel<<<1, 512>>>(ei);                                             // 3
    count_kernel<<<(TOTE + 255) / 256, 256>>>(ei);                            // 4
    conv_mma_kernel<0><<<NN * MTILES, 256, CONV_SMEM>>>(                      // 5 (ncu)
        x1h, x1l, w1h, w1l, sp_b1, sp_g1, sp_e1, x2h, x2l, nullptr);
    scan_kernel<<<1, 512>>>();                                                // 6
    scatter_kernel<<<(TOTE + 255) / 256, 256>>>(ei);                          // 7
    conv_mma_kernel<1><<<NN * MTILES, 256, CONV_SMEM>>>(                      // 8
        x2h, x2l, w2h, w2l, sp_b2, sp_g2, sp_e2, nullptr, nullptr, xp);
    pool_kernel<<<NN * HIDC, 128>>>(xp);                                      // 9
    gat_h_kernel<<<NN, 128>>>(xnode, g1_lin, g1_as, g1_ad);                   // 10
    gat_aggr_kernel<<<NN, 128>>>(g1_b, xg);                                   // 11
    gat_h_kernel<<<NN, 128>>>(xg, g2_lin, g2_as, g2_ad);                      // 12
    gat_aggr_kernel<<<NN, 128>>>(g2_b, xg);                                   // 13
    gterm_kernel<<<NN, 64>>>(op_w, op_b);                                     // 14
    op_kernel<<<dim3(NN, 8), 256>>>(xp, op_w, out);                           // 15

    (void)in_sizes; (void)n_in; (void)out_size;
}

// round 6
// speedup vs baseline: 3.3427x; 1.1580x over previous
#include <cuda_runtime.h>
#include <cuda_bf16.h>
#include <math.h>
#include <stdint.h>

#define NN   512
#define CINC 64
#define HIDC 128
#define HWSZ 1024
#define HH   32
#define WW   32
#define HEADS 4
#define NE   16384
#define TOTE (NE + NN)
#define POSN 1224          // padded positions per image: 36 rows x 34 cols
#define MTILES 9           // 9 M-tiles of 128 cover p in [0,1152)

// conv smem: A slabs 2 bufs x 2 terms x 200 rows x 80B = 64000
//            B stages 2 bufs x 2 terms x 128 rows x 80B = 40960
#define A_TERM  16000
#define A_BUF   32000
#define B_BASE  64000
#define B_TERM  10240
#define B_BUF   20480
#define CONV_SMEM (64000 + 40960)

// op smem: X (hw x ci) 2 terms x 128 x 272 = 69632; W (co x ci) 2 x 64 x 272
#define OP_RS   272
#define OPX_T   34816
#define OPW_0   69632
#define OPW_T   17408
#define OP_SMEM (69632 + 34816)

// ================= helpers =================
__device__ __forceinline__ uint32_t smem_u32(const void* p) {
    return (uint32_t)__cvta_generic_to_shared(p);
}
__device__ __forceinline__ void ldmx4(uint32_t* r, uint32_t a) {
    asm volatile("ldmatrix.sync.aligned.m8n8.x4.shared.b16 {%0,%1,%2,%3}, [%4];"
                 : "=r"(r[0]), "=r"(r[1]), "=r"(r[2]), "=r"(r[3]) : "r"(a));
}
__device__ __forceinline__ void mma16816(float* c, const uint32_t* a,
                                         uint32_t b0, uint32_t b1) {
    asm volatile(
        "mma.sync.aligned.m16n8k16.row.col.f32.bf16.bf16.f32 "
        "{%0,%1,%2,%3}, {%4,%5,%6,%7}, {%8,%9}, {%0,%1,%2,%3};"
        : "+f"(c[0]), "+f"(c[1]), "+f"(c[2]), "+f"(c[3])
        : "r"(a[0]), "r"(a[1]), "r"(a[2]), "r"(a[3]), "r"(b0), "r"(b1));
}
__device__ __forceinline__ void cpasync16(uint32_t sa, const void* g) {
    unsigned long long ga = (unsigned long long)__cvta_generic_to_global(g);
    asm volatile("cp.async.cg.shared.global [%0], [%1], 16;" :: "r"(sa), "l"(ga));
}
#define CP_COMMIT() asm volatile("cp.async.commit_group;")
#define CP_WAIT(N)  asm volatile("cp.async.wait_group %0;" :: "n"(N))

__device__ __forceinline__ uint32_t pack_bf2(__nv_bfloat16 a, __nv_bfloat16 b) {
    return (uint32_t)__bfloat16_as_ushort(a) | ((uint32_t)__bfloat16_as_ushort(b) << 16);
}

// ================= device scratch =================
__device__ __nv_bfloat16 g_x1h[(size_t)NN * POSN * HIDC]; // border stays zero
__device__ __nv_bfloat16 g_x1l[(size_t)NN * POSN * HIDC];
__device__ __nv_bfloat16 g_x2h[(size_t)NN * POSN * HIDC];
__device__ __nv_bfloat16 g_x2l[(size_t)NN * POSN * HIDC];
__device__ __nv_bfloat16 g_xph[(size_t)NN * HWSZ * HIDC]; // conv2 out [n][hw][ci]
__device__ __nv_bfloat16 g_xpl[(size_t)NN * HWSZ * HIDC];
__device__ __nv_bfloat16 g_w1h[9 * HIDC * HIDC];
__device__ __nv_bfloat16 g_w1l[9 * HIDC * HIDC];
__device__ __nv_bfloat16 g_w2h[9 * HIDC * HIDC];
__device__ __nv_bfloat16 g_w2l[9 * HIDC * HIDC];
__device__ __nv_bfloat16 g_woph[CINC * HIDC];
__device__ __nv_bfloat16 g_wopl[CINC * HIDC];
__device__ float g_xnode[NN * HIDC];
__device__ float g_hfeat[NN * HEADS * HIDC];
__device__ float g_as[NN * HEADS];
__device__ float g_ad[NN * HEADS];
__device__ float g_xg[NN * HIDC];
__device__ float g_gterm[NN * CINC];
__device__ int   g_cnt[NN];
__device__ int   g_row[NN + 1];
__device__ int   g_fill[NN];
__device__ int   g_csr[TOTE];
__device__ int   g_is64;

// ================= CSR build =================
__global__ void setup_kernel(const int* __restrict__ ei) {
    int t = threadIdx.x;
    if (t < NN) g_cnt[t] = 0;
    if (t == 0) {
        int acc = 0;
        for (int i = 0; i < 128; i++) acc |= ei[2 * i + 1];
        g_is64 = (acc == 0) ? 1 : 0;
    }
}
__device__ __forceinline__ void read_edge(const int* __restrict__ ei, int i,
                                          int is64, int& s, int& d) {
    if (i < NE) {
        if (is64) { s = ei[2 * i]; d = ei[2 * (NE + i)]; }
        else      { s = ei[i];     d = ei[NE + i]; }
    } else { s = i - NE; d = i - NE; }
}
__global__ void count_kernel(const int* __restrict__ ei) {
    int i = blockIdx.x * blockDim.x + threadIdx.x;
    if (i >= TOTE) return;
    int s, d; read_edge(ei, i, g_is64, s, d);
    atomicAdd(&g_cnt[d], 1);
}
__global__ void scan_kernel() {
    __shared__ int sc[NN];
    int t = threadIdx.x;
    int c = g_cnt[t];
    sc[t] = c; __syncthreads();
    for (int off = 1; off < NN; off <<= 1) {
        int v = (t >= off) ? sc[t - off] : 0;
        __syncthreads(); sc[t] += v; __syncthreads();
    }
    g_row[t + 1] = sc[t];
    if (t == 0) g_row[0] = 0;
    g_fill[t] = sc[t] - c;
}
__global__ void scatter_kernel(const int* __restrict__ ei) {
    int i = blockIdx.x * blockDim.x + threadIdx.x;
    if (i >= TOTE) return;
    int s, d; read_edge(ei, i, g_is64, s, d);
    int pos = atomicAdd(&g_fill[d], 1);
    g_csr[pos] = s;
}

// ================= weight prep =================
__global__ void wprep_kernel(const float* __restrict__ w,
                             __nv_bfloat16* __restrict__ bh,
                             __nv_bfloat16* __restrict__ bl) {
    int idx = blockIdx.x * 256 + threadIdx.x;
    if (idx >= HIDC * HIDC * 9) return;
    int tap = idx % 9;
    int ci = (idx / 9) % HIDC;
    int co = idx / (9 * HIDC);
    float v = w[idx];
    __nv_bfloat16 h = __float2bfloat16(v);
    float r = v - __bfloat162float(h);
    bh[(tap * HIDC + co) * HIDC + ci] = h;
    bl[(tap * HIDC + co) * HIDC + ci] = __float2bfloat16(r);
}
__global__ void wprep_op_kernel(const float* __restrict__ w) {
    int idx = blockIdx.x * 256 + threadIdx.x;
    if (idx >= CINC * HIDC) return;
    float v = w[idx];
    __nv_bfloat16 h = __float2bfloat16(v);
    g_woph[idx] = h;
    g_wopl[idx] = __float2bfloat16(v - __bfloat162float(h));
}

// ================= fe: 1x1 conv + BN + ReLU + conf -> padded bf16 hi/lo ===
__global__ __launch_bounds__(256) void fe_kernel(
    const float* __restrict__ x, const float* __restrict__ fw,
    const float* __restrict__ fb, const float* __restrict__ fg,
    const float* __restrict__ fbe, const float* __restrict__ conf,
    __nv_bfloat16* __restrict__ xh, __nv_bfloat16* __restrict__ xl) {
    __shared__ float xs[32 * 128];
    __shared__ float ws[32 * 128];
    int n = blockIdx.x, px0 = blockIdx.y * 128;
    int tid = threadIdx.x;
    int pg = tid & 31, og = tid >> 5;
    int px = pg * 4, ob = og * 16;
    float acc[16][4];
#pragma unroll
    for (int i = 0; i < 16; i++)
#pragma unroll
        for (int j = 0; j < 4; j++) acc[i][j] = 0.f;

    for (int kc = 0; kc < CINC; kc += 32) {
        __syncthreads();
        for (int idx = tid; idx < 32 * 128; idx += 256) {
            int k = idx >> 7, p = idx & 127;
            xs[idx] = x[(n * CINC + kc + k) * HWSZ + px0 + p];
            int o = idx & 127, k2 = idx >> 7;
            ws[idx] = fw[o * CINC + kc + k2];
        }
        __syncthreads();
#pragma unroll
        for (int k = 0; k < 32; k++) {
            float4 bx = *(const float4*)&xs[k * 128 + px];
#pragma unroll
            for (int jo = 0; jo < 4; jo++) {
                float4 av = *(const float4*)&ws[k * 128 + ob + jo * 4];
                float wv[4] = {av.x, av.y, av.z, av.w};
#pragma unroll
                for (int l = 0; l < 4; l++) {
                    acc[jo * 4 + l][0] += wv[l] * bx.x;
                    acc[jo * 4 + l][1] += wv[l] * bx.y;
                    acc[jo * 4 + l][2] += wv[l] * bx.z;
                    acc[jo * 4 + l][3] += wv[l] * bx.w;
                }
            }
        }
    }
    float4 cf = *(const float4*)&conf[n * HWSZ + px0 + px];
    float cfa[4] = {cf.x, cf.y, cf.z, cf.w};
    const float inv = rsqrtf(1.0f + 1e-5f);
    float sc16[16], sh16[16];
#pragma unroll
    for (int ol = 0; ol < 16; ol++) {
        int o = ob + ol;
        sc16[ol] = fg[o] * inv;
        sh16[ol] = fbe[o] + fb[o] * sc16[ol];
    }
#pragma unroll
    for (int j = 0; j < 4; j++) {
        int hw = px0 + px + j;
        int h = hw >> 5, w = hw & 31;
        size_t base = ((size_t)n * POSN + (h + 1) * 34 + (w + 1)) * HIDC + ob;
        uint32_t hv[8], lv[8];
#pragma unroll
        for (int q = 0; q < 8; q++) {
            float v0 = fmaxf(acc[2 * q][j]     * sc16[2 * q]     + sh16[2 * q],     0.f) * cfa[j];
            float v1 = fmaxf(acc[2 * q + 1][j] * sc16[2 * q + 1] + sh16[2 * q + 1], 0.f) * cfa[j];
            __nv_bfloat16 h0 = __float2bfloat16(v0);
            __nv_bfloat16 h1 = __float2bfloat16(v1);
            __nv_bfloat16 l0 = __float2bfloat16(v0 - __bfloat162float(h0));
            __nv_bfloat16 l1 = __float2bfloat16(v1 - __bfloat162float(h1));
            hv[q] = pack_bf2(h0, h1);
            lv[q] = pack_bf2(l0, l1);
        }
        *(uint4*)(xh + base)     = make_uint4(hv[0], hv[1], hv[2], hv[3]);
        *(uint4*)(xh + base + 8) = make_uint4(hv[4], hv[5], hv[6], hv[7]);
        *(uint4*)(xl + base)     = make_uint4(lv[0], lv[1], lv[2], lv[3]);
        *(uint4*)(xl + base + 8) = make_uint4(lv[4], lv[5], lv[6], lv[7]);
    }
}

// ================= mma.sync conv, A-slab reuse =================
// out[p, co] = sum_{tap,ci} Xpad[p + off(tap), ci] * W[tap, co, ci]
// ci chunks outer (4, A slab of 198 rows double-buffered),
// taps inner (9, B double-buffered). One cp.async group per stage.
template <int MODE>
__global__ __launch_bounds__(256, 2) void conv_mma_kernel(
    const __nv_bfloat16* __restrict__ Xh, const __nv_bfloat16* __restrict__ Xl,
    const __nv_bfloat16* __restrict__ Wh, const __nv_bfloat16* __restrict__ Wl,
    const float* __restrict__ bb, const float* __restrict__ gg,
    const float* __restrict__ be,
    __nv_bfloat16* __restrict__ Oh, __nv_bfloat16* __restrict__ Ol) {
    extern __shared__ __align__(16) char dsm[];
    __shared__ float s_sc[HIDC], s_sh[HIDC];

    int tid = threadIdx.x, lane = tid & 31, warp = tid >> 5;
    int warpm = warp >> 2, warpn = warp & 3;
    int n = blockIdx.x / MTILES, mt = blockIdx.x % MTILES;
    int pbase = mt * 128;

    if (tid < HIDC) {
        const float inv = rsqrtf(1.0f + 1e-5f);
        float sc = gg[tid] * inv;
        s_sc[tid] = sc;
        s_sh[tid] = be[tid] + bb[tid] * sc;
    }

    float C[4][4][4];
#pragma unroll
    for (int m = 0; m < 4; m++)
#pragma unroll
        for (int nt = 0; nt < 4; nt++)
#pragma unroll
            for (int r = 0; r < 4; r++) C[m][nt][r] = 0.f;

    uint32_t sbase = smem_u32(dsm);

    // A slab for ci-chunk cic: rows [pbase, pbase+198), cols cic*32..+32, 2 terms
    auto loadA = [&](int cic, int buf) {
        uint32_t s0 = sbase + buf * A_BUF;
        size_t gb = ((size_t)(n * POSN + pbase)) * HIDC + cic * 32;
#pragma unroll
        for (int i = 0; i < 7; i++) {
            int idx = i * 256 + tid;
            if (idx < 1584) {
                int term = idx >= 792;
                int idx2 = idx - term * 792;
                int r = idx2 >> 2, sg = idx2 & 3;
                const __nv_bfloat16* g = (term ? Xl : Xh) + gb + (size_t)r * HIDC + sg * 8;
                cpasync16(s0 + term * A_TERM + r * 80 + sg * 16, g);
            }
        }
    };
    // B stage (tap, cic): 128 co x 32 ci, 2 terms
    auto loadB = [&](int tap, int cic, int buf) {
        uint32_t s0 = sbase + B_BASE + buf * B_BUF;
        size_t gb = ((size_t)tap * HIDC) * HIDC + cic * 32;
#pragma unroll
        for (int i = 0; i < 4; i++) {
            int idx = i * 256 + tid;
            int term = idx >> 9;
            int r = (idx >> 2) & 127, sg = idx & 3;
            const __nv_bfloat16* g = (term ? Wl : Wh) + gb + (size_t)r * HIDC + sg * 8;
            cpasync16(s0 + term * B_TERM + r * 80 + sg * 16, g);
        }
    };

    int a_row = lane & 15, a_ko = (lane >> 4) * 16;
    int b_row = (lane & 7) + ((lane >> 4) & 1) * 8;
    int b_ko = ((lane >> 3) & 1) * 16;

    auto compute_stage = [&](int bufB, int bufA, int tapoff) {
        uint32_t sA = sbase + bufA * A_BUF;
        uint32_t sB = sbase + B_BASE + bufB * B_BUF;
#pragma unroll
        for (int ks = 0; ks < 2; ks++) {
            uint32_t ah[4][4], al[4][4];
#pragma unroll
            for (int m = 0; m < 4; m++) {
                uint32_t ra = (uint32_t)(tapoff + warpm * 64 + m * 16 + a_row) * 80 + ks * 32 + a_ko;
                ldmx4(ah[m], sA + ra);
                ldmx4(al[m], sA + A_TERM + ra);
            }
#pragma unroll
            for (int ntp = 0; ntp < 2; ntp++) {
                uint32_t rbh[4], rbl[4];
                uint32_t rb = (uint32_t)(warpn * 32 + ntp * 16 + b_row) * 80 + ks * 32 + b_ko;
                ldmx4(rbh, sB + rb);
                ldmx4(rbl, sB + B_TERM + rb);
#pragma unroll
                for (int q = 0; q < 2; q++) {
                    int nt = ntp * 2 + q;
#pragma unroll
                    for (int m = 0; m < 4; m++) {
                        mma16816(C[m][nt], ah[m], rbh[2 * q], rbh[2 * q + 1]);
                        mma16816(C[m][nt], ah[m], rbl[2 * q], rbl[2 * q + 1]);
                        mma16816(C[m][nt], al[m], rbh[2 * q], rbh[2 * q + 1]);
                    }
                }
            }
        }
    };

    // prologue group
    loadA(0, 0);
    loadB(0, 0, 0);
    CP_COMMIT();

#pragma unroll 1
    for (int s = 0; s < 36; s++) {
        int cic = s / 9, tap = s - cic * 9;
        // prefetch group for s+1 (+ next A slab at tap==0)
        if (s + 1 < 36) {
            int s1 = s + 1;
            int cic1 = s1 / 9;
            loadB(s1 - cic1 * 9, cic1, s1 & 1);
        }
        if (tap == 0 && cic < 3) loadA(cic + 1, (cic + 1) & 1);
        CP_COMMIT();
        CP_WAIT(1);
        __syncthreads();
        int tapoff = (tap / 3) * 34 + (tap % 3);
        compute_stage(s & 1, cic & 1, tapoff);
        __syncthreads();
    }

    // ---- epilogue ----
    int g4 = lane >> 2;
    int t2 = (lane & 3) * 2;
#pragma unroll
    for (int m = 0; m < 4; m++) {
#pragma unroll
        for (int nt = 0; nt < 4; nt++) {
            int co = warpn * 32 + nt * 8 + t2;
            float sc0 = s_sc[co], sh0 = s_sh[co];
            float sc1 = s_sc[co + 1], sh1 = s_sh[co + 1];
#pragma unroll
            for (int half = 0; half < 2; half++) {
                int p = pbase + warpm * 64 + m * 16 + g4 + half * 8;
                float v0 = C[m][nt][half * 2 + 0] * sc0 + sh0;
                float v1 = C[m][nt][half * 2 + 1] * sc1 + sh1;
                int h = p / 34, w = p % 34;
                bool valid = (w < 32) && (h < 32);
                v0 = valid ? fmaxf(v0, 0.f) : 0.f;
                v1 = valid ? fmaxf(v1, 0.f) : 0.f;
                __nv_bfloat16 h0 = __float2bfloat16(v0);
                __nv_bfloat16 h1 = __float2bfloat16(v1);
                __nv_bfloat16 l0 = __float2bfloat16(v0 - __bfloat162float(h0));
                __nv_bfloat16 l1 = __float2bfloat16(v1 - __bfloat162float(h1));
                if (MODE == 0) {
                    size_t q2 = ((size_t)n * POSN + p + 35) * HIDC + co;
                    *(uint32_t*)(Oh + q2) = pack_bf2(h0, h1);
                    *(uint32_t*)(Ol + q2) = pack_bf2(l0, l1);
                } else if (valid) {
                    size_t q2 = ((size_t)n * HWSZ + h * WW + w) * HIDC + co;
                    *(uint32_t*)(Oh + q2) = pack_bf2(h0, h1);
                    *(uint32_t*)(Ol + q2) = pack_bf2(l0, l1);
                }
            }
        }
    }
}

// ================= global average pool (from hi/lo [n][hw][ci]) ==========
__global__ __launch_bounds__(512) void pool_kernel(
    const __nv_bfloat16* __restrict__ Xh, const __nv_bfloat16* __restrict__ Xl) {
    __shared__ float red[512];
    int n = blockIdx.x, tid = threadIdx.x;
    int ci = tid & 127, qr = tid >> 7;
    float acc = 0.f;
    size_t base = ((size_t)n * HWSZ + qr * 256) * HIDC + ci;
#pragma unroll 4
    for (int i = 0; i < 256; i++) {
        size_t idx = base + (size_t)i * HIDC;
        acc += __bfloat162float(Xh[idx]) + __bfloat162float(Xl[idx]);
    }
    red[tid] = acc;
    __syncthreads();
    if (tid < 128)
        g_xnode[n * HIDC + tid] =
            (red[tid] + red[tid + 128] + red[tid + 256] + red[tid + 384]) * (1.f / 1024.f);
}

// ================= GAT =================
__global__ __launch_bounds__(128) void gat_h_kernel(
    const float* __restrict__ xin, const float* __restrict__ lin,
    const float* __restrict__ asw, const float* __restrict__ adw) {
    int n = blockIdx.x, t = threadIdx.x;
    __shared__ float xr[HIDC];
    __shared__ float red[HIDC];
    xr[t] = xin[n * HIDC + t];
    __syncthreads();
    float hv[HEADS];
#pragma unroll
    for (int j = 0; j < HEADS; j++) {
        int col = j * HIDC + t;
        float s = 0.f;
        for (int k = 0; k < HIDC; k++) s += xr[k] * lin[k * (HEADS * HIDC) + col];
        hv[j] = s;
        g_hfeat[n * (HEADS * HIDC) + col] = s;
    }
#pragma unroll
    for (int j = 0; j < HEADS; j++) {
        red[t] = hv[j] * asw[j * HIDC + t];
        __syncthreads();
        for (int off = 64; off > 0; off >>= 1) {
            if (t < off) red[t] += red[t + off];
            __syncthreads();
        }
        if (t == 0) g_as[n * HEADS + j] = red[0];
        __syncthreads();
        red[t] = hv[j] * adw[j * HIDC + t];
        __syncthreads();
        for (int off = 64; off > 0; off >>= 1) {
            if (t < off) red[t] += red[t + off];
            __syncthreads();
        }
        if (t == 0) g_ad[n * HEADS + j] = red[0];
        __syncthreads();
    }
}

__global__ __launch_bounds__(128) void gat_aggr_kernel(
    const float* __restrict__ bias, float* __restrict__ xout) {
    int n = blockIdx.x, t = threadIdx.x;
    float adn[HEADS];
#pragma unroll
    for (int j = 0; j < HEADS; j++) adn[j] = g_ad[n * HEADS + j];
    int rs = g_row[n], re = g_row[n + 1];
    float mx[HEADS] = {-1e30f, -1e30f, -1e30f, -1e30f};
    for (int ei = rs; ei < re; ei++) {
        int s = g_csr[ei];
#pragma unroll
        for (int j = 0; j < HEADS; j++) {
            float e = g_as[s * HEADS + j] + adn[j];
            e = (e > 0.f) ? e : 0.2f * e;
            mx[j] = fmaxf(mx[j], e);
        }
    }
    float den[HEADS] = {0.f, 0.f, 0.f, 0.f};
    float acc[HEADS] = {0.f, 0.f, 0.f, 0.f};
    for (int ei = rs; ei < re; ei++) {
        int s = g_csr[ei];
#pragma unroll
        for (int j = 0; j < HEADS; j++) {
            float e = g_as[s * HEADS + j] + adn[j];
            e = (e > 0.f) ? e : 0.2f * e;
            float ex = __expf(e - mx[j]);
            den[j] += ex;
            acc[j] += ex * g_hfeat[s * (HEADS * HIDC) + j * HIDC + t];
        }
    }
    float o = 0.f;
#pragma unroll
    for (int j = 0; j < HEADS; j++) o += acc[j] / (den[j] + 1e-16f);
    o = o * 0.25f + bias[t];
    xout[n * HIDC + t] = fmaxf(o, 0.f);
}

// ================= gterm =================
__global__ __launch_bounds__(64) void gterm_kernel(
    const float* __restrict__ opw, const float* __restrict__ opb) {
    int n = blockIdx.x, t = threadIdx.x;
    __shared__ float xg[HIDC];
    xg[t] = g_xg[n * HIDC + t];
    xg[t + 64] = g_xg[n * HIDC + t + 64];
    __syncthreads();
    float s = opb[t];
    for (int o = 0; o < HIDC; o++) s += xg[o] * opw[t * HIDC + o];
    g_gterm[n * CINC + t] = s;
}

// ================= op: out = gterm + xp @ op_w^T (mma.sync) =================
// M = co (64, 4 m16), N = hw (128 per block, 16 n8). 8 warps: warpm=warp>>1,
// warpn=warp&1 (64-hw half). K=128, single-shot smem load.
__global__ __launch_bounds__(256) void op_mma_kernel(
    const __nv_bfloat16* __restrict__ Xh, const __nv_bfloat16* __restrict__ Xl,
    float* __restrict__ out) {
    extern __shared__ __align__(16) char dsm[];
    int tid = threadIdx.x, lane = tid & 31, warp = tid >> 5;
    int warpm = warp >> 1, warpn = warp & 1;
    int n = blockIdx.x, hw0 = blockIdx.y * 128;
    uint32_t sbase = smem_u32(dsm);

    // X (hw x ci): 128 rows x 16 segs x 2 terms
#pragma unroll
    for (int i = 0; i < 16; i++) {
        int idx = i * 256 + tid;
        int term = idx >> 11;
        int idx2 = idx & 2047;
        int r = idx2 >> 4, sg = idx2 & 15;
        const __nv_bfloat16* g = (term ? Xl : Xh) +
            ((size_t)n * HWSZ + hw0 + r) * HIDC + sg * 8;
        cpasync16(sbase + term * OPX_T + r * OP_RS + sg * 16, g);
    }
    // W (co x ci): 64 rows x 16 segs x 2 terms
#pragma unroll
    for (int i = 0; i < 8; i++) {
        int idx = i * 256 + tid;
        int term = idx >> 10;
        int r = (idx >> 4) & 63, sg = idx & 15;
        const __nv_bfloat16* g = (term ? g_wopl : g_woph) + r * HIDC + sg * 8;
        cpasync16(sbase + OPW_0 + term * OPW_T + r * OP_RS + sg * 16, g);
    }
    CP_COMMIT();

    float C[8][4];
#pragma unroll
    for (int nt = 0; nt < 8; nt++)
#pragma unroll
        for (int r = 0; r < 4; r++) C[nt][r] = 0.f;

    int a_row = lane & 15, a_ko = (lane >> 4) * 16;
    int b_row = (lane & 7) + ((lane >> 4) & 1) * 8;
    int b_ko = ((lane >> 3) & 1) * 16;

    CP_WAIT(0);
    __syncthreads();

#pragma unroll 1
    for (int kc = 0; kc < 8; kc++) {
        uint32_t awh[4], awl[4];
        uint32_t ra = (uint32_t)(warpm * 16 + a_row) * OP_RS + kc * 32 + a_ko;
        ldmx4(awh, sbase + OPW_0 + ra);
        ldmx4(awl, sbase + OPW_0 + OPW_T + ra);
#pragma unroll
        for (int ntp = 0; ntp < 4; ntp++) {
            uint32_t xbh[4], xbl[4];
            uint32_t rb = (uint32_t)(warpn * 64 + ntp * 16 + b_row) * OP_RS + kc * 32 + b_ko;
            ldmx4(xbh, sbase + rb);
            ldmx4(xbl, sbase + OPX_T + rb);
#pragma unroll
            for (int q = 0; q < 2; q++) {
                int nt = ntp * 2 + q;
                mma16816(C[nt], awh, xbh[2 * q], xbh[2 * q + 1]);
                mma16816(C[nt], awh, xbl[2 * q], xbl[2 * q + 1]);
                mma16816(C[nt], awl, xbh[2 * q], xbh[2 * q + 1]);
            }
        }
    }

    // epilogue: C rows = co, cols = hw (coalesced f32x2 stores)
    int g4 = lane >> 2, t2 = (lane & 3) * 2;
    int co_a = warpm * 16 + g4;
    int co_b = co_a + 8;
    float gta = g_gterm[n * CINC + co_a];
    float gtb = g_gterm[n * CINC + co_b];
#pragma unroll
    for (int nt = 0; nt < 8; nt++) {
        int hw = hw0 + warpn * 64 + nt * 8 + t2;
        float2 va = make_float2(C[nt][0] + gta, C[nt][1] + gta);
        float2 vb = make_float2(C[nt][2] + gtb, C[nt][3] + gtb);
        *(float2*)&out[((size_t)n * CINC + co_a) * HWSZ + hw] = va;
        *(float2*)&out[((size_t)n * CINC + co_b) * HWSZ + hw] = vb;
    }
}

// ================= launch =================
extern "C" void kernel_launch(void* const* d_in, const int* in_sizes, int n_in,
                              void* d_out, int out_size) {
    const float* x    = (const float*)d_in[0];
    const int*   ei   = (const int*)d_in[1];
    const float* conf = (const float*)d_in[2];
    const float* fe_w = (const float*)d_in[3];
    const float* fe_b = (const float*)d_in[4];
    const float* fe_g = (const float*)d_in[5];
    const float* fe_be= (const float*)d_in[6];
    const float* sp_w1= (const float*)d_in[7];
    const float* sp_b1= (const float*)d_in[8];
    const float* sp_g1= (const float*)d_in[9];
    const float* sp_e1= (const float*)d_in[10];
    const float* sp_w2= (const float*)d_in[11];
    const float* sp_b2= (const float*)d_in[12];
    const float* sp_g2= (const float*)d_in[13];
    const float* sp_e2= (const float*)d_in[14];
    const float* g1_lin=(const float*)d_in[15];
    const float* g1_as= (const float*)d_in[16];
    const float* g1_ad= (const float*)d_in[17];
    const float* g1_b = (const float*)d_in[18];
    const float* g2_lin=(const float*)d_in[19];
    const float* g2_as= (const float*)d_in[20];
    const float* g2_ad= (const float*)d_in[21];
    const float* g2_b = (const float*)d_in[22];
    const float* op_w = (const float*)d_in[23];
    const float* op_b = (const float*)d_in[24];
    float* out = (float*)d_out;

    void *p1h, *p1l, *p2h, *p2l, *pph, *ppl, *pw1h, *pw1l, *pw2h, *pw2l, *pXn, *pXg;
    cudaGetSymbolAddress(&p1h, g_x1h);
    cudaGetSymbolAddress(&p1l, g_x1l);
    cudaGetSymbolAddress(&p2h, g_x2h);
    cudaGetSymbolAddress(&p2l, g_x2l);
    cudaGetSymbolAddress(&pph, g_xph);
    cudaGetSymbolAddress(&ppl, g_xpl);
    cudaGetSymbolAddress(&pw1h, g_w1h);
    cudaGetSymbolAddress(&pw1l, g_w1l);
    cudaGetSymbolAddress(&pw2h, g_w2h);
    cudaGetSymbolAddress(&pw2l, g_w2l);
    cudaGetSymbolAddress(&pXn, g_xnode);
    cudaGetSymbolAddress(&pXg, g_xg);
    __nv_bfloat16* x1h = (__nv_bfloat16*)p1h;
    __nv_bfloat16* x1l = (__nv_bfloat16*)p1l;
    __nv_bfloat16* x2h = (__nv_bfloat16*)p2h;
    __nv_bfloat16* x2l = (__nv_bfloat16*)p2l;
    __nv_bfloat16* xph = (__nv_bfloat16*)pph;
    __nv_bfloat16* xpl = (__nv_bfloat16*)ppl;
    __nv_bfloat16* w1h = (__nv_bfloat16*)pw1h;
    __nv_bfloat16* w1l = (__nv_bfloat16*)pw1l;
    __nv_bfloat16* w2h = (__nv_bfloat16*)pw2h;
    __nv_bfloat16* w2l = (__nv_bfloat16*)pw2l;
    float* xnode = (float*)pXn;
    float* xg = (float*)pXg;

    cudaFuncSetAttribute(conv_mma_kernel<0>, cudaFuncAttributeMaxDynamicSharedMemorySize, CONV_SMEM);
    cudaFuncSetAttribute(conv_mma_kernel<1>, cudaFuncAttributeMaxDynamicSharedMemorySize, CONV_SMEM);
    cudaFuncSetAttribute(op_mma_kernel, cudaFuncAttributeMaxDynamicSharedMemorySize, OP_SMEM);

    const int WPN = (HIDC * HIDC * 9 + 255) / 256;

    fe_kernel<<<dim3(NN, 8), 256>>>(x, fe_w, fe_b, fe_g, fe_be, conf, x1h, x1l); // 0
    wprep_kernel<<<WPN, 256>>>(sp_w1, w1h, w1l);                              // 1
    wprep_kernel<<<WPN, 256>>>(sp_w2, w2h, w2l);                              // 2
    wprep_op_kernel<<<(CINC * HIDC + 255) / 256, 256>>>(op_w);                // 3
    setup_kernel<<<1, 512>>>(ei);                                             // 4
    conv_mma_kernel<0><<<NN * MTILES, 256, CONV_SMEM>>>(                      // 5 (ncu)
        x1h, x1l, w1h, w1l, sp_b1, sp_g1, sp_e1, x2h, x2l);
    count_kernel<<<(TOTE + 255) / 256, 256>>>(ei);                            // 6
    scan_kernel<<<1, 512>>>();                                                // 7
    scatter_kernel<<<(TOTE + 255) / 256, 256>>>(ei);                          // 8
    conv_mma_kernel<1><<<NN * MTILES, 256, CONV_SMEM>>>(                      // 9
        x2h, x2l, w2h, w2l, sp_b2, sp_g2, sp_e2, xph, xpl);
    pool_kernel<<<NN, 512>>>(xph, xpl);                                       // 10
    gat_h_kernel<<<NN, 128>>>(xnode, g1_lin, g1_as, g1_ad);                   // 11
    gat_aggr_kernel<<<NN, 128>>>(g1_b, xg);                                   // 12
    gat_h_kernel<<<NN, 128>>>(xg, g2_lin, g2_as, g2_ad);                      // 13
    gat_aggr_kernel<<<NN, 128>>>(g2_b, xg);                                   // 14
    gterm_kernel<<<NN, 64>>>(op_w, op_b);                                     // 15
    op_mma_kernel<<<dim3(NN, 8), 256, OP_SMEM>>>(xph, xpl, out);              // 16

    (void)in_sizes; (void)n_in; (void)out_size;
}

// round 7
// speedup vs baseline: 4.4384x; 1.3278x over previous
#include <cuda_runtime.h>
#include <cuda_fp16.h>
#include <math.h>
#include <stdint.h>

#define NN   512
#define CINC 64
#define HIDC 128
#define HWSZ 1024
#define HH   32
#define WW   32
#define HEADS 4
#define NE   16384
#define TOTE (NE + NN)
#define POSN 1224          // padded positions per image: 36 rows x 34 cols
#define MTILES 9           // 9 M-tiles of 128 cover p in [0,1152)

// conv smem: A slabs 2 bufs x 2 terms x 200 rows x 80B = 64000
//            B stages 2 bufs x 1 term x 128 rows x 80B = 20480
#define A_TERM  16000
#define A_BUF   32000
#define B_BASE  64000
#define B_BUF   10240
#define CONV_SMEM (64000 + 20480)

// op smem: X (hw x ci) 2 terms x 128 x 272 = 69632; W (co x ci) 2 x 64 x 272
#define OP_RS   272
#define OPX_T   34816
#define OPW_0   69632
#define OPW_T   17408
#define OP_SMEM (69632 + 34816)

// ================= helpers =================
__device__ __forceinline__ uint32_t smem_u32(const void* p) {
    return (uint32_t)__cvta_generic_to_shared(p);
}
__device__ __forceinline__ void ldmx4(uint32_t* r, uint32_t a) {
    asm volatile("ldmatrix.sync.aligned.m8n8.x4.shared.b16 {%0,%1,%2,%3}, [%4];"
                 : "=r"(r[0]), "=r"(r[1]), "=r"(r[2]), "=r"(r[3]) : "r"(a));
}
__device__ __forceinline__ void mma16816(float* c, const uint32_t* a,
                                         uint32_t b0, uint32_t b1) {
    asm volatile(
        "mma.sync.aligned.m16n8k16.row.col.f32.f16.f16.f32 "
        "{%0,%1,%2,%3}, {%4,%5,%6,%7}, {%8,%9}, {%0,%1,%2,%3};"
        : "+f"(c[0]), "+f"(c[1]), "+f"(c[2]), "+f"(c[3])
        : "r"(a[0]), "r"(a[1]), "r"(a[2]), "r"(a[3]), "r"(b0), "r"(b1));
}
__device__ __forceinline__ void cpasync16(uint32_t sa, const void* g) {
    unsigned long long ga = (unsigned long long)__cvta_generic_to_global(g);
    asm volatile("cp.async.cg.shared.global [%0], [%1], 16;" :: "r"(sa), "l"(ga));
}
#define CP_COMMIT() asm volatile("cp.async.commit_group;")
#define CP_WAIT(N)  asm volatile("cp.async.wait_group %0;" :: "n"(N))

__device__ __forceinline__ uint32_t pack_h2(__half a, __half b) {
    return (uint32_t)__half_as_ushort(a) | ((uint32_t)__half_as_ushort(b) << 16);
}

// ================= device scratch =================
__device__ __half g_x1h[(size_t)NN * POSN * HIDC]; // border stays zero
__device__ __half g_x1l[(size_t)NN * POSN * HIDC];
__device__ __half g_x2h[(size_t)NN * POSN * HIDC];
__device__ __half g_x2l[(size_t)NN * POSN * HIDC];
__device__ __half g_xph[(size_t)NN * HWSZ * HIDC]; // conv2 out [n][hw][ci]
__device__ __half g_xpl[(size_t)NN * HWSZ * HIDC];
__device__ __half g_w1h[9 * HIDC * HIDC];
__device__ __half g_w2h[9 * HIDC * HIDC];
__device__ __half g_woph[CINC * HIDC];
__device__ __half g_wopl[CINC * HIDC];
__device__ float g_xnode[NN * HIDC];
__device__ float g_hfeat[NN * HEADS * HIDC];
__device__ float g_as[NN * HEADS];
__device__ float g_ad[NN * HEADS];
__device__ float g_xg[NN * HIDC];
__device__ float g_gterm[NN * CINC];
__device__ int   g_cnt[NN];
__device__ int   g_row[NN + 1];
__device__ int   g_fill[NN];
__device__ int   g_csr[TOTE];
__device__ int   g_is64;

// ================= CSR build =================
__global__ void setup_kernel(const int* __restrict__ ei) {
    int t = threadIdx.x;
    if (t < NN) g_cnt[t] = 0;
    if (t == 0) {
        int acc = 0;
        for (int i = 0; i < 128; i++) acc |= ei[2 * i + 1];
        g_is64 = (acc == 0) ? 1 : 0;
    }
}
__device__ __forceinline__ void read_edge(const int* __restrict__ ei, int i,
                                          int is64, int& s, int& d) {
    if (i < NE) {
        if (is64) { s = ei[2 * i]; d = ei[2 * (NE + i)]; }
        else      { s = ei[i];     d = ei[NE + i]; }
    } else { s = i - NE; d = i - NE; }
}
__global__ void count_kernel(const int* __restrict__ ei) {
    int i = blockIdx.x * blockDim.x + threadIdx.x;
    if (i >= TOTE) return;
    int s, d; read_edge(ei, i, g_is64, s, d);
    atomicAdd(&g_cnt[d], 1);
}
__global__ void scan_kernel() {
    __shared__ int sc[NN];
    int t = threadIdx.x;
    int c = g_cnt[t];
    sc[t] = c; __syncthreads();
    for (int off = 1; off < NN; off <<= 1) {
        int v = (t >= off) ? sc[t - off] : 0;
        __syncthreads(); sc[t] += v; __syncthreads();
    }
    g_row[t + 1] = sc[t];
    if (t == 0) g_row[0] = 0;
    g_fill[t] = sc[t] - c;
}
__global__ void scatter_kernel(const int* __restrict__ ei) {
    int i = blockIdx.x * blockDim.x + threadIdx.x;
    if (i >= TOTE) return;
    int s, d; read_edge(ei, i, g_is64, s, d);
    int pos = atomicAdd(&g_fill[d], 1);
    g_csr[pos] = s;
}

// ================= weight prep: fp32 [co][ci][tap] -> fp16 [tap][co][ci]
__global__ void wprep_kernel(const float* __restrict__ w,
                             __half* __restrict__ bh) {
    int idx = blockIdx.x * 256 + threadIdx.x;
    if (idx >= HIDC * HIDC * 9) return;
    int tap = idx % 9;
    int ci = (idx / 9) % HIDC;
    int co = idx / (9 * HIDC);
    bh[(tap * HIDC + co) * HIDC + ci] = __float2half_rn(w[idx]);
}
__global__ void wprep_op_kernel(const float* __restrict__ w) {
    int idx = blockIdx.x * 256 + threadIdx.x;
    if (idx >= CINC * HIDC) return;
    float v = w[idx];
    __half h = __float2half_rn(v);
    g_woph[idx] = h;
    g_wopl[idx] = __float2half_rn(v - __half2float(h));
}

// ================= fe: 1x1 conv + BN + ReLU + conf -> padded fp16 hi/lo ===
__global__ __launch_bounds__(256) void fe_kernel(
    const float* __restrict__ x, const float* __restrict__ fw,
    const float* __restrict__ fb, const float* __restrict__ fg,
    const float* __restrict__ fbe, const float* __restrict__ conf,
    __half* __restrict__ xh, __half* __restrict__ xl) {
    __shared__ float xs[32 * 128];
    __shared__ float ws[32 * 128];
    int n = blockIdx.x, px0 = blockIdx.y * 128;
    int tid = threadIdx.x;
    int pg = tid & 31, og = tid >> 5;
    int px = pg * 4, ob = og * 16;
    float acc[16][4];
#pragma unroll
    for (int i = 0; i < 16; i++)
#pragma unroll
        for (int j = 0; j < 4; j++) acc[i][j] = 0.f;

    for (int kc = 0; kc < CINC; kc += 32) {
        __syncthreads();
        for (int idx = tid; idx < 32 * 128; idx += 256) {
            int k = idx >> 7, p = idx & 127;
            xs[idx] = x[(n * CINC + kc + k) * HWSZ + px0 + p];
            int o = idx & 127, k2 = idx >> 7;
            ws[idx] = fw[o * CINC + kc + k2];
        }
        __syncthreads();
#pragma unroll
        for (int k = 0; k < 32; k++) {
            float4 bx = *(const float4*)&xs[k * 128 + px];
#pragma unroll
            for (int jo = 0; jo < 4; jo++) {
                float4 av = *(const float4*)&ws[k * 128 + ob + jo * 4];
                float wv[4] = {av.x, av.y, av.z, av.w};
#pragma unroll
                for (int l = 0; l < 4; l++) {
                    acc[jo * 4 + l][0] += wv[l] * bx.x;
                    acc[jo * 4 + l][1] += wv[l] * bx.y;
                    acc[jo * 4 + l][2] += wv[l] * bx.z;
                    acc[jo * 4 + l][3] += wv[l] * bx.w;
                }
            }
        }
    }
    float4 cf = *(const float4*)&conf[n * HWSZ + px0 + px];
    float cfa[4] = {cf.x, cf.y, cf.z, cf.w};
    const float inv = rsqrtf(1.0f + 1e-5f);
    float sc16[16], sh16[16];
#pragma unroll
    for (int ol = 0; ol < 16; ol++) {
        int o = ob + ol;
        sc16[ol] = fg[o] * inv;
        sh16[ol] = fbe[o] + fb[o] * sc16[ol];
    }
#pragma unroll
    for (int j = 0; j < 4; j++) {
        int hw = px0 + px + j;
        int h = hw >> 5, w = hw & 31;
        size_t base = ((size_t)n * POSN + (h + 1) * 34 + (w + 1)) * HIDC + ob;
        uint32_t hv[8], lv[8];
#pragma unroll
        for (int q = 0; q < 8; q++) {
            float v0 = fmaxf(acc[2 * q][j]     * sc16[2 * q]     + sh16[2 * q],     0.f) * cfa[j];
            float v1 = fmaxf(acc[2 * q + 1][j] * sc16[2 * q + 1] + sh16[2 * q + 1], 0.f) * cfa[j];
            __half h0 = __float2half_rn(v0);
            __half h1 = __float2half_rn(v1);
            __half l0 = __float2half_rn(v0 - __half2float(h0));
            __half l1 = __float2half_rn(v1 - __half2float(h1));
            hv[q] = pack_h2(h0, h1);
            lv[q] = pack_h2(l0, l1);
        }
        *(uint4*)(xh + base)     = make_uint4(hv[0], hv[1], hv[2], hv[3]);
        *(uint4*)(xh + base + 8) = make_uint4(hv[4], hv[5], hv[6], hv[7]);
        *(uint4*)(xl + base)     = make_uint4(lv[0], lv[1], lv[2], lv[3]);
        *(uint4*)(xl + base + 8) = make_uint4(lv[4], lv[5], lv[6], lv[7]);
    }
}

// ================= mma.sync conv, fp16 2-term, A-slab reuse =================
// out[p, co] = sum_{tap,ci} Xpad[p + off(tap), ci] * W[tap, co, ci]
// x split hi/lo fp16 (exact), w single fp16. 2 MMAs per tile-product.
template <int MODE>
__global__ __launch_bounds__(256, 2) void conv_mma_kernel(
    const __half* __restrict__ Xh, const __half* __restrict__ Xl,
    const __half* __restrict__ Wh,
    const float* __restrict__ bb, const float* __restrict__ gg,
    const float* __restrict__ be,
    __half* __restrict__ Oh, __half* __restrict__ Ol) {
    extern __shared__ __align__(16) char dsm[];
    __shared__ float s_sc[HIDC], s_sh[HIDC];

    int tid = threadIdx.x, lane = tid & 31, warp = tid >> 5;
    int warpm = warp >> 2, warpn = warp & 3;
    int n = blockIdx.x / MTILES, mt = blockIdx.x % MTILES;
    int pbase = mt * 128;

    if (tid < HIDC) {
        const float inv = rsqrtf(1.0f + 1e-5f);
        float sc = gg[tid] * inv;
        s_sc[tid] = sc;
        s_sh[tid] = be[tid] + bb[tid] * sc;
    }

    float C[4][4][4];
#pragma unroll
    for (int m = 0; m < 4; m++)
#pragma unroll
        for (int nt = 0; nt < 4; nt++)
#pragma unroll
            for (int r = 0; r < 4; r++) C[m][nt][r] = 0.f;

    uint32_t sbase = smem_u32(dsm);

    // A slab for ci-chunk cic: rows [pbase, pbase+198), cols cic*32..+32, 2 terms
    auto loadA = [&](int cic, int buf) {
        uint32_t s0 = sbase + buf * A_BUF;
        size_t gb = ((size_t)(n * POSN + pbase)) * HIDC + cic * 32;
#pragma unroll
        for (int i = 0; i < 7; i++) {
            int idx = i * 256 + tid;
            if (idx < 1584) {
                int term = idx >= 792;
                int idx2 = idx - term * 792;
                int r = idx2 >> 2, sg = idx2 & 3;
                const __half* g = (term ? Xl : Xh) + gb + (size_t)r * HIDC + sg * 8;
                cpasync16(s0 + term * A_TERM + r * 80 + sg * 16, g);
            }
        }
    };
    // B stage (tap, cic): 128 co x 32 ci, single term
    auto loadB = [&](int tap, int cic, int buf) {
        uint32_t s0 = sbase + B_BASE + buf * B_BUF;
        size_t gb = ((size_t)tap * HIDC) * HIDC + cic * 32;
#pragma unroll
        for (int i = 0; i < 2; i++) {
            int idx = i * 256 + tid;
            int r = idx >> 2, sg = idx & 3;
            cpasync16(s0 + r * 80 + sg * 16, Wh + gb + (size_t)r * HIDC + sg * 8);
        }
    };

    int a_row = lane & 15, a_ko = (lane >> 4) * 16;
    int b_row = (lane & 7) + ((lane >> 4) & 1) * 8;
    int b_ko = ((lane >> 3) & 1) * 16;

    auto compute_stage = [&](int bufB, int bufA, int tapoff) {
        uint32_t sA = sbase + bufA * A_BUF;
        uint32_t sB = sbase + B_BASE + bufB * B_BUF;
#pragma unroll
        for (int ks = 0; ks < 2; ks++) {
            uint32_t ah[4][4], al[4][4];
#pragma unroll
            for (int m = 0; m < 4; m++) {
                uint32_t ra = (uint32_t)(tapoff + warpm * 64 + m * 16 + a_row) * 80 + ks * 32 + a_ko;
                ldmx4(ah[m], sA + ra);
                ldmx4(al[m], sA + A_TERM + ra);
            }
#pragma unroll
            for (int ntp = 0; ntp < 2; ntp++) {
                uint32_t rbh[4];
                uint32_t rb = (uint32_t)(warpn * 32 + ntp * 16 + b_row) * 80 + ks * 32 + b_ko;
                ldmx4(rbh, sB + rb);
#pragma unroll
                for (int q = 0; q < 2; q++) {
                    int nt = ntp * 2 + q;
#pragma unroll
                    for (int m = 0; m < 4; m++) {
                        mma16816(C[m][nt], ah[m], rbh[2 * q], rbh[2 * q + 1]);
                        mma16816(C[m][nt], al[m], rbh[2 * q], rbh[2 * q + 1]);
                    }
                }
            }
        }
    };

    // prologue group
    loadA(0, 0);
    loadB(0, 0, 0);
    CP_COMMIT();

#pragma unroll 1
    for (int s = 0; s < 36; s++) {
        int cic = s / 9, tap = s - cic * 9;
        if (s + 1 < 36) {
            int s1 = s + 1;
            int cic1 = s1 / 9;
            loadB(s1 - cic1 * 9, cic1, s1 & 1);
        }
        if (tap == 0 && cic < 3) loadA(cic + 1, (cic + 1) & 1);
        CP_COMMIT();
        CP_WAIT(1);
        __syncthreads();
        int tapoff = (tap / 3) * 34 + (tap % 3);
        compute_stage(s & 1, cic & 1, tapoff);
        __syncthreads();
    }

    // ---- epilogue ----
    int g4 = lane >> 2;
    int t2 = (lane & 3) * 2;
#pragma unroll
    for (int m = 0; m < 4; m++) {
#pragma unroll
        for (int nt = 0; nt < 4; nt++) {
            int co = warpn * 32 + nt * 8 + t2;
            float sc0 = s_sc[co], sh0 = s_sh[co];
            float sc1 = s_sc[co + 1], sh1 = s_sh[co + 1];
#pragma unroll
            for (int half = 0; half < 2; half++) {
                int p = pbase + warpm * 64 + m * 16 + g4 + half * 8;
                float v0 = C[m][nt][half * 2 + 0] * sc0 + sh0;
                float v1 = C[m][nt][half * 2 + 1] * sc1 + sh1;
                int h = p / 34, w = p % 34;
                bool valid = (w < 32) && (h < 32);
                v0 = valid ? fmaxf(v0, 0.f) : 0.f;
                v1 = valid ? fmaxf(v1, 0.f) : 0.f;
                __half h0 = __float2half_rn(v0);
                __half h1 = __float2half_rn(v1);
                __half l0 = __float2half_rn(v0 - __half2float(h0));
                __half l1 = __float2half_rn(v1 - __half2float(h1));
                if (MODE == 0) {
                    size_t q2 = ((size_t)n * POSN + p + 35) * HIDC + co;
                    *(uint32_t*)(Oh + q2) = pack_h2(h0, h1);
                    *(uint32_t*)(Ol + q2) = pack_h2(l0, l1);
                } else if (valid) {
                    size_t q2 = ((size_t)n * HWSZ + h * WW + w) * HIDC + co;
                    *(uint32_t*)(Oh + q2) = pack_h2(h0, h1);
                    *(uint32_t*)(Ol + q2) = pack_h2(l0, l1);
                }
            }
        }
    }
}

// ================= global average pool (from hi/lo [n][hw][ci]) ==========
__global__ __launch_bounds__(512) void pool_kernel(
    const __half* __restrict__ Xh, const __half* __restrict__ Xl) {
    __shared__ float red[512];
    int n = blockIdx.x, tid = threadIdx.x;
    int ci = tid & 127, qr = tid >> 7;
    float acc = 0.f;
    size_t base = ((size_t)n * HWSZ + qr * 256) * HIDC + ci;
#pragma unroll 4
    for (int i = 0; i < 256; i++) {
        size_t idx = base + (size_t)i * HIDC;
        acc += __half2float(Xh[idx]) + __half2float(Xl[idx]);
    }
    red[tid] = acc;
    __syncthreads();
    if (tid < 128)
        g_xnode[n * HIDC + tid] =
            (red[tid] + red[tid + 128] + red[tid + 256] + red[tid + 384]) * (1.f / 1024.f);
}

// ================= GAT =================
__global__ __launch_bounds__(128) void gat_h_kernel(
    const float* __restrict__ xin, const float* __restrict__ lin,
    const float* __restrict__ asw, const float* __restrict__ adw) {
    int n = blockIdx.x, t = threadIdx.x;
    __shared__ float xr[HIDC];
    __shared__ float red[HIDC];
    xr[t] = xin[n * HIDC + t];
    __syncthreads();
    float hv[HEADS];
#pragma unroll
    for (int j = 0; j < HEADS; j++) {
        int col = j * HIDC + t;
        float s = 0.f;
        for (int k = 0; k < HIDC; k++) s += xr[k] * lin[k * (HEADS * HIDC) + col];
        hv[j] = s;
        g_hfeat[n * (HEADS * HIDC) + col] = s;
    }
#pragma unroll
    for (int j = 0; j < HEADS; j++) {
        red[t] = hv[j] * asw[j * HIDC + t];
        __syncthreads();
        for (int off = 64; off > 0; off >>= 1) {
            if (t < off) red[t] += red[t + off];
            __syncthreads();
        }
        if (t == 0) g_as[n * HEADS + j] = red[0];
        __syncthreads();
        red[t] = hv[j] * adw[j * HIDC + t];
        __syncthreads();
        for (int off = 64; off > 0; off >>= 1) {
            if (t < off) red[t] += red[t + off];
            __syncthreads();
        }
        if (t == 0) g_ad[n * HEADS + j] = red[0];
        __syncthreads();
    }
}

__global__ __launch_bounds__(128) void gat_aggr_kernel(
    const float* __restrict__ bias, float* __restrict__ xout) {
    int n = blockIdx.x, t = threadIdx.x;
    float adn[HEADS];
#pragma unroll
    for (int j = 0; j < HEADS; j++) adn[j] = g_ad[n * HEADS + j];
    int rs = g_row[n], re = g_row[n + 1];
    float mx[HEADS] = {-1e30f, -1e30f, -1e30f, -1e30f};
    for (int ei = rs; ei < re; ei++) {
        int s = g_csr[ei];
#pragma unroll
        for (int j = 0; j < HEADS; j++) {
            float e = g_as[s * HEADS + j] + adn[j];
            e = (e > 0.f) ? e : 0.2f * e;
            mx[j] = fmaxf(mx[j], e);
        }
    }
    float den[HEADS] = {0.f, 0.f, 0.f, 0.f};
    float acc[HEADS] = {0.f, 0.f, 0.f, 0.f};
    for (int ei = rs; ei < re; ei++) {
        int s = g_csr[ei];
#pragma unroll
        for (int j = 0; j < HEADS; j++) {
            float e = g_as[s * HEADS + j] + adn[j];
            e = (e > 0.f) ? e : 0.2f * e;
            float ex = __expf(e - mx[j]);
            den[j] += ex;
            acc[j] += ex * g_hfeat[s * (HEADS * HIDC) + j * HIDC + t];
        }
    }
    float o = 0.f;
#pragma unroll
    for (int j = 0; j < HEADS; j++) o += acc[j] / (den[j] + 1e-16f);
    o = o * 0.25f + bias[t];
    xout[n * HIDC + t] = fmaxf(o, 0.f);
}

// ================= gterm =================
__global__ __launch_bounds__(64) void gterm_kernel(
    const float* __restrict__ opw, const float* __restrict__ opb) {
    int n = blockIdx.x, t = threadIdx.x;
    __shared__ float xg[HIDC];
    xg[t] = g_xg[n * HIDC + t];
    xg[t + 64] = g_xg[n * HIDC + t + 64];
    __syncthreads();
    float s = opb[t];
    for (int o = 0; o < HIDC; o++) s += xg[o] * opw[t * HIDC + o];
    g_gterm[n * CINC + t] = s;
}

// ================= op: out = gterm + xp @ op_w^T (mma.sync fp16 3-term) ====
__global__ __launch_bounds__(256) void op_mma_kernel(
    const __half* __restrict__ Xh, const __half* __restrict__ Xl,
    float* __restrict__ out) {
    extern __shared__ __align__(16) char dsm[];
    int tid = threadIdx.x, lane = tid & 31, warp = tid >> 5;
    int warpm = warp >> 1, warpn = warp & 1;
    int n = blockIdx.x, hw0 = blockIdx.y * 128;
    uint32_t sbase = smem_u32(dsm);

    // X (hw x ci): 128 rows x 16 segs x 2 terms
#pragma unroll
    for (int i = 0; i < 16; i++) {
        int idx = i * 256 + tid;
        int term = idx >> 11;
        int idx2 = idx & 2047;
        int r = idx2 >> 4, sg = idx2 & 15;
        const __half* g = (term ? Xl : Xh) +
            ((size_t)n * HWSZ + hw0 + r) * HIDC + sg * 8;
        cpasync16(sbase + term * OPX_T + r * OP_RS + sg * 16, g);
    }
    // W (co x ci): 64 rows x 16 segs x 2 terms
#pragma unroll
    for (int i = 0; i < 8; i++) {
        int idx = i * 256 + tid;
        int term = idx >> 10;
        int r = (idx >> 4) & 63, sg = idx & 15;
        const __half* g = (term ? g_wopl : g_woph) + r * HIDC + sg * 8;
        cpasync16(sbase + OPW_0 + term * OPW_T + r * OP_RS + sg * 16, g);
    }
    CP_COMMIT();

    float C[8][4];
#pragma unroll
    for (int nt = 0; nt < 8; nt++)
#pragma unroll
        for (int r = 0; r < 4; r++) C[nt][r] = 0.f;

    int a_row = lane & 15, a_ko = (lane >> 4) * 16;
    int b_row = (lane & 7) + ((lane >> 4) & 1) * 8;
    int b_ko = ((lane >> 3) & 1) * 16;

    CP_WAIT(0);
    __syncthreads();

#pragma unroll 1
    for (int kc = 0; kc < 8; kc++) {
        uint32_t awh[4], awl[4];
        uint32_t ra = (uint32_t)(warpm * 16 + a_row) * OP_RS + kc * 32 + a_ko;
        ldmx4(awh, sbase + OPW_0 + ra);
        ldmx4(awl, sbase + OPW_0 + OPW_T + ra);
#pragma unroll
        for (int ntp = 0; ntp < 4; ntp++) {
            uint32_t xbh[4], xbl[4];
            uint32_t rb = (uint32_t)(warpn * 64 + ntp * 16 + b_row) * OP_RS + kc * 32 + b_ko;
            ldmx4(xbh, sbase + rb);
            ldmx4(xbl, sbase + OPX_T + rb);
#pragma unroll
            for (int q = 0; q < 2; q++) {
                int nt = ntp * 2 + q;
                mma16816(C[nt], awh, xbh[2 * q], xbh[2 * q + 1]);
                mma16816(C[nt], awh, xbl[2 * q], xbl[2 * q + 1]);
                mma16816(C[nt], awl, xbh[2 * q], xbh[2 * q + 1]);
            }
        }
    }

    int g4 = lane >> 2, t2 = (lane & 3) * 2;
    int co_a = warpm * 16 + g4;
    int co_b = co_a + 8;
    float gta = g_gterm[n * CINC + co_a];
    float gtb = g_gterm[n * CINC + co_b];
#pragma unroll
    for (int nt = 0; nt < 8; nt++) {
        int hw = hw0 + warpn * 64 + nt * 8 + t2;
        float2 va = make_float2(C[nt][0] + gta, C[nt][1] + gta);
        float2 vb = make_float2(C[nt][2] + gtb, C[nt][3] + gtb);
        *(float2*)&out[((size_t)n * CINC + co_a) * HWSZ + hw] = va;
        *(float2*)&out[((size_t)n * CINC + co_b) * HWSZ + hw] = vb;
    }
}

// ================= launch =================
extern "C" void kernel_launch(void* const* d_in, const int* in_sizes, int n_in,
                              void* d_out, int out_size) {
    const float* x    = (const float*)d_in[0];
    const int*   ei   = (const int*)d_in[1];
    const float* conf = (const float*)d_in[2];
    const float* fe_w = (const float*)d_in[3];
    const float* fe_b = (const float*)d_in[4];
    const float* fe_g = (const float*)d_in[5];
    const float* fe_be= (const float*)d_in[6];
    const float* sp_w1= (const float*)d_in[7];
    const float* sp_b1= (const float*)d_in[8];
    const float* sp_g1= (const float*)d_in[9];
    const float* sp_e1= (const float*)d_in[10];
    const float* sp_w2= (const float*)d_in[11];
    const float* sp_b2= (const float*)d_in[12];
    const float* sp_g2= (const float*)d_in[13];
    const float* sp_e2= (const float*)d_in[14];
    const float* g1_lin=(const float*)d_in[15];
    const float* g1_as= (const float*)d_in[16];
    const float* g1_ad= (const float*)d_in[17];
    const float* g1_b = (const float*)d_in[18];
    const float* g2_lin=(const float*)d_in[19];
    const float* g2_as= (const float*)d_in[20];
    const float* g2_ad= (const float*)d_in[21];
    const float* g2_b = (const float*)d_in[22];
    const float* op_w = (const float*)d_in[23];
    const float* op_b = (const float*)d_in[24];
    float* out = (float*)d_out;

    void *p1h, *p1l, *p2h, *p2l, *pph, *ppl, *pw1h, *pw2h, *pXn, *pXg;
    cudaGetSymbolAddress(&p1h, g_x1h);
    cudaGetSymbolAddress(&p1l, g_x1l);
    cudaGetSymbolAddress(&p2h, g_x2h);
    cudaGetSymbolAddress(&p2l, g_x2l);
    cudaGetSymbolAddress(&pph, g_xph);
    cudaGetSymbolAddress(&ppl, g_xpl);
    cudaGetSymbolAddress(&pw1h, g_w1h);
    cudaGetSymbolAddress(&pw2h, g_w2h);
    cudaGetSymbolAddress(&pXn, g_xnode);
    cudaGetSymbolAddress(&pXg, g_xg);
    __half* x1h = (__half*)p1h;
    __half* x1l = (__half*)p1l;
    __half* x2h = (__half*)p2h;
    __half* x2l = (__half*)p2l;
    __half* xph = (__half*)pph;
    __half* xpl = (__half*)ppl;
    __half* w1h = (__half*)pw1h;
    __half* w2h = (__half*)pw2h;
    float* xnode = (float*)pXn;
    float* xg = (float*)pXg;

    cudaFuncSetAttribute(conv_mma_kernel<0>, cudaFuncAttributeMaxDynamicSharedMemorySize, CONV_SMEM);
    cudaFuncSetAttribute(conv_mma_kernel<1>, cudaFuncAttributeMaxDynamicSharedMemorySize, CONV_SMEM);
    cudaFuncSetAttribute(op_mma_kernel, cudaFuncAttributeMaxDynamicSharedMemorySize, OP_SMEM);

    const int WPN = (HIDC * HIDC * 9 + 255) / 256;

    fe_kernel<<<dim3(NN, 8), 256>>>(x, fe_w, fe_b, fe_g, fe_be, conf, x1h, x1l); // 0
    wprep_kernel<<<WPN, 256>>>(sp_w1, w1h);                                   // 1
    wprep_kernel<<<WPN, 256>>>(sp_w2, w2h);                                   // 2
    conv_mma_kernel<0><<<NN * MTILES, 256, CONV_SMEM>>>(                      // 3 (ncu)
        x1h, x1l, w1h, sp_b1, sp_g1, sp_e1, x2h, x2l);
    wprep_op_kernel<<<(CINC * HIDC + 255) / 256, 256>>>(op_w);                // 4
    setup_kernel<<<1, 512>>>(ei);                                             // 5
    count_kernel<<<(TOTE + 255) / 256, 256>>>(ei);                            // 6
    scan_kernel<<<1, 512>>>();                                                // 7
    scatter_kernel<<<(TOTE + 255) / 256, 256>>>(ei);                          // 8
    conv_mma_kernel<1><<<NN * MTILES, 256, CONV_SMEM>>>(                      // 9
        x2h, x2l, w2h, sp_b2, sp_g2, sp_e2, xph, xpl);
    pool_kernel<<<NN, 512>>>(xph, xpl);                                       // 10
    gat_h_kernel<<<NN, 128>>>(xnode, g1_lin, g1_as, g1_ad);                   // 11
    gat_aggr_kernel<<<NN, 128>>>(g1_b, xg);                                   // 12
    gat_h_kernel<<<NN, 128>>>(xg, g2_lin, g2_as, g2_ad);                      // 13
    gat_aggr_kernel<<<NN, 128>>>(g2_b, xg);                                   // 14
    gterm_kernel<<<NN, 64>>>(op_w, op_b);                                     // 15
    op_mma_kernel<<<dim3(NN, 8), 256, OP_SMEM>>>(xph, xpl, out);              // 16

    (void)in_sizes; (void)n_in; (void)out_size;
}

// round 8
// speedup vs baseline: 4.8701x; 1.0973x over previous
#include <cuda_runtime.h>
#include <cuda_fp16.h>
#include <math.h>
#include <stdint.h>

#define NN   512
#define CINC 64
#define HIDC 128
#define HWSZ 1024
#define HH   32
#define WW   32
#define HEADS 4
#define NE   16384
#define TOTE (NE + NN)
#define POSN 1224          // padded positions per image: 36 rows x 34 cols
#define MTILES 9           // 9 M-tiles of 128 cover p in [0,1152)

// conv smem: A slabs 2 bufs x 2 terms x 200 rows x 80B = 64000
//            B ring   3 bufs x 128 rows x 80B = 30720
#define A_TERM  16000
#define A_BUF   32000
#define B_BASE  64000
#define B_BUF   10240
#define CONV_SMEM (64000 + 30720)

// fe smem: Xh/Xl 128px x 144B, Wh 128co x 144B
#define FE_RS   144
#define FE_XH   0
#define FE_XL   18432
#define FE_W    36864
#define FE_SMEM 55296

// op smem: X (hw x ci) 2 terms x 128 x 272 = 69632; W (co x ci) 2 x 64 x 272
#define OP_RS   272
#define OPX_T   34816
#define OPW_0   69632
#define OPW_T   17408
#define OP_SMEM (69632 + 34816)

// ================= helpers =================
__device__ __forceinline__ uint32_t smem_u32(const void* p) {
    return (uint32_t)__cvta_generic_to_shared(p);
}
__device__ __forceinline__ void ldmx4(uint32_t* r, uint32_t a) {
    asm volatile("ldmatrix.sync.aligned.m8n8.x4.shared.b16 {%0,%1,%2,%3}, [%4];"
                 : "=r"(r[0]), "=r"(r[1]), "=r"(r[2]), "=r"(r[3]) : "r"(a));
}
__device__ __forceinline__ void mma16816(float* c, const uint32_t* a,
                                         uint32_t b0, uint32_t b1) {
    asm volatile(
        "mma.sync.aligned.m16n8k16.row.col.f32.f16.f16.f32 "
        "{%0,%1,%2,%3}, {%4,%5,%6,%7}, {%8,%9}, {%0,%1,%2,%3};"
        : "+f"(c[0]), "+f"(c[1]), "+f"(c[2]), "+f"(c[3])
        : "r"(a[0]), "r"(a[1]), "r"(a[2]), "r"(a[3]), "r"(b0), "r"(b1));
}
__device__ __forceinline__ void cpasync16(uint32_t sa, const void* g) {
    unsigned long long ga = (unsigned long long)__cvta_generic_to_global(g);
    asm volatile("cp.async.cg.shared.global [%0], [%1], 16;" :: "r"(sa), "l"(ga));
}
#define CP_COMMIT() asm volatile("cp.async.commit_group;")
#define CP_WAIT(N)  asm volatile("cp.async.wait_group %0;" :: "n"(N))

__device__ __forceinline__ uint32_t pack_h2(__half a, __half b) {
    return (uint32_t)__half_as_ushort(a) | ((uint32_t)__half_as_ushort(b) << 16);
}

// ================= device scratch =================
__device__ __half g_x1h[(size_t)NN * POSN * HIDC]; // border stays zero
__device__ __half g_x1l[(size_t)NN * POSN * HIDC];
__device__ __half g_x2h[(size_t)NN * POSN * HIDC];
__device__ __half g_x2l[(size_t)NN * POSN * HIDC];
__device__ __half g_xph[(size_t)NN * HWSZ * HIDC]; // conv2 out [n][hw][ci]
__device__ __half g_xpl[(size_t)NN * HWSZ * HIDC];
__device__ __half g_w1h[9 * HIDC * HIDC];
__device__ __half g_w2h[9 * HIDC * HIDC];
__device__ __half g_woph[CINC * HIDC];
__device__ __half g_wopl[CINC * HIDC];
__device__ float g_xnode[NN * HIDC];
__device__ float g_hfeat[NN * HEADS * HIDC];
__device__ float g_as[NN * HEADS];
__device__ float g_ad[NN * HEADS];
__device__ float g_xg[NN * HIDC];
__device__ float g_gterm[NN * CINC];
__device__ int   g_cnt[NN];
__device__ int   g_row[NN + 1];
__device__ int   g_fill[NN];
__device__ int   g_csr[TOTE];
__device__ int   g_is64;

// ================= CSR build =================
__global__ void setup_kernel(const int* __restrict__ ei) {
    int t = threadIdx.x;
    if (t < NN) g_cnt[t] = 0;
    if (t == 0) {
        int acc = 0;
        for (int i = 0; i < 128; i++) acc |= ei[2 * i + 1];
        g_is64 = (acc == 0) ? 1 : 0;
    }
}
__device__ __forceinline__ void read_edge(const int* __restrict__ ei, int i,
                                          int is64, int& s, int& d) {
    if (i < NE) {
        if (is64) { s = ei[2 * i]; d = ei[2 * (NE + i)]; }
        else      { s = ei[i];     d = ei[NE + i]; }
    } else { s = i - NE; d = i - NE; }
}
__global__ void count_kernel(const int* __restrict__ ei) {
    int i = blockIdx.x * blockDim.x + threadIdx.x;
    if (i >= TOTE) return;
    int s, d; read_edge(ei, i, g_is64, s, d);
    atomicAdd(&g_cnt[d], 1);
}
__global__ void scan_kernel() {
    __shared__ int sc[NN];
    int t = threadIdx.x;
    int c = g_cnt[t];
    sc[t] = c; __syncthreads();
    for (int off = 1; off < NN; off <<= 1) {
        int v = (t >= off) ? sc[t - off] : 0;
        __syncthreads(); sc[t] += v; __syncthreads();
    }
    g_row[t + 1] = sc[t];
    if (t == 0) g_row[0] = 0;
    g_fill[t] = sc[t] - c;
}
__global__ void scatter_kernel(const int* __restrict__ ei) {
    int i = blockIdx.x * blockDim.x + threadIdx.x;
    if (i >= TOTE) return;
    int s, d; read_edge(ei, i, g_is64, s, d);
    int pos = atomicAdd(&g_fill[d], 1);
    g_csr[pos] = s;
}

// ================= weight prep: fp32 [co][ci][tap] -> fp16 [tap][co][ci]
__global__ void wprep_kernel(const float* __restrict__ w,
                             __half* __restrict__ bh) {
    int idx = blockIdx.x * 256 + threadIdx.x;
    if (idx >= HIDC * HIDC * 9) return;
    int tap = idx % 9;
    int ci = (idx / 9) % HIDC;
    int co = idx / (9 * HIDC);
    bh[(tap * HIDC + co) * HIDC + ci] = __float2half_rn(w[idx]);
}
__global__ void wprep_op_kernel(const float* __restrict__ w) {
    int idx = blockIdx.x * 256 + threadIdx.x;
    if (idx >= CINC * HIDC) return;
    float v = w[idx];
    __half h = __float2half_rn(v);
    g_woph[idx] = h;
    g_wopl[idx] = __float2half_rn(v - __half2float(h));
}

// ================= fe (mma.sync): 1x1 conv + BN + ReLU + conf =============
// M=128 px, N=128 co, K=64 ci. x split hi/lo fp16, W single fp16.
// 8 warps 2(m:px64) x 4(n:co32). Output -> padded fp16 hi/lo layout.
__global__ __launch_bounds__(256) void fe_mma_kernel(
    const float* __restrict__ x, const float* __restrict__ fw,
    const float* __restrict__ fb, const float* __restrict__ fg,
    const float* __restrict__ fbe, const float* __restrict__ conf,
    __half* __restrict__ xh, __half* __restrict__ xl) {
    extern __shared__ __align__(16) char dsm[];
    __shared__ float s_conf[128];
    __shared__ float s_sc[HIDC], s_sh[HIDC];

    int tid = threadIdx.x, lane = tid & 31, warp = tid >> 5;
    int warpm = warp >> 2, warpn = warp & 3;
    int n = blockIdx.x, px0 = blockIdx.y * 128;
    uint32_t sbase = smem_u32(dsm);

    if (tid < 128) {
        s_conf[tid] = conf[n * HWSZ + px0 + tid];
        const float inv = rsqrtf(1.0f + 1e-5f);
        float sc = fg[tid] * inv;
        s_sc[tid] = sc;
        s_sh[tid] = fbe[tid] + fb[tid] * sc;
    }

    // stage W: [co][ci] fp32 -> fp16 smem [co*144 + ci*2]
#pragma unroll
    for (int i = 0; i < 16; i++) {
        int idx = i * 256 + tid;
        int cp = idx & 31, co = idx >> 5;
        float2 v = *(const float2*)(fw + co * CINC + cp * 2);
        *(uint32_t*)(dsm + FE_W + co * FE_RS + cp * 4) =
            pack_h2(__float2half_rn(v.x), __float2half_rn(v.y));
    }
    // stage X transposed: x[n][ci][px] fp32 -> smem [px*144 + ci*2] hi/lo
#pragma unroll
    for (int i = 0; i < 16; i++) {
        int idx = i * 256 + tid;
        int p = idx & 127, cp = idx >> 7;
        float a = x[((size_t)n * CINC + 2 * cp) * HWSZ + px0 + p];
        float b = x[((size_t)n * CINC + 2 * cp + 1) * HWSZ + px0 + p];
        __half ha = __float2half_rn(a), hb = __float2half_rn(b);
        __half la = __float2half_rn(a - __half2float(ha));
        __half lb = __float2half_rn(b - __half2float(hb));
        *(uint32_t*)(dsm + FE_XH + p * FE_RS + cp * 4) = pack_h2(ha, hb);
        *(uint32_t*)(dsm + FE_XL + p * FE_RS + cp * 4) = pack_h2(la, lb);
    }
    __syncthreads();

    float C[4][4][4];
#pragma unroll
    for (int m = 0; m < 4; m++)
#pragma unroll
        for (int nt = 0; nt < 4; nt++)
#pragma unroll
            for (int r = 0; r < 4; r++) C[m][nt][r] = 0.f;

    int a_row = lane & 15, a_ko = (lane >> 4) * 16;
    int b_row = (lane & 7) + ((lane >> 4) & 1) * 8;
    int b_ko = ((lane >> 3) & 1) * 16;

#pragma unroll
    for (int kq = 0; kq < 4; kq++) {
        uint32_t ah[4][4], al[4][4];
#pragma unroll
        for (int m = 0; m < 4; m++) {
            uint32_t ra = (uint32_t)(warpm * 64 + m * 16 + a_row) * FE_RS + kq * 32 + a_ko;
            ldmx4(ah[m], sbase + FE_XH + ra);
            ldmx4(al[m], sbase + FE_XL + ra);
        }
#pragma unroll
        for (int ntp = 0; ntp < 2; ntp++) {
            uint32_t bw[4];
            uint32_t rb = (uint32_t)(warpn * 32 + ntp * 16 + b_row) * FE_RS + kq * 32 + b_ko;
            ldmx4(bw, sbase + FE_W + rb);
#pragma unroll
            for (int q = 0; q < 2; q++) {
                int nt = ntp * 2 + q;
#pragma unroll
                for (int m = 0; m < 4; m++) {
                    mma16816(C[m][nt], ah[m], bw[2 * q], bw[2 * q + 1]);
                    mma16816(C[m][nt], al[m], bw[2 * q], bw[2 * q + 1]);
                }
            }
        }
    }

    // epilogue: BN + ReLU + conf, write padded hi/lo
    int g4 = lane >> 2, t2 = (lane & 3) * 2;
#pragma unroll
    for (int m = 0; m < 4; m++) {
#pragma unroll
        for (int nt = 0; nt < 4; nt++) {
            int co = warpn * 32 + nt * 8 + t2;
            float sc0 = s_sc[co], sh0 = s_sh[co];
            float sc1 = s_sc[co + 1], sh1 = s_sh[co + 1];
#pragma unroll
            for (int half = 0; half < 2; half++) {
                int pl = warpm * 64 + m * 16 + g4 + half * 8;
                float cf = s_conf[pl];
                float v0 = fmaxf(C[m][nt][half * 2 + 0] * sc0 + sh0, 0.f) * cf;
                float v1 = fmaxf(C[m][nt][half * 2 + 1] * sc1 + sh1, 0.f) * cf;
                __half h0 = __float2half_rn(v0);
                __half h1 = __float2half_rn(v1);
                __half l0 = __float2half_rn(v0 - __half2float(h0));
                __half l1 = __float2half_rn(v1 - __half2float(h1));
                int hw = px0 + pl;
                int h = hw >> 5, w = hw & 31;
                size_t q2 = ((size_t)n * POSN + (h + 1) * 34 + (w + 1)) * HIDC + co;
                *(uint32_t*)(xh + q2) = pack_h2(h0, h1);
                *(uint32_t*)(xl + q2) = pack_h2(l0, l1);
            }
        }
    }
}

// ================= mma.sync conv, fp16 2-term, one-sync pipeline ==========
// out[p, co] = sum_{tap,ci} Xpad[p + off(tap), ci] * W[tap, co, ci]
// A slabs (198 rows) double-buffered per ci-chunk; B 3-deep ring;
// ONE __syncthreads per stage (load into (s+2)%3 == (s-1)%3 is safe after
// the top barrier: all warps finished reading it in stage s-1).
template <int MODE>
__global__ __launch_bounds__(256, 2) void conv_mma_kernel(
    const __half* __restrict__ Xh, const __half* __restrict__ Xl,
    const __half* __restrict__ Wh,
    const float* __restrict__ bb, const float* __restrict__ gg,
    const float* __restrict__ be,
    __half* __restrict__ Oh, __half* __restrict__ Ol) {
    extern __shared__ __align__(16) char dsm[];
    __shared__ float s_sc[HIDC], s_sh[HIDC];

    int tid = threadIdx.x, lane = tid & 31, warp = tid >> 5;
    int warpm = warp >> 2, warpn = warp & 3;
    int n = blockIdx.x / MTILES, mt = blockIdx.x % MTILES;
    int pbase = mt * 128;

    if (tid < HIDC) {
        const float inv = rsqrtf(1.0f + 1e-5f);
        float sc = gg[tid] * inv;
        s_sc[tid] = sc;
        s_sh[tid] = be[tid] + bb[tid] * sc;
    }

    float C[4][4][4];
#pragma unroll
    for (int m = 0; m < 4; m++)
#pragma unroll
        for (int nt = 0; nt < 4; nt++)
#pragma unroll
            for (int r = 0; r < 4; r++) C[m][nt][r] = 0.f;

    uint32_t sbase = smem_u32(dsm);

    auto loadA = [&](int cic, int buf) {
        uint32_t s0 = sbase + buf * A_BUF;
        size_t gb = ((size_t)(n * POSN + pbase)) * HIDC + cic * 32;
#pragma unroll
        for (int i = 0; i < 7; i++) {
            int idx = i * 256 + tid;
            if (idx < 1584) {
                int term = idx >= 792;
                int idx2 = idx - term * 792;
                int r = idx2 >> 2, sg = idx2 & 3;
                const __half* g = (term ? Xl : Xh) + gb + (size_t)r * HIDC + sg * 8;
                cpasync16(s0 + term * A_TERM + r * 80 + sg * 16, g);
            }
        }
    };
    auto loadB = [&](int tap, int cic, int buf) {
        uint32_t s0 = sbase + B_BASE + buf * B_BUF;
        size_t gb = ((size_t)tap * HIDC) * HIDC + cic * 32;
#pragma unroll
        for (int i = 0; i < 2; i++) {
            int idx = i * 256 + tid;
            int r = idx >> 2, sg = idx & 3;
            cpasync16(s0 + r * 80 + sg * 16, Wh + gb + (size_t)r * HIDC + sg * 8);
        }
    };

    int a_row = lane & 15, a_ko = (lane >> 4) * 16;
    int b_row = (lane & 7) + ((lane >> 4) & 1) * 8;
    int b_ko = ((lane >> 3) & 1) * 16;

    auto compute_stage = [&](int bufB, int bufA, int tapoff) {
        uint32_t sA = sbase + bufA * A_BUF;
        uint32_t sB = sbase + B_BASE + bufB * B_BUF;
#pragma unroll
        for (int ks = 0; ks < 2; ks++) {
            uint32_t ah[4][4], al[4][4];
#pragma unroll
            for (int m = 0; m < 4; m++) {
                uint32_t ra = (uint32_t)(tapoff + warpm * 64 + m * 16 + a_row) * 80 + ks * 32 + a_ko;
                ldmx4(ah[m], sA + ra);
                ldmx4(al[m], sA + A_TERM + ra);
            }
#pragma unroll
            for (int ntp = 0; ntp < 2; ntp++) {
                uint32_t rbh[4];
                uint32_t rb = (uint32_t)(warpn * 32 + ntp * 16 + b_row) * 80 + ks * 32 + b_ko;
                ldmx4(rbh, sB + rb);
#pragma unroll
                for (int q = 0; q < 2; q++) {
                    int nt = ntp * 2 + q;
#pragma unroll
                    for (int m = 0; m < 4; m++) {
                        mma16816(C[m][nt], ah[m], rbh[2 * q], rbh[2 * q + 1]);
                        mma16816(C[m][nt], al[m], rbh[2 * q], rbh[2 * q + 1]);
                    }
                }
            }
        }
    };

    // prologue: stages 0,1 in flight
    loadA(0, 0);
    loadB(0, 0, 0);
    CP_COMMIT();
    loadB(1, 0, 1);
    CP_COMMIT();

#pragma unroll 1
    for (int s = 0; s < 36; s++) {
        int cic = s / 9, tap = s - cic * 9;
        CP_WAIT(1);
        __syncthreads();
        int tapoff = (tap / 3) * 34 + (tap % 3);
        compute_stage(s % 3, cic & 1, tapoff);
        if (s + 2 < 36) {
            int s2 = s + 2;
            int cic2 = s2 / 9;
            loadB(s2 - cic2 * 9, cic2, s2 % 3);
        }
        if (tap == 0 && cic < 3) loadA(cic + 1, (cic + 1) & 1);
        CP_COMMIT();
    }

    // ---- epilogue ----
    int g4 = lane >> 2;
    int t2 = (lane & 3) * 2;
#pragma unroll
    for (int m = 0; m < 4; m++) {
#pragma unroll
        for (int nt = 0; nt < 4; nt++) {
            int co = warpn * 32 + nt * 8 + t2;
            float sc0 = s_sc[co], sh0 = s_sh[co];
            float sc1 = s_sc[co + 1], sh1 = s_sh[co + 1];
#pragma unroll
            for (int half = 0; half < 2; half++) {
                int p = pbase + warpm * 64 + m * 16 + g4 + half * 8;
                float v0 = C[m][nt][half * 2 + 0] * sc0 + sh0;
                float v1 = C[m][nt][half * 2 + 1] * sc1 + sh1;
                int h = p / 34, w = p % 34;
                bool valid = (w < 32) && (h < 32);
                v0 = valid ? fmaxf(v0, 0.f) : 0.f;
                v1 = valid ? fmaxf(v1, 0.f) : 0.f;
                __half h0 = __float2half_rn(v0);
                __half h1 = __float2half_rn(v1);
                __half l0 = __float2half_rn(v0 - __half2float(h0));
                __half l1 = __float2half_rn(v1 - __half2float(h1));
                if (MODE == 0) {
                    size_t q2 = ((size_t)n * POSN + p + 35) * HIDC + co;
                    *(uint32_t*)(Oh + q2) = pack_h2(h0, h1);
                    *(uint32_t*)(Ol + q2) = pack_h2(l0, l1);
                } else if (valid) {
                    size_t q2 = ((size_t)n * HWSZ + h * WW + w) * HIDC + co;
                    *(uint32_t*)(Oh + q2) = pack_h2(h0, h1);
                    *(uint32_t*)(Ol + q2) = pack_h2(l0, l1);
                }
            }
        }
    }
}

// ================= global average pool (from hi/lo [n][hw][ci]) ==========
__global__ __launch_bounds__(512) void pool_kernel(
    const __half* __restrict__ Xh, const __half* __restrict__ Xl) {
    __shared__ float red[512];
    int n = blockIdx.x, tid = threadIdx.x;
    int ci = tid & 127, qr = tid >> 7;
    float acc = 0.f;
    size_t base = ((size_t)n * HWSZ + qr * 256) * HIDC + ci;
#pragma unroll 4
    for (int i = 0; i < 256; i++) {
        size_t idx = base + (size_t)i * HIDC;
        acc += __half2float(Xh[idx]) + __half2float(Xl[idx]);
    }
    red[tid] = acc;
    __syncthreads();
    if (tid < 128)
        g_xnode[n * HIDC + tid] =
            (red[tid] + red[tid + 128] + red[tid + 256] + red[tid + 384]) * (1.f / 1024.f);
}

// ================= GAT =================
__global__ __launch_bounds__(128) void gat_h_kernel(
    const float* __restrict__ xin, const float* __restrict__ lin,
    const float* __restrict__ asw, const float* __restrict__ adw) {
    int n = blockIdx.x, t = threadIdx.x;
    __shared__ float xr[HIDC];
    __shared__ float red[HIDC];
    xr[t] = xin[n * HIDC + t];
    __syncthreads();
    float hv[HEADS];
#pragma unroll
    for (int j = 0; j < HEADS; j++) {
        int col = j * HIDC + t;
        float s = 0.f;
        for (int k = 0; k < HIDC; k++) s += xr[k] * lin[k * (HEADS * HIDC) + col];
        hv[j] = s;
        g_hfeat[n * (HEADS * HIDC) + col] = s;
    }
#pragma unroll
    for (int j = 0; j < HEADS; j++) {
        red[t] = hv[j] * asw[j * HIDC + t];
        __syncthreads();
        for (int off = 64; off > 0; off >>= 1) {
            if (t < off) red[t] += red[t + off];
            __syncthreads();
        }
        if (t == 0) g_as[n * HEADS + j] = red[0];
        __syncthreads();
        red[t] = hv[j] * adw[j * HIDC + t];
        __syncthreads();
        for (int off = 64; off > 0; off >>= 1) {
            if (t < off) red[t] += red[t + off];
            __syncthreads();
        }
        if (t == 0) g_ad[n * HEADS + j] = red[0];
        __syncthreads();
    }
}

__global__ __launch_bounds__(128) void gat_aggr_kernel(
    const float* __restrict__ bias, float* __restrict__ xout) {
    int n = blockIdx.x, t = threadIdx.x;
    float adn[HEADS];
#pragma unroll
    for (int j = 0; j < HEADS; j++) adn[j] = g_ad[n * HEADS + j];
    int rs = g_row[n], re = g_row[n + 1];
    float mx[HEADS] = {-1e30f, -1e30f, -1e30f, -1e30f};
    for (int ei = rs; ei < re; ei++) {
        int s = g_csr[ei];
#pragma unroll
        for (int j = 0; j < HEADS; j++) {
            float e = g_as[s * HEADS + j] + adn[j];
            e = (e > 0.f) ? e : 0.2f * e;
            mx[j] = fmaxf(mx[j], e);
        }
    }
    float den[HEADS] = {0.f, 0.f, 0.f, 0.f};
    float acc[HEADS] = {0.f, 0.f, 0.f, 0.f};
    for (int ei = rs; ei < re; ei++) {
        int s = g_csr[ei];
#pragma unroll
        for (int j = 0; j < HEADS; j++) {
            float e = g_as[s * HEADS + j] + adn[j];
            e = (e > 0.f) ? e : 0.2f * e;
            float ex = __expf(e - mx[j]);
            den[j] += ex;
            acc[j] += ex * g_hfeat[s * (HEADS * HIDC) + j * HIDC + t];
        }
    }
    float o = 0.f;
#pragma unroll
    for (int j = 0; j < HEADS; j++) o += acc[j] / (den[j] + 1e-16f);
    o = o * 0.25f + bias[t];
    xout[n * HIDC + t] = fmaxf(o, 0.f);
}

// ================= gterm =================
__global__ __launch_bounds__(64) void gterm_kernel(
    const float* __restrict__ opw, const float* __restrict__ opb) {
    int n = blockIdx.x, t = threadIdx.x;
    __shared__ float xg[HIDC];
    xg[t] = g_xg[n * HIDC + t];
    xg[t + 64] = g_xg[n * HIDC + t + 64];
    __syncthreads();
    float s = opb[t];
    for (int o = 0; o < HIDC; o++) s += xg[o] * opw[t * HIDC + o];
    g_gterm[n * CINC + t] = s;
}

// ================= op: out = gterm + xp @ op_w^T (mma.sync fp16 3-term) ====
__global__ __launch_bounds__(256) void op_mma_kernel(
    const __half* __restrict__ Xh, const __half* __restrict__ Xl,
    float* __restrict__ out) {
    extern __shared__ __align__(16) char dsm[];
    int tid = threadIdx.x, lane = tid & 31, warp = tid >> 5;
    int warpm = warp >> 1, warpn = warp & 1;
    int n = blockIdx.x, hw0 = blockIdx.y * 128;
    uint32_t sbase = smem_u32(dsm);

#pragma unroll
    for (int i = 0; i < 16; i++) {
        int idx = i * 256 + tid;
        int term = idx >> 11;
        int idx2 = idx & 2047;
        int r = idx2 >> 4, sg = idx2 & 15;
        const __half* g = (term ? Xl : Xh) +
            ((size_t)n * HWSZ + hw0 + r) * HIDC + sg * 8;
        cpasync16(sbase + term * OPX_T + r * OP_RS + sg * 16, g);
    }
#pragma unroll
    for (int i = 0; i < 8; i++) {
        int idx = i * 256 + tid;
        int term = idx >> 10;
        int r = (idx >> 4) & 63, sg = idx & 15;
        const __half* g = (term ? g_wopl : g_woph) + r * HIDC + sg * 8;
        cpasync16(sbase + OPW_0 + term * OPW_T + r * OP_RS + sg * 16, g);
    }
    CP_COMMIT();

    float C[8][4];
#pragma unroll
    for (int nt = 0; nt < 8; nt++)
#pragma unroll
        for (int r = 0; r < 4; r++) C[nt][r] = 0.f;

    int a_row = lane & 15, a_ko = (lane >> 4) * 16;
    int b_row = (lane & 7) + ((lane >> 4) & 1) * 8;
    int b_ko = ((lane >> 3) & 1) * 16;

    CP_WAIT(0);
    __syncthreads();

#pragma unroll 1
    for (int kc = 0; kc < 8; kc++) {
        uint32_t awh[4], awl[4];
        uint32_t ra = (uint32_t)(warpm * 16 + a_row) * OP_RS + kc * 32 + a_ko;
        ldmx4(awh, sbase + OPW_0 + ra);
        ldmx4(awl, sbase + OPW_0 + OPW_T + ra);
#pragma unroll
        for (int ntp = 0; ntp < 4; ntp++) {
            uint32_t xbh[4], xbl[4];
            uint32_t rb = (uint32_t)(warpn * 64 + ntp * 16 + b_row) * OP_RS + kc * 32 + b_ko;
            ldmx4(xbh, sbase + rb);
            ldmx4(xbl, sbase + OPX_T + rb);
#pragma unroll
            for (int q = 0; q < 2; q++) {
                int nt = ntp * 2 + q;
                mma16816(C[nt], awh, xbh[2 * q], xbh[2 * q + 1]);
                mma16816(C[nt], awh, xbl[2 * q], xbl[2 * q + 1]);
                mma16816(C[nt], awl, xbh[2 * q], xbh[2 * q + 1]);
            }
        }
    }

    int g4 = lane >> 2, t2 = (lane & 3) * 2;
    int co_a = warpm * 16 + g4;
    int co_b = co_a + 8;
    float gta = g_gterm[n * CINC + co_a];
    float gtb = g_gterm[n * CINC + co_b];
#pragma unroll
    for (int nt = 0; nt < 8; nt++) {
        int hw = hw0 + warpn * 64 + nt * 8 + t2;
        float2 va = make_float2(C[nt][0] + gta, C[nt][1] + gta);
        float2 vb = make_float2(C[nt][2] + gtb, C[nt][3] + gtb);
        *(float2*)&out[((size_t)n * CINC + co_a) * HWSZ + hw] = va;
        *(float2*)&out[((size_t)n * CINC + co_b) * HWSZ + hw] = vb;
    }
}

// ================= launch =================
extern "C" void kernel_launch(void* const* d_in, const int* in_sizes, int n_in,
                              void* d_out, int out_size) {
    const float* x    = (const float*)d_in[0];
    const int*   ei   = (const int*)d_in[1];
    const float* conf = (const float*)d_in[2];
    const float* fe_w = (const float*)d_in[3];
    const float* fe_b = (const float*)d_in[4];
    const float* fe_g = (const float*)d_in[5];
    const float* fe_be= (const float*)d_in[6];
    const float* sp_w1= (const float*)d_in[7];
    const float* sp_b1= (const float*)d_in[8];
    const float* sp_g1= (const float*)d_in[9];
    const float* sp_e1= (const float*)d_in[10];
    const float* sp_w2= (const float*)d_in[11];
    const float* sp_b2= (const float*)d_in[12];
    const float* sp_g2= (const float*)d_in[13];
    const float* sp_e2= (const float*)d_in[14];
    const float* g1_lin=(const float*)d_in[15];
    const float* g1_as= (const float*)d_in[16];
    const float* g1_ad= (const float*)d_in[17];
    const float* g1_b = (const float*)d_in[18];
    const float* g2_lin=(const float*)d_in[19];
    const float* g2_as= (const float*)d_in[20];
    const float* g2_ad= (const float*)d_in[21];
    const float* g2_b = (const float*)d_in[22];
    const float* op_w = (const float*)d_in[23];
    const float* op_b = (const float*)d_in[24];
    float* out = (float*)d_out;

    void *p1h, *p1l, *p2h, *p2l, *pph, *ppl, *pw1h, *pw2h, *pXn, *pXg;
    cudaGetSymbolAddress(&p1h, g_x1h);
    cudaGetSymbolAddress(&p1l, g_x1l);
    cudaGetSymbolAddress(&p2h, g_x2h);
    cudaGetSymbolAddress(&p2l, g_x2l);
    cudaGetSymbolAddress(&pph, g_xph);
    cudaGetSymbolAddress(&ppl, g_xpl);
    cudaGetSymbolAddress(&pw1h, g_w1h);
    cudaGetSymbolAddress(&pw2h, g_w2h);
    cudaGetSymbolAddress(&pXn, g_xnode);
    cudaGetSymbolAddress(&pXg, g_xg);
    __half* x1h = (__half*)p1h;
    __half* x1l = (__half*)p1l;
    __half* x2h = (__half*)p2h;
    __half* x2l = (__half*)p2l;
    __half* xph = (__half*)pph;
    __half* xpl = (__half*)ppl;
    __half* w1h = (__half*)pw1h;
    __half* w2h = (__half*)pw2h;
    float* xnode = (float*)pXn;
    float* xg = (float*)pXg;

    cudaFuncSetAttribute(conv_mma_kernel<0>, cudaFuncAttributeMaxDynamicSharedMemorySize, CONV_SMEM);
    cudaFuncSetAttribute(conv_mma_kernel<1>, cudaFuncAttributeMaxDynamicSharedMemorySize, CONV_SMEM);
    cudaFuncSetAttribute(fe_mma_kernel, cudaFuncAttributeMaxDynamicSharedMemorySize, FE_SMEM);
    cudaFuncSetAttribute(op_mma_kernel, cudaFuncAttributeMaxDynamicSharedMemorySize, OP_SMEM);

    const int WPN = (HIDC * HIDC * 9 + 255) / 256;

    fe_mma_kernel<<<dim3(NN, 8), 256, FE_SMEM>>>(x, fe_w, fe_b, fe_g, fe_be, conf, x1h, x1l); // 0
    wprep_kernel<<<WPN, 256>>>(sp_w1, w1h);                                   // 1
    wprep_kernel<<<WPN, 256>>>(sp_w2, w2h);                                   // 2
    conv_mma_kernel<0><<<NN * MTILES, 256, CONV_SMEM>>>(                      // 3 (ncu)
        x1h, x1l, w1h, sp_b1, sp_g1, sp_e1, x2h, x2l);
    wprep_op_kernel<<<(CINC * HIDC + 255) / 256, 256>>>(op_w);                // 4
    setup_kernel<<<1, 512>>>(ei);                                             // 5
    count_kernel<<<(TOTE + 255) / 256, 256>>>(ei);                            // 6
    scan_kernel<<<1, 512>>>();                                                // 7
    scatter_kernel<<<(TOTE + 255) / 256, 256>>>(ei);                          // 8
    conv_mma_kernel<1><<<NN * MTILES, 256, CONV_SMEM>>>(                      // 9
        x2h, x2l, w2h, sp_b2, sp_g2, sp_e2, xph, xpl);
    pool_kernel<<<NN, 512>>>(xph, xpl);                                       // 10
    gat_h_kernel<<<NN, 128>>>(xnode, g1_lin, g1_as, g1_ad);                   // 11
    gat_aggr_kernel<<<NN, 128>>>(g1_b, xg);                                   // 12
    gat_h_kernel<<<NN, 128>>>(xg, g2_lin, g2_as, g2_ad);                      // 13
    gat_aggr_kernel<<<NN, 128>>>(g2_b, xg);                                   // 14
    gterm_kernel<<<NN, 64>>>(op_w, op_b);                                     // 15
    op_mma_kernel<<<dim3(NN, 8), 256, OP_SMEM>>>(xph, xpl, out);              // 16

    (void)in_sizes; (void)n_in; (void)out_size;
}

// round 9
// speedup vs baseline: 7.4199x; 1.5236x over previous
#include <cuda_runtime.h>
#include <cuda_fp16.h>
#include <math.h>
#include <stdint.h>

#define NN   512
#define CINC 64
#define HIDC 128
#define HWSZ 1024
#define HH   32
#define WW   32
#define HEADS 4
#define NE   16384
#define TOTE (NE + NN)
#define POSN 1224          // padded positions per image: 36 rows x 34 cols
#define MTILES 9           // 9 M-tiles of 128 cover p in [0,1152)

// conv smem: A slabs 2 bufs x 198 rows x 80B = 32000
//            B ring   3 bufs x 128 rows x 80B = 30720
#define A_BUF   16000
#define B_BASE  32000
#define B_BUF   10240
#define CONV_SMEM (32000 + 30720)

// fe smem: Xh/Xl 128px x 144B, Wh 128co x 144B
#define FE_RS   144
#define FE_XH   0
#define FE_XL   18432
#define FE_W    36864
#define FE_SMEM 55296

// op smem: X (hw x ci) 2 terms x 128 x 272 = 69632; W (co x ci) 2 x 64 x 272
#define OP_RS   272
#define OPX_T   34816
#define OPW_0   69632
#define OPW_T   17408
#define OP_SMEM (69632 + 34816)

// ================= helpers =================
__device__ __forceinline__ uint32_t smem_u32(const void* p) {
    return (uint32_t)__cvta_generic_to_shared(p);
}
__device__ __forceinline__ void ldmx4(uint32_t* r, uint32_t a) {
    asm volatile("ldmatrix.sync.aligned.m8n8.x4.shared.b16 {%0,%1,%2,%3}, [%4];"
                 : "=r"(r[0]), "=r"(r[1]), "=r"(r[2]), "=r"(r[3]) : "r"(a));
}
__device__ __forceinline__ void mma16816(float* c, const uint32_t* a,
                                         uint32_t b0, uint32_t b1) {
    asm volatile(
        "mma.sync.aligned.m16n8k16.row.col.f32.f16.f16.f32 "
        "{%0,%1,%2,%3}, {%4,%5,%6,%7}, {%8,%9}, {%0,%1,%2,%3};"
        : "+f"(c[0]), "+f"(c[1]), "+f"(c[2]), "+f"(c[3])
        : "r"(a[0]), "r"(a[1]), "r"(a[2]), "r"(a[3]), "r"(b0), "r"(b1));
}
__device__ __forceinline__ void cpasync16(uint32_t sa, const void* g) {
    unsigned long long ga = (unsigned long long)__cvta_generic_to_global(g);
    asm volatile("cp.async.cg.shared.global [%0], [%1], 16;" :: "r"(sa), "l"(ga));
}
#define CP_COMMIT() asm volatile("cp.async.commit_group;")
#define CP_WAIT(N)  asm volatile("cp.async.wait_group %0;" :: "n"(N))

__device__ __forceinline__ uint32_t pack_h2(__half a, __half b) {
    return (uint32_t)__half_as_ushort(a) | ((uint32_t)__half_as_ushort(b) << 16);
}

// ================= device scratch =================
__device__ __half g_x1h[(size_t)NN * POSN * HIDC]; // border stays zero
__device__ __half g_x2h[(size_t)NN * POSN * HIDC];
__device__ __half g_xph[(size_t)NN * HWSZ * HIDC]; // conv2 out [n][hw][ci]
__device__ __half g_xpl[(size_t)NN * HWSZ * HIDC];
__device__ __half g_w1h[9 * HIDC * HIDC];
__device__ __half g_w2h[9 * HIDC * HIDC];
__device__ __half g_woph[CINC * HIDC];
__device__ __half g_wopl[CINC * HIDC];
__device__ float g_xnode[NN * HIDC];
__device__ float g_hfeat[NN * HEADS * HIDC];
__device__ float g_as[NN * HEADS];
__device__ float g_ad[NN * HEADS];
__device__ float g_xg[NN * HIDC];
__device__ float g_gterm[NN * CINC];
__device__ int   g_cnt[NN];
__device__ int   g_row[NN + 1];
__device__ int   g_fill[NN];
__device__ int   g_csr[TOTE];
__device__ int   g_is64;

// ================= CSR build =================
__global__ void setup_kernel(const int* __restrict__ ei) {
    int t = threadIdx.x;
    if (t < NN) g_cnt[t] = 0;
    if (t == 0) {
        int acc = 0;
        for (int i = 0; i < 128; i++) acc |= ei[2 * i + 1];
        g_is64 = (acc == 0) ? 1 : 0;
    }
}
__device__ __forceinline__ void read_edge(const int* __restrict__ ei, int i,
                                          int is64, int& s, int& d) {
    if (i < NE) {
        if (is64) { s = ei[2 * i]; d = ei[2 * (NE + i)]; }
        else      { s = ei[i];     d = ei[NE + i]; }
    } else { s = i - NE; d = i - NE; }
}
__global__ void count_kernel(const int* __restrict__ ei) {
    int i = blockIdx.x * blockDim.x + threadIdx.x;
    if (i >= TOTE) return;
    int s, d; read_edge(ei, i, g_is64, s, d);
    atomicAdd(&g_cnt[d], 1);
}
__global__ void scan_kernel() {
    __shared__ int sc[NN];
    int t = threadIdx.x;
    int c = g_cnt[t];
    sc[t] = c; __syncthreads();
    for (int off = 1; off < NN; off <<= 1) {
        int v = (t >= off) ? sc[t - off] : 0;
        __syncthreads(); sc[t] += v; __syncthreads();
    }
    g_row[t + 1] = sc[t];
    if (t == 0) g_row[0] = 0;
    g_fill[t] = sc[t] - c;
}
__global__ void scatter_kernel(const int* __restrict__ ei) {
    int i = blockIdx.x * blockDim.x + threadIdx.x;
    if (i >= TOTE) return;
    int s, d; read_edge(ei, i, g_is64, s, d);
    int pos = atomicAdd(&g_fill[d], 1);
    g_csr[pos] = s;
}

// ================= weight prep: fp32 [co][ci][tap] -> fp16 [tap][co][ci]
__global__ void wprep_kernel(const float* __restrict__ w,
                             __half* __restrict__ bh) {
    int idx = blockIdx.x * 256 + threadIdx.x;
    if (idx >= HIDC * HIDC * 9) return;
    int tap = idx % 9;
    int ci = (idx / 9) % HIDC;
    int co = idx / (9 * HIDC);
    bh[(tap * HIDC + co) * HIDC + ci] = __float2half_rn(w[idx]);
}
__global__ void wprep_op_kernel(const float* __restrict__ w) {
    int idx = blockIdx.x * 256 + threadIdx.x;
    if (idx >= CINC * HIDC) return;
    float v = w[idx];
    __half h = __float2half_rn(v);
    g_woph[idx] = h;
    g_wopl[idx] = __float2half_rn(v - __half2float(h));
}

// ================= fe (mma.sync): 1x1 conv + BN + ReLU + conf =============
// M=128 px, N=128 co, K=64 ci. x split hi/lo fp16 (exact), W single fp16.
__global__ __launch_bounds__(256) void fe_mma_kernel(
    const float* __restrict__ x, const float* __restrict__ fw,
    const float* __restrict__ fb, const float* __restrict__ fg,
    const float* __restrict__ fbe, const float* __restrict__ conf,
    __half* __restrict__ xh) {
    extern __shared__ __align__(16) char dsm[];
    __shared__ float s_conf[128];
    __shared__ float s_sc[HIDC], s_sh[HIDC];

    int tid = threadIdx.x, lane = tid & 31, warp = tid >> 5;
    int warpm = warp >> 2, warpn = warp & 3;
    int n = blockIdx.x, px0 = blockIdx.y * 128;
    uint32_t sbase = smem_u32(dsm);

    if (tid < 128) {
        s_conf[tid] = conf[n * HWSZ + px0 + tid];
        const float inv = rsqrtf(1.0f + 1e-5f);
        float sc = fg[tid] * inv;
        s_sc[tid] = sc;
        s_sh[tid] = fbe[tid] + fb[tid] * sc;
    }

#pragma unroll
    for (int i = 0; i < 16; i++) {
        int idx = i * 256 + tid;
        int cp = idx & 31, co = idx >> 5;
        float2 v = *(const float2*)(fw + co * CINC + cp * 2);
        *(uint32_t*)(dsm + FE_W + co * FE_RS + cp * 4) =
            pack_h2(__float2half_rn(v.x), __float2half_rn(v.y));
    }
#pragma unroll
    for (int i = 0; i < 16; i++) {
        int idx = i * 256 + tid;
        int p = idx & 127, cp = idx >> 7;
        float a = x[((size_t)n * CINC + 2 * cp) * HWSZ + px0 + p];
        float b = x[((size_t)n * CINC + 2 * cp + 1) * HWSZ + px0 + p];
        __half ha = __float2half_rn(a), hb = __float2half_rn(b);
        __half la = __float2half_rn(a - __half2float(ha));
        __half lb = __float2half_rn(b - __half2float(hb));
        *(uint32_t*)(dsm + FE_XH + p * FE_RS + cp * 4) = pack_h2(ha, hb);
        *(uint32_t*)(dsm + FE_XL + p * FE_RS + cp * 4) = pack_h2(la, lb);
    }
    __syncthreads();

    float C[4][4][4];
#pragma unroll
    for (int m = 0; m < 4; m++)
#pragma unroll
        for (int nt = 0; nt < 4; nt++)
#pragma unroll
            for (int r = 0; r < 4; r++) C[m][nt][r] = 0.f;

    int a_row = lane & 15, a_ko = (lane >> 4) * 16;
    int b_row = (lane & 7) + ((lane >> 4) & 1) * 8;
    int b_ko = ((lane >> 3) & 1) * 16;

#pragma unroll
    for (int kq = 0; kq < 4; kq++) {
        uint32_t ah[4][4], al[4][4];
#pragma unroll
        for (int m = 0; m < 4; m++) {
            uint32_t ra = (uint32_t)(warpm * 64 + m * 16 + a_row) * FE_RS + kq * 32 + a_ko;
            ldmx4(ah[m], sbase + FE_XH + ra);
            ldmx4(al[m], sbase + FE_XL + ra);
        }
#pragma unroll
        for (int ntp = 0; ntp < 2; ntp++) {
            uint32_t bw[4];
            uint32_t rb = (uint32_t)(warpn * 32 + ntp * 16 + b_row) * FE_RS + kq * 32 + b_ko;
            ldmx4(bw, sbase + FE_W + rb);
#pragma unroll
            for (int q = 0; q < 2; q++) {
                int nt = ntp * 2 + q;
#pragma unroll
                for (int m = 0; m < 4; m++) {
                    mma16816(C[m][nt], ah[m], bw[2 * q], bw[2 * q + 1]);
                    mma16816(C[m][nt], al[m], bw[2 * q], bw[2 * q + 1]);
                }
            }
        }
    }

    int g4 = lane >> 2, t2 = (lane & 3) * 2;
#pragma unroll
    for (int m = 0; m < 4; m++) {
#pragma unroll
        for (int nt = 0; nt < 4; nt++) {
            int co = warpn * 32 + nt * 8 + t2;
            float sc0 = s_sc[co], sh0 = s_sh[co];
            float sc1 = s_sc[co + 1], sh1 = s_sh[co + 1];
#pragma unroll
            for (int half = 0; half < 2; half++) {
                int pl = warpm * 64 + m * 16 + g4 + half * 8;
                float cf = s_conf[pl];
                float v0 = fmaxf(C[m][nt][half * 2 + 0] * sc0 + sh0, 0.f) * cf;
                float v1 = fmaxf(C[m][nt][half * 2 + 1] * sc1 + sh1, 0.f) * cf;
                int hw = px0 + pl;
                int h = hw >> 5, w = hw & 31;
                size_t q2 = ((size_t)n * POSN + (h + 1) * 34 + (w + 1)) * HIDC + co;
                *(uint32_t*)(xh + q2) =
                    pack_h2(__float2half_rn(v0), __float2half_rn(v1));
            }
        }
    }
}

// ================= mma.sync conv, fp16 single-term, one-sync pipeline =====
// out[p, co] = sum_{tap,ci} Xpad[p + off(tap), ci] * W[tap, co, ci]
// A slabs (198 rows) double-buffered per ci-chunk; B 3-deep ring; 1 sync/stage.
// MODE 0: write padded fp16 (hi only). MODE 1: write [n][hw][ci] hi/lo for op.
template <int MODE>
__global__ __launch_bounds__(256, 2) void conv_mma_kernel(
    const __half* __restrict__ Xh,
    const __half* __restrict__ Wh,
    const float* __restrict__ bb, const float* __restrict__ gg,
    const float* __restrict__ be,
    __half* __restrict__ Oh, __half* __restrict__ Ol) {
    extern __shared__ __align__(16) char dsm[];
    __shared__ float s_sc[HIDC], s_sh[HIDC];

    int tid = threadIdx.x, lane = tid & 31, warp = tid >> 5;
    int warpm = warp >> 2, warpn = warp & 3;
    int n = blockIdx.x / MTILES, mt = blockIdx.x % MTILES;
    int pbase = mt * 128;

    if (tid < HIDC) {
        const float inv = rsqrtf(1.0f + 1e-5f);
        float sc = gg[tid] * inv;
        s_sc[tid] = sc;
        s_sh[tid] = be[tid] + bb[tid] * sc;
    }

    float C[4][4][4];
#pragma unroll
    for (int m = 0; m < 4; m++)
#pragma unroll
        for (int nt = 0; nt < 4; nt++)
#pragma unroll
            for (int r = 0; r < 4; r++) C[m][nt][r] = 0.f;

    uint32_t sbase = smem_u32(dsm);

    // A slab for ci-chunk cic: rows [pbase, pbase+198), cols cic*32..+32
    auto loadA = [&](int cic, int buf) {
        uint32_t s0 = sbase + buf * A_BUF;
        size_t gb = ((size_t)(n * POSN + pbase)) * HIDC + cic * 32;
#pragma unroll
        for (int i = 0; i < 4; i++) {
            int idx = i * 256 + tid;
            if (idx < 792) {
                int r = idx >> 2, sg = idx & 3;
                cpasync16(s0 + r * 80 + sg * 16, Xh + gb + (size_t)r * HIDC + sg * 8);
            }
        }
    };
    auto loadB = [&](int tap, int cic, int buf) {
        uint32_t s0 = sbase + B_BASE + buf * B_BUF;
        size_t gb = ((size_t)tap * HIDC) * HIDC + cic * 32;
#pragma unroll
        for (int i = 0; i < 2; i++) {
            int idx = i * 256 + tid;
            int r = idx >> 2, sg = idx & 3;
            cpasync16(s0 + r * 80 + sg * 16, Wh + gb + (size_t)r * HIDC + sg * 8);
        }
    };

    int a_row = lane & 15, a_ko = (lane >> 4) * 16;
    int b_row = (lane & 7) + ((lane >> 4) & 1) * 8;
    int b_ko = ((lane >> 3) & 1) * 16;

    auto compute_stage = [&](int bufB, int bufA, int tapoff) {
        uint32_t sA = sbase + bufA * A_BUF;
        uint32_t sB = sbase + B_BASE + bufB * B_BUF;
#pragma unroll
        for (int ks = 0; ks < 2; ks++) {
            uint32_t ah[4][4];
#pragma unroll
            for (int m = 0; m < 4; m++) {
                uint32_t ra = (uint32_t)(tapoff + warpm * 64 + m * 16 + a_row) * 80 + ks * 32 + a_ko;
                ldmx4(ah[m], sA + ra);
            }
#pragma unroll
            for (int ntp = 0; ntp < 2; ntp++) {
                uint32_t rbh[4];
                uint32_t rb = (uint32_t)(warpn * 32 + ntp * 16 + b_row) * 80 + ks * 32 + b_ko;
                ldmx4(rbh, sB + rb);
#pragma unroll
                for (int q = 0; q < 2; q++) {
                    int nt = ntp * 2 + q;
#pragma unroll
                    for (int m = 0; m < 4; m++)
                        mma16816(C[m][nt], ah[m], rbh[2 * q], rbh[2 * q + 1]);
                }
            }
        }
    };

    // prologue: stages 0,1 in flight
    loadA(0, 0);
    loadB(0, 0, 0);
    CP_COMMIT();
    loadB(1, 0, 1);
    CP_COMMIT();

#pragma unroll 1
    for (int s = 0; s < 36; s++) {
        int cic = s / 9, tap = s - cic * 9;
        CP_WAIT(1);
        __syncthreads();
        int tapoff = (tap / 3) * 34 + (tap % 3);
        compute_stage(s % 3, cic & 1, tapoff);
        if (s + 2 < 36) {
            int s2 = s + 2;
            int cic2 = s2 / 9;
            loadB(s2 - cic2 * 9, cic2, s2 % 3);
        }
        if (tap == 0 && cic < 3) loadA(cic + 1, (cic + 1) & 1);
        CP_COMMIT();
    }

    // ---- epilogue ----
    int g4 = lane >> 2;
    int t2 = (lane & 3) * 2;
#pragma unroll
    for (int m = 0; m < 4; m++) {
#pragma unroll
        for (int nt = 0; nt < 4; nt++) {
            int co = warpn * 32 + nt * 8 + t2;
            float sc0 = s_sc[co], sh0 = s_sh[co];
            float sc1 = s_sc[co + 1], sh1 = s_sh[co + 1];
#pragma unroll
            for (int half = 0; half < 2; half++) {
                int p = pbase + warpm * 64 + m * 16 + g4 + half * 8;
                float v0 = C[m][nt][half * 2 + 0] * sc0 + sh0;
                float v1 = C[m][nt][half * 2 + 1] * sc1 + sh1;
                int h = p / 34, w = p % 34;
                bool valid = (w < 32) && (h < 32);
                v0 = valid ? fmaxf(v0, 0.f) : 0.f;
                v1 = valid ? fmaxf(v1, 0.f) : 0.f;
                __half h0 = __float2half_rn(v0);
                __half h1 = __float2half_rn(v1);
                if (MODE == 0) {
                    size_t q2 = ((size_t)n * POSN + p + 35) * HIDC + co;
                    *(uint32_t*)(Oh + q2) = pack_h2(h0, h1);
                } else if (valid) {
                    __half l0 = __float2half_rn(v0 - __half2float(h0));
                    __half l1 = __float2half_rn(v1 - __half2float(h1));
                    size_t q2 = ((size_t)n * HWSZ + h * WW + w) * HIDC + co;
                    *(uint32_t*)(Oh + q2) = pack_h2(h0, h1);
                    *(uint32_t*)(Ol + q2) = pack_h2(l0, l1);
                }
            }
        }
    }
}

// ================= global average pool (from hi/lo [n][hw][ci]) ==========
__global__ __launch_bounds__(512) void pool_kernel(
    const __half* __restrict__ Xh, const __half* __restrict__ Xl) {
    __shared__ float red[512];
    int n = blockIdx.x, tid = threadIdx.x;
    int ci = tid & 127, qr = tid >> 7;
    float acc = 0.f;
    size_t base = ((size_t)n * HWSZ + qr * 256) * HIDC + ci;
#pragma unroll 4
    for (int i = 0; i < 256; i++) {
        size_t idx = base + (size_t)i * HIDC;
        acc += __half2float(Xh[idx]) + __half2float(Xl[idx]);
    }
    red[tid] = acc;
    __syncthreads();
    if (tid < 128)
        g_xnode[n * HIDC + tid] =
            (red[tid] + red[tid + 128] + red[tid + 256] + red[tid + 384]) * (1.f / 1024.f);
}

// ================= GAT =================
__global__ __launch_bounds__(128) void gat_h_kernel(
    const float* __restrict__ xin, const float* __restrict__ lin,
    const float* __restrict__ asw, const float* __restrict__ adw) {
    int n = blockIdx.x, t = threadIdx.x;
    __shared__ float xr[HIDC];
    __shared__ float red[HIDC];
    xr[t] = xin[n * HIDC + t];
    __syncthreads();
    float hv[HEADS];
#pragma unroll
    for (int j = 0; j < HEADS; j++) {
        int col = j * HIDC + t;
        float s = 0.f;
        for (int k = 0; k < HIDC; k++) s += xr[k] * lin[k * (HEADS * HIDC) + col];
        hv[j] = s;
        g_hfeat[n * (HEADS * HIDC) + col] = s;
    }
#pragma unroll
    for (int j = 0; j < HEADS; j++) {
        red[t] = hv[j] * asw[j * HIDC + t];
        __syncthreads();
        for (int off = 64; off > 0; off >>= 1) {
            if (t < off) red[t] += red[t + off];
            __syncthreads();
        }
        if (t == 0) g_as[n * HEADS + j] = red[0];
        __syncthreads();
        red[t] = hv[j] * adw[j * HIDC + t];
        __syncthreads();
        for (int off = 64; off > 0; off >>= 1) {
            if (t < off) red[t] += red[t + off];
            __syncthreads();
        }
        if (t == 0) g_ad[n * HEADS + j] = red[0];
        __syncthreads();
    }
}

__global__ __launch_bounds__(128) void gat_aggr_kernel(
    const float* __restrict__ bias, float* __restrict__ xout) {
    int n = blockIdx.x, t = threadIdx.x;
    float adn[HEADS];
#pragma unroll
    for (int j = 0; j < HEADS; j++) adn[j] = g_ad[n * HEADS + j];
    int rs = g_row[n], re = g_row[n + 1];
    float mx[HEADS] = {-1e30f, -1e30f, -1e30f, -1e30f};
    for (int ei = rs; ei < re; ei++) {
        int s = g_csr[ei];
#pragma unroll
        for (int j = 0; j < HEADS; j++) {
            float e = g_as[s * HEADS + j] + adn[j];
            e = (e > 0.f) ? e : 0.2f * e;
            mx[j] = fmaxf(mx[j], e);
        }
    }
    float den[HEADS] = {0.f, 0.f, 0.f, 0.f};
    float acc[HEADS] = {0.f, 0.f, 0.f, 0.f};
    for (int ei = rs; ei < re; ei++) {
        int s = g_csr[ei];
#pragma unroll
        for (int j = 0; j < HEADS; j++) {
            float e = g_as[s * HEADS + j] + adn[j];
            e = (e > 0.f) ? e : 0.2f * e;
            float ex = __expf(e - mx[j]);
            den[j] += ex;
            acc[j] += ex * g_hfeat[s * (HEADS * HIDC) + j * HIDC + t];
        }
    }
    float o = 0.f;
#pragma unroll
    for (int j = 0; j < HEADS; j++) o += acc[j] / (den[j] + 1e-16f);
    o = o * 0.25f + bias[t];
    xout[n * HIDC + t] = fmaxf(o, 0.f);
}

// ================= gterm =================
__global__ __launch_bounds__(64) void gterm_kernel(
    const float* __restrict__ opw, const float* __restrict__ opb) {
    int n = blockIdx.x, t = threadIdx.x;
    __shared__ float xg[HIDC];
    xg[t] = g_xg[n * HIDC + t];
    xg[t + 64] = g_xg[n * HIDC + t + 64];
    __syncthreads();
    float s = opb[t];
    for (int o = 0; o < HIDC; o++) s += xg[o] * opw[t * HIDC + o];
    g_gterm[n * CINC + t] = s;
}

// ================= op: out = gterm + xp @ op_w^T (mma.sync fp16 3-term) ====
__global__ __launch_bounds__(256) void op_mma_kernel(
    const __half* __restrict__ Xh, const __half* __restrict__ Xl,
    float* __restrict__ out) {
    extern __shared__ __align__(16) char dsm[];
    int tid = threadIdx.x, lane = tid & 31, warp = tid >> 5;
    int warpm = warp >> 1, warpn = warp & 1;
    int n = blockIdx.x, hw0 = blockIdx.y * 128;
    uint32_t sbase = smem_u32(dsm);

#pragma unroll
    for (int i = 0; i < 16; i++) {
        int idx = i * 256 + tid;
        int term = idx >> 11;
        int idx2 = idx & 2047;
        int r = idx2 >> 4, sg = idx2 & 15;
        const __half* g = (term ? Xl : Xh) +
            ((size_t)n * HWSZ + hw0 + r) * HIDC + sg * 8;
        cpasync16(sbase + term * OPX_T + r * OP_RS + sg * 16, g);
    }
#pragma unroll
    for (int i = 0; i < 8; i++) {
        int idx = i * 256 + tid;
        int term = idx >> 10;
        int r = (idx >> 4) & 63, sg = idx & 15;
        const __half* g = (term ? g_wopl : g_woph) + r * HIDC + sg * 8;
        cpasync16(sbase + OPW_0 + term * OPW_T + r * OP_RS + sg * 16, g);
    }
    CP_COMMIT();

    float C[8][4];
#pragma unroll
    for (int nt = 0; nt < 8; nt++)
#pragma unroll
        for (int r = 0; r < 4; r++) C[nt][r] = 0.f;

    int a_row = lane & 15, a_ko = (lane >> 4) * 16;
    int b_row = (lane & 7) + ((lane >> 4) & 1) * 8;
    int b_ko = ((lane >> 3) & 1) * 16;

    CP_WAIT(0);
    __syncthreads();

#pragma unroll 1
    for (int kc = 0; kc < 8; kc++) {
        uint32_t awh[4], awl[4];
        uint32_t ra = (uint32_t)(warpm * 16 + a_row) * OP_RS + kc * 32 + a_ko;
        ldmx4(awh, sbase + OPW_0 + ra);
        ldmx4(awl, sbase + OPW_0 + OPW_T + ra);
#pragma unroll
        for (int ntp = 0; ntp < 4; ntp++) {
            uint32_t xbh[4], xbl[4];
            uint32_t rb = (uint32_t)(warpn * 64 + ntp * 16 + b_row) * OP_RS + kc * 32 + b_ko;
            ldmx4(xbh, sbase + rb);
            ldmx4(xbl, sbase + OPX_T + rb);
#pragma unroll
            for (int q = 0; q < 2; q++) {
                int nt = ntp * 2 + q;
                mma16816(C[nt], awh, xbh[2 * q], xbh[2 * q + 1]);
                mma16816(C[nt], awh, xbl[2 * q], xbl[2 * q + 1]);
                mma16816(C[nt], awl, xbh[2 * q], xbh[2 * q + 1]);
            }
        }
    }

    int g4 = lane >> 2, t2 = (lane & 3) * 2;
    int co_a = warpm * 16 + g4;
    int co_b = co_a + 8;
    float gta = g_gterm[n * CINC + co_a];
    float gtb = g_gterm[n * CINC + co_b];
#pragma unroll
    for (int nt = 0; nt < 8; nt++) {
        int hw = hw0 + warpn * 64 + nt * 8 + t2;
        float2 va = make_float2(C[nt][0] + gta, C[nt][1] + gta);
        float2 vb = make_float2(C[nt][2] + gtb, C[nt][3] + gtb);
        *(float2*)&out[((size_t)n * CINC + co_a) * HWSZ + hw] = va;
        *(float2*)&out[((size_t)n * CINC + co_b) * HWSZ + hw] = vb;
    }
}

// ================= launch =================
extern "C" void kernel_launch(void* const* d_in, const int* in_sizes, int n_in,
                              void* d_out, int out_size) {
    const float* x    = (const float*)d_in[0];
    const int*   ei   = (const int*)d_in[1];
    const float* conf = (const float*)d_in[2];
    const float* fe_w = (const float*)d_in[3];
    const float* fe_b = (const float*)d_in[4];
    const float* fe_g = (const float*)d_in[5];
    const float* fe_be= (const float*)d_in[6];
    const float* sp_w1= (const float*)d_in[7];
    const float* sp_b1= (const float*)d_in[8];
    const float* sp_g1= (const float*)d_in[9];
    const float* sp_e1= (const float*)d_in[10];
    const float* sp_w2= (const float*)d_in[11];
    const float* sp_b2= (const float*)d_in[12];
    const float* sp_g2= (const float*)d_in[13];
    const float* sp_e2= (const float*)d_in[14];
    const float* g1_lin=(const float*)d_in[15];
    const float* g1_as= (const float*)d_in[16];
    const float* g1_ad= (const float*)d_in[17];
    const float* g1_b = (const float*)d_in[18];
    const float* g2_lin=(const float*)d_in[19];
    const float* g2_as= (const float*)d_in[20];
    const float* g2_ad= (const float*)d_in[21];
    const float* g2_b = (const float*)d_in[22];
    const float* op_w = (const float*)d_in[23];
    const float* op_b = (const float*)d_in[24];
    float* out = (float*)d_out;

    void *p1h, *p2h, *pph, *ppl, *pw1h, *pw2h, *pXn, *pXg;
    cudaGetSymbolAddress(&p1h, g_x1h);
    cudaGetSymbolAddress(&p2h, g_x2h);
    cudaGetSymbolAddress(&pph, g_xph);
    cudaGetSymbolAddress(&ppl, g_xpl);
    cudaGetSymbolAddress(&pw1h, g_w1h);
    cudaGetSymbolAddress(&pw2h, g_w2h);
    cudaGetSymbolAddress(&pXn, g_xnode);
    cudaGetSymbolAddress(&pXg, g_xg);
    __half* x1h = (__half*)p1h;
    __half* x2h = (__half*)p2h;
    __half* xph = (__half*)pph;
    __half* xpl = (__half*)ppl;
    __half* w1h = (__half*)pw1h;
    __half* w2h = (__half*)pw2h;
    float* xnode = (float*)pXn;
    float* xg = (float*)pXg;

    cudaFuncSetAttribute(conv_mma_kernel<0>, cudaFuncAttributeMaxDynamicSharedMemorySize, CONV_SMEM);
    cudaFuncSetAttribute(conv_mma_kernel<1>, cudaFuncAttributeMaxDynamicSharedMemorySize, CONV_SMEM);
    cudaFuncSetAttribute(fe_mma_kernel, cudaFuncAttributeMaxDynamicSharedMemorySize, FE_SMEM);
    cudaFuncSetAttribute(op_mma_kernel, cudaFuncAttributeMaxDynamicSharedMemorySize, OP_SMEM);

    const int WPN = (HIDC * HIDC * 9 + 255) / 256;

    fe_mma_kernel<<<dim3(NN, 8), 256, FE_SMEM>>>(x, fe_w, fe_b, fe_g, fe_be, conf, x1h); // 0
    wprep_kernel<<<WPN, 256>>>(sp_w1, w1h);                                   // 1
    wprep_kernel<<<WPN, 256>>>(sp_w2, w2h);                                   // 2
    conv_mma_kernel<0><<<NN * MTILES, 256, CONV_SMEM>>>(                      // 3 (ncu)
        x1h, w1h, sp_b1, sp_g1, sp_e1, x2h, nullptr);
    wprep_op_kernel<<<(CINC * HIDC + 255) / 256, 256>>>(op_w);                // 4
    setup_kernel<<<1, 512>>>(ei);                                             // 5
    count_kernel<<<(TOTE + 255) / 256, 256>>>(ei);                            // 6
    scan_kernel<<<1, 512>>>();                                                // 7
    scatter_kernel<<<(TOTE + 255) / 256, 256>>>(ei);                          // 8
    conv_mma_kernel<1><<<NN * MTILES, 256, CONV_SMEM>>>(                      // 9
        x2h, w2h, sp_b2, sp_g2, sp_e2, xph, xpl);
    pool_kernel<<<NN, 512>>>(xph, xpl);                                       // 10
    gat_h_kernel<<<NN, 128>>>(xnode, g1_lin, g1_as, g1_ad);                   // 11
    gat_aggr_kernel<<<NN, 128>>>(g1_b, xg);                                   // 12
    gat_h_kernel<<<NN, 128>>>(xg, g2_lin, g2_as, g2_ad);                      // 13
    gat_aggr_kernel<<<NN, 128>>>(g2_b, xg);                                   // 14
    gterm_kernel<<<NN, 64>>>(op_w, op_b);                                     // 15
    op_mma_kernel<<<dim3(NN, 8), 256, OP_SMEM>>>(xph, xpl, out);              // 16

    (void)in_sizes; (void)n_in; (void)out_size;
}

// round 10
// speedup vs baseline: 8.3071x; 1.1196x over previous
#include <cuda_runtime.h>
#include <cuda_fp16.h>
#include <math.h>
#include <stdint.h>

#define NN   512
#define CINC 64
#define HIDC 128
#define HWSZ 1024
#define HH   32
#define WW   32
#define HEADS 4
#define NE   16384
#define TOTE (NE + NN)
#define POSN 1224          // padded positions per image: 36 rows x 34 cols
#define MTILES 9           // 9 M-tiles of 128 cover p in [0,1152)

// conv smem: A 4 resident slabs x 198 rows x 80B = 64000
//            B ring 2 bufs x 128 rows x 144B = 36864
#define A_SLAB  16000
#define B_BASE  64000
#define B_BUF   18432
#define CONV_SMEM (64000 + 36864)

// fe smem: Xh/Xl 128px x 144B, Wh 128co x 144B
#define FE_RS   144
#define FE_XH   0
#define FE_XL   18432
#define FE_W    36864
#define FE_SMEM 55296

// op smem: X (hw x ci) 128 x 272 = 34816; W (co x ci) 2 terms x 64 x 272
#define OP_RS   272
#define OPW_0   34816
#define OPW_T   17408
#define OP_SMEM (34816 + 34816)

// ================= helpers =================
__device__ __forceinline__ uint32_t smem_u32(const void* p) {
    return (uint32_t)__cvta_generic_to_shared(p);
}
__device__ __forceinline__ void ldmx4(uint32_t* r, uint32_t a) {
    asm volatile("ldmatrix.sync.aligned.m8n8.x4.shared.b16 {%0,%1,%2,%3}, [%4];"
                 : "=r"(r[0]), "=r"(r[1]), "=r"(r[2]), "=r"(r[3]) : "r"(a));
}
__device__ __forceinline__ void mma16816(float* c, const uint32_t* a,
                                         uint32_t b0, uint32_t b1) {
    asm volatile(
        "mma.sync.aligned.m16n8k16.row.col.f32.f16.f16.f32 "
        "{%0,%1,%2,%3}, {%4,%5,%6,%7}, {%8,%9}, {%0,%1,%2,%3};"
        : "+f"(c[0]), "+f"(c[1]), "+f"(c[2]), "+f"(c[3])
        : "r"(a[0]), "r"(a[1]), "r"(a[2]), "r"(a[3]), "r"(b0), "r"(b1));
}
__device__ __forceinline__ void cpasync16(uint32_t sa, const void* g) {
    unsigned long long ga = (unsigned long long)__cvta_generic_to_global(g);
    asm volatile("cp.async.cg.shared.global [%0], [%1], 16;" :: "r"(sa), "l"(ga));
}
#define CP_COMMIT() asm volatile("cp.async.commit_group;")
#define CP_WAIT(N)  asm volatile("cp.async.wait_group %0;" :: "n"(N))

__device__ __forceinline__ uint32_t pack_h2(__half a, __half b) {
    return (uint32_t)__half_as_ushort(a) | ((uint32_t)__half_as_ushort(b) << 16);
}

// ================= device scratch =================
__device__ __half g_x1h[(size_t)NN * POSN * HIDC]; // border stays zero
__device__ __half g_x2h[(size_t)NN * POSN * HIDC];
__device__ __half g_xph[(size_t)NN * HWSZ * HIDC]; // conv2 out [n][hw][ci]
__device__ __half g_w1h[9 * HIDC * HIDC];
__device__ __half g_w2h[9 * HIDC * HIDC];
__device__ __half g_woph[CINC * HIDC];
__device__ __half g_wopl[CINC * HIDC];
__device__ float g_xnode[NN * HIDC];
__device__ float g_hfeat[NN * HEADS * HIDC];
__device__ float g_as[NN * HEADS];
__device__ float g_ad[NN * HEADS];
__device__ float g_xg[NN * HIDC];
__device__ float g_gterm[NN * CINC];
__device__ int   g_cnt[NN];
__device__ int   g_row[NN + 1];
__device__ int   g_fill[NN];
__device__ int   g_csr[TOTE];
__device__ int   g_is64;

// ================= CSR build =================
__global__ void setup_kernel(const int* __restrict__ ei) {
    int t = threadIdx.x;
    if (t < NN) g_cnt[t] = 0;
    if (t == 0) {
        int acc = 0;
        for (int i = 0; i < 128; i++) acc |= ei[2 * i + 1];
        g_is64 = (acc == 0) ? 1 : 0;
    }
}
__device__ __forceinline__ void read_edge(const int* __restrict__ ei, int i,
                                          int is64, int& s, int& d) {
    if (i < NE) {
        if (is64) { s = ei[2 * i]; d = ei[2 * (NE + i)]; }
        else      { s = ei[i];     d = ei[NE + i]; }
    } else { s = i - NE; d = i - NE; }
}
__global__ void count_kernel(const int* __restrict__ ei) {
    int i = blockIdx.x * blockDim.x + threadIdx.x;
    if (i >= TOTE) return;
    int s, d; read_edge(ei, i, g_is64, s, d);
    atomicAdd(&g_cnt[d], 1);
}
__global__ void scan_kernel() {
    __shared__ int sc[NN];
    int t = threadIdx.x;
    int c = g_cnt[t];
    sc[t] = c; __syncthreads();
    for (int off = 1; off < NN; off <<= 1) {
        int v = (t >= off) ? sc[t - off] : 0;
        __syncthreads(); sc[t] += v; __syncthreads();
    }
    g_row[t + 1] = sc[t];
    if (t == 0) g_row[0] = 0;
    g_fill[t] = sc[t] - c;
}
__global__ void scatter_kernel(const int* __restrict__ ei) {
    int i = blockIdx.x * blockDim.x + threadIdx.x;
    if (i >= TOTE) return;
    int s, d; read_edge(ei, i, g_is64, s, d);
    int pos = atomicAdd(&g_fill[d], 1);
    g_csr[pos] = s;
}

// ================= weight prep: fp32 [co][ci][tap] -> fp16 [tap][co][ci]
__global__ void wprep_kernel(const float* __restrict__ w,
                             __half* __restrict__ bh) {
    int idx = blockIdx.x * 256 + threadIdx.x;
    if (idx >= HIDC * HIDC * 9) return;
    int tap = idx % 9;
    int ci = (idx / 9) % HIDC;
    int co = idx / (9 * HIDC);
    bh[(tap * HIDC + co) * HIDC + ci] = __float2half_rn(w[idx]);
}
__global__ void wprep_op_kernel(const float* __restrict__ w) {
    int idx = blockIdx.x * 256 + threadIdx.x;
    if (idx >= CINC * HIDC) return;
    float v = w[idx];
    __half h = __float2half_rn(v);
    g_woph[idx] = h;
    g_wopl[idx] = __float2half_rn(v - __half2float(h));
}

// ================= fe (mma.sync): 1x1 conv + BN + ReLU + conf =============
// M=128 px, N=128 co, K=64 ci. x split hi/lo fp16 (exact), W single fp16.
__global__ __launch_bounds__(256) void fe_mma_kernel(
    const float* __restrict__ x, const float* __restrict__ fw,
    const float* __restrict__ fb, const float* __restrict__ fg,
    const float* __restrict__ fbe, const float* __restrict__ conf,
    __half* __restrict__ xh) {
    extern __shared__ __align__(16) char dsm[];
    __shared__ float s_conf[128];
    __shared__ float s_sc[HIDC], s_sh[HIDC];

    int tid = threadIdx.x, lane = tid & 31, warp = tid >> 5;
    int warpm = warp >> 2, warpn = warp & 3;
    int n = blockIdx.x, px0 = blockIdx.y * 128;
    uint32_t sbase = smem_u32(dsm);

    if (tid < 128) {
        s_conf[tid] = conf[n * HWSZ + px0 + tid];
        const float inv = rsqrtf(1.0f + 1e-5f);
        float sc = fg[tid] * inv;
        s_sc[tid] = sc;
        s_sh[tid] = fbe[tid] + fb[tid] * sc;
    }

#pragma unroll
    for (int i = 0; i < 16; i++) {
        int idx = i * 256 + tid;
        int cp = idx & 31, co = idx >> 5;
        float2 v = *(const float2*)(fw + co * CINC + cp * 2);
        *(uint32_t*)(dsm + FE_W + co * FE_RS + cp * 4) =
            pack_h2(__float2half_rn(v.x), __float2half_rn(v.y));
    }
#pragma unroll
    for (int i = 0; i < 16; i++) {
        int idx = i * 256 + tid;
        int p = idx & 127, cp = idx >> 7;
        float a = x[((size_t)n * CINC + 2 * cp) * HWSZ + px0 + p];
        float b = x[((size_t)n * CINC + 2 * cp + 1) * HWSZ + px0 + p];
        __half ha = __float2half_rn(a), hb = __float2half_rn(b);
        __half la = __float2half_rn(a - __half2float(ha));
        __half lb = __float2half_rn(b - __half2float(hb));
        *(uint32_t*)(dsm + FE_XH + p * FE_RS + cp * 4) = pack_h2(ha, hb);
        *(uint32_t*)(dsm + FE_XL + p * FE_RS + cp * 4) = pack_h2(la, lb);
    }
    __syncthreads();

    float C[4][4][4];
#pragma unroll
    for (int m = 0; m < 4; m++)
#pragma unroll
        for (int nt = 0; nt < 4; nt++)
#pragma unroll
            for (int r = 0; r < 4; r++) C[m][nt][r] = 0.f;

    int a_row = lane & 15, a_ko = (lane >> 4) * 16;
    int b_row = (lane & 7) + ((lane >> 4) & 1) * 8;
    int b_ko = ((lane >> 3) & 1) * 16;

#pragma unroll
    for (int kq = 0; kq < 4; kq++) {
        uint32_t ah[4][4], al[4][4];
#pragma unroll
        for (int m = 0; m < 4; m++) {
            uint32_t ra = (uint32_t)(warpm * 64 + m * 16 + a_row) * FE_RS + kq * 32 + a_ko;
            ldmx4(ah[m], sbase + FE_XH + ra);
            ldmx4(al[m], sbase + FE_XL + ra);
        }
#pragma unroll
        for (int ntp = 0; ntp < 2; ntp++) {
            uint32_t bw[4];
            uint32_t rb = (uint32_t)(warpn * 32 + ntp * 16 + b_row) * FE_RS + kq * 32 + b_ko;
            ldmx4(bw, sbase + FE_W + rb);
#pragma unroll
            for (int q = 0; q < 2; q++) {
                int nt = ntp * 2 + q;
#pragma unroll
                for (int m = 0; m < 4; m++) {
                    mma16816(C[m][nt], ah[m], bw[2 * q], bw[2 * q + 1]);
                    mma16816(C[m][nt], al[m], bw[2 * q], bw[2 * q + 1]);
                }
            }
        }
    }

    int g4 = lane >> 2, t2 = (lane & 3) * 2;
#pragma unroll
    for (int m = 0; m < 4; m++) {
#pragma unroll
        for (int nt = 0; nt < 4; nt++) {
            int co = warpn * 32 + nt * 8 + t2;
            float sc0 = s_sc[co], sh0 = s_sh[co];
            float sc1 = s_sc[co + 1], sh1 = s_sh[co + 1];
#pragma unroll
            for (int half = 0; half < 2; half++) {
                int pl = warpm * 64 + m * 16 + g4 + half * 8;
                float cf = s_conf[pl];
                float v0 = fmaxf(C[m][nt][half * 2 + 0] * sc0 + sh0, 0.f) * cf;
                float v1 = fmaxf(C[m][nt][half * 2 + 1] * sc1 + sh1, 0.f) * cf;
                int hw = px0 + pl;
                int h = hw >> 5, w = hw & 31;
                size_t q2 = ((size_t)n * POSN + (h + 1) * 34 + (w + 1)) * HIDC + co;
                *(uint32_t*)(xh + q2) =
                    pack_h2(__float2half_rn(v0), __float2half_rn(v1));
            }
        }
    }
}

// ================= mma.sync conv, fp16 single-term =================
// out[p, co] = sum_{tap,ci} Xpad[p + off(tap), ci] * W[tap, co, ci]
// All 4 A slabs resident (loaded once). 18 stages = 9 taps x 2 ci-pairs
// (K=64 per stage); B ring-2; ONE __syncthreads per stage.
// MODE 0: write padded fp16. MODE 1: write [n][hw][ci] fp16.
template <int MODE>
__global__ __launch_bounds__(256, 2) void conv_mma_kernel(
    const __half* __restrict__ Xh,
    const __half* __restrict__ Wh,
    const float* __restrict__ bb, const float* __restrict__ gg,
    const float* __restrict__ be,
    __half* __restrict__ Oh) {
    extern __shared__ __align__(16) char dsm[];
    __shared__ float s_sc[HIDC], s_sh[HIDC];

    int tid = threadIdx.x, lane = tid & 31, warp = tid >> 5;
    int warpm = warp >> 2, warpn = warp & 3;
    int n = blockIdx.x / MTILES, mt = blockIdx.x % MTILES;
    int pbase = mt * 128;

    if (tid < HIDC) {
        const float inv = rsqrtf(1.0f + 1e-5f);
        float sc = gg[tid] * inv;
        s_sc[tid] = sc;
        s_sh[tid] = be[tid] + bb[tid] * sc;
    }

    float C[4][4][4];
#pragma unroll
    for (int m = 0; m < 4; m++)
#pragma unroll
        for (int nt = 0; nt < 4; nt++)
#pragma unroll
            for (int r = 0; r < 4; r++) C[m][nt][r] = 0.f;

    uint32_t sbase = smem_u32(dsm);

    // A slab for ci-chunk cic: rows [pbase, pbase+198), cols cic*32..+32
    auto loadA = [&](int cic) {
        uint32_t s0 = sbase + cic * A_SLAB;
        size_t gb = ((size_t)(n * POSN + pbase)) * HIDC + cic * 32;
#pragma unroll
        for (int i = 0; i < 4; i++) {
            int idx = i * 256 + tid;
            if (idx < 792) {
                int r = idx >> 2, sg = idx & 3;
                cpasync16(s0 + r * 80 + sg * 16, Xh + gb + (size_t)r * HIDC + sg * 8);
            }
        }
    };
    // B stage (tap, pair): 128 co x 64 ci, row stride 144
    auto loadB = [&](int tap, int pair, int buf) {
        uint32_t s0 = sbase + B_BASE + buf * B_BUF;
        size_t gb = ((size_t)tap * HIDC) * HIDC + pair * 64;
#pragma unroll
        for (int i = 0; i < 4; i++) {
            int idx = i * 256 + tid;
            int r = idx >> 3, sg = idx & 7;
            cpasync16(s0 + r * 144 + sg * 16, Wh + gb + (size_t)r * HIDC + sg * 8);
        }
    };

    int a_row = lane & 15, a_ko = (lane >> 4) * 16;
    int b_row = (lane & 7) + ((lane >> 4) & 1) * 8;
    int b_ko = ((lane >> 3) & 1) * 16;

    auto compute_stage = [&](int bufB, int pair, int tapoff) {
        uint32_t sB = sbase + B_BASE + bufB * B_BUF;
#pragma unroll
        for (int c2 = 0; c2 < 2; c2++) {
            uint32_t sA = sbase + (pair * 2 + c2) * A_SLAB;
            uint32_t bhalf = c2 * 64;
#pragma unroll
            for (int ks = 0; ks < 2; ks++) {
                uint32_t ah[4][4];
#pragma unroll
                for (int m = 0; m < 4; m++) {
                    uint32_t ra = (uint32_t)(tapoff + warpm * 64 + m * 16 + a_row) * 80 + ks * 32 + a_ko;
                    ldmx4(ah[m], sA + ra);
                }
#pragma unroll
                for (int ntp = 0; ntp < 2; ntp++) {
                    uint32_t rbh[4];
                    uint32_t rb = (uint32_t)(warpn * 32 + ntp * 16 + b_row) * 144 + bhalf + ks * 32 + b_ko;
                    ldmx4(rbh, sB + rb);
#pragma unroll
                    for (int q = 0; q < 2; q++) {
                        int nt = ntp * 2 + q;
#pragma unroll
                        for (int m = 0; m < 4; m++)
                            mma16816(C[m][nt], ah[m], rbh[2 * q], rbh[2 * q + 1]);
                    }
                }
            }
        }
    };

    // prologue: all A slabs + B stage 0 in one group
    loadA(0); loadA(1); loadA(2); loadA(3);
    loadB(0, 0, 0);
    CP_COMMIT();

#pragma unroll 1
    for (int s = 0; s < 18; s++) {
        int pair = s / 9, tap = s - pair * 9;
        CP_WAIT(0);
        __syncthreads();
        if (s + 1 < 18) {
            int s1 = s + 1;
            int p1 = s1 / 9;
            loadB(s1 - p1 * 9, p1, s1 & 1);  // target buf read in stage s-1: safe
        }
        CP_COMMIT();
        int tapoff = (tap / 3) * 34 + (tap % 3);
        compute_stage(s & 1, pair, tapoff);
    }

    // ---- epilogue ----
    int g4 = lane >> 2;
    int t2 = (lane & 3) * 2;
#pragma unroll
    for (int m = 0; m < 4; m++) {
#pragma unroll
        for (int nt = 0; nt < 4; nt++) {
            int co = warpn * 32 + nt * 8 + t2;
            float sc0 = s_sc[co], sh0 = s_sh[co];
            float sc1 = s_sc[co + 1], sh1 = s_sh[co + 1];
#pragma unroll
            for (int half = 0; half < 2; half++) {
                int p = pbase + warpm * 64 + m * 16 + g4 + half * 8;
                float v0 = C[m][nt][half * 2 + 0] * sc0 + sh0;
                float v1 = C[m][nt][half * 2 + 1] * sc1 + sh1;
                int h = p / 34, w = p % 34;
                bool valid = (w < 32) && (h < 32);
                v0 = valid ? fmaxf(v0, 0.f) : 0.f;
                v1 = valid ? fmaxf(v1, 0.f) : 0.f;
                uint32_t pk = pack_h2(__float2half_rn(v0), __float2half_rn(v1));
                if (MODE == 0) {
                    size_t q2 = ((size_t)n * POSN + p + 35) * HIDC + co;
                    *(uint32_t*)(Oh + q2) = pk;
                } else if (valid) {
                    size_t q2 = ((size_t)n * HWSZ + h * WW + w) * HIDC + co;
                    *(uint32_t*)(Oh + q2) = pk;
                }
            }
        }
    }
}

// ================= global average pool (from [n][hw][ci] fp16) ===========
__global__ __launch_bounds__(512) void pool_kernel(
    const __half* __restrict__ Xh) {
    __shared__ float red[512];
    int n = blockIdx.x, tid = threadIdx.x;
    int ci = tid & 127, qr = tid >> 7;
    float acc = 0.f;
    size_t base = ((size_t)n * HWSZ + qr * 256) * HIDC + ci;
#pragma unroll 4
    for (int i = 0; i < 256; i++)
        acc += __half2float(Xh[base + (size_t)i * HIDC]);
    red[tid] = acc;
    __syncthreads();
    if (tid < 128)
        g_xnode[n * HIDC + tid] =
            (red[tid] + red[tid + 128] + red[tid + 256] + red[tid + 384]) * (1.f / 1024.f);
}

// ================= GAT =================
__global__ __launch_bounds__(128) void gat_h_kernel(
    const float* __restrict__ xin, const float* __restrict__ lin,
    const float* __restrict__ asw, const float* __restrict__ adw) {
    int n = blockIdx.x, t = threadIdx.x;
    __shared__ float xr[HIDC];
    __shared__ float red[HIDC];
    xr[t] = xin[n * HIDC + t];
    __syncthreads();
    float hv[HEADS];
#pragma unroll
    for (int j = 0; j < HEADS; j++) {
        int col = j * HIDC + t;
        float s = 0.f;
        for (int k = 0; k < HIDC; k++) s += xr[k] * lin[k * (HEADS * HIDC) + col];
        hv[j] = s;
        g_hfeat[n * (HEADS * HIDC) + col] = s;
    }
#pragma unroll
    for (int j = 0; j < HEADS; j++) {
        red[t] = hv[j] * asw[j * HIDC + t];
        __syncthreads();
        for (int off = 64; off > 0; off >>= 1) {
            if (t < off) red[t] += red[t + off];
            __syncthreads();
        }
        if (t == 0) g_as[n * HEADS + j] = red[0];
        __syncthreads();
        red[t] = hv[j] * adw[j * HIDC + t];
        __syncthreads();
        for (int off = 64; off > 0; off >>= 1) {
            if (t < off) red[t] += red[t + off];
            __syncthreads();
        }
        if (t == 0) g_ad[n * HEADS + j] = red[0];
        __syncthreads();
    }
}

__global__ __launch_bounds__(128) void gat_aggr_kernel(
    const float* __restrict__ bias, float* __restrict__ xout) {
    int n = blockIdx.x, t = threadIdx.x;
    float adn[HEADS];
#pragma unroll
    for (int j = 0; j < HEADS; j++) adn[j] = g_ad[n * HEADS + j];
    int rs = g_row[n], re = g_row[n + 1];
    float mx[HEADS] = {-1e30f, -1e30f, -1e30f, -1e30f};
    for (int ei = rs; ei < re; ei++) {
        int s = g_csr[ei];
#pragma unroll
        for (int j = 0; j < HEADS; j++) {
            float e = g_as[s * HEADS + j] + adn[j];
            e = (e > 0.f) ? e : 0.2f * e;
            mx[j] = fmaxf(mx[j], e);
        }
    }
    float den[HEADS] = {0.f, 0.f, 0.f, 0.f};
    float acc[HEADS] = {0.f, 0.f, 0.f, 0.f};
    for (int ei = rs; ei < re; ei++) {
        int s = g_csr[ei];
#pragma unroll
        for (int j = 0; j < HEADS; j++) {
            float e = g_as[s * HEADS + j] + adn[j];
            e = (e > 0.f) ? e : 0.2f * e;
            float ex = __expf(e - mx[j]);
            den[j] += ex;
            acc[j] += ex * g_hfeat[s * (HEADS * HIDC) + j * HIDC + t];
        }
    }
    float o = 0.f;
#pragma unroll
    for (int j = 0; j < HEADS; j++) o += acc[j] / (den[j] + 1e-16f);
    o = o * 0.25f + bias[t];
    xout[n * HIDC + t] = fmaxf(o, 0.f);
}

// ================= gterm =================
__global__ __launch_bounds__(64) void gterm_kernel(
    const float* __restrict__ opw, const float* __restrict__ opb) {
    int n = blockIdx.x, t = threadIdx.x;
    __shared__ float xg[HIDC];
    xg[t] = g_xg[n * HIDC + t];
    xg[t + 64] = g_xg[n * HIDC + t + 64];
    __syncthreads();
    float s = opb[t];
    for (int o = 0; o < HIDC; o++) s += xg[o] * opw[t * HIDC + o];
    g_gterm[n * CINC + t] = s;
}

// ================= op: out = gterm + xp @ op_w^T (fp16 2-term) =============
__global__ __launch_bounds__(256) void op_mma_kernel(
    const __half* __restrict__ Xh,
    float* __restrict__ out) {
    extern __shared__ __align__(16) char dsm[];
    int tid = threadIdx.x, lane = tid & 31, warp = tid >> 5;
    int warpm = warp >> 1, warpn = warp & 1;
    int n = blockIdx.x, hw0 = blockIdx.y * 128;
    uint32_t sbase = smem_u32(dsm);

    // X (hw x ci): 128 rows x 16 segs
#pragma unroll
    for (int i = 0; i < 8; i++) {
        int idx = i * 256 + tid;
        int r = idx >> 4, sg = idx & 15;
        const __half* g = Xh + ((size_t)n * HWSZ + hw0 + r) * HIDC + sg * 8;
        cpasync16(sbase + r * OP_RS + sg * 16, g);
    }
    // W (co x ci): 2 terms x 64 rows x 16 segs
#pragma unroll
    for (int i = 0; i < 8; i++) {
        int idx = i * 256 + tid;
        int term = idx >> 10;
        int r = (idx >> 4) & 63, sg = idx & 15;
        const __half* g = (term ? g_wopl : g_woph) + r * HIDC + sg * 8;
        cpasync16(sbase + OPW_0 + term * OPW_T + r * OP_RS + sg * 16, g);
    }
    CP_COMMIT();

    float C[8][4];
#pragma unroll
    for (int nt = 0; nt < 8; nt++)
#pragma unroll
        for (int r = 0; r < 4; r++) C[nt][r] = 0.f;

    int a_row = lane & 15, a_ko = (lane >> 4) * 16;
    int b_row = (lane & 7) + ((lane >> 4) & 1) * 8;
    int b_ko = ((lane >> 3) & 1) * 16;

    CP_WAIT(0);
    __syncthreads();

#pragma unroll 1
    for (int kc = 0; kc < 8; kc++) {
        uint32_t awh[4], awl[4];
        uint32_t ra = (uint32_t)(warpm * 16 + a_row) * OP_RS + kc * 32 + a_ko;
        ldmx4(awh, sbase + OPW_0 + ra);
        ldmx4(awl, sbase + OPW_0 + OPW_T + ra);
#pragma unroll
        for (int ntp = 0; ntp < 4; ntp++) {
            uint32_t xbh[4];
            uint32_t rb = (uint32_t)(warpn * 64 + ntp * 16 + b_row) * OP_RS + kc * 32 + b_ko;
            ldmx4(xbh, sbase + rb);
#pragma unroll
            for (int q = 0; q < 2; q++) {
                int nt = ntp * 2 + q;
                mma16816(C[nt], awh, xbh[2 * q], xbh[2 * q + 1]);
                mma16816(C[nt], awl, xbh[2 * q], xbh[2 * q + 1]);
            }
        }
    }

    int g4 = lane >> 2, t2 = (lane & 3) * 2;
    int co_a = warpm * 16 + g4;
    int co_b = co_a + 8;
    float gta = g_gterm[n * CINC + co_a];
    float gtb = g_gterm[n * CINC + co_b];
#pragma unroll
    for (int nt = 0; nt < 8; nt++) {
        int hw = hw0 + warpn * 64 + nt * 8 + t2;
        float2 va = make_float2(C[nt][0] + gta, C[nt][1] + gta);
        float2 vb = make_float2(C[nt][2] + gtb, C[nt][3] + gtb);
        *(float2*)&out[((size_t)n * CINC + co_a) * HWSZ + hw] = va;
        *(float2*)&out[((size_t)n * CINC + co_b) * HWSZ + hw] = vb;
    }
}

// ================= launch =================
extern "C" void kernel_launch(void* const* d_in, const int* in_sizes, int n_in,
                              void* d_out, int out_size) {
    const float* x    = (const float*)d_in[0];
    const int*   ei   = (const int*)d_in[1];
    const float* conf = (const float*)d_in[2];
    const float* fe_w = (const float*)d_in[3];
    const float* fe_b = (const float*)d_in[4];
    const float* fe_g = (const float*)d_in[5];
    const float* fe_be= (const float*)d_in[6];
    const float* sp_w1= (const float*)d_in[7];
    const float* sp_b1= (const float*)d_in[8];
    const float* sp_g1= (const float*)d_in[9];
    const float* sp_e1= (const float*)d_in[10];
    const float* sp_w2= (const float*)d_in[11];
    const float* sp_b2= (const float*)d_in[12];
    const float* sp_g2= (const float*)d_in[13];
    const float* sp_e2= (const float*)d_in[14];
    const float* g1_lin=(const float*)d_in[15];
    const float* g1_as= (const float*)d_in[16];
    const float* g1_ad= (const float*)d_in[17];
    const float* g1_b = (const float*)d_in[18];
    const float* g2_lin=(const float*)d_in[19];
    const float* g2_as= (const float*)d_in[20];
    const float* g2_ad= (const float*)d_in[21];
    const float* g2_b = (const float*)d_in[22];
    const float* op_w = (const float*)d_in[23];
    const float* op_b = (const float*)d_in[24];
    float* out = (float*)d_out;

    void *p1h, *p2h, *pph, *pw1h, *pw2h, *pXn, *pXg;
    cudaGetSymbolAddress(&p1h, g_x1h);
    cudaGetSymbolAddress(&p2h, g_x2h);
    cudaGetSymbolAddress(&pph, g_xph);
    cudaGetSymbolAddress(&pw1h, g_w1h);
    cudaGetSymbolAddress(&pw2h, g_w2h);
    cudaGetSymbolAddress(&pXn, g_xnode);
    cudaGetSymbolAddress(&pXg, g_xg);
    __half* x1h = (__half*)p1h;
    __half* x2h = (__half*)p2h;
    __half* xph = (__half*)pph;
    __half* w1h = (__half*)pw1h;
    __half* w2h = (__half*)pw2h;
    float* xnode = (float*)pXn;
    float* xg = (float*)pXg;

    cudaFuncSetAttribute(conv_mma_kernel<0>, cudaFuncAttributeMaxDynamicSharedMemorySize, CONV_SMEM);
    cudaFuncSetAttribute(conv_mma_kernel<1>, cudaFuncAttributeMaxDynamicSharedMemorySize, CONV_SMEM);
    cudaFuncSetAttribute(fe_mma_kernel, cudaFuncAttributeMaxDynamicSharedMemorySize, FE_SMEM);
    cudaFuncSetAttribute(op_mma_kernel, cudaFuncAttributeMaxDynamicSharedMemorySize, OP_SMEM);

    const int WPN = (HIDC * HIDC * 9 + 255) / 256;

    fe_mma_kernel<<<dim3(NN, 8), 256, FE_SMEM>>>(x, fe_w, fe_b, fe_g, fe_be, conf, x1h); // 0
    wprep_kernel<<<WPN, 256>>>(sp_w1, w1h);                                   // 1
    wprep_kernel<<<WPN, 256>>>(sp_w2, w2h);                                   // 2
    conv_mma_kernel<0><<<NN * MTILES, 256, CONV_SMEM>>>(                      // 3 (ncu)
        x1h, w1h, sp_b1, sp_g1, sp_e1, x2h);
    wprep_op_kernel<<<(CINC * HIDC + 255) / 256, 256>>>(op_w);                // 4
    setup_kernel<<<1, 512>>>(ei);                                             // 5
    count_kernel<<<(TOTE + 255) / 256, 256>>>(ei);                            // 6
    scan_kernel<<<1, 512>>>();                                                // 7
    scatter_kernel<<<(TOTE + 255) / 256, 256>>>(ei);                          // 8
    conv_mma_kernel<1><<<NN * MTILES, 256, CONV_SMEM>>>(                      // 9
        x2h, w2h, sp_b2, sp_g2, sp_e2, xph);
    pool_kernel<<<NN, 512>>>(xph);                                            // 10
    gat_h_kernel<<<NN, 128>>>(xnode, g1_lin, g1_as, g1_ad);                   // 11
    gat_aggr_kernel<<<NN, 128>>>(g1_b, xg);                                   // 12
    gat_h_kernel<<<NN, 128>>>(xg, g2_lin, g2_as, g2_ad);                      // 13
    gat_aggr_kernel<<<NN, 128>>>(g2_b, xg);                                   // 14
    gterm_kernel<<<NN, 64>>>(op_w, op_b);                                     // 15
    op_mma_kernel<<<dim3(NN, 8), 256, OP_SMEM>>>(xph, out);                   // 16

    (void)in_sizes; (void)n_in; (void)out_size;
}

// round 11
// speedup vs baseline: 9.0827x; 1.0934x over previous
#include <cuda_runtime.h>
#include <cuda_fp16.h>
#include <math.h>
#include <stdint.h>

#define NN   512
#define CINC 64
#define HIDC 128
#define HWSZ 1024
#define HH   32
#define WW   32
#define HEADS 4
#define NE   16384
#define TOTE (NE + NN)
#define POSN 1224          // padded positions per image: 36 rows x 34 cols
#define MTILES 9           // 9 M-tiles of 128 cover p in [0,1152)

// conv smem: A 4 resident slabs x 198 rows x 80B (=15840, pad to 16000)
//            B: 4 pairs x ring2 x (32 rows x 144B = 4608)
#define A_SLAB  16000
#define B_BASE  64000
#define B_PAIR  9216
#define CONV_SMEM (64000 + 4 * B_PAIR)

// fe smem: Xh/Xl 128px x 144B, Wh 128co x 144B
#define FE_RS   144
#define FE_XH   0
#define FE_XL   18432
#define FE_W    36864
#define FE_SMEM 55296

// op smem: X (hw x ci) 128 x 272 = 34816; W (co x ci) 2 terms x 64 x 272
#define OP_RS   272
#define OPW_0   34816
#define OPW_T   17408
#define OP_SMEM (34816 + 34816)

// ================= helpers =================
__device__ __forceinline__ uint32_t smem_u32(const void* p) {
    return (uint32_t)__cvta_generic_to_shared(p);
}
__device__ __forceinline__ void ldmx4(uint32_t* r, uint32_t a) {
    asm volatile("ldmatrix.sync.aligned.m8n8.x4.shared.b16 {%0,%1,%2,%3}, [%4];"
                 : "=r"(r[0]), "=r"(r[1]), "=r"(r[2]), "=r"(r[3]) : "r"(a));
}
__device__ __forceinline__ void mma16816(float* c, const uint32_t* a,
                                         uint32_t b0, uint32_t b1) {
    asm volatile(
        "mma.sync.aligned.m16n8k16.row.col.f32.f16.f16.f32 "
        "{%0,%1,%2,%3}, {%4,%5,%6,%7}, {%8,%9}, {%0,%1,%2,%3};"
        : "+f"(c[0]), "+f"(c[1]), "+f"(c[2]), "+f"(c[3])
        : "r"(a[0]), "r"(a[1]), "r"(a[2]), "r"(a[3]), "r"(b0), "r"(b1));
}
__device__ __forceinline__ void cpasync16(uint32_t sa, const void* g) {
    unsigned long long ga = (unsigned long long)__cvta_generic_to_global(g);
    asm volatile("cp.async.cg.shared.global [%0], [%1], 16;" :: "r"(sa), "l"(ga));
}
#define CP_COMMIT() asm volatile("cp.async.commit_group;")
#define CP_WAIT(N)  asm volatile("cp.async.wait_group %0;" :: "n"(N))
#define BAR_PAIR(id) asm volatile("bar.sync %0, 64;" :: "r"(id) : "memory")

__device__ __forceinline__ uint32_t pack_h2(__half a, __half b) {
    return (uint32_t)__half_as_ushort(a) | ((uint32_t)__half_as_ushort(b) << 16);
}

// ================= device scratch =================
__device__ __half g_x1h[(size_t)NN * POSN * HIDC]; // border stays zero
__device__ __half g_x2h[(size_t)NN * POSN * HIDC];
__device__ __half g_xph[(size_t)NN * HWSZ * HIDC]; // conv2 out [n][hw][ci]
__device__ __half g_w1h[9 * HIDC * HIDC];
__device__ __half g_w2h[9 * HIDC * HIDC];
__device__ __half g_woph[CINC * HIDC];
__device__ __half g_wopl[CINC * HIDC];
__device__ float g_part[(size_t)NN * MTILES * 8 * 32]; // pool partials
__device__ float g_xnode[NN * HIDC];
__device__ float g_hfeat[NN * HEADS * HIDC];
__device__ float g_as[NN * HEADS];
__device__ float g_ad[NN * HEADS];
__device__ float g_xg[NN * HIDC];
__device__ float g_gterm[NN * CINC];
__device__ int   g_row[NN + 1];
__device__ int   g_csr[TOTE];

// ================= CSR build (one block, 512 threads) =================
__device__ __forceinline__ void read_edge(const int* __restrict__ ei, int i,
                                          int is64, int& s, int& d) {
    if (i < NE) {
        if (is64) { s = ei[2 * i]; d = ei[2 * (NE + i)]; }
        else      { s = ei[i];     d = ei[NE + i]; }
    } else { s = i - NE; d = i - NE; }
}
__global__ __launch_bounds__(512) void csr_build_kernel(const int* __restrict__ ei) {
    __shared__ int scnt[NN];
    __shared__ int sfill[NN];
    __shared__ int s_is64;
    int t = threadIdx.x;
    if (t == 0) {
        int acc = 0;
        for (int i = 0; i < 128; i++) acc |= ei[2 * i + 1];
        s_is64 = (acc == 0) ? 1 : 0;
    }
    scnt[t] = 0;
    __syncthreads();
    int is64 = s_is64;
    for (int i = t; i < TOTE; i += 512) {
        int s, d; read_edge(ei, i, is64, s, d);
        atomicAdd(&scnt[d], 1);
    }
    __syncthreads();
    int c = scnt[t];
    // inclusive scan over scnt
    for (int off = 1; off < NN; off <<= 1) {
        int v = (t >= off) ? scnt[t - off] : 0;
        __syncthreads();
        scnt[t] += v;
        __syncthreads();
    }
    g_row[t + 1] = scnt[t];
    if (t == 0) g_row[0] = 0;
    sfill[t] = scnt[t] - c;
    __syncthreads();
    for (int i = t; i < TOTE; i += 512) {
        int s, d; read_edge(ei, i, is64, s, d);
        int pos = atomicAdd(&sfill[d], 1);
        g_csr[pos] = s;
    }
}

// ================= weight prep: fp32 [co][ci][tap] -> fp16 [tap][co][ci]
__global__ void wprep_kernel(const float* __restrict__ w,
                             __half* __restrict__ bh) {
    int idx = blockIdx.x * 256 + threadIdx.x;
    if (idx >= HIDC * HIDC * 9) return;
    int tap = idx % 9;
    int ci = (idx / 9) % HIDC;
    int co = idx / (9 * HIDC);
    bh[(tap * HIDC + co) * HIDC + ci] = __float2half_rn(w[idx]);
}
__global__ void wprep_op_kernel(const float* __restrict__ w) {
    int idx = blockIdx.x * 256 + threadIdx.x;
    if (idx >= CINC * HIDC) return;
    float v = w[idx];
    __half h = __float2half_rn(v);
    g_woph[idx] = h;
    g_wopl[idx] = __float2half_rn(v - __half2float(h));
}

// ================= fe (mma.sync): 1x1 conv + BN + ReLU + conf =============
__global__ __launch_bounds__(256) void fe_mma_kernel(
    const float* __restrict__ x, const float* __restrict__ fw,
    const float* __restrict__ fb, const float* __restrict__ fg,
    const float* __restrict__ fbe, const float* __restrict__ conf,
    __half* __restrict__ xh) {
    extern __shared__ __align__(16) char dsm[];
    __shared__ float s_conf[128];
    __shared__ float s_sc[HIDC], s_sh[HIDC];

    int tid = threadIdx.x, lane = tid & 31, warp = tid >> 5;
    int warpm = warp >> 2, warpn = warp & 3;
    int n = blockIdx.x, px0 = blockIdx.y * 128;
    uint32_t sbase = smem_u32(dsm);

    if (tid < 128) {
        s_conf[tid] = conf[n * HWSZ + px0 + tid];
        const float inv = rsqrtf(1.0f + 1e-5f);
        float sc = fg[tid] * inv;
        s_sc[tid] = sc;
        s_sh[tid] = fbe[tid] + fb[tid] * sc;
    }

#pragma unroll
    for (int i = 0; i < 16; i++) {
        int idx = i * 256 + tid;
        int cp = idx & 31, co = idx >> 5;
        float2 v = *(const float2*)(fw + co * CINC + cp * 2);
        *(uint32_t*)(dsm + FE_W + co * FE_RS + cp * 4) =
            pack_h2(__float2half_rn(v.x), __float2half_rn(v.y));
    }
#pragma unroll
    for (int i = 0; i < 16; i++) {
        int idx = i * 256 + tid;
        int p = idx & 127, cp = idx >> 7;
        float a = x[((size_t)n * CINC + 2 * cp) * HWSZ + px0 + p];
        float b = x[((size_t)n * CINC + 2 * cp + 1) * HWSZ + px0 + p];
        __half ha = __float2half_rn(a), hb = __float2half_rn(b);
        __half la = __float2half_rn(a - __half2float(ha));
        __half lb = __float2half_rn(b - __half2float(hb));
        *(uint32_t*)(dsm + FE_XH + p * FE_RS + cp * 4) = pack_h2(ha, hb);
        *(uint32_t*)(dsm + FE_XL + p * FE_RS + cp * 4) = pack_h2(la, lb);
    }
    __syncthreads();

    float C[4][4][4];
#pragma unroll
    for (int m = 0; m < 4; m++)
#pragma unroll
        for (int nt = 0; nt < 4; nt++)
#pragma unroll
            for (int r = 0; r < 4; r++) C[m][nt][r] = 0.f;

    int a_row = lane & 15, a_ko = (lane >> 4) * 16;
    int b_row = (lane & 7) + ((lane >> 4) & 1) * 8;
    int b_ko = ((lane >> 3) & 1) * 16;

#pragma unroll
    for (int kq = 0; kq < 4; kq++) {
        uint32_t ah[4][4], al[4][4];
#pragma unroll
        for (int m = 0; m < 4; m++) {
            uint32_t ra = (uint32_t)(warpm * 64 + m * 16 + a_row) * FE_RS + kq * 32 + a_ko;
            ldmx4(ah[m], sbase + FE_XH + ra);
            ldmx4(al[m], sbase + FE_XL + ra);
        }
#pragma unroll
        for (int ntp = 0; ntp < 2; ntp++) {
            uint32_t bw[4];
            uint32_t rb = (uint32_t)(warpn * 32 + ntp * 16 + b_row) * FE_RS + kq * 32 + b_ko;
            ldmx4(bw, sbase + FE_W + rb);
#pragma unroll
            for (int q = 0; q < 2; q++) {
                int nt = ntp * 2 + q;
#pragma unroll
                for (int m = 0; m < 4; m++) {
                    mma16816(C[m][nt], ah[m], bw[2 * q], bw[2 * q + 1]);
                    mma16816(C[m][nt], al[m], bw[2 * q], bw[2 * q + 1]);
                }
            }
        }
    }

    int g4 = lane >> 2, t2 = (lane & 3) * 2;
#pragma unroll
    for (int m = 0; m < 4; m++) {
#pragma unroll
        for (int nt = 0; nt < 4; nt++) {
            int co = warpn * 32 + nt * 8 + t2;
            float sc0 = s_sc[co], sh0 = s_sh[co];
            float sc1 = s_sc[co + 1], sh1 = s_sh[co + 1];
#pragma unroll
            for (int half = 0; half < 2; half++) {
                int pl = warpm * 64 + m * 16 + g4 + half * 8;
                float cf = s_conf[pl];
                float v0 = fmaxf(C[m][nt][half * 2 + 0] * sc0 + sh0, 0.f) * cf;
                float v1 = fmaxf(C[m][nt][half * 2 + 1] * sc1 + sh1, 0.f) * cf;
                int hw = px0 + pl;
                int h = hw >> 5, w = hw & 31;
                size_t q2 = ((size_t)n * POSN + (h + 1) * 34 + (w + 1)) * HIDC + co;
                *(uint32_t*)(xh + q2) =
                    pack_h2(__float2half_rn(v0), __float2half_rn(v1));
            }
        }
    }
}

// ================= mma.sync conv: barrier-free B pipelines =================
// out[p, co] = sum_{tap,ci} Xpad[p + off(tap), ci] * W[tap, co, ci]
// All 4 A slabs resident (one block barrier after prologue). B is per-pair:
// warps (warpm0/1, warpn) share a 32-co B ring-2 loaded by warpm0's warp and
// synced with named barrier (1+warpn, 64). No block barriers in mainloop.
// MODE 0: write padded fp16. MODE 1: write [n][hw][ci] fp16 + pool partials.
template <int MODE>
__global__ __launch_bounds__(256, 2) void conv_mma_kernel(
    const __half* __restrict__ Xh,
    const __half* __restrict__ Wh,
    const float* __restrict__ bb, const float* __restrict__ gg,
    const float* __restrict__ be,
    __half* __restrict__ Oh, float* __restrict__ Part) {
    extern __shared__ __align__(16) char dsm[];
    __shared__ float s_sc[HIDC], s_sh[HIDC];

    int tid = threadIdx.x, lane = tid & 31, warp = tid >> 5;
    int warpm = warp >> 2, warpn = warp & 3;
    int n = blockIdx.x / MTILES, mt = blockIdx.x % MTILES;
    int pbase = mt * 128;

    if (tid < HIDC) {
        const float inv = rsqrtf(1.0f + 1e-5f);
        float sc = gg[tid] * inv;
        s_sc[tid] = sc;
        s_sh[tid] = be[tid] + bb[tid] * sc;
    }

    float C[4][4][4];
#pragma unroll
    for (int m = 0; m < 4; m++)
#pragma unroll
        for (int nt = 0; nt < 4; nt++)
#pragma unroll
            for (int r = 0; r < 4; r++) C[m][nt][r] = 0.f;

    uint32_t sbase = smem_u32(dsm);
    uint32_t sB0 = sbase + B_BASE + warpn * B_PAIR;
    bool loader = (warpm == 0);

    // B stage s1 into buf: 32 co rows x 64 ci, stride 144. Loader warp only.
    auto loadB = [&](int s1, int buf) {
        int pairci = s1 / 9, tap = s1 - pairci * 9;
        uint32_t s0 = sB0 + buf * 4608;
        size_t gb = ((size_t)(tap * HIDC + warpn * 32)) * HIDC + pairci * 64;
#pragma unroll
        for (int i = 0; i < 8; i++) {
            int seg = i * 32 + lane;
            int r = seg >> 3, sg = seg & 7;
            cpasync16(s0 + r * 144 + sg * 16, Wh + gb + (size_t)r * HIDC + sg * 8);
        }
    };

    // prologue: A slabs (all threads) + B stage 0 (loader warps); one group
    {
        size_t gbase = ((size_t)(n * POSN + pbase)) * HIDC;
#pragma unroll
        for (int cic = 0; cic < 4; cic++) {
            uint32_t s0 = sbase + cic * A_SLAB;
            size_t gb = gbase + cic * 32;
#pragma unroll
            for (int i = 0; i < 4; i++) {
                int idx = i * 256 + tid;
                if (idx < 792) {
                    int r = idx >> 2, sg = idx & 3;
                    cpasync16(s0 + r * 80 + sg * 16, Xh + gb + (size_t)r * HIDC + sg * 8);
                }
            }
        }
        if (loader) loadB(0, 0);
        CP_COMMIT();
        CP_WAIT(0);
        __syncthreads();
    }

    int a_row = lane & 15, a_ko = (lane >> 4) * 16;
    int b_row = (lane & 7) + ((lane >> 4) & 1) * 8;
    int b_ko = ((lane >> 3) & 1) * 16;
    int barid = 1 + warpn;

#pragma unroll 1
    for (int s = 0; s < 18; s++) {
        int pair = s / 9, tap = s - pair * 9;
        CP_WAIT(0);          // loader: B(s) landed (issued a full stage ago)
        BAR_PAIR(barid);     // B(s) visible to both warps; both done with buf (s+1)&1
        if (loader && s + 1 < 18) {
            loadB(s + 1, (s + 1) & 1);
            CP_COMMIT();
        }
        int tapoff = (tap / 3) * 34 + (tap % 3);
        uint32_t sB = sB0 + (s & 1) * 4608;
#pragma unroll
        for (int c2 = 0; c2 < 2; c2++) {
            uint32_t sA = sbase + (pair * 2 + c2) * A_SLAB;
            uint32_t bhalf = c2 * 64;
#pragma unroll
            for (int ks = 0; ks < 2; ks++) {
                uint32_t ah[4][4];
#pragma unroll
                for (int m = 0; m < 4; m++) {
                    uint32_t ra = (uint32_t)(tapoff + warpm * 64 + m * 16 + a_row) * 80 + ks * 32 + a_ko;
                    ldmx4(ah[m], sA + ra);
                }
#pragma unroll
                for (int ntp = 0; ntp < 2; ntp++) {
                    uint32_t rbh[4];
                    uint32_t rb = (uint32_t)(ntp * 16 + b_row) * 144 + bhalf + ks * 32 + b_ko;
                    ldmx4(rbh, sB + rb);
#pragma unroll
                    for (int q = 0; q < 2; q++) {
                        int nt = ntp * 2 + q;
#pragma unroll
                        for (int m = 0; m < 4; m++)
                            mma16816(C[m][nt], ah[m], rbh[2 * q], rbh[2 * q + 1]);
                    }
                }
            }
        }
    }

    // ---- epilogue ----
    int g4 = lane >> 2;
    int t2 = (lane & 3) * 2;
    float ps[4][2];
    if (MODE == 1)
#pragma unroll
        for (int nt = 0; nt < 4; nt++) { ps[nt][0] = 0.f; ps[nt][1] = 0.f; }
#pragma unroll
    for (int m = 0; m < 4; m++) {
#pragma unroll
        for (int nt = 0; nt < 4; nt++) {
            int co = warpn * 32 + nt * 8 + t2;
            float sc0 = s_sc[co], sh0 = s_sh[co];
            float sc1 = s_sc[co + 1], sh1 = s_sh[co + 1];
#pragma unroll
            for (int half = 0; half < 2; half++) {
                int p = pbase + warpm * 64 + m * 16 + g4 + half * 8;
                float v0 = C[m][nt][half * 2 + 0] * sc0 + sh0;
                float v1 = C[m][nt][half * 2 + 1] * sc1 + sh1;
                int h = p / 34, w = p % 34;
                bool valid = (w < 32) && (h < 32);
                v0 = valid ? fmaxf(v0, 0.f) : 0.f;
                v1 = valid ? fmaxf(v1, 0.f) : 0.f;
                uint32_t pk = pack_h2(__float2half_rn(v0), __float2half_rn(v1));
                if (MODE == 0) {
                    size_t q2 = ((size_t)n * POSN + p + 35) * HIDC + co;
                    *(uint32_t*)(Oh + q2) = pk;
                } else {
                    ps[nt][0] += v0;
                    ps[nt][1] += v1;
                    if (valid) {
                        size_t q2 = ((size_t)n * HWSZ + h * WW + w) * HIDC + co;
                        *(uint32_t*)(Oh + q2) = pk;
                    }
                }
            }
        }
    }
    if (MODE == 1) {
        // reduce over g4 lanes (bits 2..4); lanes 0-3 hold per-t2 sums
#pragma unroll
        for (int nt = 0; nt < 4; nt++)
#pragma unroll
            for (int q = 0; q < 2; q++) {
                float v = ps[nt][q];
                v += __shfl_xor_sync(0xffffffffu, v, 4);
                v += __shfl_xor_sync(0xffffffffu, v, 8);
                v += __shfl_xor_sync(0xffffffffu, v, 16);
                ps[nt][q] = v;
            }
        if (lane < 4) {
            size_t base = (((size_t)n * MTILES + mt) * 8 + warp) * 32;
#pragma unroll
            for (int nt = 0; nt < 4; nt++) {
                Part[base + nt * 8 + lane * 2 + 0] = ps[nt][0];
                Part[base + nt * 8 + lane * 2 + 1] = ps[nt][1];
            }
        }
    }
}

// ================= pool reduce: 18 partials per (n, ci) =================
__global__ __launch_bounds__(128) void pool_reduce_kernel() {
    int n = blockIdx.x, ci = threadIdx.x;
    int wn = ci >> 5, col = ci & 31;
    float s = 0.f;
#pragma unroll 1
    for (int mt = 0; mt < MTILES; mt++) {
        size_t b = (((size_t)n * MTILES + mt) * 8);
        s += g_part[(b + wn) * 32 + col];          // warpm=0
        s += g_part[(b + 4 + wn) * 32 + col];      // warpm=1
    }
    g_xnode[n * HIDC + ci] = s * (1.f / 1024.f);
}

// ================= GAT =================
__global__ __launch_bounds__(128) void gat_h_kernel(
    const float* __restrict__ xin, const float* __restrict__ lin,
    const float* __restrict__ asw, const float* __restrict__ adw) {
    int n = blockIdx.x, t = threadIdx.x;
    __shared__ float xr[HIDC];
    __shared__ float red[HIDC];
    xr[t] = xin[n * HIDC + t];
    __syncthreads();
    float hv[HEADS];
#pragma unroll
    for (int j = 0; j < HEADS; j++) {
        int col = j * HIDC + t;
        float s = 0.f;
        for (int k = 0; k < HIDC; k++) s += xr[k] * lin[k * (HEADS * HIDC) + col];
        hv[j] = s;
        g_hfeat[n * (HEADS * HIDC) + col] = s;
    }
#pragma unroll
    for (int j = 0; j < HEADS; j++) {
        red[t] = hv[j] * asw[j * HIDC + t];
        __syncthreads();
        for (int off = 64; off > 0; off >>= 1) {
            if (t < off) red[t] += red[t + off];
            __syncthreads();
        }
        if (t == 0) g_as[n * HEADS + j] = red[0];
        __syncthreads();
        red[t] = hv[j] * adw[j * HIDC + t];
        __syncthreads();
        for (int off = 64; off > 0; off >>= 1) {
            if (t < off) red[t] += red[t + off];
            __syncthreads();
        }
        if (t == 0) g_ad[n * HEADS + j] = red[0];
        __syncthreads();
    }
}

__global__ __launch_bounds__(128) void gat_aggr_kernel(
    const float* __restrict__ bias, float* __restrict__ xout) {
    int n = blockIdx.x, t = threadIdx.x;
    float adn[HEADS];
#pragma unroll
    for (int j = 0; j < HEADS; j++) adn[j] = g_ad[n * HEADS + j];
    int rs = g_row[n], re = g_row[n + 1];
    float mx[HEADS] = {-1e30f, -1e30f, -1e30f, -1e30f};
    for (int ei = rs; ei < re; ei++) {
        int s = g_csr[ei];
#pragma unroll
        for (int j = 0; j < HEADS; j++) {
            float e = g_as[s * HEADS + j] + adn[j];
            e = (e > 0.f) ? e : 0.2f * e;
            mx[j] = fmaxf(mx[j], e);
        }
    }
    float den[HEADS] = {0.f, 0.f, 0.f, 0.f};
    float acc[HEADS] = {0.f, 0.f, 0.f, 0.f};
    for (int ei = rs; ei < re; ei++) {
        int s = g_csr[ei];
#pragma unroll
        for (int j = 0; j < HEADS; j++) {
            float e = g_as[s * HEADS + j] + adn[j];
            e = (e > 0.f) ? e : 0.2f * e;
            float ex = __expf(e - mx[j]);
            den[j] += ex;
            acc[j] += ex * g_hfeat[s * (HEADS * HIDC) + j * HIDC + t];
        }
    }
    float o = 0.f;
#pragma unroll
    for (int j = 0; j < HEADS; j++) o += acc[j] / (den[j] + 1e-16f);
    o = o * 0.25f + bias[t];
    xout[n * HIDC + t] = fmaxf(o, 0.f);
}

// ================= gterm =================
__global__ __launch_bounds__(64) void gterm_kernel(
    const float* __restrict__ opw, const float* __restrict__ opb) {
    int n = blockIdx.x, t = threadIdx.x;
    __shared__ float xg[HIDC];
    xg[t] = g_xg[n * HIDC + t];
    xg[t + 64] = g_xg[n * HIDC + t + 64];
    __syncthreads();
    float s = opb[t];
    for (int o = 0; o < HIDC; o++) s += xg[o] * opw[t * HIDC + o];
    g_gterm[n * CINC + t] = s;
}

// ================= op: out = gterm + xp @ op_w^T (fp16 2-term) =============
__global__ __launch_bounds__(256) void op_mma_kernel(
    const __half* __restrict__ Xh,
    float* __restrict__ out) {
    extern __shared__ __align__(16) char dsm[];
    int tid = threadIdx.x, lane = tid & 31, warp = tid >> 5;
    int warpm = warp >> 1, warpn = warp & 1;
    int n = blockIdx.x, hw0 = blockIdx.y * 128;
    uint32_t sbase = smem_u32(dsm);

#pragma unroll
    for (int i = 0; i < 8; i++) {
        int idx = i * 256 + tid;
        int r = idx >> 4, sg = idx & 15;
        const __half* g = Xh + ((size_t)n * HWSZ + hw0 + r) * HIDC + sg * 8;
        cpasync16(sbase + r * OP_RS + sg * 16, g);
    }
#pragma unroll
    for (int i = 0; i < 8; i++) {
        int idx = i * 256 + tid;
        int term = idx >> 10;
        int r = (idx >> 4) & 63, sg = idx & 15;
        const __half* g = (term ? g_wopl : g_woph) + r * HIDC + sg * 8;
        cpasync16(sbase + OPW_0 + term * OPW_T + r * OP_RS + sg * 16, g);
    }
    CP_COMMIT();

    float C[8][4];
#pragma unroll
    for (int nt = 0; nt < 8; nt++)
#pragma unroll
        for (int r = 0; r < 4; r++) C[nt][r] = 0.f;

    int a_row = lane & 15, a_ko = (lane >> 4) * 16;
    int b_row = (lane & 7) + ((lane >> 4) & 1) * 8;
    int b_ko = ((lane >> 3) & 1) * 16;

    CP_WAIT(0);
    __syncthreads();

#pragma unroll 1
    for (int kc = 0; kc < 8; kc++) {
        uint32_t awh[4], awl[4];
        uint32_t ra = (uint32_t)(warpm * 16 + a_row) * OP_RS + kc * 32 + a_ko;
        ldmx4(awh, sbase + OPW_0 + ra);
        ldmx4(awl, sbase + OPW_0 + OPW_T + ra);
#pragma unroll
        for (int ntp = 0; ntp < 4; ntp++) {
            uint32_t xbh[4];
            uint32_t rb = (uint32_t)(warpn * 64 + ntp * 16 + b_row) * OP_RS + kc * 32 + b_ko;
            ldmx4(xbh, sbase + rb);
#pragma unroll
            for (int q = 0; q < 2; q++) {
                int nt = ntp * 2 + q;
                mma16816(C[nt], awh, xbh[2 * q], xbh[2 * q + 1]);
                mma16816(C[nt], awl, xbh[2 * q], xbh[2 * q + 1]);
            }
        }
    }

    int g4 = lane >> 2, t2 = (lane & 3) * 2;
    int co_a = warpm * 16 + g4;
    int co_b = co_a + 8;
    float gta = g_gterm[n * CINC + co_a];
    float gtb = g_gterm[n * CINC + co_b];
#pragma unroll
    for (int nt = 0; nt < 8; nt++) {
        int hw = hw0 + warpn * 64 + nt * 8 + t2;
        float2 va = make_float2(C[nt][0] + gta, C[nt][1] + gta);
        float2 vb = make_float2(C[nt][2] + gtb, C[nt][3] + gtb);
        *(float2*)&out[((size_t)n * CINC + co_a) * HWSZ + hw] = va;
        *(float2*)&out[((size_t)n * CINC + co_b) * HWSZ + hw] = vb;
    }
}

// ================= launch =================
extern "C" void kernel_launch(void* const* d_in, const int* in_sizes, int n_in,
                              void* d_out, int out_size) {
    const float* x    = (const float*)d_in[0];
    const int*   ei   = (const int*)d_in[1];
    const float* conf = (const float*)d_in[2];
    const float* fe_w = (const float*)d_in[3];
    const float* fe_b = (const float*)d_in[4];
    const float* fe_g = (const float*)d_in[5];
    const float* fe_be= (const float*)d_in[6];
    const float* sp_w1= (const float*)d_in[7];
    const float* sp_b1= (const float*)d_in[8];
    const float* sp_g1= (const float*)d_in[9];
    const float* sp_e1= (const float*)d_in[10];
    const float* sp_w2= (const float*)d_in[11];
    const float* sp_b2= (const float*)d_in[12];
    const float* sp_g2= (const float*)d_in[13];
    const float* sp_e2= (const float*)d_in[14];
    const float* g1_lin=(const float*)d_in[15];
    const float* g1_as= (const float*)d_in[16];
    const float* g1_ad= (const float*)d_in[17];
    const float* g1_b = (const float*)d_in[18];
    const float* g2_lin=(const float*)d_in[19];
    const float* g2_as= (const float*)d_in[20];
    const float* g2_ad= (const float*)d_in[21];
    const float* g2_b = (const float*)d_in[22];
    const float* op_w = (const float*)d_in[23];
    const float* op_b = (const float*)d_in[24];
    float* out = (float*)d_out;

    void *p1h, *p2h, *pph, *pw1h, *pw2h, *pXn, *pXg, *pPart;
    cudaGetSymbolAddress(&p1h, g_x1h);
    cudaGetSymbolAddress(&p2h, g_x2h);
    cudaGetSymbolAddress(&pph, g_xph);
    cudaGetSymbolAddress(&pw1h, g_w1h);
    cudaGetSymbolAddress(&pw2h, g_w2h);
    cudaGetSymbolAddress(&pXn, g_xnode);
    cudaGetSymbolAddress(&pXg, g_xg);
    cudaGetSymbolAddress(&pPart, g_part);
    __half* x1h = (__half*)p1h;
    __half* x2h = (__half*)p2h;
    __half* xph = (__half*)pph;
    __half* w1h = (__half*)pw1h;
    __half* w2h = (__half*)pw2h;
    float* xnode = (float*)pXn;
    float* xg = (float*)pXg;
    float* part = (float*)pPart;

    cudaFuncSetAttribute(conv_mma_kernel<0>, cudaFuncAttributeMaxDynamicSharedMemorySize, CONV_SMEM);
    cudaFuncSetAttribute(conv_mma_kernel<1>, cudaFuncAttributeMaxDynamicSharedMemorySize, CONV_SMEM);
    cudaFuncSetAttribute(fe_mma_kernel, cudaFuncAttributeMaxDynamicSharedMemorySize, FE_SMEM);
    cudaFuncSetAttribute(op_mma_kernel, cudaFuncAttributeMaxDynamicSharedMemorySize, OP_SMEM);

    const int WPN = (HIDC * HIDC * 9 + 255) / 256;

    fe_mma_kernel<<<dim3(NN, 8), 256, FE_SMEM>>>(x, fe_w, fe_b, fe_g, fe_be, conf, x1h); // 0
    wprep_kernel<<<WPN, 256>>>(sp_w1, w1h);                                   // 1
    wprep_kernel<<<WPN, 256>>>(sp_w2, w2h);                                   // 2
    conv_mma_kernel<0><<<NN * MTILES, 256, CONV_SMEM>>>(                      // 3 (ncu)
        x1h, w1h, sp_b1, sp_g1, sp_e1, x2h, nullptr);
    wprep_op_kernel<<<(CINC * HIDC + 255) / 256, 256>>>(op_w);                // 4
    csr_build_kernel<<<1, 512>>>(ei);                                         // 5
    conv_mma_kernel<1><<<NN * MTILES, 256, CONV_SMEM>>>(                      // 6
        x2h, w2h, sp_b2, sp_g2, sp_e2, xph, part);
    pool_reduce_kernel<<<NN, 128>>>();                                        // 7
    gat_h_kernel<<<NN, 128>>>(xnode, g1_lin, g1_as, g1_ad);                   // 8
    gat_aggr_kernel<<<NN, 128>>>(g1_b, xg);                                   // 9
    gat_h_kernel<<<NN, 128>>>(xg, g2_lin, g2_as, g2_ad);                      // 10
    gat_aggr_kernel<<<NN, 128>>>(g2_b, xg);                                   // 11
    gterm_kernel<<<NN, 64>>>(op_w, op_b);                                     // 12
    op_mma_kernel<<<dim3(NN, 8), 256, OP_SMEM>>>(xph, out);                   // 13

    (void)in_sizes; (void)n_in; (void)out_size;
}

// round 12
// speedup vs baseline: 9.1417x; 1.0065x over previous
#include <cuda_runtime.h>
#include <cuda_fp16.h>
#include <math.h>
#include <stdint.h>

#define NN   512
#define CINC 64
#define HIDC 128
#define HWSZ 1024
#define HH   32
#define WW   32
#define HEADS 4
#define NE   16384
#define TOTE (NE + NN)
#define POSN 1224          // padded positions per image: 36 rows x 34 cols
#define MTILES 9           // 9 M-tiles of 128 cover p in [0,1152)

// conv smem: A 4 resident slabs x 198 rows x 80B (pad 16000)
//            B: 4 pairs x ring2 x (32 rows x 144B = 4608)
#define A_SLAB  16000
#define B_BASE  64000
#define B_PAIR  9216
#define CONV_SMEM (64000 + 4 * B_PAIR)

// fe smem
#define FE_RS   144
#define FE_XH   0
#define FE_XL   18432
#define FE_W    36864
#define FE_SMEM 55296

// op smem
#define OP_RS   272
#define OPW_0   34816
#define OPW_T   17408
#define OP_SMEM (34816 + 34816)

// ================= helpers =================
__device__ __forceinline__ uint32_t smem_u32(const void* p) {
    return (uint32_t)__cvta_generic_to_shared(p);
}
__device__ __forceinline__ void ldmx4(uint32_t* r, uint32_t a) {
    asm volatile("ldmatrix.sync.aligned.m8n8.x4.shared.b16 {%0,%1,%2,%3}, [%4];"
                 : "=r"(r[0]), "=r"(r[1]), "=r"(r[2]), "=r"(r[3]) : "r"(a));
}
__device__ __forceinline__ void mma16816(float* c, const uint32_t* a,
                                         uint32_t b0, uint32_t b1) {
    asm volatile(
        "mma.sync.aligned.m16n8k16.row.col.f32.f16.f16.f32 "
        "{%0,%1,%2,%3}, {%4,%5,%6,%7}, {%8,%9}, {%0,%1,%2,%3};"
        : "+f"(c[0]), "+f"(c[1]), "+f"(c[2]), "+f"(c[3])
        : "r"(a[0]), "r"(a[1]), "r"(a[2]), "r"(a[3]), "r"(b0), "r"(b1));
}
__device__ __forceinline__ void cpasync16(uint32_t sa, const void* g) {
    unsigned long long ga = (unsigned long long)__cvta_generic_to_global(g);
    asm volatile("cp.async.cg.shared.global [%0], [%1], 16;" :: "r"(sa), "l"(ga));
}
#define CP_COMMIT() asm volatile("cp.async.commit_group;")
#define CP_WAIT(N)  asm volatile("cp.async.wait_group %0;" :: "n"(N))
#define BAR_PAIR(id) asm volatile("bar.sync %0, 64;" :: "r"(id) : "memory")

__device__ __forceinline__ uint32_t pack_h2(__half a, __half b) {
    return (uint32_t)__half_as_ushort(a) | ((uint32_t)__half_as_ushort(b) << 16);
}

// ================= device scratch =================
__device__ __half g_x1h[(size_t)NN * POSN * HIDC]; // border stays zero
__device__ __half g_x2h[(size_t)NN * POSN * HIDC];
__device__ __half g_xph[(size_t)NN * HWSZ * HIDC]; // conv2 out [n][hw][ci]
__device__ __half g_w1h[9 * HIDC * HIDC];
__device__ __half g_w2h[9 * HIDC * HIDC];
__device__ __half g_woph[CINC * HIDC];
__device__ __half g_wopl[CINC * HIDC];
__device__ float g_part[(size_t)NN * MTILES * 8 * 32]; // pool partials
__device__ float g_hfeat[NN * HEADS * HIDC];
__device__ float g_as[NN * HEADS];
__device__ float g_ad[NN * HEADS];
__device__ float g_xg[NN * HIDC];
__device__ float g_gterm[NN * CINC];
__device__ int   g_row[NN + 1];
__device__ int   g_csr[TOTE];

// ================= CSR build (one block, 512 threads) =================
__device__ __forceinline__ void read_edge(const int* __restrict__ ei, int i,
                                          int is64, int& s, int& d) {
    if (i < NE) {
        if (is64) { s = ei[2 * i]; d = ei[2 * (NE + i)]; }
        else      { s = ei[i];     d = ei[NE + i]; }
    } else { s = i - NE; d = i - NE; }
}
__global__ __launch_bounds__(512) void csr_build_kernel(const int* __restrict__ ei) {
    __shared__ int scnt[NN];
    __shared__ int sfill[NN];
    __shared__ int s_is64;
    int t = threadIdx.x;
    if (t == 0) {
        int acc = 0;
        for (int i = 0; i < 128; i++) acc |= ei[2 * i + 1];
        s_is64 = (acc == 0) ? 1 : 0;
    }
    scnt[t] = 0;
    __syncthreads();
    int is64 = s_is64;
    for (int i = t; i < TOTE; i += 512) {
        int s, d; read_edge(ei, i, is64, s, d);
        atomicAdd(&scnt[d], 1);
    }
    __syncthreads();
    int c = scnt[t];
    for (int off = 1; off < NN; off <<= 1) {
        int v = (t >= off) ? scnt[t - off] : 0;
        __syncthreads();
        scnt[t] += v;
        __syncthreads();
    }
    g_row[t + 1] = scnt[t];
    if (t == 0) g_row[0] = 0;
    sfill[t] = scnt[t] - c;
    __syncthreads();
    for (int i = t; i < TOTE; i += 512) {
        int s, d; read_edge(ei, i, is64, s, d);
        int pos = atomicAdd(&sfill[d], 1);
        g_csr[pos] = s;
    }
}

// ================= fused weight prep =================
__global__ void wprep_all_kernel(const float* __restrict__ w1,
                                 const float* __restrict__ w2,
                                 const float* __restrict__ wop) {
    const int WN = HIDC * HIDC * 9;
    int idx = blockIdx.x * 256 + threadIdx.x;
    if (idx < 2 * WN) {
        int j = (idx < WN) ? idx : idx - WN;
        int tap = j % 9;
        int ci = (j / 9) % HIDC;
        int co = j / (9 * HIDC);
        if (idx < WN)
            g_w1h[(tap * HIDC + co) * HIDC + ci] = __float2half_rn(w1[j]);
        else
            g_w2h[(tap * HIDC + co) * HIDC + ci] = __float2half_rn(w2[j]);
    } else if (idx < 2 * WN + CINC * HIDC) {
        int j = idx - 2 * WN;
        float v = wop[j];
        __half h = __float2half_rn(v);
        g_woph[j] = h;
        g_wopl[j] = __float2half_rn(v - __half2float(h));
    }
}

// ================= fe (mma.sync): 1x1 conv + BN + ReLU + conf =============
__global__ __launch_bounds__(256) void fe_mma_kernel(
    const float* __restrict__ x, const float* __restrict__ fw,
    const float* __restrict__ fb, const float* __restrict__ fg,
    const float* __restrict__ fbe, const float* __restrict__ conf,
    __half* __restrict__ xh) {
    extern __shared__ __align__(16) char dsm[];
    __shared__ float s_conf[128];
    __shared__ float s_sc[HIDC], s_sh[HIDC];

    int tid = threadIdx.x, lane = tid & 31, warp = tid >> 5;
    int warpm = warp >> 2, warpn = warp & 3;
    int n = blockIdx.x, px0 = blockIdx.y * 128;
    uint32_t sbase = smem_u32(dsm);

    if (tid < 128) {
        s_conf[tid] = conf[n * HWSZ + px0 + tid];
        const float inv = rsqrtf(1.0f + 1e-5f);
        float sc = fg[tid] * inv;
        s_sc[tid] = sc;
        s_sh[tid] = fbe[tid] + fb[tid] * sc;
    }

#pragma unroll
    for (int i = 0; i < 16; i++) {
        int idx = i * 256 + tid;
        int cp = idx & 31, co = idx >> 5;
        float2 v = *(const float2*)(fw + co * CINC + cp * 2);
        *(uint32_t*)(dsm + FE_W + co * FE_RS + cp * 4) =
            pack_h2(__float2half_rn(v.x), __float2half_rn(v.y));
    }
#pragma unroll
    for (int i = 0; i < 16; i++) {
        int idx = i * 256 + tid;
        int p = idx & 127, cp = idx >> 7;
        float a = x[((size_t)n * CINC + 2 * cp) * HWSZ + px0 + p];
        float b = x[((size_t)n * CINC + 2 * cp + 1) * HWSZ + px0 + p];
        __half ha = __float2half_rn(a), hb = __float2half_rn(b);
        __half la = __float2half_rn(a - __half2float(ha));
        __half lb = __float2half_rn(b - __half2float(hb));
        *(uint32_t*)(dsm + FE_XH + p * FE_RS + cp * 4) = pack_h2(ha, hb);
        *(uint32_t*)(dsm + FE_XL + p * FE_RS + cp * 4) = pack_h2(la, lb);
    }
    __syncthreads();

    float C[4][4][4];
#pragma unroll
    for (int m = 0; m < 4; m++)
#pragma unroll
        for (int nt = 0; nt < 4; nt++)
#pragma unroll
            for (int r = 0; r < 4; r++) C[m][nt][r] = 0.f;

    int a_row = lane & 15, a_ko = (lane >> 4) * 16;
    int b_row = (lane & 7) + ((lane >> 4) & 1) * 8;
    int b_ko = ((lane >> 3) & 1) * 16;

#pragma unroll
    for (int kq = 0; kq < 4; kq++) {
        uint32_t ah[4][4], al[4][4];
#pragma unroll
        for (int m = 0; m < 4; m++) {
            uint32_t ra = (uint32_t)(warpm * 64 + m * 16 + a_row) * FE_RS + kq * 32 + a_ko;
            ldmx4(ah[m], sbase + FE_XH + ra);
            ldmx4(al[m], sbase + FE_XL + ra);
        }
#pragma unroll
        for (int ntp = 0; ntp < 2; ntp++) {
            uint32_t bw[4];
            uint32_t rb = (uint32_t)(warpn * 32 + ntp * 16 + b_row) * FE_RS + kq * 32 + b_ko;
            ldmx4(bw, sbase + FE_W + rb);
#pragma unroll
            for (int q = 0; q < 2; q++) {
                int nt = ntp * 2 + q;
#pragma unroll
                for (int m = 0; m < 4; m++) {
                    mma16816(C[m][nt], ah[m], bw[2 * q], bw[2 * q + 1]);
                    mma16816(C[m][nt], al[m], bw[2 * q], bw[2 * q + 1]);
                }
            }
        }
    }

    int g4 = lane >> 2, t2 = (lane & 3) * 2;
#pragma unroll
    for (int m = 0; m < 4; m++) {
#pragma unroll
        for (int nt = 0; nt < 4; nt++) {
            int co = warpn * 32 + nt * 8 + t2;
            float sc0 = s_sc[co], sh0 = s_sh[co];
            float sc1 = s_sc[co + 1], sh1 = s_sh[co + 1];
#pragma unroll
            for (int half = 0; half < 2; half++) {
                int pl = warpm * 64 + m * 16 + g4 + half * 8;
                float cf = s_conf[pl];
                float v0 = fmaxf(C[m][nt][half * 2 + 0] * sc0 + sh0, 0.f) * cf;
                float v1 = fmaxf(C[m][nt][half * 2 + 1] * sc1 + sh1, 0.f) * cf;
                int hw = px0 + pl;
                int h = hw >> 5, w = hw & 31;
                size_t q2 = ((size_t)n * POSN + (h + 1) * 34 + (w + 1)) * HIDC + co;
                *(uint32_t*)(xh + q2) =
                    pack_h2(__float2half_rn(v0), __float2half_rn(v1));
            }
        }
    }
}

// ================= mma.sync conv: barrier-free B pipelines =================
// MODE 0: write padded fp16. MODE 1: write [n][hw][ci] fp16 + pool partials.
template <int MODE>
__global__ __launch_bounds__(256, 2) void conv_mma_kernel(
    const __half* __restrict__ Xh,
    const __half* __restrict__ Wh,
    const float* __restrict__ bb, const float* __restrict__ gg,
    const float* __restrict__ be,
    __half* __restrict__ Oh, float* __restrict__ Part) {
    extern __shared__ __align__(16) char dsm[];
    __shared__ float s_sc[HIDC], s_sh[HIDC];

    int tid = threadIdx.x, lane = tid & 31, warp = tid >> 5;
    int warpm = warp >> 2, warpn = warp & 3;
    int n = blockIdx.x / MTILES, mt = blockIdx.x % MTILES;
    int pbase = mt * 128;

    if (tid < HIDC) {
        const float inv = rsqrtf(1.0f + 1e-5f);
        float sc = gg[tid] * inv;
        s_sc[tid] = sc;
        s_sh[tid] = be[tid] + bb[tid] * sc;
    }

    float C[4][4][4];
#pragma unroll
    for (int m = 0; m < 4; m++)
#pragma unroll
        for (int nt = 0; nt < 4; nt++)
#pragma unroll
            for (int r = 0; r < 4; r++) C[m][nt][r] = 0.f;

    uint32_t sbase = smem_u32(dsm);
    uint32_t sB0 = sbase + B_BASE + warpn * B_PAIR;
    bool loader = (warpm == 0);

    auto loadB = [&](int s1, uint32_t buf) {
        int pairci = s1 / 9, tap = s1 - pairci * 9;
        uint32_t s0 = sB0 + buf * 4608;
        size_t gb = ((size_t)(tap * HIDC + warpn * 32)) * HIDC + pairci * 64;
#pragma unroll
        for (int i = 0; i < 8; i++) {
            int seg = i * 32 + lane;
            int r = seg >> 3, sg = seg & 7;
            cpasync16(s0 + r * 144 + sg * 16, Wh + gb + (size_t)r * HIDC + sg * 8);
        }
    };

    // prologue
    {
        size_t gbase = ((size_t)(n * POSN + pbase)) * HIDC;
#pragma unroll
        for (int cic = 0; cic < 4; cic++) {
            uint32_t s0 = sbase + cic * A_SLAB;
            size_t gb = gbase + cic * 32;
#pragma unroll
            for (int i = 0; i < 4; i++) {
                int idx = i * 256 + tid;
                if (idx < 792) {
                    int r = idx >> 2, sg = idx & 3;
                    cpasync16(s0 + r * 80 + sg * 16, Xh + gb + (size_t)r * HIDC + sg * 8);
                }
            }
        }
        if (loader) loadB(0, 0);
        CP_COMMIT();
        CP_WAIT(0);
        __syncthreads();
    }

    int a_row = lane & 15, a_ko = (lane >> 4) * 16;
    int b_row = (lane & 7) + ((lane >> 4) & 1) * 8;
    int b_ko = ((lane >> 3) & 1) * 16;
    int barid = 1 + warpn;

    auto do_stage = [&](int s, uint32_t buf) {
        int pair = s / 9, tap = s - pair * 9;
        CP_WAIT(0);
        BAR_PAIR(barid);
        if (loader && s + 1 < 18) {
            loadB(s + 1, buf ^ 1u);
            CP_COMMIT();
        }
        int tapoff = (tap / 3) * 34 + (tap - (tap / 3) * 3);
        uint32_t sB = sB0 + buf * 4608;
#pragma unroll
        for (int c2 = 0; c2 < 2; c2++) {
            uint32_t sA = sbase + (pair * 2 + c2) * A_SLAB;
            uint32_t bhalf = c2 * 64;
#pragma unroll
            for (int ks = 0; ks < 2; ks++) {
                uint32_t ah[4][4];
#pragma unroll
                for (int m = 0; m < 4; m++) {
                    uint32_t ra = (uint32_t)(tapoff + warpm * 64 + m * 16 + a_row) * 80 + ks * 32 + a_ko;
                    ldmx4(ah[m], sA + ra);
                }
#pragma unroll
                for (int ntp = 0; ntp < 2; ntp++) {
                    uint32_t rbh[4];
                    uint32_t rb = (uint32_t)(ntp * 16 + b_row) * 144 + bhalf + ks * 32 + b_ko;
                    ldmx4(rbh, sB + rb);
#pragma unroll
                    for (int q = 0; q < 2; q++) {
                        int nt = ntp * 2 + q;
#pragma unroll
                        for (int m = 0; m < 4; m++)
                            mma16816(C[m][nt], ah[m], rbh[2 * q], rbh[2 * q + 1]);
                    }
                }
            }
        }
    };

    // mainloop unrolled x2: even stage buf 0, odd stage buf 1
#pragma unroll 1
    for (int sp = 0; sp < 9; sp++) {
        do_stage(sp * 2, 0u);
        do_stage(sp * 2 + 1, 1u);
    }

    // ---- epilogue ----
    int g4 = lane >> 2;
    int t2 = (lane & 3) * 2;
    float ps[4][2];
    if (MODE == 1)
#pragma unroll
        for (int nt = 0; nt < 4; nt++) { ps[nt][0] = 0.f; ps[nt][1] = 0.f; }
#pragma unroll
    for (int m = 0; m < 4; m++) {
#pragma unroll
        for (int nt = 0; nt < 4; nt++) {
            int co = warpn * 32 + nt * 8 + t2;
            float sc0 = s_sc[co], sh0 = s_sh[co];
            float sc1 = s_sc[co + 1], sh1 = s_sh[co + 1];
#pragma unroll
            for (int half = 0; half < 2; half++) {
                int p = pbase + warpm * 64 + m * 16 + g4 + half * 8;
                float v0 = C[m][nt][half * 2 + 0] * sc0 + sh0;
                float v1 = C[m][nt][half * 2 + 1] * sc1 + sh1;
                int h = p / 34, w = p % 34;
                bool valid = (w < 32) && (h < 32);
                v0 = valid ? fmaxf(v0, 0.f) : 0.f;
                v1 = valid ? fmaxf(v1, 0.f) : 0.f;
                uint32_t pk = pack_h2(__float2half_rn(v0), __float2half_rn(v1));
                if (MODE == 0) {
                    size_t q2 = ((size_t)n * POSN + p + 35) * HIDC + co;
                    *(uint32_t*)(Oh + q2) = pk;
                } else {
                    ps[nt][0] += v0;
                    ps[nt][1] += v1;
                    if (valid) {
                        size_t q2 = ((size_t)n * HWSZ + h * WW + w) * HIDC + co;
                        *(uint32_t*)(Oh + q2) = pk;
                    }
                }
            }
        }
    }
    if (MODE == 1) {
#pragma unroll
        for (int nt = 0; nt < 4; nt++)
#pragma unroll
            for (int q = 0; q < 2; q++) {
                float v = ps[nt][q];
                v += __shfl_xor_sync(0xffffffffu, v, 4);
                v += __shfl_xor_sync(0xffffffffu, v, 8);
                v += __shfl_xor_sync(0xffffffffu, v, 16);
                ps[nt][q] = v;
            }
        if (lane < 4) {
            size_t base = (((size_t)n * MTILES + mt) * 8 + warp) * 32;
#pragma unroll
            for (int nt = 0; nt < 4; nt++) {
                Part[base + nt * 8 + lane * 2 + 0] = ps[nt][0];
                Part[base + nt * 8 + lane * 2 + 1] = ps[nt][1];
            }
        }
    }
}

// ================= GAT h: FIRST reduces pool partials as input ===========
template <int FIRST>
__global__ __launch_bounds__(128) void gat_h_kernel(
    const float* __restrict__ xin, const float* __restrict__ lin,
    const float* __restrict__ asw, const float* __restrict__ adw) {
    int n = blockIdx.x, t = threadIdx.x;
    __shared__ float xr[HIDC];
    __shared__ float red[HIDC];
    if (FIRST) {
        int wn = t >> 5, col = t & 31;
        float s = 0.f;
#pragma unroll 1
        for (int mt = 0; mt < MTILES; mt++) {
            size_t b = (((size_t)n * MTILES + mt) * 8);
            s += g_part[(b + wn) * 32 + col];
            s += g_part[(b + 4 + wn) * 32 + col];
        }
        xr[t] = s * (1.f / 1024.f);
    } else {
        xr[t] = xin[n * HIDC + t];
    }
    __syncthreads();
    float hv[HEADS];
#pragma unroll
    for (int j = 0; j < HEADS; j++) {
        int col = j * HIDC + t;
        float s = 0.f;
        for (int k = 0; k < HIDC; k++) s += xr[k] * lin[k * (HEADS * HIDC) + col];
        hv[j] = s;
        g_hfeat[n * (HEADS * HIDC) + col] = s;
    }
#pragma unroll
    for (int j = 0; j < HEADS; j++) {
        red[t] = hv[j] * asw[j * HIDC + t];
        __syncthreads();
        for (int off = 64; off > 0; off >>= 1) {
            if (t < off) red[t] += red[t + off];
            __syncthreads();
        }
        if (t == 0) g_as[n * HEADS + j] = red[0];
        __syncthreads();
        red[t] = hv[j] * adw[j * HIDC + t];
        __syncthreads();
        for (int off = 64; off > 0; off >>= 1) {
            if (t < off) red[t] += red[t + off];
            __syncthreads();
        }
        if (t == 0) g_ad[n * HEADS + j] = red[0];
        __syncthreads();
    }
}

// ================= GAT aggregate; GT=1 also computes gterm ===============
template <int GT>
__global__ __launch_bounds__(128) void gat_aggr_kernel(
    const float* __restrict__ bias, float* __restrict__ xout,
    const float* __restrict__ opw, const float* __restrict__ opb) {
    __shared__ float sxg[HIDC];
    int n = blockIdx.x, t = threadIdx.x;
    float adn[HEADS];
#pragma unroll
    for (int j = 0; j < HEADS; j++) adn[j] = g_ad[n * HEADS + j];
    int rs = g_row[n], re = g_row[n + 1];
    float mx[HEADS] = {-1e30f, -1e30f, -1e30f, -1e30f};
    for (int ei = rs; ei < re; ei++) {
        int s = g_csr[ei];
#pragma unroll
        for (int j = 0; j < HEADS; j++) {
            float e = g_as[s * HEADS + j] + adn[j];
            e = (e > 0.f) ? e : 0.2f * e;
            mx[j] = fmaxf(mx[j], e);
        }
    }
    float den[HEADS] = {0.f, 0.f, 0.f, 0.f};
    float acc[HEADS] = {0.f, 0.f, 0.f, 0.f};
    for (int ei = rs; ei < re; ei++) {
        int s = g_csr[ei];
#pragma unroll
        for (int j = 0; j < HEADS; j++) {
            float e = g_as[s * HEADS + j] + adn[j];
            e = (e > 0.f) ? e : 0.2f * e;
            float ex = __expf(e - mx[j]);
            den[j] += ex;
            acc[j] += ex * g_hfeat[s * (HEADS * HIDC) + j * HIDC + t];
        }
    }
    float o = 0.f;
#pragma unroll
    for (int j = 0; j < HEADS; j++) o += acc[j] / (den[j] + 1e-16f);
    o = o * 0.25f + bias[t];
    o = fmaxf(o, 0.f);
    if (GT == 0) {
        xout[n * HIDC + t] = o;
    } else {
        sxg[t] = o;
        __syncthreads();
        if (t < CINC) {
            float s = opb[t];
            for (int k = 0; k < HIDC; k++) s += sxg[k] * opw[t * HIDC + k];
            g_gterm[n * CINC + t] = s;
        }
    }
}

// ================= op: out = gterm + xp @ op_w^T (fp16 2-term) =============
__global__ __launch_bounds__(256) void op_mma_kernel(
    const __half* __restrict__ Xh,
    float* __restrict__ out) {
    extern __shared__ __align__(16) char dsm[];
    int tid = threadIdx.x, lane = tid & 31, warp = tid >> 5;
    int warpm = warp >> 1, warpn = warp & 1;
    int n = blockIdx.x, hw0 = blockIdx.y * 128;
    uint32_t sbase = smem_u32(dsm);

#pragma unroll
    for (int i = 0; i < 8; i++) {
        int idx = i * 256 + tid;
        int r = idx >> 4, sg = idx & 15;
        const __half* g = Xh + ((size_t)n * HWSZ + hw0 + r) * HIDC + sg * 8;
        cpasync16(sbase + r * OP_RS + sg * 16, g);
    }
#pragma unroll
    for (int i = 0; i < 8; i++) {
        int idx = i * 256 + tid;
        int term = idx >> 10;
        int r = (idx >> 4) & 63, sg = idx & 15;
        const __half* g = (term ? g_wopl : g_woph) + r * HIDC + sg * 8;
        cpasync16(sbase + OPW_0 + term * OPW_T + r * OP_RS + sg * 16, g);
    }
    CP_COMMIT();

    float C[8][4];
#pragma unroll
    for (int nt = 0; nt < 8; nt++)
#pragma unroll
        for (int r = 0; r < 4; r++) C[nt][r] = 0.f;

    int a_row = lane & 15, a_ko = (lane >> 4) * 16;
    int b_row = (lane & 7) + ((lane >> 4) & 1) * 8;
    int b_ko = ((lane >> 3) & 1) * 16;

    CP_WAIT(0);
    __syncthreads();

#pragma unroll 1
    for (int kc = 0; kc < 8; kc++) {
        uint32_t awh[4], awl[4];
        uint32_t ra = (uint32_t)(warpm * 16 + a_row) * OP_RS + kc * 32 + a_ko;
        ldmx4(awh, sbase + OPW_0 + ra);
        ldmx4(awl, sbase + OPW_0 + OPW_T + ra);
#pragma unroll
        for (int ntp = 0; ntp < 4; ntp++) {
            uint32_t xbh[4];
            uint32_t rb = (uint32_t)(warpn * 64 + ntp * 16 + b_row) * OP_RS + kc * 32 + b_ko;
            ldmx4(xbh, sbase + rb);
#pragma unroll
            for (int q = 0; q < 2; q++) {
                int nt = ntp * 2 + q;
                mma16816(C[nt], awh, xbh[2 * q], xbh[2 * q + 1]);
                mma16816(C[nt], awl, xbh[2 * q], xbh[2 * q + 1]);
            }
        }
    }

    int g4 = lane >> 2, t2 = (lane & 3) * 2;
    int co_a = warpm * 16 + g4;
    int co_b = co_a + 8;
    float gta = g_gterm[n * CINC + co_a];
    float gtb = g_gterm[n * CINC + co_b];
#pragma unroll
    for (int nt = 0; nt < 8; nt++) {
        int hw = hw0 + warpn * 64 + nt * 8 + t2;
        float2 va = make_float2(C[nt][0] + gta, C[nt][1] + gta);
        float2 vb = make_float2(C[nt][2] + gtb, C[nt][3] + gtb);
        *(float2*)&out[((size_t)n * CINC + co_a) * HWSZ + hw] = va;
        *(float2*)&out[((size_t)n * CINC + co_b) * HWSZ + hw] = vb;
    }
}

// ================= launch =================
extern "C" void kernel_launch(void* const* d_in, const int* in_sizes, int n_in,
                              void* d_out, int out_size) {
    const float* x    = (const float*)d_in[0];
    const int*   ei   = (const int*)d_in[1];
    const float* conf = (const float*)d_in[2];
    const float* fe_w = (const float*)d_in[3];
    const float* fe_b = (const float*)d_in[4];
    const float* fe_g = (const float*)d_in[5];
    const float* fe_be= (const float*)d_in[6];
    const float* sp_w1= (const float*)d_in[7];
    const float* sp_b1= (const float*)d_in[8];
    const float* sp_g1= (const float*)d_in[9];
    const float* sp_e1= (const float*)d_in[10];
    const float* sp_w2= (const float*)d_in[11];
    const float* sp_b2= (const float*)d_in[12];
    const float* sp_g2= (const float*)d_in[13];
    const float* sp_e2= (const float*)d_in[14];
    const float* g1_lin=(const float*)d_in[15];
    const float* g1_as= (const float*)d_in[16];
    const float* g1_ad= (const float*)d_in[17];
    const float* g1_b = (const float*)d_in[18];
    const float* g2_lin=(const float*)d_in[19];
    const float* g2_as= (const float*)d_in[20];
    const float* g2_ad= (const float*)d_in[21];
    const float* g2_b = (const float*)d_in[22];
    const float* op_w = (const float*)d_in[23];
    const float* op_b = (const float*)d_in[24];
    float* out = (float*)d_out;

    void *p1h, *p2h, *pph, *pw1h, *pw2h, *pXg, *pPart;
    cudaGetSymbolAddress(&p1h, g_x1h);
    cudaGetSymbolAddress(&p2h, g_x2h);
    cudaGetSymbolAddress(&pph, g_xph);
    cudaGetSymbolAddress(&pw1h, g_w1h);
    cudaGetSymbolAddress(&pw2h, g_w2h);
    cudaGetSymbolAddress(&pXg, g_xg);
    cudaGetSymbolAddress(&pPart, g_part);
    __half* x1h = (__half*)p1h;
    __half* x2h = (__half*)p2h;
    __half* xph = (__half*)pph;
    __half* w1h = (__half*)pw1h;
    __half* w2h = (__half*)pw2h;
    float* xg = (float*)pXg;
    float* part = (float*)pPart;

    cudaFuncSetAttribute(conv_mma_kernel<0>, cudaFuncAttributeMaxDynamicSharedMemorySize, CONV_SMEM);
    cudaFuncSetAttribute(conv_mma_kernel<1>, cudaFuncAttributeMaxDynamicSharedMemorySize, CONV_SMEM);
    cudaFuncSetAttribute(fe_mma_kernel, cudaFuncAttributeMaxDynamicSharedMemorySize, FE_SMEM);
    cudaFuncSetAttribute(op_mma_kernel, cudaFuncAttributeMaxDynamicSharedMemorySize, OP_SMEM);

    const int WTOT = 2 * HIDC * HIDC * 9 + CINC * HIDC;

    fe_mma_kernel<<<dim3(NN, 8), 256, FE_SMEM>>>(x, fe_w, fe_b, fe_g, fe_be, conf, x1h); // 0
    wprep_all_kernel<<<(WTOT + 255) / 256, 256>>>(sp_w1, sp_w2, op_w);        // 1
    csr_build_kernel<<<1, 512>>>(ei);                                         // 2
    conv_mma_kernel<0><<<NN * MTILES, 256, CONV_SMEM>>>(                      // 3 (ncu)
        x1h, w1h, sp_b1, sp_g1, sp_e1, x2h, nullptr);
    conv_mma_kernel<1><<<NN * MTILES, 256, CONV_SMEM>>>(                      // 4
        x2h, w2h, sp_b2, sp_g2, sp_e2, xph, part);
    gat_h_kernel<1><<<NN, 128>>>(nullptr, g1_lin, g1_as, g1_ad);              // 5
    gat_aggr_kernel<0><<<NN, 128>>>(g1_b, xg, nullptr, nullptr);              // 6
    gat_h_kernel<0><<<NN, 128>>>(xg, g2_lin, g2_as, g2_ad);                   // 7
    gat_aggr_kernel<1><<<NN, 128>>>(g2_b, nullptr, op_w, op_b);               // 8
    op_mma_kernel<<<dim3(NN, 8), 256, OP_SMEM>>>(xph, out);                   // 9

    (void)in_sizes; (void)n_in; (void)out_size;
}

// round 13
// speedup vs baseline: 9.4865x; 1.0377x over previous
#include <cuda_runtime.h>
#include <cuda_fp16.h>
#include <math.h>
#include <stdint.h>

#define NN   512
#define CINC 64
#define HIDC 128
#define HWSZ 1024
#define HH   32
#define WW   32
#define HEADS 4
#define NE   16384
#define TOTE (NE + NN)
#define POSN 1224
#define MTILES 9

#define A_SLAB  16000
#define B_BASE  64000
#define B_PAIR  9216
#define CONV_SMEM (64000 + 4 * B_PAIR)

// fe smem: Xh 128px x 144B, W 128co x 144B
#define FE_RS   144
#define FE_XH   0
#define FE_W    18432
#define FE_SMEM 36864

// op smem: X 128 x 272; W 64 x 272
#define OP_RS   272
#define OPW_0   34816
#define OP_SMEM (34816 + 17408)

// ================= helpers =================
__device__ __forceinline__ uint32_t smem_u32(const void* p) {
    return (uint32_t)__cvta_generic_to_shared(p);
}
__device__ __forceinline__ void ldmx4(uint32_t* r, uint32_t a) {
    asm volatile("ldmatrix.sync.aligned.m8n8.x4.shared.b16 {%0,%1,%2,%3}, [%4];"
                 : "=r"(r[0]), "=r"(r[1]), "=r"(r[2]), "=r"(r[3]) : "r"(a));
}
__device__ __forceinline__ void mma16816(float* c, const uint32_t* a,
                                         uint32_t b0, uint32_t b1) {
    asm volatile(
        "mma.sync.aligned.m16n8k16.row.col.f32.f16.f16.f32 "
        "{%0,%1,%2,%3}, {%4,%5,%6,%7}, {%8,%9}, {%0,%1,%2,%3};"
        : "+f"(c[0]), "+f"(c[1]), "+f"(c[2]), "+f"(c[3])
        : "r"(a[0]), "r"(a[1]), "r"(a[2]), "r"(a[3]), "r"(b0), "r"(b1));
}
__device__ __forceinline__ void cpasync16(uint32_t sa, const void* g) {
    unsigned long long ga = (unsigned long long)__cvta_generic_to_global(g);
    asm volatile("cp.async.cg.shared.global [%0], [%1], 16;" :: "r"(sa), "l"(ga));
}
#define CP_COMMIT() asm volatile("cp.async.commit_group;")
#define CP_WAIT(N)  asm volatile("cp.async.wait_group %0;" :: "n"(N))
#define BAR_PAIR(id) asm volatile("bar.sync %0, 64;" :: "r"(id) : "memory")

__device__ __forceinline__ uint32_t pack_h2(__half a, __half b) {
    return (uint32_t)__half_as_ushort(a) | ((uint32_t)__half_as_ushort(b) << 16);
}

// ================= device scratch =================
__device__ __half g_x1h[(size_t)NN * POSN * HIDC]; // border stays zero
__device__ __half g_x2h[(size_t)NN * POSN * HIDC];
__device__ __half g_xph[(size_t)NN * HWSZ * HIDC];
__device__ __half g_w1h[9 * HIDC * HIDC];
__device__ __half g_w2h[9 * HIDC * HIDC];
__device__ __half g_woph[CINC * HIDC];
__device__ float g_part[(size_t)NN * MTILES * 8 * 32];
__device__ float g_hfeat[NN * HEADS * HIDC];
__device__ float g_as[NN * HEADS];
__device__ float g_ad[NN * HEADS];
__device__ float g_hfeat2[NN * HEADS * HIDC];
__device__ float g_as2[NN * HEADS];
__device__ float g_ad2[NN * HEADS];
__device__ float g_gterm[NN * CINC];
__device__ int   g_row[NN + 1];
__device__ int   g_csr[TOTE];

// ================= prep: block 0 = CSR build, rest = weight prep =========
__device__ __forceinline__ void read_edge(const int* __restrict__ ei, int i,
                                          int is64, int& s, int& d) {
    if (i < NE) {
        if (is64) { s = ei[2 * i]; d = ei[2 * (NE + i)]; }
        else      { s = ei[i];     d = ei[NE + i]; }
    } else { s = i - NE; d = i - NE; }
}
__global__ __launch_bounds__(512) void prep_kernel(
    const int* __restrict__ ei,
    const float* __restrict__ w1, const float* __restrict__ w2,
    const float* __restrict__ wop) {
    if (blockIdx.x == 0) {
        __shared__ int scnt[NN];
        __shared__ int sfill[NN];
        __shared__ int s_is64;
        int t = threadIdx.x;
        if (t == 0) {
            int acc = 0;
            for (int i = 0; i < 128; i++) acc |= ei[2 * i + 1];
            s_is64 = (acc == 0) ? 1 : 0;
        }
        scnt[t] = 0;
        __syncthreads();
        int is64 = s_is64;
        for (int i = t; i < TOTE; i += 512) {
            int s, d; read_edge(ei, i, is64, s, d);
            atomicAdd(&scnt[d], 1);
        }
        __syncthreads();
        int c = scnt[t];
        for (int off = 1; off < NN; off <<= 1) {
            int v = (t >= off) ? scnt[t - off] : 0;
            __syncthreads();
            scnt[t] += v;
            __syncthreads();
        }
        g_row[t + 1] = scnt[t];
        if (t == 0) g_row[0] = 0;
        sfill[t] = scnt[t] - c;
        __syncthreads();
        for (int i = t; i < TOTE; i += 512) {
            int s, d; read_edge(ei, i, is64, s, d);
            int pos = atomicAdd(&sfill[d], 1);
            g_csr[pos] = s;
        }
    } else {
        const int WN = HIDC * HIDC * 9;
        int idx = (blockIdx.x - 1) * 512 + threadIdx.x;
        if (idx < 2 * WN) {
            int j = (idx < WN) ? idx : idx - WN;
            int tap = j % 9;
            int ci = (j / 9) % HIDC;
            int co = j / (9 * HIDC);
            if (idx < WN)
                g_w1h[(tap * HIDC + co) * HIDC + ci] = __float2half_rn(w1[j]);
            else
                g_w2h[(tap * HIDC + co) * HIDC + ci] = __float2half_rn(w2[j]);
        } else if (idx < 2 * WN + CINC * HIDC) {
            int j = idx - 2 * WN;
            g_woph[j] = __float2half_rn(wop[j]);
        }
    }
}

// ================= fe (mma.sync, 1-term fp16) =============
__global__ __launch_bounds__(256) void fe_mma_kernel(
    const float* __restrict__ x, const float* __restrict__ fw,
    const float* __restrict__ fb, const float* __restrict__ fg,
    const float* __restrict__ fbe, const float* __restrict__ conf,
    __half* __restrict__ xh) {
    extern __shared__ __align__(16) char dsm[];
    __shared__ float s_conf[128];
    __shared__ float s_sc[HIDC], s_sh[HIDC];

    int tid = threadIdx.x, lane = tid & 31, warp = tid >> 5;
    int warpm = warp >> 2, warpn = warp & 3;
    int n = blockIdx.x, px0 = blockIdx.y * 128;
    uint32_t sbase = smem_u32(dsm);

    if (tid < 128) {
        s_conf[tid] = conf[n * HWSZ + px0 + tid];
        const float inv = rsqrtf(1.0f + 1e-5f);
        float sc = fg[tid] * inv;
        s_sc[tid] = sc;
        s_sh[tid] = fbe[tid] + fb[tid] * sc;
    }

#pragma unroll
    for (int i = 0; i < 16; i++) {
        int idx = i * 256 + tid;
        int cp = idx & 31, co = idx >> 5;
        float2 v = *(const float2*)(fw + co * CINC + cp * 2);
        *(uint32_t*)(dsm + FE_W + co * FE_RS + cp * 4) =
            pack_h2(__float2half_rn(v.x), __float2half_rn(v.y));
    }
#pragma unroll
    for (int i = 0; i < 16; i++) {
        int idx = i * 256 + tid;
        int p = idx & 127, cp = idx >> 7;
        float a = x[((size_t)n * CINC + 2 * cp) * HWSZ + px0 + p];
        float b = x[((size_t)n * CINC + 2 * cp + 1) * HWSZ + px0 + p];
        *(uint32_t*)(dsm + FE_XH + p * FE_RS + cp * 4) =
            pack_h2(__float2half_rn(a), __float2half_rn(b));
    }
    __syncthreads();

    float C[4][4][4];
#pragma unroll
    for (int m = 0; m < 4; m++)
#pragma unroll
        for (int nt = 0; nt < 4; nt++)
#pragma unroll
            for (int r = 0; r < 4; r++) C[m][nt][r] = 0.f;

    int a_row = lane & 15, a_ko = (lane >> 4) * 16;
    int b_row = (lane & 7) + ((lane >> 4) & 1) * 8;
    int b_ko = ((lane >> 3) & 1) * 16;

#pragma unroll
    for (int kq = 0; kq < 4; kq++) {
        uint32_t ah[4][4];
#pragma unroll
        for (int m = 0; m < 4; m++) {
            uint32_t ra = (uint32_t)(warpm * 64 + m * 16 + a_row) * FE_RS + kq * 32 + a_ko;
            ldmx4(ah[m], sbase + FE_XH + ra);
        }
#pragma unroll
        for (int ntp = 0; ntp < 2; ntp++) {
            uint32_t bw[4];
            uint32_t rb = (uint32_t)(warpn * 32 + ntp * 16 + b_row) * FE_RS + kq * 32 + b_ko;
            ldmx4(bw, sbase + FE_W + rb);
#pragma unroll
            for (int q = 0; q < 2; q++) {
                int nt = ntp * 2 + q;
#pragma unroll
                for (int m = 0; m < 4; m++)
                    mma16816(C[m][nt], ah[m], bw[2 * q], bw[2 * q + 1]);
            }
        }
    }

    int g4 = lane >> 2, t2 = (lane & 3) * 2;
#pragma unroll
    for (int m = 0; m < 4; m++) {
#pragma unroll
        for (int nt = 0; nt < 4; nt++) {
            int co = warpn * 32 + nt * 8 + t2;
            float sc0 = s_sc[co], sh0 = s_sh[co];
            float sc1 = s_sc[co + 1], sh1 = s_sh[co + 1];
#pragma unroll
            for (int half = 0; half < 2; half++) {
                int pl = warpm * 64 + m * 16 + g4 + half * 8;
                float cf = s_conf[pl];
                float v0 = fmaxf(C[m][nt][half * 2 + 0] * sc0 + sh0, 0.f) * cf;
                float v1 = fmaxf(C[m][nt][half * 2 + 1] * sc1 + sh1, 0.f) * cf;
                int hw = px0 + pl;
                int h = hw >> 5, w = hw & 31;
                size_t q2 = ((size_t)n * POSN + (h + 1) * 34 + (w + 1)) * HIDC + co;
                *(uint32_t*)(xh + q2) =
                    pack_h2(__float2half_rn(v0), __float2half_rn(v1));
            }
        }
    }
}

// ================= mma.sync conv (unchanged structure) =================
template <int MODE>
__global__ __launch_bounds__(256, 2) void conv_mma_kernel(
    const __half* __restrict__ Xh,
    const __half* __restrict__ Wh,
    const float* __restrict__ bb, const float* __restrict__ gg,
    const float* __restrict__ be,
    __half* __restrict__ Oh, float* __restrict__ Part) {
    extern __shared__ __align__(16) char dsm[];
    __shared__ float s_sc[HIDC], s_sh[HIDC];

    int tid = threadIdx.x, lane = tid & 31, warp = tid >> 5;
    int warpm = warp >> 2, warpn = warp & 3;
    int n = blockIdx.x / MTILES, mt = blockIdx.x % MTILES;
    int pbase = mt * 128;

    if (tid < HIDC) {
        const float inv = rsqrtf(1.0f + 1e-5f);
        float sc = gg[tid] * inv;
        s_sc[tid] = sc;
        s_sh[tid] = be[tid] + bb[tid] * sc;
    }

    float C[4][4][4];
#pragma unroll
    for (int m = 0; m < 4; m++)
#pragma unroll
        for (int nt = 0; nt < 4; nt++)
#pragma unroll
            for (int r = 0; r < 4; r++) C[m][nt][r] = 0.f;

    uint32_t sbase = smem_u32(dsm);
    uint32_t sB0 = sbase + B_BASE + warpn * B_PAIR;
    bool loader = (warpm == 0);

    auto loadB = [&](int s1, uint32_t buf) {
        int pairci = s1 / 9, tap = s1 - pairci * 9;
        uint32_t s0 = sB0 + buf * 4608;
        size_t gb = ((size_t)(tap * HIDC + warpn * 32)) * HIDC + pairci * 64;
#pragma unroll
        for (int i = 0; i < 8; i++) {
            int seg = i * 32 + lane;
            int r = seg >> 3, sg = seg & 7;
            cpasync16(s0 + r * 144 + sg * 16, Wh + gb + (size_t)r * HIDC + sg * 8);
        }
    };

    {
        size_t gbase = ((size_t)(n * POSN + pbase)) * HIDC;
#pragma unroll
        for (int cic = 0; cic < 4; cic++) {
            uint32_t s0 = sbase + cic * A_SLAB;
            size_t gb = gbase + cic * 32;
#pragma unroll
            for (int i = 0; i < 4; i++) {
                int idx = i * 256 + tid;
                if (idx < 792) {
                    int r = idx >> 2, sg = idx & 3;
                    cpasync16(s0 + r * 80 + sg * 16, Xh + gb + (size_t)r * HIDC + sg * 8);
                }
            }
        }
        if (loader) loadB(0, 0);
        CP_COMMIT();
        CP_WAIT(0);
        __syncthreads();
    }

    int a_row = lane & 15, a_ko = (lane >> 4) * 16;
    int b_row = (lane & 7) + ((lane >> 4) & 1) * 8;
    int b_ko = ((lane >> 3) & 1) * 16;
    int barid = 1 + warpn;

    auto do_stage = [&](int s, uint32_t buf) {
        int pair = s / 9, tap = s - pair * 9;
        CP_WAIT(0);
        BAR_PAIR(barid);
        if (loader && s + 1 < 18) {
            loadB(s + 1, buf ^ 1u);
            CP_COMMIT();
        }
        int tapoff = (tap / 3) * 34 + (tap - (tap / 3) * 3);
        uint32_t sB = sB0 + buf * 4608;
#pragma unroll
        for (int c2 = 0; c2 < 2; c2++) {
            uint32_t sA = sbase + (pair * 2 + c2) * A_SLAB;
            uint32_t bhalf = c2 * 64;
#pragma unroll
            for (int ks = 0; ks < 2; ks++) {
                uint32_t ah[4][4];
#pragma unroll
                for (int m = 0; m < 4; m++) {
                    uint32_t ra = (uint32_t)(tapoff + warpm * 64 + m * 16 + a_row) * 80 + ks * 32 + a_ko;
                    ldmx4(ah[m], sA + ra);
                }
#pragma unroll
                for (int ntp = 0; ntp < 2; ntp++) {
                    uint32_t rbh[4];
                    uint32_t rb = (uint32_t)(ntp * 16 + b_row) * 144 + bhalf + ks * 32 + b_ko;
                    ldmx4(rbh, sB + rb);
#pragma unroll
                    for (int q = 0; q < 2; q++) {
                        int nt = ntp * 2 + q;
#pragma unroll
                        for (int m = 0; m < 4; m++)
                            mma16816(C[m][nt], ah[m], rbh[2 * q], rbh[2 * q + 1]);
                    }
                }
            }
        }
    };

#pragma unroll 1
    for (int sp = 0; sp < 9; sp++) {
        do_stage(sp * 2, 0u);
        do_stage(sp * 2 + 1, 1u);
    }

    int g4 = lane >> 2;
    int t2 = (lane & 3) * 2;
    float ps[4][2];
    if (MODE == 1)
#pragma unroll
        for (int nt = 0; nt < 4; nt++) { ps[nt][0] = 0.f; ps[nt][1] = 0.f; }
#pragma unroll
    for (int m = 0; m < 4; m++) {
#pragma unroll
        for (int nt = 0; nt < 4; nt++) {
            int co = warpn * 32 + nt * 8 + t2;
            float sc0 = s_sc[co], sh0 = s_sh[co];
            float sc1 = s_sc[co + 1], sh1 = s_sh[co + 1];
#pragma unroll
            for (int half = 0; half < 2; half++) {
                int p = pbase + warpm * 64 + m * 16 + g4 + half * 8;
                float v0 = C[m][nt][half * 2 + 0] * sc0 + sh0;
                float v1 = C[m][nt][half * 2 + 1] * sc1 + sh1;
                int h = p / 34, w = p % 34;
                bool valid = (w < 32) && (h < 32);
                v0 = valid ? fmaxf(v0, 0.f) : 0.f;
                v1 = valid ? fmaxf(v1, 0.f) : 0.f;
                uint32_t pk = pack_h2(__float2half_rn(v0), __float2half_rn(v1));
                if (MODE == 0) {
                    size_t q2 = ((size_t)n * POSN + p + 35) * HIDC + co;
                    *(uint32_t*)(Oh + q2) = pk;
                } else {
                    ps[nt][0] += v0;
                    ps[nt][1] += v1;
                    if (valid) {
                        size_t q2 = ((size_t)n * HWSZ + h * WW + w) * HIDC + co;
                        *(uint32_t*)(Oh + q2) = pk;
                    }
                }
            }
        }
    }
    if (MODE == 1) {
#pragma unroll
        for (int nt = 0; nt < 4; nt++)
#pragma unroll
            for (int q = 0; q < 2; q++) {
                float v = ps[nt][q];
                v += __shfl_xor_sync(0xffffffffu, v, 4);
                v += __shfl_xor_sync(0xffffffffu, v, 8);
                v += __shfl_xor_sync(0xffffffffu, v, 16);
                ps[nt][q] = v;
            }
        if (lane < 4) {
            size_t base = (((size_t)n * MTILES + mt) * 8 + warp) * 32;
#pragma unroll
            for (int nt = 0; nt < 4; nt++) {
                Part[base + nt * 8 + lane * 2 + 0] = ps[nt][0];
                Part[base + nt * 8 + lane * 2 + 1] = ps[nt][1];
            }
        }
    }
}

// ================= GAT layer-1 h (pool-reduce input) ===========
__global__ __launch_bounds__(128) void gat_h1_kernel(
    const float* __restrict__ lin,
    const float* __restrict__ asw, const float* __restrict__ adw) {
    int n = blockIdx.x, t = threadIdx.x;
    __shared__ float xr[HIDC];
    __shared__ float red[HIDC];
    {
        int wn = t >> 5, col = t & 31;
        float s = 0.f;
#pragma unroll 1
        for (int mt = 0; mt < MTILES; mt++) {
            size_t b = (((size_t)n * MTILES + mt) * 8);
            s += g_part[(b + wn) * 32 + col];
            s += g_part[(b + 4 + wn) * 32 + col];
        }
        xr[t] = s * (1.f / 1024.f);
    }
    __syncthreads();
    float hv[HEADS];
#pragma unroll
    for (int j = 0; j < HEADS; j++) {
        int col = j * HIDC + t;
        float s = 0.f;
        for (int k = 0; k < HIDC; k++) s += xr[k] * lin[k * (HEADS * HIDC) + col];
        hv[j] = s;
        g_hfeat[n * (HEADS * HIDC) + col] = s;
    }
#pragma unroll
    for (int j = 0; j < HEADS; j++) {
        red[t] = hv[j] * asw[j * HIDC + t];
        __syncthreads();
        for (int off = 64; off > 0; off >>= 1) {
            if (t < off) red[t] += red[t + off];
            __syncthreads();
        }
        if (t == 0) g_as[n * HEADS + j] = red[0];
        __syncthreads();
        red[t] = hv[j] * adw[j * HIDC + t];
        __syncthreads();
        for (int off = 64; off > 0; off >>= 1) {
            if (t < off) red[t] += red[t + off];
            __syncthreads();
        }
        if (t == 0) g_ad[n * HEADS + j] = red[0];
        __syncthreads();
    }
}

// ============== fused: aggr layer-1 + h layer-2 (into *2 buffers) ========
__global__ __launch_bounds__(128) void gat_aggr1_h2_kernel(
    const float* __restrict__ bias,
    const float* __restrict__ lin2,
    const float* __restrict__ asw2, const float* __restrict__ adw2) {
    __shared__ float xr[HIDC];
    __shared__ float red[HIDC];
    int n = blockIdx.x, t = threadIdx.x;
    float adn[HEADS];
#pragma unroll
    for (int j = 0; j < HEADS; j++) adn[j] = g_ad[n * HEADS + j];
    int rs = g_row[n], re = g_row[n + 1];
    float mx[HEADS] = {-1e30f, -1e30f, -1e30f, -1e30f};
    for (int ei = rs; ei < re; ei++) {
        int s = g_csr[ei];
#pragma unroll
        for (int j = 0; j < HEADS; j++) {
            float e = g_as[s * HEADS + j] + adn[j];
            e = (e > 0.f) ? e : 0.2f * e;
            mx[j] = fmaxf(mx[j], e);
        }
    }
    float den[HEADS] = {0.f, 0.f, 0.f, 0.f};
    float acc[HEADS] = {0.f, 0.f, 0.f, 0.f};
    for (int ei = rs; ei < re; ei++) {
        int s = g_csr[ei];
#pragma unroll
        for (int j = 0; j < HEADS; j++) {
            float e = g_as[s * HEADS + j] + adn[j];
            e = (e > 0.f) ? e : 0.2f * e;
            float ex = __expf(e - mx[j]);
            den[j] += ex;
            acc[j] += ex * g_hfeat[s * (HEADS * HIDC) + j * HIDC + t];
        }
    }
    float o = 0.f;
#pragma unroll
    for (int j = 0; j < HEADS; j++) o += acc[j] / (den[j] + 1e-16f);
    o = o * 0.25f + bias[t];
    xr[t] = fmaxf(o, 0.f);
    __syncthreads();
    // layer-2 h
    float hv[HEADS];
#pragma unroll
    for (int j = 0; j < HEADS; j++) {
        int col = j * HIDC + t;
        float s = 0.f;
        for (int k = 0; k < HIDC; k++) s += xr[k] * lin2[k * (HEADS * HIDC) + col];
        hv[j] = s;
        g_hfeat2[n * (HEADS * HIDC) + col] = s;
    }
#pragma unroll
    for (int j = 0; j < HEADS; j++) {
        red[t] = hv[j] * asw2[j * HIDC + t];
        __syncthreads();
        for (int off = 64; off > 0; off >>= 1) {
            if (t < off) red[t] += red[t + off];
            __syncthreads();
        }
        if (t == 0) g_as2[n * HEADS + j] = red[0];
        __syncthreads();
        red[t] = hv[j] * adw2[j * HIDC + t];
        __syncthreads();
        for (int off = 64; off > 0; off >>= 1) {
            if (t < off) red[t] += red[t + off];
            __syncthreads();
        }
        if (t == 0) g_ad2[n * HEADS + j] = red[0];
        __syncthreads();
    }
}

// ================= GAT aggr layer-2 + gterm ===============
__global__ __launch_bounds__(128) void gat_aggr2_kernel(
    const float* __restrict__ bias,
    const float* __restrict__ opw, const float* __restrict__ opb) {
    __shared__ float sxg[HIDC];
    int n = blockIdx.x, t = threadIdx.x;
    float adn[HEADS];
#pragma unroll
    for (int j = 0; j < HEADS; j++) adn[j] = g_ad2[n * HEADS + j];
    int rs = g_row[n], re = g_row[n + 1];
    float mx[HEADS] = {-1e30f, -1e30f, -1e30f, -1e30f};
    for (int ei = rs; ei < re; ei++) {
        int s = g_csr[ei];
#pragma unroll
        for (int j = 0; j < HEADS; j++) {
            float e = g_as2[s * HEADS + j] + adn[j];
            e = (e > 0.f) ? e : 0.2f * e;
            mx[j] = fmaxf(mx[j], e);
        }
    }
    float den[HEADS] = {0.f, 0.f, 0.f, 0.f};
    float acc[HEADS] = {0.f, 0.f, 0.f, 0.f};
    for (int ei = rs; ei < re; ei++) {
        int s = g_csr[ei];
#pragma unroll
        for (int j = 0; j < HEADS; j++) {
            float e = g_as2[s * HEADS + j] + adn[j];
            e = (e > 0.f) ? e : 0.2f * e;
            float ex = __expf(e - mx[j]);
            den[j] += ex;
            acc[j] += ex * g_hfeat2[s * (HEADS * HIDC) + j * HIDC + t];
        }
    }
    float o = 0.f;
#pragma unroll
    for (int j = 0; j < HEADS; j++) o += acc[j] / (den[j] + 1e-16f);
    o = o * 0.25f + bias[t];
    sxg[t] = fmaxf(o, 0.f);
    __syncthreads();
    if (t < CINC) {
        float s = opb[t];
        for (int k = 0; k < HIDC; k++) s += sxg[k] * opw[t * HIDC + k];
        g_gterm[n * CINC + t] = s;
    }
}

// ================= op: out = gterm + xp @ op_w^T (1-term fp16) =============
__global__ __launch_bounds__(256) void op_mma_kernel(
    const __half* __restrict__ Xh,
    float* __restrict__ out) {
    extern __shared__ __align__(16) char dsm[];
    int tid = threadIdx.x, lane = tid & 31, warp = tid >> 5;
    int warpm = warp >> 1, warpn = warp & 1;
    int n = blockIdx.x, hw0 = blockIdx.y * 128;
    uint32_t sbase = smem_u32(dsm);

#pragma unroll
    for (int i = 0; i < 8; i++) {
        int idx = i * 256 + tid;
        int r = idx >> 4, sg = idx & 15;
        const __half* g = Xh + ((size_t)n * HWSZ + hw0 + r) * HIDC + sg * 8;
        cpasync16(sbase + r * OP_RS + sg * 16, g);
    }
#pragma unroll
    for (int i = 0; i < 4; i++) {
        int idx = i * 256 + tid;
        int r = idx >> 4, sg = idx & 15;
        cpasync16(sbase + OPW_0 + r * OP_RS + sg * 16, g_woph + r * HIDC + sg * 8);
    }
    CP_COMMIT();

    float C[8][4];
#pragma unroll
    for (int nt = 0; nt < 8; nt++)
#pragma unroll
        for (int r = 0; r < 4; r++) C[nt][r] = 0.f;

    int a_row = lane & 15, a_ko = (lane >> 4) * 16;
    int b_row = (lane & 7) + ((lane >> 4) & 1) * 8;
    int b_ko = ((lane >> 3) & 1) * 16;

    CP_WAIT(0);
    __syncthreads();

#pragma unroll 1
    for (int kc = 0; kc < 8; kc++) {
        uint32_t awh[4];
        uint32_t ra = (uint32_t)(warpm * 16 + a_row) * OP_RS + kc * 32 + a_ko;
        ldmx4(awh, sbase + OPW_0 + ra);
#pragma unroll
        for (int ntp = 0; ntp < 4; ntp++) {
            uint32_t xbh[4];
            uint32_t rb = (uint32_t)(warpn * 64 + ntp * 16 + b_row) * OP_RS + kc * 32 + b_ko;
            ldmx4(xbh, sbase + rb);
#pragma unroll
            for (int q = 0; q < 2; q++)
                mma16816(C[ntp * 2 + q], awh, xbh[2 * q], xbh[2 * q + 1]);
        }
    }

    int g4 = lane >> 2, t2 = (lane & 3) * 2;
    int co_a = warpm * 16 + g4;
    int co_b = co_a + 8;
    float gta = g_gterm[n * CINC + co_a];
    float gtb = g_gterm[n * CINC + co_b];
#pragma unroll
    for (int nt = 0; nt < 8; nt++) {
        int hw = hw0 + warpn * 64 + nt * 8 + t2;
        float2 va = make_float2(C[nt][0] + gta, C[nt][1] + gta);
        float2 vb = make_float2(C[nt][2] + gtb, C[nt][3] + gtb);
        *(float2*)&out[((size_t)n * CINC + co_a) * HWSZ + hw] = va;
        *(float2*)&out[((size_t)n * CINC + co_b) * HWSZ + hw] = vb;
    }
}

// ================= launch =================
extern "C" void kernel_launch(void* const* d_in, const int* in_sizes, int n_in,
                              void* d_out, int out_size) {
    const float* x    = (const float*)d_in[0];
    const int*   ei   = (const int*)d_in[1];
    const float* conf = (const float*)d_in[2];
    const float* fe_w = (const float*)d_in[3];
    const float* fe_b = (const float*)d_in[4];
    const float* fe_g = (const float*)d_in[5];
    const float* fe_be= (const float*)d_in[6];
    const float* sp_w1= (const float*)d_in[7];
    const float* sp_b1= (const float*)d_in[8];
    const float* sp_g1= (const float*)d_in[9];
    const float* sp_e1= (const float*)d_in[10];
    const float* sp_w2= (const float*)d_in[11];
    const float* sp_b2= (const float*)d_in[12];
    const float* sp_g2= (const float*)d_in[13];
    const float* sp_e2= (const float*)d_in[14];
    const float* g1_lin=(const float*)d_in[15];
    const float* g1_as= (const float*)d_in[16];
    const float* g1_ad= (const float*)d_in[17];
    const float* g1_b = (const float*)d_in[18];
    const float* g2_lin=(const float*)d_in[19];
    const float* g2_as= (const float*)d_in[20];
    const float* g2_ad= (const float*)d_in[21];
    const float* g2_b = (const float*)d_in[22];
    const float* op_w = (const float*)d_in[23];
    const float* op_b = (const float*)d_in[24];
    float* out = (float*)d_out;

    void *p1h, *p2h, *pph, *pw1h, *pw2h, *pPart;
    cudaGetSymbolAddress(&p1h, g_x1h);
    cudaGetSymbolAddress(&p2h, g_x2h);
    cudaGetSymbolAddress(&pph, g_xph);
    cudaGetSymbolAddress(&pw1h, g_w1h);
    cudaGetSymbolAddress(&pw2h, g_w2h);
    cudaGetSymbolAddress(&pPart, g_part);
    __half* x1h = (__half*)p1h;
    __half* x2h = (__half*)p2h;
    __half* xph = (__half*)pph;
    __half* w1h = (__half*)pw1h;
    __half* w2h = (__half*)pw2h;
    float* part = (float*)pPart;

    cudaFuncSetAttribute(conv_mma_kernel<0>, cudaFuncAttributeMaxDynamicSharedMemorySize, CONV_SMEM);
    cudaFuncSetAttribute(conv_mma_kernel<1>, cudaFuncAttributeMaxDynamicSharedMemorySize, CONV_SMEM);
    cudaFuncSetAttribute(fe_mma_kernel, cudaFuncAttributeMaxDynamicSharedMemorySize, FE_SMEM);
    cudaFuncSetAttribute(op_mma_kernel, cudaFuncAttributeMaxDynamicSharedMemorySize, OP_SMEM);

    const int WTOT = 2 * HIDC * HIDC * 9 + CINC * HIDC;
    const int PREP_BLOCKS = 1 + (WTOT + 511) / 512;

    fe_mma_kernel<<<dim3(NN, 8), 256, FE_SMEM>>>(x, fe_w, fe_b, fe_g, fe_be, conf, x1h); // 0
    prep_kernel<<<PREP_BLOCKS, 512>>>(ei, sp_w1, sp_w2, op_w);                // 1
    conv_mma_kernel<0><<<NN * MTILES, 256, CONV_SMEM>>>(                      // 2
        x1h, w1h, sp_b1, sp_g1, sp_e1, x2h, nullptr);
    conv_mma_kernel<1><<<NN * MTILES, 256, CONV_SMEM>>>(                      // 3 (ncu)
        x2h, w2h, sp_b2, sp_g2, sp_e2, xph, part);
    gat_h1_kernel<<<NN, 128>>>(g1_lin, g1_as, g1_ad);                         // 4
    gat_aggr1_h2_kernel<<<NN, 128>>>(g1_b, g2_lin, g2_as, g2_ad);             // 5
    gat_aggr2_kernel<<<NN, 128>>>(g2_b, op_w, op_b);                          // 6
    op_mma_kernel<<<dim3(NN, 8), 256, OP_SMEM>>>(xph, out);                   // 7

    (void)in_sizes; (void)n_in; (void)out_size;
}

// round 14
// speedup vs baseline: 9.5213x; 1.0037x over previous
#include <cuda_runtime.h>
#include <cuda_fp16.h>
#include <math.h>
#include <stdint.h>

#define NN   512
#define CINC 64
#define HIDC 128
#define HWSZ 1024
#define HH   32
#define WW   32
#define HEADS 4
#define NE   16384
#define TOTE (NE + NN)
#define POSN 1224
#define MTILES 9

#define A_SLAB  16000
#define B_BASE  64000
#define B_PAIR  9216
#define CONV_SMEM (64000 + 4 * B_PAIR)

#define FE_RS   144
#define FE_XH   0
#define FE_W    18432
#define FE_SMEM 36864

#define OP_RS   272
#define OPW_0   34816
#define OP_SMEM (34816 + 17408)

// ================= helpers =================
__device__ __forceinline__ uint32_t smem_u32(const void* p) {
    return (uint32_t)__cvta_generic_to_shared(p);
}
__device__ __forceinline__ void ldmx4(uint32_t* r, uint32_t a) {
    asm volatile("ldmatrix.sync.aligned.m8n8.x4.shared.b16 {%0,%1,%2,%3}, [%4];"
                 : "=r"(r[0]), "=r"(r[1]), "=r"(r[2]), "=r"(r[3]) : "r"(a));
}
__device__ __forceinline__ void mma16816(float* c, const uint32_t* a,
                                         uint32_t b0, uint32_t b1) {
    asm volatile(
        "mma.sync.aligned.m16n8k16.row.col.f32.f16.f16.f32 "
        "{%0,%1,%2,%3}, {%4,%5,%6,%7}, {%8,%9}, {%0,%1,%2,%3};"
        : "+f"(c[0]), "+f"(c[1]), "+f"(c[2]), "+f"(c[3])
        : "r"(a[0]), "r"(a[1]), "r"(a[2]), "r"(a[3]), "r"(b0), "r"(b1));
}
__device__ __forceinline__ void cpasync16(uint32_t sa, const void* g) {
    unsigned long long ga = (unsigned long long)__cvta_generic_to_global(g);
    asm volatile("cp.async.cg.shared.global [%0], [%1], 16;" :: "r"(sa), "l"(ga));
}
#define CP_COMMIT() asm volatile("cp.async.commit_group;")
#define CP_WAIT(N)  asm volatile("cp.async.wait_group %0;" :: "n"(N))
#define BAR_PAIR(id) asm volatile("bar.sync %0, 64;" :: "r"(id) : "memory")

__device__ __forceinline__ uint32_t pack_h2(__half a, __half b) {
    return (uint32_t)__half_as_ushort(a) | ((uint32_t)__half_as_ushort(b) << 16);
}
__device__ __forceinline__ float warp_sum(float v) {
#pragma unroll
    for (int off = 16; off > 0; off >>= 1)
        v += __shfl_xor_sync(0xffffffffu, v, off);
    return v;
}

// ================= device scratch =================
__device__ __half g_x1h[(size_t)NN * POSN * HIDC]; // border stays zero
__device__ __half g_x2h[(size_t)NN * POSN * HIDC];
__device__ __half g_xph[(size_t)NN * HWSZ * HIDC];
__device__ __half g_w1h[9 * HIDC * HIDC];
__device__ __half g_w2h[9 * HIDC * HIDC];
__device__ __half g_woph[CINC * HIDC];
__device__ float g_part[(size_t)NN * MTILES * 8 * 32];
__device__ float g_hfeat[NN * HEADS * HIDC];
__device__ float g_as[NN * HEADS];
__device__ float g_ad[NN * HEADS];
__device__ float g_hfeat2[NN * HEADS * HIDC];
__device__ float g_as2[NN * HEADS];
__device__ float g_ad2[NN * HEADS];
__device__ float g_gterm[NN * CINC];
__device__ int   g_row[NN + 1];
__device__ int   g_csr[TOTE];

// ================= prep: block 0 = CSR build, rest = weight prep =========
__device__ __forceinline__ void read_edge(const int* __restrict__ ei, int i,
                                          int is64, int& s, int& d) {
    if (i < NE) {
        if (is64) { s = ei[2 * i]; d = ei[2 * (NE + i)]; }
        else      { s = ei[i];     d = ei[NE + i]; }
    } else { s = i - NE; d = i - NE; }
}
__global__ __launch_bounds__(512) void prep_kernel(
    const int* __restrict__ ei,
    const float* __restrict__ w1, const float* __restrict__ w2,
    const float* __restrict__ wop) {
    if (blockIdx.x == 0) {
        __shared__ int scnt[NN];
        __shared__ int sfill[NN];
        __shared__ int s_is64;
        int t = threadIdx.x;
        if (t == 0) {
            int acc = 0;
            for (int i = 0; i < 128; i++) acc |= ei[2 * i + 1];
            s_is64 = (acc == 0) ? 1 : 0;
        }
        scnt[t] = 0;
        __syncthreads();
        int is64 = s_is64;
        for (int i = t; i < TOTE; i += 512) {
            int s, d; read_edge(ei, i, is64, s, d);
            atomicAdd(&scnt[d], 1);
        }
        __syncthreads();
        int c = scnt[t];
        for (int off = 1; off < NN; off <<= 1) {
            int v = (t >= off) ? scnt[t - off] : 0;
            __syncthreads();
            scnt[t] += v;
            __syncthreads();
        }
        g_row[t + 1] = scnt[t];
        if (t == 0) g_row[0] = 0;
        sfill[t] = scnt[t] - c;
        __syncthreads();
        for (int i = t; i < TOTE; i += 512) {
            int s, d; read_edge(ei, i, is64, s, d);
            int pos = atomicAdd(&sfill[d], 1);
            g_csr[pos] = s;
        }
    } else {
        const int WN = HIDC * HIDC * 9;
        int idx = (blockIdx.x - 1) * 512 + threadIdx.x;
        if (idx < 2 * WN) {
            int j = (idx < WN) ? idx : idx - WN;
            int tap = j % 9;
            int ci = (j / 9) % HIDC;
            int co = j / (9 * HIDC);
            if (idx < WN)
                g_w1h[(tap * HIDC + co) * HIDC + ci] = __float2half_rn(w1[j]);
            else
                g_w2h[(tap * HIDC + co) * HIDC + ci] = __float2half_rn(w2[j]);
        } else if (idx < 2 * WN + CINC * HIDC) {
            int j = idx - 2 * WN;
            g_woph[j] = __float2half_rn(wop[j]);
        }
    }
}

// ================= fe (mma.sync, 1-term fp16) =============
__global__ __launch_bounds__(256) void fe_mma_kernel(
    const float* __restrict__ x, const float* __restrict__ fw,
    const float* __restrict__ fb, const float* __restrict__ fg,
    const float* __restrict__ fbe, const float* __restrict__ conf,
    __half* __restrict__ xh) {
    extern __shared__ __align__(16) char dsm[];
    __shared__ float s_conf[128];
    __shared__ float s_sc[HIDC], s_sh[HIDC];

    int tid = threadIdx.x, lane = tid & 31, warp = tid >> 5;
    int warpm = warp >> 2, warpn = warp & 3;
    int n = blockIdx.x, px0 = blockIdx.y * 128;
    uint32_t sbase = smem_u32(dsm);

    if (tid < 128) {
        s_conf[tid] = conf[n * HWSZ + px0 + tid];
        const float inv = rsqrtf(1.0f + 1e-5f);
        float sc = fg[tid] * inv;
        s_sc[tid] = sc;
        s_sh[tid] = fbe[tid] + fb[tid] * sc;
    }

#pragma unroll
    for (int i = 0; i < 16; i++) {
        int idx = i * 256 + tid;
        int cp = idx & 31, co = idx >> 5;
        float2 v = *(const float2*)(fw + co * CINC + cp * 2);
        *(uint32_t*)(dsm + FE_W + co * FE_RS + cp * 4) =
            pack_h2(__float2half_rn(v.x), __float2half_rn(v.y));
    }
#pragma unroll
    for (int i = 0; i < 16; i++) {
        int idx = i * 256 + tid;
        int p = idx & 127, cp = idx >> 7;
        float a = x[((size_t)n * CINC + 2 * cp) * HWSZ + px0 + p];
        float b = x[((size_t)n * CINC + 2 * cp + 1) * HWSZ + px0 + p];
        *(uint32_t*)(dsm + FE_XH + p * FE_RS + cp * 4) =
            pack_h2(__float2half_rn(a), __float2half_rn(b));
    }
    __syncthreads();

    float C[4][4][4];
#pragma unroll
    for (int m = 0; m < 4; m++)
#pragma unroll
        for (int nt = 0; nt < 4; nt++)
#pragma unroll
            for (int r = 0; r < 4; r++) C[m][nt][r] = 0.f;

    int a_row = lane & 15, a_ko = (lane >> 4) * 16;
    int b_row = (lane & 7) + ((lane >> 4) & 1) * 8;
    int b_ko = ((lane >> 3) & 1) * 16;

#pragma unroll
    for (int kq = 0; kq < 4; kq++) {
        uint32_t ah[4][4];
#pragma unroll
        for (int m = 0; m < 4; m++) {
            uint32_t ra = (uint32_t)(warpm * 64 + m * 16 + a_row) * FE_RS + kq * 32 + a_ko;
            ldmx4(ah[m], sbase + FE_XH + ra);
        }
#pragma unroll
        for (int ntp = 0; ntp < 2; ntp++) {
            uint32_t bw[4];
            uint32_t rb = (uint32_t)(warpn * 32 + ntp * 16 + b_row) * FE_RS + kq * 32 + b_ko;
            ldmx4(bw, sbase + FE_W + rb);
#pragma unroll
            for (int q = 0; q < 2; q++) {
                int nt = ntp * 2 + q;
#pragma unroll
                for (int m = 0; m < 4; m++)
                    mma16816(C[m][nt], ah[m], bw[2 * q], bw[2 * q + 1]);
            }
        }
    }

    int g4 = lane >> 2, t2 = (lane & 3) * 2;
#pragma unroll
    for (int m = 0; m < 4; m++) {
#pragma unroll
        for (int nt = 0; nt < 4; nt++) {
            int co = warpn * 32 + nt * 8 + t2;
            float sc0 = s_sc[co], sh0 = s_sh[co];
            float sc1 = s_sc[co + 1], sh1 = s_sh[co + 1];
#pragma unroll
            for (int half = 0; half < 2; half++) {
                int pl = warpm * 64 + m * 16 + g4 + half * 8;
                float cf = s_conf[pl];
                float v0 = fmaxf(C[m][nt][half * 2 + 0] * sc0 + sh0, 0.f) * cf;
                float v1 = fmaxf(C[m][nt][half * 2 + 1] * sc1 + sh1, 0.f) * cf;
                int hw = px0 + pl;
                int h = hw >> 5, w = hw & 31;
                size_t q2 = ((size_t)n * POSN + (h + 1) * 34 + (w + 1)) * HIDC + co;
                *(uint32_t*)(xh + q2) =
                    pack_h2(__float2half_rn(v0), __float2half_rn(v1));
            }
        }
    }
}

// ================= mma.sync conv (unchanged from R13) =================
template <int MODE>
__global__ __launch_bounds__(256, 2) void conv_mma_kernel(
    const __half* __restrict__ Xh,
    const __half* __restrict__ Wh,
    const float* __restrict__ bb, const float* __restrict__ gg,
    const float* __restrict__ be,
    __half* __restrict__ Oh, float* __restrict__ Part) {
    extern __shared__ __align__(16) char dsm[];
    __shared__ float s_sc[HIDC], s_sh[HIDC];

    int tid = threadIdx.x, lane = tid & 31, warp = tid >> 5;
    int warpm = warp >> 2, warpn = warp & 3;
    int n = blockIdx.x / MTILES, mt = blockIdx.x % MTILES;
    int pbase = mt * 128;

    if (tid < HIDC) {
        const float inv = rsqrtf(1.0f + 1e-5f);
        float sc = gg[tid] * inv;
        s_sc[tid] = sc;
        s_sh[tid] = be[tid] + bb[tid] * sc;
    }

    float C[4][4][4];
#pragma unroll
    for (int m = 0; m < 4; m++)
#pragma unroll
        for (int nt = 0; nt < 4; nt++)
#pragma unroll
            for (int r = 0; r < 4; r++) C[m][nt][r] = 0.f;

    uint32_t sbase = smem_u32(dsm);
    uint32_t sB0 = sbase + B_BASE + warpn * B_PAIR;
    bool loader = (warpm == 0);

    auto loadB = [&](int s1, uint32_t buf) {
        int pairci = s1 / 9, tap = s1 - pairci * 9;
        uint32_t s0 = sB0 + buf * 4608;
        size_t gb = ((size_t)(tap * HIDC + warpn * 32)) * HIDC + pairci * 64;
#pragma unroll
        for (int i = 0; i < 8; i++) {
            int seg = i * 32 + lane;
            int r = seg >> 3, sg = seg & 7;
            cpasync16(s0 + r * 144 + sg * 16, Wh + gb + (size_t)r * HIDC + sg * 8);
        }
    };

    {
        size_t gbase = ((size_t)(n * POSN + pbase)) * HIDC;
#pragma unroll
        for (int cic = 0; cic < 4; cic++) {
            uint32_t s0 = sbase + cic * A_SLAB;
            size_t gb = gbase + cic * 32;
#pragma unroll
            for (int i = 0; i < 4; i++) {
                int idx = i * 256 + tid;
                if (idx < 792) {
                    int r = idx >> 2, sg = idx & 3;
                    cpasync16(s0 + r * 80 + sg * 16, Xh + gb + (size_t)r * HIDC + sg * 8);
                }
            }
        }
        if (loader) loadB(0, 0);
        CP_COMMIT();
        CP_WAIT(0);
        __syncthreads();
    }

    int a_row = lane & 15, a_ko = (lane >> 4) * 16;
    int b_row = (lane & 7) + ((lane >> 4) & 1) * 8;
    int b_ko = ((lane >> 3) & 1) * 16;
    int barid = 1 + warpn;

    auto do_stage = [&](int s, uint32_t buf) {
        int pair = s / 9, tap = s - pair * 9;
        CP_WAIT(0);
        BAR_PAIR(barid);
        if (loader && s + 1 < 18) {
            loadB(s + 1, buf ^ 1u);
            CP_COMMIT();
        }
        int tapoff = (tap / 3) * 34 + (tap - (tap / 3) * 3);
        uint32_t sB = sB0 + buf * 4608;
#pragma unroll
        for (int c2 = 0; c2 < 2; c2++) {
            uint32_t sA = sbase + (pair * 2 + c2) * A_SLAB;
            uint32_t bhalf = c2 * 64;
#pragma unroll
            for (int ks = 0; ks < 2; ks++) {
                uint32_t ah[4][4];
#pragma unroll
                for (int m = 0; m < 4; m++) {
                    uint32_t ra = (uint32_t)(tapoff + warpm * 64 + m * 16 + a_row) * 80 + ks * 32 + a_ko;
                    ldmx4(ah[m], sA + ra);
                }
#pragma unroll
                for (int ntp = 0; ntp < 2; ntp++) {
                    uint32_t rbh[4];
                    uint32_t rb = (uint32_t)(ntp * 16 + b_row) * 144 + bhalf + ks * 32 + b_ko;
                    ldmx4(rbh, sB + rb);
#pragma unroll
                    for (int q = 0; q < 2; q++) {
                        int nt = ntp * 2 + q;
#pragma unroll
                        for (int m = 0; m < 4; m++)
                            mma16816(C[m][nt], ah[m], rbh[2 * q], rbh[2 * q + 1]);
                    }
                }
            }
        }
    };

#pragma unroll 1
    for (int sp = 0; sp < 9; sp++) {
        do_stage(sp * 2, 0u);
        do_stage(sp * 2 + 1, 1u);
    }

    int g4 = lane >> 2;
    int t2 = (lane & 3) * 2;
    float ps[4][2];
    if (MODE == 1)
#pragma unroll
        for (int nt = 0; nt < 4; nt++) { ps[nt][0] = 0.f; ps[nt][1] = 0.f; }
#pragma unroll
    for (int m = 0; m < 4; m++) {
#pragma unroll
        for (int nt = 0; nt < 4; nt++) {
            int co = warpn * 32 + nt * 8 + t2;
            float sc0 = s_sc[co], sh0 = s_sh[co];
            float sc1 = s_sc[co + 1], sh1 = s_sh[co + 1];
#pragma unroll
            for (int half = 0; half < 2; half++) {
                int p = pbase + warpm * 64 + m * 16 + g4 + half * 8;
                float v0 = C[m][nt][half * 2 + 0] * sc0 + sh0;
                float v1 = C[m][nt][half * 2 + 1] * sc1 + sh1;
                int h = p / 34, w = p % 34;
                bool valid = (w < 32) && (h < 32);
                v0 = valid ? fmaxf(v0, 0.f) : 0.f;
                v1 = valid ? fmaxf(v1, 0.f) : 0.f;
                uint32_t pk = pack_h2(__float2half_rn(v0), __float2half_rn(v1));
                if (MODE == 0) {
                    size_t q2 = ((size_t)n * POSN + p + 35) * HIDC + co;
                    *(uint32_t*)(Oh + q2) = pk;
                } else {
                    ps[nt][0] += v0;
                    ps[nt][1] += v1;
                    if (valid) {
                        size_t q2 = ((size_t)n * HWSZ + h * WW + w) * HIDC + co;
                        *(uint32_t*)(Oh + q2) = pk;
                    }
                }
            }
        }
    }
    if (MODE == 1) {
#pragma unroll
        for (int nt = 0; nt < 4; nt++)
#pragma unroll
            for (int q = 0; q < 2; q++) {
                float v = ps[nt][q];
                v += __shfl_xor_sync(0xffffffffu, v, 4);
                v += __shfl_xor_sync(0xffffffffu, v, 8);
                v += __shfl_xor_sync(0xffffffffu, v, 16);
                ps[nt][q] = v;
            }
        if (lane < 4) {
            size_t base = (((size_t)n * MTILES + mt) * 8 + warp) * 32;
#pragma unroll
            for (int nt = 0; nt < 4; nt++) {
                Part[base + nt * 8 + lane * 2 + 0] = ps[nt][0];
                Part[base + nt * 8 + lane * 2 + 1] = ps[nt][1];
            }
        }
    }
}

// ===== shared h-stage: xr (smem, 128) -> hfeat/as/ad buffers =====
__device__ __forceinline__ void gat_h_stage(
    int n, int t, const float* xr, float* red,
    const float* __restrict__ lin,
    const float* __restrict__ asw, const float* __restrict__ adw,
    float* __restrict__ hfeat, float* __restrict__ asv, float* __restrict__ adv) {
    int lane = t & 31, wid = t >> 5;
    float hv[HEADS];
#pragma unroll
    for (int j = 0; j < HEADS; j++) {
        int col = j * HIDC + t;
        float s = 0.f;
        for (int k = 0; k < HIDC; k++) s += xr[k] * lin[k * (HEADS * HIDC) + col];
        hv[j] = s;
        hfeat[n * (HEADS * HIDC) + col] = s;
    }
#pragma unroll
    for (int j = 0; j < HEADS; j++) {
        float pa = warp_sum(hv[j] * asw[j * HIDC + t]);
        float pd = warp_sum(hv[j] * adw[j * HIDC + t]);
        if (lane == 0) { red[wid] = pa; red[4 + wid] = pd; }
        __syncthreads();
        if (t == 0) {
            asv[n * HEADS + j] = red[0] + red[1] + red[2] + red[3];
            adv[n * HEADS + j] = red[4] + red[5] + red[6] + red[7];
        }
        __syncthreads();
    }
}

// ===== shared aggr-stage (online softmax, single edge pass) =====
__device__ __forceinline__ float gat_aggr_stage(
    int n, int t,
    const float* __restrict__ hfeat, const float* __restrict__ asv,
    const float* __restrict__ adv, const float* __restrict__ bias) {
    float adn[HEADS];
#pragma unroll
    for (int j = 0; j < HEADS; j++) adn[j] = adv[n * HEADS + j];
    int rs = g_row[n], re = g_row[n + 1];
    float m[HEADS]  = {-1e30f, -1e30f, -1e30f, -1e30f};
    float den[HEADS] = {0.f, 0.f, 0.f, 0.f};
    float acc[HEADS] = {0.f, 0.f, 0.f, 0.f};
    for (int ei = rs; ei < re; ei++) {
        int s = g_csr[ei];
#pragma unroll
        for (int j = 0; j < HEADS; j++) {
            float e = asv[s * HEADS + j] + adn[j];
            e = (e > 0.f) ? e : 0.2f * e;
            float hval = hfeat[s * (HEADS * HIDC) + j * HIDC + t];
            if (e > m[j]) {                    // uniform across block
                float sc = __expf(m[j] - e);
                den[j] = den[j] * sc + 1.f;
                acc[j] = acc[j] * sc + hval;
                m[j] = e;
            } else {
                float ex = __expf(e - m[j]);
                den[j] += ex;
                acc[j] += ex * hval;
            }
        }
    }
    float o = 0.f;
#pragma unroll
    for (int j = 0; j < HEADS; j++) o += acc[j] / (den[j] + 1e-16f);
    return fmaxf(o * 0.25f + bias[t], 0.f);
}

// ================= GAT layer-1 h (pool-reduce input) ===========
__global__ __launch_bounds__(128) void gat_h1_kernel(
    const float* __restrict__ lin,
    const float* __restrict__ asw, const float* __restrict__ adw) {
    int n = blockIdx.x, t = threadIdx.x;
    __shared__ float xr[HIDC];
    __shared__ float red[8];
    {
        int wn = t >> 5, col = t & 31;
        float s = 0.f;
#pragma unroll 1
        for (int mt = 0; mt < MTILES; mt++) {
            size_t b = (((size_t)n * MTILES + mt) * 8);
            s += g_part[(b + wn) * 32 + col];
            s += g_part[(b + 4 + wn) * 32 + col];
        }
        xr[t] = s * (1.f / 1024.f);
    }
    __syncthreads();
    gat_h_stage(n, t, xr, red, lin, asw, adw, g_hfeat, g_as, g_ad);
}

// ============== fused: aggr layer-1 (online) + h layer-2 ========
__global__ __launch_bounds__(128) void gat_aggr1_h2_kernel(
    const float* __restrict__ bias,
    const float* __restrict__ lin2,
    const float* __restrict__ asw2, const float* __restrict__ adw2) {
    __shared__ float xr[HIDC];
    __shared__ float red[8];
    int n = blockIdx.x, t = threadIdx.x;
    xr[t] = gat_aggr_stage(n, t, g_hfeat, g_as, g_ad, bias);
    __syncthreads();
    gat_h_stage(n, t, xr, red, lin2, asw2, adw2, g_hfeat2, g_as2, g_ad2);
}

// ================= GAT aggr layer-2 (online) + gterm ===============
__global__ __launch_bounds__(128) void gat_aggr2_kernel(
    const float* __restrict__ bias,
    const float* __restrict__ opw, const float* __restrict__ opb) {
    __shared__ float sxg[HIDC];
    int n = blockIdx.x, t = threadIdx.x;
    sxg[t] = gat_aggr_stage(n, t, g_hfeat2, g_as2, g_ad2, bias);
    __syncthreads();
    if (t < CINC) {
        float s = opb[t];
        for (int k = 0; k < HIDC; k++) s += sxg[k] * opw[t * HIDC + k];
        g_gterm[n * CINC + t] = s;
    }
}

// ================= op: out = gterm + xp @ op_w^T (1-term fp16) =============
__global__ __launch_bounds__(256) void op_mma_kernel(
    const __half* __restrict__ Xh,
    float* __restrict__ out) {
    extern __shared__ __align__(16) char dsm[];
    int tid = threadIdx.x, lane = tid & 31, warp = tid >> 5;
    int warpm = warp >> 1, warpn = warp & 1;
    int n = blockIdx.x, hw0 = blockIdx.y * 128;
    uint32_t sbase = smem_u32(dsm);

#pragma unroll
    for (int i = 0; i < 8; i++) {
        int idx = i * 256 + tid;
        int r = idx >> 4, sg = idx & 15;
        const __half* g = Xh + ((size_t)n * HWSZ + hw0 + r) * HIDC + sg * 8;
        cpasync16(sbase + r * OP_RS + sg * 16, g);
    }
#pragma unroll
    for (int i = 0; i < 4; i++) {
        int idx = i * 256 + tid;
        int r = idx >> 4, sg = idx & 15;
        cpasync16(sbase + OPW_0 + r * OP_RS + sg * 16, g_woph + r * HIDC + sg * 8);
    }
    CP_COMMIT();

    float C[8][4];
#pragma unroll
    for (int nt = 0; nt < 8; nt++)
#pragma unroll
        for (int r = 0; r < 4; r++) C[nt][r] = 0.f;

    int a_row = lane & 15, a_ko = (lane >> 4) * 16;
    int b_row = (lane & 7) + ((lane >> 4) & 1) * 8;
    int b_ko = ((lane >> 3) & 1) * 16;

    CP_WAIT(0);
    __syncthreads();

#pragma unroll 1
    for (int kc = 0; kc < 8; kc++) {
        uint32_t awh[4];
        uint32_t ra = (uint32_t)(warpm * 16 + a_row) * OP_RS + kc * 32 + a_ko;
        ldmx4(awh, sbase + OPW_0 + ra);
#pragma unroll
        for (int ntp = 0; ntp < 4; ntp++) {
            uint32_t xbh[4];
            uint32_t rb = (uint32_t)(warpn * 64 + ntp * 16 + b_row) * OP_RS + kc * 32 + b_ko;
            ldmx4(xbh, sbase + rb);
#pragma unroll
            for (int q = 0; q < 2; q++)
                mma16816(C[ntp * 2 + q], awh, xbh[2 * q], xbh[2 * q + 1]);
        }
    }

    int g4 = lane >> 2, t2 = (lane & 3) * 2;
    int co_a = warpm * 16 + g4;
    int co_b = co_a + 8;
    float gta = g_gterm[n * CINC + co_a];
    float gtb = g_gterm[n * CINC + co_b];
#pragma unroll
    for (int nt = 0; nt < 8; nt++) {
        int hw = hw0 + warpn * 64 + nt * 8 + t2;
        float2 va = make_float2(C[nt][0] + gta, C[nt][1] + gta);
        float2 vb = make_float2(C[nt][2] + gtb, C[nt][3] + gtb);
        *(float2*)&out[((size_t)n * CINC + co_a) * HWSZ + hw] = va;
        *(float2*)&out[((size_t)n * CINC + co_b) * HWSZ + hw] = vb;
    }
}

// ================= launch =================
extern "C" void kernel_launch(void* const* d_in, const int* in_sizes, int n_in,
                              void* d_out, int out_size) {
    const float* x    = (const float*)d_in[0];
    const int*   ei   = (const int*)d_in[1];
    const float* conf = (const float*)d_in[2];
    const float* fe_w = (const float*)d_in[3];
    const float* fe_b = (const float*)d_in[4];
    const float* fe_g = (const float*)d_in[5];
    const float* fe_be= (const float*)d_in[6];
    const float* sp_w1= (const float*)d_in[7];
    const float* sp_b1= (const float*)d_in[8];
    const float* sp_g1= (const float*)d_in[9];
    const float* sp_e1= (const float*)d_in[10];
    const float* sp_w2= (const float*)d_in[11];
    const float* sp_b2= (const float*)d_in[12];
    const float* sp_g2= (const float*)d_in[13];
    const float* sp_e2= (const float*)d_in[14];
    const float* g1_lin=(const float*)d_in[15];
    const float* g1_as= (const float*)d_in[16];
    const float* g1_ad= (const float*)d_in[17];
    const float* g1_b = (const float*)d_in[18];
    const float* g2_lin=(const float*)d_in[19];
    const float* g2_as= (const float*)d_in[20];
    const float* g2_ad= (const float*)d_in[21];
    const float* g2_b = (const float*)d_in[22];
    const float* op_w = (const float*)d_in[23];
    const float* op_b = (const float*)d_in[24];
    float* out = (float*)d_out;

    void *p1h, *p2h, *pph, *pw1h, *pw2h, *pPart;
    cudaGetSymbolAddress(&p1h, g_x1h);
    cudaGetSymbolAddress(&p2h, g_x2h);
    cudaGetSymbolAddress(&pph, g_xph);
    cudaGetSymbolAddress(&pw1h, g_w1h);
    cudaGetSymbolAddress(&pw2h, g_w2h);
    cudaGetSymbolAddress(&pPart, g_part);
    __half* x1h = (__half*)p1h;
    __half* x2h = (__half*)p2h;
    __half* xph = (__half*)pph;
    __half* w1h = (__half*)pw1h;
    __half* w2h = (__half*)pw2h;
    float* part = (float*)pPart;

    cudaFuncSetAttribute(conv_mma_kernel<0>, cudaFuncAttributeMaxDynamicSharedMemorySize, CONV_SMEM);
    cudaFuncSetAttribute(conv_mma_kernel<1>, cudaFuncAttributeMaxDynamicSharedMemorySize, CONV_SMEM);
    cudaFuncSetAttribute(fe_mma_kernel, cudaFuncAttributeMaxDynamicSharedMemorySize, FE_SMEM);
    cudaFuncSetAttribute(op_mma_kernel, cudaFuncAttributeMaxDynamicSharedMemorySize, OP_SMEM);

    const int WTOT = 2 * HIDC * HIDC * 9 + CINC * HIDC;
    const int PREP_BLOCKS = 1 + (WTOT + 511) / 512;

    fe_mma_kernel<<<dim3(NN, 8), 256, FE_SMEM>>>(x, fe_w, fe_b, fe_g, fe_be, conf, x1h); // 0
    prep_kernel<<<PREP_BLOCKS, 512>>>(ei, sp_w1, sp_w2, op_w);                // 1
    conv_mma_kernel<0><<<NN * MTILES, 256, CONV_SMEM>>>(                      // 2
        x1h, w1h, sp_b1, sp_g1, sp_e1, x2h, nullptr);
    conv_mma_kernel<1><<<NN * MTILES, 256, CONV_SMEM>>>(                      // 3 (ncu)
        x2h, w2h, sp_b2, sp_g2, sp_e2, xph, part);
    gat_h1_kernel<<<NN, 128>>>(g1_lin, g1_as, g1_ad);                         // 4
    gat_aggr1_h2_kernel<<<NN, 128>>>(g1_b, g2_lin, g2_as, g2_ad);             // 5
    gat_aggr2_kernel<<<NN, 128>>>(g2_b, op_w, op_b);                          // 6
    op_mma_kernel<<<dim3(NN, 8), 256, OP_SMEM>>>(xph, out);                   // 7

    (void)in_sizes; (void)n_in; (void)out_size;
}

// round 15
// speedup vs baseline: 9.5989x; 1.0081x over previous
#include <cuda_runtime.h>
#include <cuda_fp16.h>
#include <math.h>
#include <stdint.h>

#define NN   512
#define CINC 64
#define HIDC 128
#define HWSZ 1024
#define HH   32
#define WW   32
#define HEADS 4
#define NE   16384
#define TOTE (NE + NN)
#define POSN 1224
#define MTILES 9
#define WN   (HIDC * HIDC * 9)
#define WTOT (2 * WN + CINC * HIDC)

#define A_SLAB  16000
#define B_BASE  64000
#define B_PAIR  9216
#define CONV_SMEM (64000 + 4 * B_PAIR)

#define FE_RS   144
#define FE_XH   0
#define FE_W    18432
#define FE_SMEM 36864

#define OP_RS   272
#define OPW_0   34816
#define OP_SMEM (34816 + 17408)

// ================= helpers =================
__device__ __forceinline__ uint32_t smem_u32(const void* p) {
    return (uint32_t)__cvta_generic_to_shared(p);
}
__device__ __forceinline__ void ldmx4(uint32_t* r, uint32_t a) {
    asm volatile("ldmatrix.sync.aligned.m8n8.x4.shared.b16 {%0,%1,%2,%3}, [%4];"
                 : "=r"(r[0]), "=r"(r[1]), "=r"(r[2]), "=r"(r[3]) : "r"(a));
}
__device__ __forceinline__ void mma16816(float* c, const uint32_t* a,
                                         uint32_t b0, uint32_t b1) {
    asm volatile(
        "mma.sync.aligned.m16n8k16.row.col.f32.f16.f16.f32 "
        "{%0,%1,%2,%3}, {%4,%5,%6,%7}, {%8,%9}, {%0,%1,%2,%3};"
        : "+f"(c[0]), "+f"(c[1]), "+f"(c[2]), "+f"(c[3])
        : "r"(a[0]), "r"(a[1]), "r"(a[2]), "r"(a[3]), "r"(b0), "r"(b1));
}
__device__ __forceinline__ void cpasync16(uint32_t sa, const void* g) {
    unsigned long long ga = (unsigned long long)__cvta_generic_to_global(g);
    asm volatile("cp.async.cg.shared.global [%0], [%1], 16;" :: "r"(sa), "l"(ga));
}
#define CP_COMMIT() asm volatile("cp.async.commit_group;")
#define CP_WAIT(N)  asm volatile("cp.async.wait_group %0;" :: "n"(N))
#define BAR_PAIR(id) asm volatile("bar.sync %0, 64;" :: "r"(id) : "memory")

__device__ __forceinline__ uint32_t pack_h2(__half a, __half b) {
    return (uint32_t)__half_as_ushort(a) | ((uint32_t)__half_as_ushort(b) << 16);
}
__device__ __forceinline__ float warp_sum(float v) {
#pragma unroll
    for (int off = 16; off > 0; off >>= 1)
        v += __shfl_xor_sync(0xffffffffu, v, off);
    return v;
}

// ================= device scratch =================
__device__ __half g_x1h[(size_t)NN * POSN * HIDC]; // border stays zero
__device__ __half g_x2h[(size_t)NN * POSN * HIDC];
__device__ __half g_xph[(size_t)NN * HWSZ * HIDC];
__device__ __half g_w1h[9 * HIDC * HIDC];
__device__ __half g_w2h[9 * HIDC * HIDC];
__device__ __half g_woph[CINC * HIDC];
__device__ float g_part[(size_t)NN * MTILES * 8 * 32];
__device__ float g_hfeat[NN * HEADS * HIDC];
__device__ float g_as[NN * HEADS];
__device__ float g_ad[NN * HEADS];
__device__ float g_hfeat2[NN * HEADS * HIDC];
__device__ float g_as2[NN * HEADS];
__device__ float g_ad2[NN * HEADS];
__device__ float g_gterm[NN * CINC];
__device__ int   g_row[NN + 1];
__device__ int   g_csr[TOTE];
__device__ volatile unsigned g_barc[2];   // monotonic ticket counters

__device__ __forceinline__ void read_edge(const int* __restrict__ ei, int i,
                                          int is64, int& s, int& d) {
    if (i < NE) {
        if (is64) { s = ei[2 * i]; d = ei[2 * (NE + i)]; }
        else      { s = ei[i];     d = ei[NE + i]; }
    } else { s = i - NE; d = i - NE; }
}

// ================= fe: 1x1 conv MMA + distributed wprep + CSR (block 0,0) =
__global__ __launch_bounds__(256) void fe_mma_kernel(
    const float* __restrict__ x, const float* __restrict__ fw,
    const float* __restrict__ fb, const float* __restrict__ fg,
    const float* __restrict__ fbe, const float* __restrict__ conf,
    __half* __restrict__ xh,
    const int* __restrict__ ei,
    const float* __restrict__ w1, const float* __restrict__ w2,
    const float* __restrict__ wop) {
    extern __shared__ __align__(16) char dsm[];
    __shared__ float s_conf[128];
    __shared__ float s_sc[HIDC], s_sh[HIDC];
    __shared__ int scnt[NN];
    __shared__ int sfill[NN];
    __shared__ int stmp[256];
    __shared__ int s_is64;

    int tid = threadIdx.x, lane = tid & 31, warp = tid >> 5;
    int warpm = warp >> 2, warpn = warp & 3;
    int n = blockIdx.x, px0 = blockIdx.y * 128;
    uint32_t sbase = smem_u32(dsm);

    // --- distributed weight prep (1 elem per thread across the grid) ---
    {
        int gidx = (blockIdx.y * NN + blockIdx.x) * 256 + tid;
        if (gidx < 2 * WN) {
            int j = (gidx < WN) ? gidx : gidx - WN;
            int tap = j % 9;
            int ci = (j / 9) % HIDC;
            int co = j / (9 * HIDC);
            if (gidx < WN)
                g_w1h[(tap * HIDC + co) * HIDC + ci] = __float2half_rn(w1[j]);
            else
                g_w2h[(tap * HIDC + co) * HIDC + ci] = __float2half_rn(w2[j]);
        } else if (gidx < WTOT) {
            int j = gidx - 2 * WN;
            g_woph[j] = __float2half_rn(wop[j]);
        }
    }

    // --- CSR build in block (0,0) only (overlaps other fe blocks) ---
    if (blockIdx.x == 0 && blockIdx.y == 0) {
        if (tid == 0) {
            int acc = 0;
            for (int i = 0; i < 128; i++) acc |= ei[2 * i + 1];
            s_is64 = (acc == 0) ? 1 : 0;
        }
        scnt[tid] = 0;
        scnt[tid + 256] = 0;
        __syncthreads();
        int is64 = s_is64;
        for (int i = tid; i < TOTE; i += 256) {
            int s, d; read_edge(ei, i, is64, s, d);
            atomicAdd(&scnt[d], 1);
        }
        __syncthreads();
        int s0 = scnt[2 * tid], s1 = scnt[2 * tid + 1];
        stmp[tid] = s0 + s1;
        __syncthreads();
        for (int off = 1; off < 256; off <<= 1) {
            int v = (tid >= off) ? stmp[tid - off] : 0;
            __syncthreads();
            stmp[tid] += v;
            __syncthreads();
        }
        int Pprev = tid ? stmp[tid - 1] : 0;
        g_row[2 * tid + 1] = Pprev + s0;
        g_row[2 * tid + 2] = Pprev + s0 + s1;
        if (tid == 0) g_row[0] = 0;
        sfill[2 * tid] = Pprev;
        sfill[2 * tid + 1] = Pprev + s0;
        __syncthreads();
        for (int i = tid; i < TOTE; i += 256) {
            int s, d; read_edge(ei, i, is64, s, d);
            int pos = atomicAdd(&sfill[d], 1);
            g_csr[pos] = s;
        }
    }

    if (tid < 128) {
        s_conf[tid] = conf[n * HWSZ + px0 + tid];
        const float inv = rsqrtf(1.0f + 1e-5f);
        float sc = fg[tid] * inv;
        s_sc[tid] = sc;
        s_sh[tid] = fbe[tid] + fb[tid] * sc;
    }

#pragma unroll
    for (int i = 0; i < 16; i++) {
        int idx = i * 256 + tid;
        int cp = idx & 31, co = idx >> 5;
        float2 v = *(const float2*)(fw + co * CINC + cp * 2);
        *(uint32_t*)(dsm + FE_W + co * FE_RS + cp * 4) =
            pack_h2(__float2half_rn(v.x), __float2half_rn(v.y));
    }
#pragma unroll
    for (int i = 0; i < 16; i++) {
        int idx = i * 256 + tid;
        int p = idx & 127, cp = idx >> 7;
        float a = x[((size_t)n * CINC + 2 * cp) * HWSZ + px0 + p];
        float b = x[((size_t)n * CINC + 2 * cp + 1) * HWSZ + px0 + p];
        *(uint32_t*)(dsm + FE_XH + p * FE_RS + cp * 4) =
            pack_h2(__float2half_rn(a), __float2half_rn(b));
    }
    __syncthreads();

    float C[4][4][4];
#pragma unroll
    for (int m = 0; m < 4; m++)
#pragma unroll
        for (int nt = 0; nt < 4; nt++)
#pragma unroll
            for (int r = 0; r < 4; r++) C[m][nt][r] = 0.f;

    int a_row = lane & 15, a_ko = (lane >> 4) * 16;
    int b_row = (lane & 7) + ((lane >> 4) & 1) * 8;
    int b_ko = ((lane >> 3) & 1) * 16;

#pragma unroll
    for (int kq = 0; kq < 4; kq++) {
        uint32_t ah[4][4];
#pragma unroll
        for (int m = 0; m < 4; m++) {
            uint32_t ra = (uint32_t)(warpm * 64 + m * 16 + a_row) * FE_RS + kq * 32 + a_ko;
            ldmx4(ah[m], sbase + FE_XH + ra);
        }
#pragma unroll
        for (int ntp = 0; ntp < 2; ntp++) {
            uint32_t bw[4];
            uint32_t rb = (uint32_t)(warpn * 32 + ntp * 16 + b_row) * FE_RS + kq * 32 + b_ko;
            ldmx4(bw, sbase + FE_W + rb);
#pragma unroll
            for (int q = 0; q < 2; q++) {
                int nt = ntp * 2 + q;
#pragma unroll
                for (int m = 0; m < 4; m++)
                    mma16816(C[m][nt], ah[m], bw[2 * q], bw[2 * q + 1]);
            }
        }
    }

    int g4 = lane >> 2, t2 = (lane & 3) * 2;
#pragma unroll
    for (int m = 0; m < 4; m++) {
#pragma unroll
        for (int nt = 0; nt < 4; nt++) {
            int co = warpn * 32 + nt * 8 + t2;
            float sc0 = s_sc[co], sh0 = s_sh[co];
            float sc1 = s_sc[co + 1], sh1 = s_sh[co + 1];
#pragma unroll
            for (int half = 0; half < 2; half++) {
                int pl = warpm * 64 + m * 16 + g4 + half * 8;
                float cf = s_conf[pl];
                float v0 = fmaxf(C[m][nt][half * 2 + 0] * sc0 + sh0, 0.f) * cf;
                float v1 = fmaxf(C[m][nt][half * 2 + 1] * sc1 + sh1, 0.f) * cf;
                int hw = px0 + pl;
                int h = hw >> 5, w = hw & 31;
                size_t q2 = ((size_t)n * POSN + (h + 1) * 34 + (w + 1)) * HIDC + co;
                *(uint32_t*)(xh + q2) =
                    pack_h2(__float2half_rn(v0), __float2half_rn(v1));
            }
        }
    }
}

// ================= mma.sync conv (unchanged) =================
template <int MODE>
__global__ __launch_bounds__(256, 2) void conv_mma_kernel(
    const __half* __restrict__ Xh,
    const __half* __restrict__ Wh,
    const float* __restrict__ bb, const float* __restrict__ gg,
    const float* __restrict__ be,
    __half* __restrict__ Oh, float* __restrict__ Part) {
    extern __shared__ __align__(16) char dsm[];
    __shared__ float s_sc[HIDC], s_sh[HIDC];

    int tid = threadIdx.x, lane = tid & 31, warp = tid >> 5;
    int warpm = warp >> 2, warpn = warp & 3;
    int n = blockIdx.x / MTILES, mt = blockIdx.x % MTILES;
    int pbase = mt * 128;

    if (tid < HIDC) {
        const float inv = rsqrtf(1.0f + 1e-5f);
        float sc = gg[tid] * inv;
        s_sc[tid] = sc;
        s_sh[tid] = be[tid] + bb[tid] * sc;
    }

    float C[4][4][4];
#pragma unroll
    for (int m = 0; m < 4; m++)
#pragma unroll
        for (int nt = 0; nt < 4; nt++)
#pragma unroll
            for (int r = 0; r < 4; r++) C[m][nt][r] = 0.f;

    uint32_t sbase = smem_u32(dsm);
    uint32_t sB0 = sbase + B_BASE + warpn * B_PAIR;
    bool loader = (warpm == 0);

    auto loadB = [&](int s1, uint32_t buf) {
        int pairci = s1 / 9, tap = s1 - pairci * 9;
        uint32_t s0 = sB0 + buf * 4608;
        size_t gb = ((size_t)(tap * HIDC + warpn * 32)) * HIDC + pairci * 64;
#pragma unroll
        for (int i = 0; i < 8; i++) {
            int seg = i * 32 + lane;
            int r = seg >> 3, sg = seg & 7;
            cpasync16(s0 + r * 144 + sg * 16, Wh + gb + (size_t)r * HIDC + sg * 8);
        }
    };

    {
        size_t gbase = ((size_t)(n * POSN + pbase)) * HIDC;
#pragma unroll
        for (int cic = 0; cic < 4; cic++) {
            uint32_t s0 = sbase + cic * A_SLAB;
            size_t gb = gbase + cic * 32;
#pragma unroll
            for (int i = 0; i < 4; i++) {
                int idx = i * 256 + tid;
                if (idx < 792) {
                    int r = idx >> 2, sg = idx & 3;
                    cpasync16(s0 + r * 80 + sg * 16, Xh + gb + (size_t)r * HIDC + sg * 8);
                }
            }
        }
        if (loader) loadB(0, 0);
        CP_COMMIT();
        CP_WAIT(0);
        __syncthreads();
    }

    int a_row = lane & 15, a_ko = (lane >> 4) * 16;
    int b_row = (lane & 7) + ((lane >> 4) & 1) * 8;
    int b_ko = ((lane >> 3) & 1) * 16;
    int barid = 1 + warpn;

    auto do_stage = [&](int s, uint32_t buf) {
        int pair = s / 9, tap = s - pair * 9;
        CP_WAIT(0);
        BAR_PAIR(barid);
        if (loader && s + 1 < 18) {
            loadB(s + 1, buf ^ 1u);
            CP_COMMIT();
        }
        int tapoff = (tap / 3) * 34 + (tap - (tap / 3) * 3);
        uint32_t sB = sB0 + buf * 4608;
#pragma unroll
        for (int c2 = 0; c2 < 2; c2++) {
            uint32_t sA = sbase + (pair * 2 + c2) * A_SLAB;
            uint32_t bhalf = c2 * 64;
#pragma unroll
            for (int ks = 0; ks < 2; ks++) {
                uint32_t ah[4][4];
#pragma unroll
                for (int m = 0; m < 4; m++) {
                    uint32_t ra = (uint32_t)(tapoff + warpm * 64 + m * 16 + a_row) * 80 + ks * 32 + a_ko;
                    ldmx4(ah[m], sA + ra);
                }
#pragma unroll
                for (int ntp = 0; ntp < 2; ntp++) {
                    uint32_t rbh[4];
                    uint32_t rb = (uint32_t)(ntp * 16 + b_row) * 144 + bhalf + ks * 32 + b_ko;
                    ldmx4(rbh, sB + rb);
#pragma unroll
                    for (int q = 0; q < 2; q++) {
                        int nt = ntp * 2 + q;
#pragma unroll
                        for (int m = 0; m < 4; m++)
                            mma16816(C[m][nt], ah[m], rbh[2 * q], rbh[2 * q + 1]);
                    }
                }
            }
        }
    };

#pragma unroll 1
    for (int sp = 0; sp < 9; sp++) {
        do_stage(sp * 2, 0u);
        do_stage(sp * 2 + 1, 1u);
    }

    int g4 = lane >> 2;
    int t2 = (lane & 3) * 2;
    float ps[4][2];
    if (MODE == 1)
#pragma unroll
        for (int nt = 0; nt < 4; nt++) { ps[nt][0] = 0.f; ps[nt][1] = 0.f; }
#pragma unroll
    for (int m = 0; m < 4; m++) {
#pragma unroll
        for (int nt = 0; nt < 4; nt++) {
            int co = warpn * 32 + nt * 8 + t2;
            float sc0 = s_sc[co], sh0 = s_sh[co];
            float sc1 = s_sc[co + 1], sh1 = s_sh[co + 1];
#pragma unroll
            for (int half = 0; half < 2; half++) {
                int p = pbase + warpm * 64 + m * 16 + g4 + half * 8;
                float v0 = C[m][nt][half * 2 + 0] * sc0 + sh0;
                float v1 = C[m][nt][half * 2 + 1] * sc1 + sh1;
                int h = p / 34, w = p % 34;
                bool valid = (w < 32) && (h < 32);
                v0 = valid ? fmaxf(v0, 0.f) : 0.f;
                v1 = valid ? fmaxf(v1, 0.f) : 0.f;
                uint32_t pk = pack_h2(__float2half_rn(v0), __float2half_rn(v1));
                if (MODE == 0) {
                    size_t q2 = ((size_t)n * POSN + p + 35) * HIDC + co;
                    *(uint32_t*)(Oh + q2) = pk;
                } else {
                    ps[nt][0] += v0;
                    ps[nt][1] += v1;
                    if (valid) {
                        size_t q2 = ((size_t)n * HWSZ + h * WW + w) * HIDC + co;
                        *(uint32_t*)(Oh + q2) = pk;
                    }
                }
            }
        }
    }
    if (MODE == 1) {
#pragma unroll
        for (int nt = 0; nt < 4; nt++)
#pragma unroll
            for (int q = 0; q < 2; q++) {
                float v = ps[nt][q];
                v += __shfl_xor_sync(0xffffffffu, v, 4);
                v += __shfl_xor_sync(0xffffffffu, v, 8);
                v += __shfl_xor_sync(0xffffffffu, v, 16);
                ps[nt][q] = v;
            }
        if (lane < 4) {
            size_t base = (((size_t)n * MTILES + mt) * 8 + warp) * 32;
#pragma unroll
            for (int nt = 0; nt < 4; nt++) {
                Part[base + nt * 8 + lane * 2 + 0] = ps[nt][0];
                Part[base + nt * 8 + lane * 2 + 1] = ps[nt][1];
            }
        }
    }
}

// ===== GAT stage helpers =====
__device__ __forceinline__ void gat_h_stage(
    int n, int t, const float* xr, float* red,
    const float* __restrict__ lin,
    const float* __restrict__ asw, const float* __restrict__ adw,
    float* __restrict__ hfeat, float* __restrict__ asv, float* __restrict__ adv) {
    int lane = t & 31, wid = t >> 5;
    float hv[HEADS];
#pragma unroll
    for (int j = 0; j < HEADS; j++) {
        int col = j * HIDC + t;
        float s = 0.f;
        for (int k = 0; k < HIDC; k++) s += xr[k] * lin[k * (HEADS * HIDC) + col];
        hv[j] = s;
        hfeat[n * (HEADS * HIDC) + col] = s;
    }
#pragma unroll
    for (int j = 0; j < HEADS; j++) {
        float pa = warp_sum(hv[j] * asw[j * HIDC + t]);
        float pd = warp_sum(hv[j] * adw[j * HIDC + t]);
        if (lane == 0) { red[wid] = pa; red[4 + wid] = pd; }
        __syncthreads();
        if (t == 0) {
            asv[n * HEADS + j] = red[0] + red[1] + red[2] + red[3];
            adv[n * HEADS + j] = red[4] + red[5] + red[6] + red[7];
        }
        __syncthreads();
    }
}

__device__ __forceinline__ float gat_aggr_stage(
    int n, int t,
    const float* __restrict__ hfeat, const float* __restrict__ asv,
    const float* __restrict__ adv, const float* __restrict__ bias) {
    float adn[HEADS];
#pragma unroll
    for (int j = 0; j < HEADS; j++) adn[j] = adv[n * HEADS + j];
    int rs = g_row[n], re = g_row[n + 1];
    float m[HEADS]  = {-1e30f, -1e30f, -1e30f, -1e30f};
    float den[HEADS] = {0.f, 0.f, 0.f, 0.f};
    float acc[HEADS] = {0.f, 0.f, 0.f, 0.f};
    for (int ei = rs; ei < re; ei++) {
        int s = g_csr[ei];
#pragma unroll
        for (int j = 0; j < HEADS; j++) {
            float e = asv[s * HEADS + j] + adn[j];
            e = (e > 0.f) ? e : 0.2f * e;
            float hval = hfeat[s * (HEADS * HIDC) + j * HIDC + t];
            if (e > m[j]) {
                float sc = __expf(m[j] - e);
                den[j] = den[j] * sc + 1.f;
                acc[j] = acc[j] * sc + hval;
                m[j] = e;
            } else {
                float ex = __expf(e - m[j]);
                den[j] += ex;
                acc[j] += ex * hval;
            }
        }
    }
    float o = 0.f;
#pragma unroll
    for (int j = 0; j < HEADS; j++) o += acc[j] / (den[j] + 1e-16f);
    return fmaxf(o * 0.25f + bias[t], 0.f);
}

// ===== replay-safe ticket grid barrier (grid == single wave) =====
__device__ __forceinline__ void grid_bar(int i, int t) {
    __threadfence();
    __syncthreads();
    if (t == 0) {
        unsigned old = atomicAdd((unsigned*)&g_barc[i], 1u);
        unsigned tgt = (old / (unsigned)NN + 1u) * (unsigned)NN;
        while (g_barc[i] < tgt) { __nanosleep(64); }
        __threadfence();
    }
    __syncthreads();
}

// ================= persistent fused GAT (h1 | aggr1+h2 | aggr2+gterm) ====
__global__ __launch_bounds__(128) void gat_fused_kernel(
    const float* __restrict__ g1_lin, const float* __restrict__ g1_as,
    const float* __restrict__ g1_ad, const float* __restrict__ g1_b,
    const float* __restrict__ g2_lin, const float* __restrict__ g2_as,
    const float* __restrict__ g2_ad, const float* __restrict__ g2_b,
    const float* __restrict__ opw, const float* __restrict__ opb) {
    __shared__ float xr[HIDC];
    __shared__ float red[8];
    int n = blockIdx.x, t = threadIdx.x;

    // phase 1: pool reduce -> h1
    {
        int wn = t >> 5, col = t & 31;
        float s = 0.f;
#pragma unroll 1
        for (int mt = 0; mt < MTILES; mt++) {
            size_t b = (((size_t)n * MTILES + mt) * 8);
            s += g_part[(b + wn) * 32 + col];
            s += g_part[(b + 4 + wn) * 32 + col];
        }
        xr[t] = s * (1.f / 1024.f);
    }
    __syncthreads();
    gat_h_stage(n, t, xr, red, g1_lin, g1_as, g1_ad, g_hfeat, g_as, g_ad);

    grid_bar(0, t);

    // phase 2: aggr1 -> h2
    float o1 = gat_aggr_stage(n, t, g_hfeat, g_as, g_ad, g1_b);
    __syncthreads();   // xr reuse: phase-1 readers done
    xr[t] = o1;
    __syncthreads();
    gat_h_stage(n, t, xr, red, g2_lin, g2_as, g2_ad, g_hfeat2, g_as2, g_ad2);

    grid_bar(1, t);

    // phase 3: aggr2 + gterm
    float o2 = gat_aggr_stage(n, t, g_hfeat2, g_as2, g_ad2, g2_b);
    __syncthreads();
    xr[t] = o2;
    __syncthreads();
    if (t < CINC) {
        float s = opb[t];
        for (int k = 0; k < HIDC; k++) s += xr[k] * opw[t * HIDC + k];
        g_gterm[n * CINC + t] = s;
    }
}

// ================= op (unchanged) =================
__global__ __launch_bounds__(256) void op_mma_kernel(
    const __half* __restrict__ Xh,
    float* __restrict__ out) {
    extern __shared__ __align__(16) char dsm[];
    int tid = threadIdx.x, lane = tid & 31, warp = tid >> 5;
    int warpm = warp >> 1, warpn = warp & 1;
    int n = blockIdx.x, hw0 = blockIdx.y * 128;
    uint32_t sbase = smem_u32(dsm);

#pragma unroll
    for (int i = 0; i < 8; i++) {
        int idx = i * 256 + tid;
        int r = idx >> 4, sg = idx & 15;
        const __half* g = Xh + ((size_t)n * HWSZ + hw0 + r) * HIDC + sg * 8;
        cpasync16(sbase + r * OP_RS + sg * 16, g);
    }
#pragma unroll
    for (int i = 0; i < 4; i++) {
        int idx = i * 256 + tid;
        int r = idx >> 4, sg = idx & 15;
        cpasync16(sbase + OPW_0 + r * OP_RS + sg * 16, g_woph + r * HIDC + sg * 8);
    }
    CP_COMMIT();

    float C[8][4];
#pragma unroll
    for (int nt = 0; nt < 8; nt++)
#pragma unroll
        for (int r = 0; r < 4; r++) C[nt][r] = 0.f;

    int a_row = lane & 15, a_ko = (lane >> 4) * 16;
    int b_row = (lane & 7) + ((lane >> 4) & 1) * 8;
    int b_ko = ((lane >> 3) & 1) * 16;

    CP_WAIT(0);
    __syncthreads();

#pragma unroll 1
    for (int kc = 0; kc < 8; kc++) {
        uint32_t awh[4];
        uint32_t ra = (uint32_t)(warpm * 16 + a_row) * OP_RS + kc * 32 + a_ko;
        ldmx4(awh, sbase + OPW_0 + ra);
#pragma unroll
        for (int ntp = 0; ntp < 4; ntp++) {
            uint32_t xbh[4];
            uint32_t rb = (uint32_t)(warpn * 64 + ntp * 16 + b_row) * OP_RS + kc * 32 + b_ko;
            ldmx4(xbh, sbase + rb);
#pragma unroll
            for (int q = 0; q < 2; q++)
                mma16816(C[ntp * 2 + q], awh, xbh[2 * q], xbh[2 * q + 1]);
        }
    }

    int g4 = lane >> 2, t2 = (lane & 3) * 2;
    int co_a = warpm * 16 + g4;
    int co_b = co_a + 8;
    float gta = g_gterm[n * CINC + co_a];
    float gtb = g_gterm[n * CINC + co_b];
#pragma unroll
    for (int nt = 0; nt < 8; nt++) {
        int hw = hw0 + warpn * 64 + nt * 8 + t2;
        float2 va = make_float2(C[nt][0] + gta, C[nt][1] + gta);
        float2 vb = make_float2(C[nt][2] + gtb, C[nt][3] + gtb);
        *(float2*)&out[((size_t)n * CINC + co_a) * HWSZ + hw] = va;
        *(float2*)&out[((size_t)n * CINC + co_b) * HWSZ + hw] = vb;
    }
}

// ================= launch =================
extern "C" void kernel_launch(void* const* d_in, const int* in_sizes, int n_in,
                              void* d_out, int out_size) {
    const float* x    = (const float*)d_in[0];
    const int*   ei   = (const int*)d_in[1];
    const float* conf = (const float*)d_in[2];
    const float* fe_w = (const float*)d_in[3];
    const float* fe_b = (const float*)d_in[4];
    const float* fe_g = (const float*)d_in[5];
    const float* fe_be= (const float*)d_in[6];
    const float* sp_w1= (const float*)d_in[7];
    const float* sp_b1= (const float*)d_in[8];
    const float* sp_g1= (const float*)d_in[9];
    const float* sp_e1= (const float*)d_in[10];
    const float* sp_w2= (const float*)d_in[11];
    const float* sp_b2= (const float*)d_in[12];
    const float* sp_g2= (const float*)d_in[13];
    const float* sp_e2= (const float*)d_in[14];
    const float* g1_lin=(const float*)d_in[15];
    const float* g1_as= (const float*)d_in[16];
    const float* g1_ad= (const float*)d_in[17];
    const float* g1_b = (const float*)d_in[18];
    const float* g2_lin=(const float*)d_in[19];
    const float* g2_as= (const float*)d_in[20];
    const float* g2_ad= (const float*)d_in[21];
    const float* g2_b = (const float*)d_in[22];
    const float* op_w = (const float*)d_in[23];
    const float* op_b = (const float*)d_in[24];
    float* out = (float*)d_out;

    void *p1h, *p2h, *pph, *pw1h, *pw2h, *pPart;
    cudaGetSymbolAddress(&p1h, g_x1h);
    cudaGetSymbolAddress(&p2h, g_x2h);
    cudaGetSymbolAddress(&pph, g_xph);
    cudaGetSymbolAddress(&pw1h, g_w1h);
    cudaGetSymbolAddress(&pw2h, g_w2h);
    cudaGetSymbolAddress(&pPart, g_part);
    __half* x1h = (__half*)p1h;
    __half* x2h = (__half*)p2h;
    __half* xph = (__half*)pph;
    __half* w1h = (__half*)pw1h;
    __half* w2h = (__half*)pw2h;
    float* part = (float*)pPart;

    cudaFuncSetAttribute(conv_mma_kernel<0>, cudaFuncAttributeMaxDynamicSharedMemorySize, CONV_SMEM);
    cudaFuncSetAttribute(conv_mma_kernel<1>, cudaFuncAttributeMaxDynamicSharedMemorySize, CONV_SMEM);
    cudaFuncSetAttribute(fe_mma_kernel, cudaFuncAttributeMaxDynamicSharedMemorySize, FE_SMEM);
    cudaFuncSetAttribute(op_mma_kernel, cudaFuncAttributeMaxDynamicSharedMemorySize, OP_SMEM);

    fe_mma_kernel<<<dim3(NN, 8), 256, FE_SMEM>>>(                             // 0
        x, fe_w, fe_b, fe_g, fe_be, conf, x1h, ei, sp_w1, sp_w2, op_w);
    conv_mma_kernel<0><<<NN * MTILES, 256, CONV_SMEM>>>(                      // 1
        x1h, w1h, sp_b1, sp_g1, sp_e1, x2h, nullptr);
    conv_mma_kernel<1><<<NN * MTILES, 256, CONV_SMEM>>>(                      // 2
        x2h, w2h, sp_b2, sp_g2, sp_e2, xph, part);
    gat_fused_kernel<<<NN, 128>>>(g1_lin, g1_as, g1_ad, g1_b,                 // 3
                                  g2_lin, g2_as, g2_ad, g2_b, op_w, op_b);
    op_mma_kernel<<<dim3(NN, 8), 256, OP_SMEM>>>(xph, out);                   // 4

    (void)in_sizes; (void)n_in; (void)out_size;
}

// round 16
// speedup vs baseline: 10.0218x; 1.0441x over previous
#include <cuda_runtime.h>
#include <cuda_fp16.h>
#include <math.h>
#include <stdint.h>

#define NN   512
#define CINC 64
#define HIDC 128
#define HWSZ 1024
#define HH   32
#define WW   32
#define HEADS 4
#define NE   16384
#define TOTE (NE + NN)
#define POSN 1224
#define MTILES 9
#define WN   (HIDC * HIDC * 9)
#define WTOT (2 * WN + CINC * HIDC)

#define A_SLAB  16000
#define B_BASE  64000
#define B_PAIR  9216
#define CONV_SMEM (64000 + 4 * B_PAIR)

#define FE_RS   144
#define FE_XH   0
#define FE_W    18432
#define FE_SMEM 36864

#define OP_RS   272
#define OPW_0   34816
#define OP_SMEM (34816 + 17408)

// ================= helpers =================
__device__ __forceinline__ uint32_t smem_u32(const void* p) {
    return (uint32_t)__cvta_generic_to_shared(p);
}
__device__ __forceinline__ void ldmx4(uint32_t* r, uint32_t a) {
    asm volatile("ldmatrix.sync.aligned.m8n8.x4.shared.b16 {%0,%1,%2,%3}, [%4];"
                 : "=r"(r[0]), "=r"(r[1]), "=r"(r[2]), "=r"(r[3]) : "r"(a));
}
__device__ __forceinline__ void mma16816(float* c, const uint32_t* a,
                                         uint32_t b0, uint32_t b1) {
    asm volatile(
        "mma.sync.aligned.m16n8k16.row.col.f32.f16.f16.f32 "
        "{%0,%1,%2,%3}, {%4,%5,%6,%7}, {%8,%9}, {%0,%1,%2,%3};"
        : "+f"(c[0]), "+f"(c[1]), "+f"(c[2]), "+f"(c[3])
        : "r"(a[0]), "r"(a[1]), "r"(a[2]), "r"(a[3]), "r"(b0), "r"(b1));
}
__device__ __forceinline__ void cpasync16(uint32_t sa, const void* g) {
    unsigned long long ga = (unsigned long long)__cvta_generic_to_global(g);
    asm volatile("cp.async.cg.shared.global [%0], [%1], 16;" :: "r"(sa), "l"(ga));
}
#define CP_COMMIT() asm volatile("cp.async.commit_group;")
#define CP_WAIT(N)  asm volatile("cp.async.wait_group %0;" :: "n"(N))
#define BAR_PAIR(id) asm volatile("bar.sync %0, 64;" :: "r"(id) : "memory")

__device__ __forceinline__ uint32_t pack_h2(__half a, __half b) {
    return (uint32_t)__half_as_ushort(a) | ((uint32_t)__half_as_ushort(b) << 16);
}
__device__ __forceinline__ float warp_sum(float v) {
#pragma unroll
    for (int off = 16; off > 0; off >>= 1)
        v += __shfl_xor_sync(0xffffffffu, v, off);
    return v;
}

// ================= device scratch =================
__device__ __half g_x1h[(size_t)NN * POSN * HIDC]; // border stays zero
__device__ __half g_x2h[(size_t)NN * POSN * HIDC];
__device__ __half g_xph[(size_t)NN * HWSZ * HIDC];
__device__ __half g_w1h[9 * HIDC * HIDC];
__device__ __half g_w2h[9 * HIDC * HIDC];
__device__ __half g_woph[CINC * HIDC];
__device__ float g_part[(size_t)NN * MTILES * 8 * 32];
__device__ float g_hfeat[NN * HEADS * HIDC];
__device__ float g_as[NN * HEADS];
__device__ float g_ad[NN * HEADS];
__device__ float g_hfeat2[NN * HEADS * HIDC];
__device__ float g_as2[NN * HEADS];
__device__ float g_ad2[NN * HEADS];
__device__ float g_gterm[NN * CINC];
__device__ int   g_row[NN + 1];
__device__ int   g_csr[TOTE];
__device__ volatile unsigned g_barc[2];   // monotonic ticket counters

__device__ __forceinline__ void read_edge(const int* __restrict__ ei, int i,
                                          int is64, int& s, int& d) {
    if (i < NE) {
        if (is64) { s = ei[2 * i]; d = ei[2 * (NE + i)]; }
        else      { s = ei[i];     d = ei[NE + i]; }
    } else { s = i - NE; d = i - NE; }
}

// ================= fe: 1x1 conv MMA + distributed wprep + CSR (block 0,0) =
__global__ __launch_bounds__(256) void fe_mma_kernel(
    const float* __restrict__ x, const float* __restrict__ fw,
    const float* __restrict__ fb, const float* __restrict__ fg,
    const float* __restrict__ fbe, const float* __restrict__ conf,
    __half* __restrict__ xh,
    const int* __restrict__ ei,
    const float* __restrict__ w1, const float* __restrict__ w2,
    const float* __restrict__ wop) {
    extern __shared__ __align__(16) char dsm[];
    __shared__ float s_conf[128];
    __shared__ float s_sc[HIDC], s_sh[HIDC];
    __shared__ int scnt[NN];
    __shared__ int sfill[NN];
    __shared__ int stmp[256];
    __shared__ int s_is64;

    int tid = threadIdx.x, lane = tid & 31, warp = tid >> 5;
    int warpm = warp >> 2, warpn = warp & 3;
    int n = blockIdx.x, px0 = blockIdx.y * 128;
    uint32_t sbase = smem_u32(dsm);

    {
        int gidx = (blockIdx.y * NN + blockIdx.x) * 256 + tid;
        if (gidx < 2 * WN) {
            int j = (gidx < WN) ? gidx : gidx - WN;
            int tap = j % 9;
            int ci = (j / 9) % HIDC;
            int co = j / (9 * HIDC);
            if (gidx < WN)
                g_w1h[(tap * HIDC + co) * HIDC + ci] = __float2half_rn(w1[j]);
            else
                g_w2h[(tap * HIDC + co) * HIDC + ci] = __float2half_rn(w2[j]);
        } else if (gidx < WTOT) {
            int j = gidx - 2 * WN;
            g_woph[j] = __float2half_rn(wop[j]);
        }
    }

    if (blockIdx.x == 0 && blockIdx.y == 0) {
        if (tid == 0) {
            int acc = 0;
            for (int i = 0; i < 128; i++) acc |= ei[2 * i + 1];
            s_is64 = (acc == 0) ? 1 : 0;
        }
        scnt[tid] = 0;
        scnt[tid + 256] = 0;
        __syncthreads();
        int is64 = s_is64;
        for (int i = tid; i < TOTE; i += 256) {
            int s, d; read_edge(ei, i, is64, s, d);
            atomicAdd(&scnt[d], 1);
        }
        __syncthreads();
        int s0 = scnt[2 * tid], s1 = scnt[2 * tid + 1];
        stmp[tid] = s0 + s1;
        __syncthreads();
        for (int off = 1; off < 256; off <<= 1) {
            int v = (tid >= off) ? stmp[tid - off] : 0;
            __syncthreads();
            stmp[tid] += v;
            __syncthreads();
        }
        int Pprev = tid ? stmp[tid - 1] : 0;
        g_row[2 * tid + 1] = Pprev + s0;
        g_row[2 * tid + 2] = Pprev + s0 + s1;
        if (tid == 0) g_row[0] = 0;
        sfill[2 * tid] = Pprev;
        sfill[2 * tid + 1] = Pprev + s0;
        __syncthreads();
        for (int i = tid; i < TOTE; i += 256) {
            int s, d; read_edge(ei, i, is64, s, d);
            int pos = atomicAdd(&sfill[d], 1);
            g_csr[pos] = s;
        }
    }

    if (tid < 128) {
        s_conf[tid] = conf[n * HWSZ + px0 + tid];
        const float inv = rsqrtf(1.0f + 1e-5f);
        float sc = fg[tid] * inv;
        s_sc[tid] = sc;
        s_sh[tid] = fbe[tid] + fb[tid] * sc;
    }

#pragma unroll
    for (int i = 0; i < 16; i++) {
        int idx = i * 256 + tid;
        int cp = idx & 31, co = idx >> 5;
        float2 v = *(const float2*)(fw + co * CINC + cp * 2);
        *(uint32_t*)(dsm + FE_W + co * FE_RS + cp * 4) =
            pack_h2(__float2half_rn(v.x), __float2half_rn(v.y));
    }
#pragma unroll
    for (int i = 0; i < 16; i++) {
        int idx = i * 256 + tid;
        int p = idx & 127, cp = idx >> 7;
        float a = x[((size_t)n * CINC + 2 * cp) * HWSZ + px0 + p];
        float b = x[((size_t)n * CINC + 2 * cp + 1) * HWSZ + px0 + p];
        *(uint32_t*)(dsm + FE_XH + p * FE_RS + cp * 4) =
            pack_h2(__float2half_rn(a), __float2half_rn(b));
    }
    __syncthreads();

    float C[4][4][4];
#pragma unroll
    for (int m = 0; m < 4; m++)
#pragma unroll
        for (int nt = 0; nt < 4; nt++)
#pragma unroll
            for (int r = 0; r < 4; r++) C[m][nt][r] = 0.f;

    int a_row = lane & 15, a_ko = (lane >> 4) * 16;
    int b_row = (lane & 7) + ((lane >> 4) & 1) * 8;
    int b_ko = ((lane >> 3) & 1) * 16;

#pragma unroll
    for (int kq = 0; kq < 4; kq++) {
        uint32_t ah[4][4];
#pragma unroll
        for (int m = 0; m < 4; m++) {
            uint32_t ra = (uint32_t)(warpm * 64 + m * 16 + a_row) * FE_RS + kq * 32 + a_ko;
            ldmx4(ah[m], sbase + FE_XH + ra);
        }
#pragma unroll
        for (int ntp = 0; ntp < 2; ntp++) {
            uint32_t bw[4];
            uint32_t rb = (uint32_t)(warpn * 32 + ntp * 16 + b_row) * FE_RS + kq * 32 + b_ko;
            ldmx4(bw, sbase + FE_W + rb);
#pragma unroll
            for (int q = 0; q < 2; q++) {
                int nt = ntp * 2 + q;
#pragma unroll
                for (int m = 0; m < 4; m++)
                    mma16816(C[m][nt], ah[m], bw[2 * q], bw[2 * q + 1]);
            }
        }
    }

    int g4 = lane >> 2, t2 = (lane & 3) * 2;
#pragma unroll
    for (int m = 0; m < 4; m++) {
#pragma unroll
        for (int nt = 0; nt < 4; nt++) {
            int co = warpn * 32 + nt * 8 + t2;
            float sc0 = s_sc[co], sh0 = s_sh[co];
            float sc1 = s_sc[co + 1], sh1 = s_sh[co + 1];
#pragma unroll
            for (int half = 0; half < 2; half++) {
                int pl = warpm * 64 + m * 16 + g4 + half * 8;
                float cf = s_conf[pl];
                float v0 = fmaxf(C[m][nt][half * 2 + 0] * sc0 + sh0, 0.f) * cf;
                float v1 = fmaxf(C[m][nt][half * 2 + 1] * sc1 + sh1, 0.f) * cf;
                int hw = px0 + pl;
                int h = hw >> 5, w = hw & 31;
                size_t q2 = ((size_t)n * POSN + (h + 1) * 34 + (w + 1)) * HIDC + co;
                *(uint32_t*)(xh + q2) =
                    pack_h2(__float2half_rn(v0), __float2half_rn(v1));
            }
        }
    }
}

// ================= mma.sync conv (unchanged) =================
template <int MODE>
__global__ __launch_bounds__(256, 2) void conv_mma_kernel(
    const __half* __restrict__ Xh,
    const __half* __restrict__ Wh,
    const float* __restrict__ bb, const float* __restrict__ gg,
    const float* __restrict__ be,
    __half* __restrict__ Oh, float* __restrict__ Part) {
    extern __shared__ __align__(16) char dsm[];
    __shared__ float s_sc[HIDC], s_sh[HIDC];

    int tid = threadIdx.x, lane = tid & 31, warp = tid >> 5;
    int warpm = warp >> 2, warpn = warp & 3;
    int n = blockIdx.x / MTILES, mt = blockIdx.x % MTILES;
    int pbase = mt * 128;

    if (tid < HIDC) {
        const float inv = rsqrtf(1.0f + 1e-5f);
        float sc = gg[tid] * inv;
        s_sc[tid] = sc;
        s_sh[tid] = be[tid] + bb[tid] * sc;
    }

    float C[4][4][4];
#pragma unroll
    for (int m = 0; m < 4; m++)
#pragma unroll
        for (int nt = 0; nt < 4; nt++)
#pragma unroll
            for (int r = 0; r < 4; r++) C[m][nt][r] = 0.f;

    uint32_t sbase = smem_u32(dsm);
    uint32_t sB0 = sbase + B_BASE + warpn * B_PAIR;
    bool loader = (warpm == 0);

    auto loadB = [&](int s1, uint32_t buf) {
        int pairci = s1 / 9, tap = s1 - pairci * 9;
        uint32_t s0 = sB0 + buf * 4608;
        size_t gb = ((size_t)(tap * HIDC + warpn * 32)) * HIDC + pairci * 64;
#pragma unroll
        for (int i = 0; i < 8; i++) {
            int seg = i * 32 + lane;
            int r = seg >> 3, sg = seg & 7;
            cpasync16(s0 + r * 144 + sg * 16, Wh + gb + (size_t)r * HIDC + sg * 8);
        }
    };

    {
        size_t gbase = ((size_t)(n * POSN + pbase)) * HIDC;
#pragma unroll
        for (int cic = 0; cic < 4; cic++) {
            uint32_t s0 = sbase + cic * A_SLAB;
            size_t gb = gbase + cic * 32;
#pragma unroll
            for (int i = 0; i < 4; i++) {
                int idx = i * 256 + tid;
                if (idx < 792) {
                    int r = idx >> 2, sg = idx & 3;
                    cpasync16(s0 + r * 80 + sg * 16, Xh + gb + (size_t)r * HIDC + sg * 8);
                }
            }
        }
        if (loader) loadB(0, 0);
        CP_COMMIT();
        CP_WAIT(0);
        __syncthreads();
    }

    int a_row = lane & 15, a_ko = (lane >> 4) * 16;
    int b_row = (lane & 7) + ((lane >> 4) & 1) * 8;
    int b_ko = ((lane >> 3) & 1) * 16;
    int barid = 1 + warpn;

    auto do_stage = [&](int s, uint32_t buf) {
        int pair = s / 9, tap = s - pair * 9;
        CP_WAIT(0);
        BAR_PAIR(barid);
        if (loader && s + 1 < 18) {
            loadB(s + 1, buf ^ 1u);
            CP_COMMIT();
        }
        int tapoff = (tap / 3) * 34 + (tap - (tap / 3) * 3);
        uint32_t sB = sB0 + buf * 4608;
#pragma unroll
        for (int c2 = 0; c2 < 2; c2++) {
            uint32_t sA = sbase + (pair * 2 + c2) * A_SLAB;
            uint32_t bhalf = c2 * 64;
#pragma unroll
            for (int ks = 0; ks < 2; ks++) {
                uint32_t ah[4][4];
#pragma unroll
                for (int m = 0; m < 4; m++) {
                    uint32_t ra = (uint32_t)(tapoff + warpm * 64 + m * 16 + a_row) * 80 + ks * 32 + a_ko;
                    ldmx4(ah[m], sA + ra);
                }
#pragma unroll
                for (int ntp = 0; ntp < 2; ntp++) {
                    uint32_t rbh[4];
                    uint32_t rb = (uint32_t)(ntp * 16 + b_row) * 144 + bhalf + ks * 32 + b_ko;
                    ldmx4(rbh, sB + rb);
#pragma unroll
                    for (int q = 0; q < 2; q++) {
                        int nt = ntp * 2 + q;
#pragma unroll
                        for (int m = 0; m < 4; m++)
                            mma16816(C[m][nt], ah[m], rbh[2 * q], rbh[2 * q + 1]);
                    }
                }
            }
        }
    };

#pragma unroll 1
    for (int sp = 0; sp < 9; sp++) {
        do_stage(sp * 2, 0u);
        do_stage(sp * 2 + 1, 1u);
    }

    int g4 = lane >> 2;
    int t2 = (lane & 3) * 2;
    float ps[4][2];
    if (MODE == 1)
#pragma unroll
        for (int nt = 0; nt < 4; nt++) { ps[nt][0] = 0.f; ps[nt][1] = 0.f; }
#pragma unroll
    for (int m = 0; m < 4; m++) {
#pragma unroll
        for (int nt = 0; nt < 4; nt++) {
            int co = warpn * 32 + nt * 8 + t2;
            float sc0 = s_sc[co], sh0 = s_sh[co];
            float sc1 = s_sc[co + 1], sh1 = s_sh[co + 1];
#pragma unroll
            for (int half = 0; half < 2; half++) {
                int p = pbase + warpm * 64 + m * 16 + g4 + half * 8;
                float v0 = C[m][nt][half * 2 + 0] * sc0 + sh0;
                float v1 = C[m][nt][half * 2 + 1] * sc1 + sh1;
                int h = p / 34, w = p % 34;
                bool valid = (w < 32) && (h < 32);
                v0 = valid ? fmaxf(v0, 0.f) : 0.f;
                v1 = valid ? fmaxf(v1, 0.f) : 0.f;
                uint32_t pk = pack_h2(__float2half_rn(v0), __float2half_rn(v1));
                if (MODE == 0) {
                    size_t q2 = ((size_t)n * POSN + p + 35) * HIDC + co;
                    *(uint32_t*)(Oh + q2) = pk;
                } else {
                    ps[nt][0] += v0;
                    ps[nt][1] += v1;
                    if (valid) {
                        size_t q2 = ((size_t)n * HWSZ + h * WW + w) * HIDC + co;
                        *(uint32_t*)(Oh + q2) = pk;
                    }
                }
            }
        }
    }
    if (MODE == 1) {
#pragma unroll
        for (int nt = 0; nt < 4; nt++)
#pragma unroll
            for (int q = 0; q < 2; q++) {
                float v = ps[nt][q];
                v += __shfl_xor_sync(0xffffffffu, v, 4);
                v += __shfl_xor_sync(0xffffffffu, v, 8);
                v += __shfl_xor_sync(0xffffffffu, v, 16);
                ps[nt][q] = v;
            }
        if (lane < 4) {
            size_t base = (((size_t)n * MTILES + mt) * 8 + warp) * 32;
#pragma unroll
            for (int nt = 0; nt < 4; nt++) {
                Part[base + nt * 8 + lane * 2 + 0] = ps[nt][0];
                Part[base + nt * 8 + lane * 2 + 1] = ps[nt][1];
            }
        }
    }
}

// ===== GAT stage helpers (512 threads: thread = (head j, col tj)) =====
__device__ __forceinline__ void gat_h_stage512(
    int n, int t, const float* xr, float* red,
    const float* __restrict__ lin,
    const float* __restrict__ asw, const float* __restrict__ adw,
    float* __restrict__ hfeat, float* __restrict__ asv, float* __restrict__ adv) {
    int tj = t & 127, j = t >> 7;
    int lane = t & 31, wid = t >> 5;
    int col = j * HIDC + tj;
    float s = 0.f;
#pragma unroll 4
    for (int k = 0; k < HIDC; k++) s += xr[k] * lin[k * (HEADS * HIDC) + col];
    hfeat[n * (HEADS * HIDC) + col] = s;
    float pa = warp_sum(s * asw[col]);
    float pd = warp_sum(s * adw[col]);
    if (lane == 0) { red[wid] = pa; red[16 + wid] = pd; }
    __syncthreads();
    if (tj == 0) {   // t = j*128, one thread per head
        asv[n * HEADS + j] = red[4 * j] + red[4 * j + 1] + red[4 * j + 2] + red[4 * j + 3];
        adv[n * HEADS + j] = red[16 + 4 * j] + red[17 + 4 * j] + red[18 + 4 * j] + red[19 + 4 * j];
    }
    __syncthreads();
}

// returns head-mean output (valid for t < 128); uses xs[4*HIDC] scratch
__device__ __forceinline__ float gat_aggr_stage512(
    int n, int t,
    const float* __restrict__ hfeat, const float* __restrict__ asv,
    const float* __restrict__ adv, const float* __restrict__ bias,
    float* xs) {
    int tj = t & 127, j = t >> 7;
    float adn = adv[n * HEADS + j];
    int rs = g_row[n], re = g_row[n + 1];
    float m = -1e30f, den = 0.f, acc = 0.f;
    for (int ei = rs; ei < re; ei++) {
        int s = g_csr[ei];
        float e = asv[s * HEADS + j] + adn;
        e = (e > 0.f) ? e : 0.2f * e;
        float hval = hfeat[s * (HEADS * HIDC) + j * HIDC + tj];
        if (e > m) {                 // uniform within the 4-warp head group
            float sc = __expf(m - e);
            den = den * sc + 1.f;
            acc = acc * sc + hval;
            m = e;
        } else {
            float ex = __expf(e - m);
            den += ex;
            acc += ex * hval;
        }
    }
    xs[j * HIDC + tj] = acc / (den + 1e-16f);
    __syncthreads();
    float o = 0.f;
    if (t < HIDC)
        o = fmaxf((xs[t] + xs[HIDC + t] + xs[2 * HIDC + t] + xs[3 * HIDC + t]) * 0.25f
                  + bias[t], 0.f);
    return o;
}

// ===== replay-safe ticket grid barrier (grid == single wave) =====
__device__ __forceinline__ void grid_bar(int i, int t) {
    __threadfence();
    __syncthreads();
    if (t == 0) {
        unsigned old = atomicAdd((unsigned*)&g_barc[i], 1u);
        unsigned tgt = (old / (unsigned)NN + 1u) * (unsigned)NN;
        while (g_barc[i] < tgt) { __nanosleep(64); }
        __threadfence();
    }
    __syncthreads();
}

// ================= persistent fused GAT, 512 threads =====================
__global__ __launch_bounds__(512) void gat_fused_kernel(
    const float* __restrict__ g1_lin, const float* __restrict__ g1_as,
    const float* __restrict__ g1_ad, const float* __restrict__ g1_b,
    const float* __restrict__ g2_lin, const float* __restrict__ g2_as,
    const float* __restrict__ g2_ad, const float* __restrict__ g2_b,
    const float* __restrict__ opw, const float* __restrict__ opb) {
    __shared__ float xr[HIDC];
    __shared__ float xs[4 * HIDC];
    __shared__ float red[32];
    int n = blockIdx.x, t = threadIdx.x;
    int tj = t & 127, j = t >> 7;

    // phase 1: pool reduce (4 groups split the 9 m-tiles) -> h1
    {
        int wn = tj >> 5, col = tj & 31;
        float s = 0.f;
        for (int mt = j; mt < MTILES; mt += 4) {
            size_t b = (((size_t)n * MTILES + mt) * 8);
            s += g_part[(b + wn) * 32 + col];
            s += g_part[(b + 4 + wn) * 32 + col];
        }
        xs[j * HIDC + tj] = s;
    }
    __syncthreads();
    if (t < HIDC)
        xr[t] = (xs[t] + xs[HIDC + t] + xs[2 * HIDC + t] + xs[3 * HIDC + t]) * (1.f / 1024.f);
    __syncthreads();
    gat_h_stage512(n, t, xr, red, g1_lin, g1_as, g1_ad, g_hfeat, g_as, g_ad);

    grid_bar(0, t);

    // phase 2: aggr1 -> h2
    float o1 = gat_aggr_stage512(n, t, g_hfeat, g_as, g_ad, g1_b, xs);
    __syncthreads();
    if (t < HIDC) xr[t] = o1;
    __syncthreads();
    gat_h_stage512(n, t, xr, red, g2_lin, g2_as, g2_ad, g_hfeat2, g_as2, g_ad2);

    grid_bar(1, t);

    // phase 3: aggr2 + gterm
    float o2 = gat_aggr_stage512(n, t, g_hfeat2, g_as2, g_ad2, g2_b, xs);
    __syncthreads();
    if (t < HIDC) xr[t] = o2;
    __syncthreads();
    if (t < CINC) {
        float s = opb[t];
        for (int k = 0; k < HIDC; k++) s += xr[k] * opw[t * HIDC + k];
        g_gterm[n * CINC + t] = s;
    }
}

// ================= op (unchanged) =================
__global__ __launch_bounds__(256) void op_mma_kernel(
    const __half* __restrict__ Xh,
    float* __restrict__ out) {
    extern __shared__ __align__(16) char dsm[];
    int tid = threadIdx.x, lane = tid & 31, warp = tid >> 5;
    int warpm = warp >> 1, warpn = warp & 1;
    int n = blockIdx.x, hw0 = blockIdx.y * 128;
    uint32_t sbase = smem_u32(dsm);

#pragma unroll
    for (int i = 0; i < 8; i++) {
        int idx = i * 256 + tid;
        int r = idx >> 4, sg = idx & 15;
        const __half* g = Xh + ((size_t)n * HWSZ + hw0 + r) * HIDC + sg * 8;
        cpasync16(sbase + r * OP_RS + sg * 16, g);
    }
#pragma unroll
    for (int i = 0; i < 4; i++) {
        int idx = i * 256 + tid;
        int r = idx >> 4, sg = idx & 15;
        cpasync16(sbase + OPW_0 + r * OP_RS + sg * 16, g_woph + r * HIDC + sg * 8);
    }
    CP_COMMIT();

    float C[8][4];
#pragma unroll
    for (int nt = 0; nt < 8; nt++)
#pragma unroll
        for (int r = 0; r < 4; r++) C[nt][r] = 0.f;

    int a_row = lane & 15, a_ko = (lane >> 4) * 16;
    int b_row = (lane & 7) + ((lane >> 4) & 1) * 8;
    int b_ko = ((lane >> 3) & 1) * 16;

    CP_WAIT(0);
    __syncthreads();

#pragma unroll 1
    for (int kc = 0; kc < 8; kc++) {
        uint32_t awh[4];
        uint32_t ra = (uint32_t)(warpm * 16 + a_row) * OP_RS + kc * 32 + a_ko;
        ldmx4(awh, sbase + OPW_0 + ra);
#pragma unroll
        for (int ntp = 0; ntp < 4; ntp++) {
            uint32_t xbh[4];
            uint32_t rb = (uint32_t)(warpn * 64 + ntp * 16 + b_row) * OP_RS + kc * 32 + b_ko;
            ldmx4(xbh, sbase + rb);
#pragma unroll
            for (int q = 0; q < 2; q++)
                mma16816(C[ntp * 2 + q], awh, xbh[2 * q], xbh[2 * q + 1]);
        }
    }

    int g4 = lane >> 2, t2 = (lane & 3) * 2;
    int co_a = warpm * 16 + g4;
    int co_b = co_a + 8;
    float gta = g_gterm[n * CINC + co_a];
    float gtb = g_gterm[n * CINC + co_b];
#pragma unroll
    for (int nt = 0; nt < 8; nt++) {
        int hw = hw0 + warpn * 64 + nt * 8 + t2;
        float2 va = make_float2(C[nt][0] + gta, C[nt][1] + gta);
        float2 vb = make_float2(C[nt][2] + gtb, C[nt][3] + gtb);
        *(float2*)&out[((size_t)n * CINC + co_a) * HWSZ + hw] = va;
        *(float2*)&out[((size_t)n * CINC + co_b) * HWSZ + hw] = vb;
    }
}

// ================= launch =================
extern "C" void kernel_launch(void* const* d_in, const int* in_sizes, int n_in,
                              void* d_out, int out_size) {
    const float* x    = (const float*)d_in[0];
    const int*   ei   = (const int*)d_in[1];
    const float* conf = (const float*)d_in[2];
    const float* fe_w = (const float*)d_in[3];
    const float* fe_b = (const float*)d_in[4];
    const float* fe_g = (const float*)d_in[5];
    const float* fe_be= (const float*)d_in[6];
    const float* sp_w1= (const float*)d_in[7];
    const float* sp_b1= (const float*)d_in[8];
    const float* sp_g1= (const float*)d_in[9];
    const float* sp_e1= (const float*)d_in[10];
    const float* sp_w2= (const float*)d_in[11];
    const float* sp_b2= (const float*)d_in[12];
    const float* sp_g2= (const float*)d_in[13];
    const float* sp_e2= (const float*)d_in[14];
    const float* g1_lin=(const float*)d_in[15];
    const float* g1_as= (const float*)d_in[16];
    const float* g1_ad= (const float*)d_in[17];
    const float* g1_b = (const float*)d_in[18];
    const float* g2_lin=(const float*)d_in[19];
    const float* g2_as= (const float*)d_in[20];
    const float* g2_ad= (const float*)d_in[21];
    const float* g2_b = (const float*)d_in[22];
    const float* op_w = (const float*)d_in[23];
    const float* op_b = (const float*)d_in[24];
    float* out = (float*)d_out;

    void *p1h, *p2h, *pph, *pw1h, *pw2h, *pPart;
    cudaGetSymbolAddress(&p1h, g_x1h);
    cudaGetSymbolAddress(&p2h, g_x2h);
    cudaGetSymbolAddress(&pph, g_xph);
    cudaGetSymbolAddress(&pw1h, g_w1h);
    cudaGetSymbolAddress(&pw2h, g_w2h);
    cudaGetSymbolAddress(&pPart, g_part);
    __half* x1h = (__half*)p1h;
    __half* x2h = (__half*)p2h;
    __half* xph = (__half*)pph;
    __half* w1h = (__half*)pw1h;
    __half* w2h = (__half*)pw2h;
    float* part = (float*)pPart;

    cudaFuncSetAttribute(conv_mma_kernel<0>, cudaFuncAttributeMaxDynamicSharedMemorySize, CONV_SMEM);
    cudaFuncSetAttribute(conv_mma_kernel<1>, cudaFuncAttributeMaxDynamicSharedMemorySize, CONV_SMEM);
    cudaFuncSetAttribute(fe_mma_kernel, cudaFuncAttributeMaxDynamicSharedMemorySize, FE_SMEM);
    cudaFuncSetAttribute(op_mma_kernel, cudaFuncAttributeMaxDynamicSharedMemorySize, OP_SMEM);

    fe_mma_kernel<<<dim3(NN, 8), 256, FE_SMEM>>>(                             // 0
        x, fe_w, fe_b, fe_g, fe_be, conf, x1h, ei, sp_w1, sp_w2, op_w);
    conv_mma_kernel<0><<<NN * MTILES, 256, CONV_SMEM>>>(                      // 1
        x1h, w1h, sp_b1, sp_g1, sp_e1, x2h, nullptr);
    conv_mma_kernel<1><<<NN * MTILES, 256, CONV_SMEM>>>(                      // 2
        x2h, w2h, sp_b2, sp_g2, sp_e2, xph, part);
    gat_fused_kernel<<<NN, 512>>>(g1_lin, g1_as, g1_ad, g1_b,                 // 3
                                  g2_lin, g2_as, g2_ad, g2_b, op_w, op_b);
    op_mma_kernel<<<dim3(NN, 8), 256, OP_SMEM>>>(xph, out);                   // 4

    (void)in_sizes; (void)n_in; (void)out_size;
}

// round 17
// speedup vs baseline: 10.0324x; 1.0011x over previous
#include <cuda_runtime.h>
#include <cuda_fp16.h>
#include <math.h>
#include <stdint.h>

#define NN   512
#define CINC 64
#define HIDC 128
#define HWSZ 1024
#define HH   32
#define WW   32
#define HEADS 4
#define NE   16384
#define TOTE (NE + NN)
#define POSN 1224
#define MTILES 9
#define WN   (HIDC * HIDC * 9)
#define WTOT (2 * WN + CINC * HIDC)
#define GATB 128          // GAT blocks (4 nodes each)

#define A_SLAB  16000
#define B_BASE  64000
#define B_PAIR  9216
#define CONV_SMEM (64000 + 4 * B_PAIR)

#define FE_RS   144
#define FE_XH   0
#define FE_W    18432
#define FE_SMEM 36864

#define OP_RS   272
#define OPW_0   34816
#define OP_SMEM (34816 + 17408)

// ================= helpers =================
__device__ __forceinline__ uint32_t smem_u32(const void* p) {
    return (uint32_t)__cvta_generic_to_shared(p);
}
__device__ __forceinline__ void ldmx4(uint32_t* r, uint32_t a) {
    asm volatile("ldmatrix.sync.aligned.m8n8.x4.shared.b16 {%0,%1,%2,%3}, [%4];"
                 : "=r"(r[0]), "=r"(r[1]), "=r"(r[2]), "=r"(r[3]) : "r"(a));
}
__device__ __forceinline__ void mma16816(float* c, const uint32_t* a,
                                         uint32_t b0, uint32_t b1) {
    asm volatile(
        "mma.sync.aligned.m16n8k16.row.col.f32.f16.f16.f32 "
        "{%0,%1,%2,%3}, {%4,%5,%6,%7}, {%8,%9}, {%0,%1,%2,%3};"
        : "+f"(c[0]), "+f"(c[1]), "+f"(c[2]), "+f"(c[3])
        : "r"(a[0]), "r"(a[1]), "r"(a[2]), "r"(a[3]), "r"(b0), "r"(b1));
}
__device__ __forceinline__ void cpasync16(uint32_t sa, const void* g) {
    unsigned long long ga = (unsigned long long)__cvta_generic_to_global(g);
    asm volatile("cp.async.cg.shared.global [%0], [%1], 16;" :: "r"(sa), "l"(ga));
}
#define CP_COMMIT() asm volatile("cp.async.commit_group;")
#define CP_WAIT(N)  asm volatile("cp.async.wait_group %0;" :: "n"(N))
#define BAR_PAIR(id) asm volatile("bar.sync %0, 64;" :: "r"(id) : "memory")

__device__ __forceinline__ uint32_t pack_h2(__half a, __half b) {
    return (uint32_t)__half_as_ushort(a) | ((uint32_t)__half_as_ushort(b) << 16);
}
__device__ __forceinline__ float warp_sum(float v) {
#pragma unroll
    for (int off = 16; off > 0; off >>= 1)
        v += __shfl_xor_sync(0xffffffffu, v, off);
    return v;
}

// ================= device scratch =================
__device__ __half g_x1h[(size_t)NN * POSN * HIDC]; // border stays zero
__device__ __half g_x2h[(size_t)NN * POSN * HIDC];
__device__ __half g_xph[(size_t)NN * HWSZ * HIDC];
__device__ __half g_w1h[9 * HIDC * HIDC];
__device__ __half g_w2h[9 * HIDC * HIDC];
__device__ __half g_woph[CINC * HIDC];
__device__ float g_part[(size_t)NN * MTILES * 8 * 32];
__device__ float g_hfeat[NN * HEADS * HIDC];
__device__ float g_as[NN * HEADS];
__device__ float g_ad[NN * HEADS];
__device__ float g_hfeat2[NN * HEADS * HIDC];
__device__ float g_as2[NN * HEADS];
__device__ float g_ad2[NN * HEADS];
__device__ float g_gterm[NN * CINC];
__device__ int   g_row[NN + 1];
__device__ int   g_csr[TOTE];
__device__ volatile unsigned g_barc[2];   // monotonic ticket counters

__device__ __forceinline__ void read_edge(const int* __restrict__ ei, int i,
                                          int is64, int& s, int& d) {
    if (i < NE) {
        if (is64) { s = ei[2 * i]; d = ei[2 * (NE + i)]; }
        else      { s = ei[i];     d = ei[NE + i]; }
    } else { s = i - NE; d = i - NE; }
}

// ================= fe: 1x1 conv MMA + distributed wprep + CSR (block 0,0) =
__global__ __launch_bounds__(256) void fe_mma_kernel(
    const float* __restrict__ x, const float* __restrict__ fw,
    const float* __restrict__ fb, const float* __restrict__ fg,
    const float* __restrict__ fbe, const float* __restrict__ conf,
    __half* __restrict__ xh,
    const int* __restrict__ ei,
    const float* __restrict__ w1, const float* __restrict__ w2,
    const float* __restrict__ wop) {
    extern __shared__ __align__(16) char dsm[];
    __shared__ float s_conf[128];
    __shared__ float s_sc[HIDC], s_sh[HIDC];
    __shared__ int scnt[NN];
    __shared__ int sfill[NN];
    __shared__ int stmp[256];
    __shared__ int s_is64;

    int tid = threadIdx.x, lane = tid & 31, warp = tid >> 5;
    int warpm = warp >> 2, warpn = warp & 3;
    int n = blockIdx.x, px0 = blockIdx.y * 128;
    uint32_t sbase = smem_u32(dsm);

    {
        int gidx = (blockIdx.y * NN + blockIdx.x) * 256 + tid;
        if (gidx < 2 * WN) {
            int j = (gidx < WN) ? gidx : gidx - WN;
            int tap = j % 9;
            int ci = (j / 9) % HIDC;
            int co = j / (9 * HIDC);
            if (gidx < WN)
                g_w1h[(tap * HIDC + co) * HIDC + ci] = __float2half_rn(w1[j]);
            else
                g_w2h[(tap * HIDC + co) * HIDC + ci] = __float2half_rn(w2[j]);
        } else if (gidx < WTOT) {
            int j = gidx - 2 * WN;
            g_woph[j] = __float2half_rn(wop[j]);
        }
    }

    if (blockIdx.x == 0 && blockIdx.y == 0) {
        if (tid == 0) {
            int acc = 0;
            for (int i = 0; i < 128; i++) acc |= ei[2 * i + 1];
            s_is64 = (acc == 0) ? 1 : 0;
        }
        scnt[tid] = 0;
        scnt[tid + 256] = 0;
        __syncthreads();
        int is64 = s_is64;
        for (int i = tid; i < TOTE; i += 256) {
            int s, d; read_edge(ei, i, is64, s, d);
            atomicAdd(&scnt[d], 1);
        }
        __syncthreads();
        int s0 = scnt[2 * tid], s1 = scnt[2 * tid + 1];
        stmp[tid] = s0 + s1;
        __syncthreads();
        for (int off = 1; off < 256; off <<= 1) {
            int v = (tid >= off) ? stmp[tid - off] : 0;
            __syncthreads();
            stmp[tid] += v;
            __syncthreads();
        }
        int Pprev = tid ? stmp[tid - 1] : 0;
        g_row[2 * tid + 1] = Pprev + s0;
        g_row[2 * tid + 2] = Pprev + s0 + s1;
        if (tid == 0) g_row[0] = 0;
        sfill[2 * tid] = Pprev;
        sfill[2 * tid + 1] = Pprev + s0;
        __syncthreads();
        for (int i = tid; i < TOTE; i += 256) {
            int s, d; read_edge(ei, i, is64, s, d);
            int pos = atomicAdd(&sfill[d], 1);
            g_csr[pos] = s;
        }
    }

    if (tid < 128) {
        s_conf[tid] = conf[n * HWSZ + px0 + tid];
        const float inv = rsqrtf(1.0f + 1e-5f);
        float sc = fg[tid] * inv;
        s_sc[tid] = sc;
        s_sh[tid] = fbe[tid] + fb[tid] * sc;
    }

#pragma unroll
    for (int i = 0; i < 16; i++) {
        int idx = i * 256 + tid;
        int cp = idx & 31, co = idx >> 5;
        float2 v = *(const float2*)(fw + co * CINC + cp * 2);
        *(uint32_t*)(dsm + FE_W + co * FE_RS + cp * 4) =
            pack_h2(__float2half_rn(v.x), __float2half_rn(v.y));
    }
#pragma unroll
    for (int i = 0; i < 16; i++) {
        int idx = i * 256 + tid;
        int p = idx & 127, cp = idx >> 7;
        float a = x[((size_t)n * CINC + 2 * cp) * HWSZ + px0 + p];
        float b = x[((size_t)n * CINC + 2 * cp + 1) * HWSZ + px0 + p];
        *(uint32_t*)(dsm + FE_XH + p * FE_RS + cp * 4) =
            pack_h2(__float2half_rn(a), __float2half_rn(b));
    }
    __syncthreads();

    float C[4][4][4];
#pragma unroll
    for (int m = 0; m < 4; m++)
#pragma unroll
        for (int nt = 0; nt < 4; nt++)
#pragma unroll
            for (int r = 0; r < 4; r++) C[m][nt][r] = 0.f;

    int a_row = lane & 15, a_ko = (lane >> 4) * 16;
    int b_row = (lane & 7) + ((lane >> 4) & 1) * 8;
    int b_ko = ((lane >> 3) & 1) * 16;

#pragma unroll
    for (int kq = 0; kq < 4; kq++) {
        uint32_t ah[4][4];
#pragma unroll
        for (int m = 0; m < 4; m++) {
            uint32_t ra = (uint32_t)(warpm * 64 + m * 16 + a_row) * FE_RS + kq * 32 + a_ko;
            ldmx4(ah[m], sbase + FE_XH + ra);
        }
#pragma unroll
        for (int ntp = 0; ntp < 2; ntp++) {
            uint32_t bw[4];
            uint32_t rb = (uint32_t)(warpn * 32 + ntp * 16 + b_row) * FE_RS + kq * 32 + b_ko;
            ldmx4(bw, sbase + FE_W + rb);
#pragma unroll
            for (int q = 0; q < 2; q++) {
                int nt = ntp * 2 + q;
#pragma unroll
                for (int m = 0; m < 4; m++)
                    mma16816(C[m][nt], ah[m], bw[2 * q], bw[2 * q + 1]);
            }
        }
    }

    int g4 = lane >> 2, t2 = (lane & 3) * 2;
#pragma unroll
    for (int m = 0; m < 4; m++) {
#pragma unroll
        for (int nt = 0; nt < 4; nt++) {
            int co = warpn * 32 + nt * 8 + t2;
            float sc0 = s_sc[co], sh0 = s_sh[co];
            float sc1 = s_sc[co + 1], sh1 = s_sh[co + 1];
#pragma unroll
            for (int half = 0; half < 2; half++) {
                int pl = warpm * 64 + m * 16 + g4 + half * 8;
                float cf = s_conf[pl];
                float v0 = fmaxf(C[m][nt][half * 2 + 0] * sc0 + sh0, 0.f) * cf;
                float v1 = fmaxf(C[m][nt][half * 2 + 1] * sc1 + sh1, 0.f) * cf;
                int hw = px0 + pl;
                int h = hw >> 5, w = hw & 31;
                size_t q2 = ((size_t)n * POSN + (h + 1) * 34 + (w + 1)) * HIDC + co;
                *(uint32_t*)(xh + q2) =
                    pack_h2(__float2half_rn(v0), __float2half_rn(v1));
            }
        }
    }
}

// ================= mma.sync conv (unchanged) =================
template <int MODE>
__global__ __launch_bounds__(256, 2) void conv_mma_kernel(
    const __half* __restrict__ Xh,
    const __half* __restrict__ Wh,
    const float* __restrict__ bb, const float* __restrict__ gg,
    const float* __restrict__ be,
    __half* __restrict__ Oh, float* __restrict__ Part) {
    extern __shared__ __align__(16) char dsm[];
    __shared__ float s_sc[HIDC], s_sh[HIDC];

    int tid = threadIdx.x, lane = tid & 31, warp = tid >> 5;
    int warpm = warp >> 2, warpn = warp & 3;
    int n = blockIdx.x / MTILES, mt = blockIdx.x % MTILES;
    int pbase = mt * 128;

    if (tid < HIDC) {
        const float inv = rsqrtf(1.0f + 1e-5f);
        float sc = gg[tid] * inv;
        s_sc[tid] = sc;
        s_sh[tid] = be[tid] + bb[tid] * sc;
    }

    float C[4][4][4];
#pragma unroll
    for (int m = 0; m < 4; m++)
#pragma unroll
        for (int nt = 0; nt < 4; nt++)
#pragma unroll
            for (int r = 0; r < 4; r++) C[m][nt][r] = 0.f;

    uint32_t sbase = smem_u32(dsm);
    uint32_t sB0 = sbase + B_BASE + warpn * B_PAIR;
    bool loader = (warpm == 0);

    auto loadB = [&](int s1, uint32_t buf) {
        int pairci = s1 / 9, tap = s1 - pairci * 9;
        uint32_t s0 = sB0 + buf * 4608;
        size_t gb = ((size_t)(tap * HIDC + warpn * 32)) * HIDC + pairci * 64;
#pragma unroll
        for (int i = 0; i < 8; i++) {
            int seg = i * 32 + lane;
            int r = seg >> 3, sg = seg & 7;
            cpasync16(s0 + r * 144 + sg * 16, Wh + gb + (size_t)r * HIDC + sg * 8);
        }
    };

    {
        size_t gbase = ((size_t)(n * POSN + pbase)) * HIDC;
#pragma unroll
        for (int cic = 0; cic < 4; cic++) {
            uint32_t s0 = sbase + cic * A_SLAB;
            size_t gb = gbase + cic * 32;
#pragma unroll
            for (int i = 0; i < 4; i++) {
                int idx = i * 256 + tid;
                if (idx < 792) {
                    int r = idx >> 2, sg = idx & 3;
                    cpasync16(s0 + r * 80 + sg * 16, Xh + gb + (size_t)r * HIDC + sg * 8);
                }
            }
        }
        if (loader) loadB(0, 0);
        CP_COMMIT();
        CP_WAIT(0);
        __syncthreads();
    }

    int a_row = lane & 15, a_ko = (lane >> 4) * 16;
    int b_row = (lane & 7) + ((lane >> 4) & 1) * 8;
    int b_ko = ((lane >> 3) & 1) * 16;
    int barid = 1 + warpn;

    auto do_stage = [&](int s, uint32_t buf) {
        int pair = s / 9, tap = s - pair * 9;
        CP_WAIT(0);
        BAR_PAIR(barid);
        if (loader && s + 1 < 18) {
            loadB(s + 1, buf ^ 1u);
            CP_COMMIT();
        }
        int tapoff = (tap / 3) * 34 + (tap - (tap / 3) * 3);
        uint32_t sB = sB0 + buf * 4608;
#pragma unroll
        for (int c2 = 0; c2 < 2; c2++) {
            uint32_t sA = sbase + (pair * 2 + c2) * A_SLAB;
            uint32_t bhalf = c2 * 64;
#pragma unroll
            for (int ks = 0; ks < 2; ks++) {
                uint32_t ah[4][4];
#pragma unroll
                for (int m = 0; m < 4; m++) {
                    uint32_t ra = (uint32_t)(tapoff + warpm * 64 + m * 16 + a_row) * 80 + ks * 32 + a_ko;
                    ldmx4(ah[m], sA + ra);
                }
#pragma unroll
                for (int ntp = 0; ntp < 2; ntp++) {
                    uint32_t rbh[4];
                    uint32_t rb = (uint32_t)(ntp * 16 + b_row) * 144 + bhalf + ks * 32 + b_ko;
                    ldmx4(rbh, sB + rb);
#pragma unroll
                    for (int q = 0; q < 2; q++) {
                        int nt = ntp * 2 + q;
#pragma unroll
                        for (int m = 0; m < 4; m++)
                            mma16816(C[m][nt], ah[m], rbh[2 * q], rbh[2 * q + 1]);
                    }
                }
            }
        }
    };

#pragma unroll 1
    for (int sp = 0; sp < 9; sp++) {
        do_stage(sp * 2, 0u);
        do_stage(sp * 2 + 1, 1u);
    }

    int g4 = lane >> 2;
    int t2 = (lane & 3) * 2;
    float ps[4][2];
    if (MODE == 1)
#pragma unroll
        for (int nt = 0; nt < 4; nt++) { ps[nt][0] = 0.f; ps[nt][1] = 0.f; }
#pragma unroll
    for (int m = 0; m < 4; m++) {
#pragma unroll
        for (int nt = 0; nt < 4; nt++) {
            int co = warpn * 32 + nt * 8 + t2;
            float sc0 = s_sc[co], sh0 = s_sh[co];
            float sc1 = s_sc[co + 1], sh1 = s_sh[co + 1];
#pragma unroll
            for (int half = 0; half < 2; half++) {
                int p = pbase + warpm * 64 + m * 16 + g4 + half * 8;
                float v0 = C[m][nt][half * 2 + 0] * sc0 + sh0;
                float v1 = C[m][nt][half * 2 + 1] * sc1 + sh1;
                int h = p / 34, w = p % 34;
                bool valid = (w < 32) && (h < 32);
                v0 = valid ? fmaxf(v0, 0.f) : 0.f;
                v1 = valid ? fmaxf(v1, 0.f) : 0.f;
                uint32_t pk = pack_h2(__float2half_rn(v0), __float2half_rn(v1));
                if (MODE == 0) {
                    size_t q2 = ((size_t)n * POSN + p + 35) * HIDC + co;
                    *(uint32_t*)(Oh + q2) = pk;
                } else {
                    ps[nt][0] += v0;
                    ps[nt][1] += v1;
                    if (valid) {
                        size_t q2 = ((size_t)n * HWSZ + h * WW + w) * HIDC + co;
                        *(uint32_t*)(Oh + q2) = pk;
                    }
                }
            }
        }
    }
    if (MODE == 1) {
#pragma unroll
        for (int nt = 0; nt < 4; nt++)
#pragma unroll
            for (int q = 0; q < 2; q++) {
                float v = ps[nt][q];
                v += __shfl_xor_sync(0xffffffffu, v, 4);
                v += __shfl_xor_sync(0xffffffffu, v, 8);
                v += __shfl_xor_sync(0xffffffffu, v, 16);
                ps[nt][q] = v;
            }
        if (lane < 4) {
            size_t base = (((size_t)n * MTILES + mt) * 8 + warp) * 32;
#pragma unroll
            for (int nt = 0; nt < 4; nt++) {
                Part[base + nt * 8 + lane * 2 + 0] = ps[nt][0];
                Part[base + nt * 8 + lane * 2 + 1] = ps[nt][1];
            }
        }
    }
}

// ===== GAT stages: 128 blocks x 512 threads, 4 nodes per block =====
// h-stage: thread (j, tj) computes col j*128+tj for ALL 4 nodes (weights
// loaded once, 4 accumulators).
__device__ __forceinline__ void gat_h_stage4(
    int n0, int t, const float xr[4][HIDC], float (*red)[4][2],
    const float* __restrict__ lin,
    const float* __restrict__ asw, const float* __restrict__ adw,
    float* __restrict__ hfeat, float* __restrict__ asv, float* __restrict__ adv) {
    int tj = t & 127, j = t >> 7;
    int lane = t & 31, w = t >> 5;
    int col = j * HIDC + tj;
    float s0 = 0.f, s1 = 0.f, s2 = 0.f, s3 = 0.f;
#pragma unroll 4
    for (int k = 0; k < HIDC; k++) {
        float lv = lin[k * (HEADS * HIDC) + col];
        s0 += xr[0][k] * lv;
        s1 += xr[1][k] * lv;
        s2 += xr[2][k] * lv;
        s3 += xr[3][k] * lv;
    }
    hfeat[(size_t)(n0 + 0) * (HEADS * HIDC) + col] = s0;
    hfeat[(size_t)(n0 + 1) * (HEADS * HIDC) + col] = s1;
    hfeat[(size_t)(n0 + 2) * (HEADS * HIDC) + col] = s2;
    hfeat[(size_t)(n0 + 3) * (HEADS * HIDC) + col] = s3;
    float aw = asw[col], dw = adw[col];
    float sv[4] = {s0, s1, s2, s3};
#pragma unroll
    for (int nl = 0; nl < 4; nl++) {
        float pa = warp_sum(sv[nl] * aw);
        float pd = warp_sum(sv[nl] * dw);
        if (lane == 0) { red[w][nl][0] = pa; red[w][nl][1] = pd; }
    }
    __syncthreads();
    if (tj == 0) {   // one thread per head j
#pragma unroll
        for (int nl = 0; nl < 4; nl++) {
            asv[(n0 + nl) * HEADS + j] = red[4 * j][nl][0] + red[4 * j + 1][nl][0]
                                       + red[4 * j + 2][nl][0] + red[4 * j + 3][nl][0];
            adv[(n0 + nl) * HEADS + j] = red[4 * j][nl][1] + red[4 * j + 1][nl][1]
                                       + red[4 * j + 2][nl][1] + red[4 * j + 3][nl][1];
        }
    }
    __syncthreads();
}

// aggr-stage: thread (nl, j, tg) = node nl, head j, cols tg*4..+3 (float4
// gather). Online softmax; e>m branch uniform per warp (warp == (nl,j)).
// Result written to xr[nl][*] (post head-mean + bias + relu).
__device__ __forceinline__ void gat_aggr_stage4(
    int n0, int t,
    const float* __restrict__ hfeat, const float* __restrict__ asv,
    const float* __restrict__ adv, const float* __restrict__ bias,
    float (*xs)[4 * HIDC], float (*xr)[HIDC]) {
    int nl = t >> 7, j = (t >> 5) & 3, tg = t & 31;
    int n = n0 + nl;
    float adn = adv[n * HEADS + j];
    int rs = g_row[n], re = g_row[n + 1];
    float m = -1e30f, den = 0.f;
    float4 acc = make_float4(0.f, 0.f, 0.f, 0.f);
    for (int ei = rs; ei < re; ei++) {
        int s = g_csr[ei];
        float e = asv[s * HEADS + j] + adn;
        e = (e > 0.f) ? e : 0.2f * e;
        float4 hv = *(const float4*)&hfeat[(size_t)(s * HEADS + j) * HIDC + tg * 4];
        if (e > m) {
            float sc = __expf(m - e);
            den = den * sc + 1.f;
            acc.x = acc.x * sc + hv.x;
            acc.y = acc.y * sc + hv.y;
            acc.z = acc.z * sc + hv.z;
            acc.w = acc.w * sc + hv.w;
            m = e;
        } else {
            float ex = __expf(e - m);
            den += ex;
            acc.x += ex * hv.x;
            acc.y += ex * hv.y;
            acc.z += ex * hv.z;
            acc.w += ex * hv.w;
        }
    }
    float inv = 1.f / (den + 1e-16f);
    xs[nl][j * HIDC + tg * 4 + 0] = acc.x * inv;
    xs[nl][j * HIDC + tg * 4 + 1] = acc.y * inv;
    xs[nl][j * HIDC + tg * 4 + 2] = acc.z * inv;
    xs[nl][j * HIDC + tg * 4 + 3] = acc.w * inv;
    __syncthreads();
    int tj = t & 127, nl2 = t >> 7;
    float o = (xs[nl2][tj] + xs[nl2][HIDC + tj] + xs[nl2][2 * HIDC + tj]
               + xs[nl2][3 * HIDC + tj]) * 0.25f + bias[tj];
    float ov = fmaxf(o, 0.f);
    __syncthreads();
    xr[nl2][tj] = ov;
    __syncthreads();
}

// ===== replay-safe ticket grid barrier (grid == single wave) =====
__device__ __forceinline__ void grid_bar(int i, int t) {
    __threadfence();
    __syncthreads();
    if (t == 0) {
        unsigned old = atomicAdd((unsigned*)&g_barc[i], 1u);
        unsigned tgt = (old / (unsigned)GATB + 1u) * (unsigned)GATB;
        while (g_barc[i] < tgt) { __nanosleep(64); }
        __threadfence();
    }
    __syncthreads();
}

// ================= persistent fused GAT: 128 blocks x 512 thr, 4 nodes ===
__global__ __launch_bounds__(512) void gat_fused_kernel(
    const float* __restrict__ g1_lin, const float* __restrict__ g1_as,
    const float* __restrict__ g1_ad, const float* __restrict__ g1_b,
    const float* __restrict__ g2_lin, const float* __restrict__ g2_as,
    const float* __restrict__ g2_ad, const float* __restrict__ g2_b,
    const float* __restrict__ opw, const float* __restrict__ opb) {
    __shared__ float xr[4][HIDC];
    __shared__ float xs[4][4 * HIDC];
    __shared__ float red[16][4][2];
    int t = threadIdx.x;
    int n0 = blockIdx.x * 4;

    // phase 1: pool reduce (thread (nl, tj)) -> h1
    {
        int nl = t >> 7, tj = t & 127;
        int wn = tj >> 5, col = tj & 31;
        float s = 0.f;
#pragma unroll 1
        for (int mt = 0; mt < MTILES; mt++) {
            size_t b = (((size_t)(n0 + nl) * MTILES + mt) * 8);
            s += g_part[(b + wn) * 32 + col];
            s += g_part[(b + 4 + wn) * 32 + col];
        }
        xr[nl][tj] = s * (1.f / 1024.f);
    }
    __syncthreads();
    gat_h_stage4(n0, t, xr, red, g1_lin, g1_as, g1_ad, g_hfeat, g_as, g_ad);

    grid_bar(0, t);

    // phase 2: aggr1 -> h2
    gat_aggr_stage4(n0, t, g_hfeat, g_as, g_ad, g1_b, xs, xr);
    gat_h_stage4(n0, t, xr, red, g2_lin, g2_as, g2_ad, g_hfeat2, g_as2, g_ad2);

    grid_bar(1, t);

    // phase 3: aggr2 + gterm
    gat_aggr_stage4(n0, t, g_hfeat2, g_as2, g_ad2, g2_b, xs, xr);
    if (t < 4 * CINC) {
        int nl = t >> 6, c = t & 63;
        float s = opb[c];
        for (int k = 0; k < HIDC; k++) s += xr[nl][k] * opw[c * HIDC + k];
        g_gterm[(n0 + nl) * CINC + c] = s;
    }
}

// ================= op (unchanged) =================
__global__ __launch_bounds__(256) void op_mma_kernel(
    const __half* __restrict__ Xh,
    float* __restrict__ out) {
    extern __shared__ __align__(16) char dsm[];
    int tid = threadIdx.x, lane = tid & 31, warp = tid >> 5;
    int warpm = warp >> 1, warpn = warp & 1;
    int n = blockIdx.x, hw0 = blockIdx.y * 128;
    uint32_t sbase = smem_u32(dsm);

#pragma unroll
    for (int i = 0; i < 8; i++) {
        int idx = i * 256 + tid;
        int r = idx >> 4, sg = idx & 15;
        const __half* g = Xh + ((size_t)n * HWSZ + hw0 + r) * HIDC + sg * 8;
        cpasync16(sbase + r * OP_RS + sg * 16, g);
    }
#pragma unroll
    for (int i = 0; i < 4; i++) {
        int idx = i * 256 + tid;
        int r = idx >> 4, sg = idx & 15;
        cpasync16(sbase + OPW_0 + r * OP_RS + sg * 16, g_woph + r * HIDC + sg * 8);
    }
    CP_COMMIT();

    float C[8][4];
#pragma unroll
    for (int nt = 0; nt < 8; nt++)
#pragma unroll
        for (int r = 0; r < 4; r++) C[nt][r] = 0.f;

    int a_row = lane & 15, a_ko = (lane >> 4) * 16;
    int b_row = (lane & 7) + ((lane >> 4) & 1) * 8;
    int b_ko = ((lane >> 3) & 1) * 16;

    CP_WAIT(0);
    __syncthreads();

#pragma unroll 1
    for (int kc = 0; kc < 8; kc++) {
        uint32_t awh[4];
        uint32_t ra = (uint32_t)(warpm * 16 + a_row) * OP_RS + kc * 32 + a_ko;
        ldmx4(awh, sbase + OPW_0 + ra);
#pragma unroll
        for (int ntp = 0; ntp < 4; ntp++) {
            uint32_t xbh[4];
            uint32_t rb = (uint32_t)(warpn * 64 + ntp * 16 + b_row) * OP_RS + kc * 32 + b_ko;
            ldmx4(xbh, sbase + rb);
#pragma unroll
            for (int q = 0; q < 2; q++)
                mma16816(C[ntp * 2 + q], awh, xbh[2 * q], xbh[2 * q + 1]);
        }
    }

    int g4 = lane >> 2, t2 = (lane & 3) * 2;
    int co_a = warpm * 16 + g4;
    int co_b = co_a + 8;
    float gta = g_gterm[n * CINC + co_a];
    float gtb = g_gterm[n * CINC + co_b];
#pragma unroll
    for (int nt = 0; nt < 8; nt++) {
        int hw = hw0 + warpn * 64 + nt * 8 + t2;
        float2 va = make_float2(C[nt][0] + gta, C[nt][1] + gta);
        float2 vb = make_float2(C[nt][2] + gtb, C[nt][3] + gtb);
        *(float2*)&out[((size_t)n * CINC + co_a) * HWSZ + hw] = va;
        *(float2*)&out[((size_t)n * CINC + co_b) * HWSZ + hw] = vb;
    }
}

// ================= launch =================
extern "C" void kernel_launch(void* const* d_in, const int* in_sizes, int n_in,
                              void* d_out, int out_size) {
    const float* x    = (const float*)d_in[0];
    const int*   ei   = (const int*)d_in[1];
    const float* conf = (const float*)d_in[2];
    const float* fe_w = (const float*)d_in[3];
    const float* fe_b = (const float*)d_in[4];
    const float* fe_g = (const float*)d_in[5];
    const float* fe_be= (const float*)d_in[6];
    const float* sp_w1= (const float*)d_in[7];
    const float* sp_b1= (const float*)d_in[8];
    const float* sp_g1= (const float*)d_in[9];
    const float* sp_e1= (const float*)d_in[10];
    const float* sp_w2= (const float*)d_in[11];
    const float* sp_b2= (const float*)d_in[12];
    const float* sp_g2= (const float*)d_in[13];
    const float* sp_e2= (const float*)d_in[14];
    const float* g1_lin=(const float*)d_in[15];
    const float* g1_as= (const float*)d_in[16];
    const float* g1_ad= (const float*)d_in[17];
    const float* g1_b = (const float*)d_in[18];
    const float* g2_lin=(const float*)d_in[19];
    const float* g2_as= (const float*)d_in[20];
    const float* g2_ad= (const float*)d_in[21];
    const float* g2_b = (const float*)d_in[22];
    const float* op_w = (const float*)d_in[23];
    const float* op_b = (const float*)d_in[24];
    float* out = (float*)d_out;

    void *p1h, *p2h, *pph, *pw1h, *pw2h, *pPart;
    cudaGetSymbolAddress(&p1h, g_x1h);
    cudaGetSymbolAddress(&p2h, g_x2h);
    cudaGetSymbolAddress(&pph, g_xph);
    cudaGetSymbolAddress(&pw1h, g_w1h);
    cudaGetSymbolAddress(&pw2h, g_w2h);
    cudaGetSymbolAddress(&pPart, g_part);
    __half* x1h = (__half*)p1h;
    __half* x2h = (__half*)p2h;
    __half* xph = (__half*)pph;
    __half* w1h = (__half*)pw1h;
    __half* w2h = (__half*)pw2h;
    float* part = (float*)pPart;

    cudaFuncSetAttribute(conv_mma_kernel<0>, cudaFuncAttributeMaxDynamicSharedMemorySize, CONV_SMEM);
    cudaFuncSetAttribute(conv_mma_kernel<1>, cudaFuncAttributeMaxDynamicSharedMemorySize, CONV_SMEM);
    cudaFuncSetAttribute(fe_mma_kernel, cudaFuncAttributeMaxDynamicSharedMemorySize, FE_SMEM);
    cudaFuncSetAttribute(op_mma_kernel, cudaFuncAttributeMaxDynamicSharedMemorySize, OP_SMEM);

    fe_mma_kernel<<<dim3(NN, 8), 256, FE_SMEM>>>(                             // 0
        x, fe_w, fe_b, fe_g, fe_be, conf, x1h, ei, sp_w1, sp_w2, op_w);
    conv_mma_kernel<0><<<NN * MTILES, 256, CONV_SMEM>>>(                      // 1
        x1h, w1h, sp_b1, sp_g1, sp_e1, x2h, nullptr);
    conv_mma_kernel<1><<<NN * MTILES, 256, CONV_SMEM>>>(                      // 2
        x2h, w2h, sp_b2, sp_g2, sp_e2, xph, part);
    gat_fused_kernel<<<GATB, 512>>>(g1_lin, g1_as, g1_ad, g1_b,               // 3
                                    g2_lin, g2_as, g2_ad, g2_b, op_w, op_b);
    op_mma_kernel<<<dim3(NN, 8), 256, OP_SMEM>>>(xph, out);                   // 4

    (void)in_sizes; (void)n_in; (void)out_size;
}